// round 1
// baseline (speedup 1.0000x reference)
#include <cuda_runtime.h>
#include <cstdint>

// Problem dims (fixed by reference setup_inputs)
#define Bb 4
#define Nn 1024
#define Ee 8192
#define Hh 128
#define BN 4096    // B*N
#define BE 32768   // B*E

// ---------------- scratch arena (no allocation allowed) ----------------
// offsets in floats
#define OFF_TA        ((size_t)0)
#define OFF_TB        (OFF_TA + (size_t)BN*Hh)
#define OFF_NODE_ENC  (OFF_TB + (size_t)BN*Hh)
#define OFF_NODE_EFF  (OFF_NODE_ENC + (size_t)BN*Hh)
#define OFF_NODE_EFF2 (OFF_NODE_EFF + (size_t)BN*Hh)
#define OFF_XCAT      (OFF_NODE_EFF2 + (size_t)BN*Hh)       // BE*64
#define OFF_TE        (OFF_XCAT + (size_t)BE*64)            // BE*128
#define OFF_TE2       (OFF_TE + (size_t)BE*Hh)
#define OFF_EDGE_ENC  (OFF_TE2 + (size_t)BE*Hh)
#define OFF_EDGE_IN   (OFF_EDGE_ENC + (size_t)BE*Hh)        // BE*384
#define OFF_EDGE_EFF  (OFF_EDGE_IN + (size_t)BE*384)
#define OFF_AGG       (OFF_EDGE_EFF + (size_t)BE*Hh)        // BN*128
#define OFF_NODE_IN   (OFF_AGG + (size_t)BN*Hh)             // BN*256
#define OFF_PCAT      (OFF_NODE_IN + (size_t)BN*256)        // BN*256
#define OFF_PH1       (OFF_PCAT + (size_t)BN*256)
#define OFF_PH2       (OFF_PH1 + (size_t)BN*Hh)
#define ARENA_FLOATS  (OFF_PH2 + (size_t)BN*Hh)

__device__ float g_arena[ARENA_FLOATS];
__device__ int   g_recv[BE];
__device__ int   g_send[BE];

// ---------------- index extraction: argmax of one-hot row ----------------
// one warp per (b,e) row of 1024 floats
__global__ void extract_idx_kernel(const float* __restrict__ R, int* __restrict__ idx)
{
    int row = blockIdx.x * 8 + (threadIdx.x >> 5);
    if (row >= BE) return;
    int lane = threadIdx.x & 31;
    const float4* p = (const float4*)(R + (size_t)row * Nn);
    int found = 0;
    #pragma unroll
    for (int i = 0; i < 8; i++) {
        int q = lane + i * 32;           // 0..255
        float4 v = p[q];
        if (v.x > 0.5f) found = q * 4 + 0;
        if (v.y > 0.5f) found = q * 4 + 1;
        if (v.z > 0.5f) found = q * 4 + 2;
        if (v.w > 0.5f) found = q * 4 + 3;
    }
    #pragma unroll
    for (int o = 16; o; o >>= 1) found = max(found, __shfl_xor_sync(0xFFFFFFFFu, found, o));
    if (lane == 0) idx[row] = found;
}

// ---------------- gathers / concats ----------------
// xcat[e, 0:32] = x[b, recv[e]], xcat[e, 32:64] = x[b, send[e]]
__global__ void gather_xcat_kernel(const float* __restrict__ x,
                                   const int* __restrict__ recv,
                                   const int* __restrict__ send,
                                   float* __restrict__ out)
{
    int t = blockIdx.x * blockDim.x + threadIdx.x;   // BE*16 float4s
    if (t >= BE * 16) return;
    int e = t >> 4, q = t & 15;
    int b = e >> 13;
    const float4* src;
    if (q < 8) {
        int n = recv[e];
        src = (const float4*)(x + ((size_t)(b << 10) + n) * 32) + q;
    } else {
        int n = send[e];
        src = (const float4*)(x + ((size_t)(b << 10) + n) * 32) + (q - 8);
    }
    ((float4*)(out + (size_t)e * 64))[q] = *src;
}

// edge_in[e, 0:128]=edge_enc[e]; [128:256]=nf[recv]; [256:384]=nf[send]
__global__ void gather_edge_in_kernel(const float* __restrict__ ee,
                                      const float* __restrict__ nf,
                                      const int* __restrict__ recv,
                                      const int* __restrict__ send,
                                      float* __restrict__ out)
{
    int t = blockIdx.x * blockDim.x + threadIdx.x;   // BE*96 float4s
    if (t >= BE * 96) return;
    int e = t / 96, q = t - e * 96;
    int b = e >> 13;
    float4 v;
    if (q < 32) {
        v = ((const float4*)(ee + (size_t)e * Hh))[q];
    } else if (q < 64) {
        int n = recv[e];
        v = ((const float4*)(nf + ((size_t)(b << 10) + n) * Hh))[q - 32];
    } else {
        int n = send[e];
        v = ((const float4*)(nf + ((size_t)(b << 10) + n) * Hh))[q - 64];
    }
    ((float4*)(out + (size_t)e * 384))[q] = v;
}

// out[m, 0:128]=A[m]; out[m, 128:256]=C2[m]   (M rows)
__global__ void concat2_kernel(const float* __restrict__ A,
                               const float* __restrict__ C2,
                               float* __restrict__ out, int M)
{
    int t = blockIdx.x * blockDim.x + threadIdx.x;   // M*64 float4s
    if (t >= M * 64) return;
    int m = t >> 6, q = t & 63;
    float4 v = (q < 32) ? ((const float4*)(A + (size_t)m * Hh))[q]
                        : ((const float4*)(C2 + (size_t)m * Hh))[q - 32];
    ((float4*)(out + (size_t)m * 256))[q] = v;
}

// scatter-add edge_eff -> agg[b, recv[e], :]
__global__ void scatter_add_kernel(const float* __restrict__ ee,
                                   const int* __restrict__ recv,
                                   float* __restrict__ agg)
{
    int t = blockIdx.x * blockDim.x + threadIdx.x;   // BE*128
    if (t >= BE * Hh) return;
    int e = t >> 7, h = t & 127;
    int b = e >> 13;
    int n = recv[e];
    atomicAdd(&agg[((size_t)(b << 10) + n) * Hh + h], ee[t]);
}

// ---------------- fp32 SGEMM, Nout=128 fixed ----------------
// BM=128, 256 threads, 8x8 thread tile. M must be multiple of 128, K mult of 16.
__global__ __launch_bounds__(256) void gemm128_kernel(
    const float* __restrict__ A, int K,
    const float* __restrict__ W, const float* __restrict__ bias,
    const float* __restrict__ resid, float* __restrict__ C, int relu)
{
    __shared__ float As[16][132];
    __shared__ float Ws[16][128];
    const int m0 = blockIdx.x * 128;
    const int tid = threadIdx.x;
    const int rg = tid >> 4;       // 0..15 -> 8 rows each
    const int cg = tid & 15;       // 0..15 -> 8 cols each

    float acc[8][8];
    #pragma unroll
    for (int i = 0; i < 8; i++)
        #pragma unroll
        for (int j = 0; j < 8; j++) acc[i][j] = 0.f;

    for (int k0 = 0; k0 < K; k0 += 16) {
        #pragma unroll
        for (int i = 0; i < 2; i++) {
            int f = tid + i * 256;               // 0..511
            int m = f >> 2, kq = (f & 3) << 2;
            float4 v = *(const float4*)(A + (size_t)(m0 + m) * K + k0 + kq);
            As[kq + 0][m] = v.x; As[kq + 1][m] = v.y;
            As[kq + 2][m] = v.z; As[kq + 3][m] = v.w;
        }
        #pragma unroll
        for (int i = 0; i < 2; i++) {
            int f = tid + i * 256;
            int kk = f >> 5, nq = (f & 31) << 2;
            *(float4*)&Ws[kk][nq] = *(const float4*)(W + (size_t)(k0 + kk) * 128 + nq);
        }
        __syncthreads();
        #pragma unroll
        for (int kk = 0; kk < 16; kk++) {
            float a[8], w[8];
            *(float4*)(a)     = *(const float4*)&As[kk][rg * 8];
            *(float4*)(a + 4) = *(const float4*)&As[kk][rg * 8 + 4];
            *(float4*)(w)     = *(const float4*)&Ws[kk][cg * 8];
            *(float4*)(w + 4) = *(const float4*)&Ws[kk][cg * 8 + 4];
            #pragma unroll
            for (int i = 0; i < 8; i++)
                #pragma unroll
                for (int j = 0; j < 8; j++) acc[i][j] += a[i] * w[j];
        }
        __syncthreads();
    }

    #pragma unroll
    for (int i = 0; i < 8; i++) {
        int m = m0 + rg * 8 + i;
        int n0 = cg * 8;
        #pragma unroll
        for (int jq = 0; jq < 2; jq++) {
            float4 v;
            float* pv = (float*)&v;
            #pragma unroll
            for (int j = 0; j < 4; j++) {
                int n = n0 + jq * 4 + j;
                float s = acc[i][jq * 4 + j] + bias[n];
                if (resid) s += resid[(size_t)m * 128 + n];
                if (relu) s = fmaxf(s, 0.f);
                pv[j] = s;
            }
            *(float4*)(C + (size_t)m * 128 + n0 + jq * 4) = v;
        }
    }
}

// BM=32, 256 threads, 4x4 thread tile. M mult of 32, K mult of 16.
__global__ __launch_bounds__(256) void gemm32_kernel(
    const float* __restrict__ A, int K,
    const float* __restrict__ W, const float* __restrict__ bias,
    const float* __restrict__ resid, float* __restrict__ C, int relu)
{
    __shared__ float As[16][36];
    __shared__ float Ws[16][128];
    const int m0 = blockIdx.x * 32;
    const int tid = threadIdx.x;
    const int rg = tid >> 5;       // 0..7 -> 4 rows each
    const int cg = tid & 31;       // 0..31 -> 4 cols each

    float acc[4][4];
    #pragma unroll
    for (int i = 0; i < 4; i++)
        #pragma unroll
        for (int j = 0; j < 4; j++) acc[i][j] = 0.f;

    for (int k0 = 0; k0 < K; k0 += 16) {
        if (tid < 128) {
            int f = tid;                          // 0..127
            int m = f >> 2, kq = (f & 3) << 2;
            float4 v = *(const float4*)(A + (size_t)(m0 + m) * K + k0 + kq);
            As[kq + 0][m] = v.x; As[kq + 1][m] = v.y;
            As[kq + 2][m] = v.z; As[kq + 3][m] = v.w;
        }
        #pragma unroll
        for (int i = 0; i < 2; i++) {
            int f = tid + i * 256;
            int kk = f >> 5, nq = (f & 31) << 2;
            *(float4*)&Ws[kk][nq] = *(const float4*)(W + (size_t)(k0 + kk) * 128 + nq);
        }
        __syncthreads();
        #pragma unroll
        for (int kk = 0; kk < 16; kk++) {
            float a[4], w[4];
            *(float4*)(a) = *(const float4*)&As[kk][rg * 4];
            *(float4*)(w) = *(const float4*)&Ws[kk][cg * 4];
            #pragma unroll
            for (int i = 0; i < 4; i++)
                #pragma unroll
                for (int j = 0; j < 4; j++) acc[i][j] += a[i] * w[j];
        }
        __syncthreads();
    }

    #pragma unroll
    for (int i = 0; i < 4; i++) {
        int m = m0 + rg * 4 + i;
        int n0 = cg * 4;
        float4 v;
        float* pv = (float*)&v;
        #pragma unroll
        for (int j = 0; j < 4; j++) {
            int n = n0 + j;
            float s = acc[i][j] + bias[n];
            if (resid) s += resid[(size_t)m * 128 + n];
            if (relu) s = fmaxf(s, 0.f);
            pv[j] = s;
        }
        *(float4*)(C + (size_t)m * 128 + n0) = v;
    }
}

// final 128->3 layer (no relu)
__global__ void gemm_out3_kernel(const float* __restrict__ A,
                                 const float* __restrict__ W,
                                 const float* __restrict__ b,
                                 float* __restrict__ out)
{
    int t = blockIdx.x * blockDim.x + threadIdx.x;   // BN*3
    if (t >= BN * 3) return;
    int m = t / 3, n = t - m * 3;
    const float* a = A + (size_t)m * 128;
    float s = b[n];
    #pragma unroll 16
    for (int k = 0; k < 128; k++) s += a[k] * W[k * 3 + n];
    out[t] = s;
}

// ---------------- launch ----------------
extern "C" void kernel_launch(void* const* d_in, const int* in_sizes, int n_in,
                              void* d_out, int out_size)
{
    const float* x    = (const float*)d_in[0];
    const float* Rr   = (const float*)d_in[1];
    const float* Rs   = (const float*)d_in[2];
    // d_in[3] = pstep (device scalar; fixed to 2 by problem setup)
    const float* neW0 = (const float*)d_in[4];  const float* neb0 = (const float*)d_in[5];
    const float* neW1 = (const float*)d_in[6];  const float* neb1 = (const float*)d_in[7];
    const float* neW2 = (const float*)d_in[8];  const float* neb2 = (const float*)d_in[9];
    const float* eeW0 = (const float*)d_in[10]; const float* eeb0 = (const float*)d_in[11];
    const float* eeW1 = (const float*)d_in[12]; const float* eeb1 = (const float*)d_in[13];
    const float* eeW2 = (const float*)d_in[14]; const float* eeb2 = (const float*)d_in[15];
    const float* npW  = (const float*)d_in[16]; const float* npb  = (const float*)d_in[17];
    const float* epW  = (const float*)d_in[18]; const float* epb  = (const float*)d_in[19];
    const float* ppW0 = (const float*)d_in[20]; const float* ppb0 = (const float*)d_in[21];
    const float* ppW1 = (const float*)d_in[22]; const float* ppb1 = (const float*)d_in[23];
    const float* ppW2 = (const float*)d_in[24]; const float* ppb2 = (const float*)d_in[25];
    float* out = (float*)d_out;

    float* arena; cudaGetSymbolAddress((void**)&arena, g_arena);
    int* recv;    cudaGetSymbolAddress((void**)&recv, g_recv);
    int* send;    cudaGetSymbolAddress((void**)&send, g_send);

    float* tA        = arena + OFF_TA;
    float* tB        = arena + OFF_TB;
    float* node_enc  = arena + OFF_NODE_ENC;
    float* node_eff  = arena + OFF_NODE_EFF;
    float* node_eff2 = arena + OFF_NODE_EFF2;
    float* xcat      = arena + OFF_XCAT;
    float* tE        = arena + OFF_TE;
    float* tE2       = arena + OFF_TE2;
    float* edge_enc  = arena + OFF_EDGE_ENC;
    float* edge_in   = arena + OFF_EDGE_IN;
    float* edge_eff  = arena + OFF_EDGE_EFF;
    float* agg       = arena + OFF_AGG;
    float* node_in   = arena + OFF_NODE_IN;
    float* pcat      = arena + OFF_PCAT;
    float* ph1       = arena + OFF_PH1;
    float* ph2       = arena + OFF_PH2;

    // 1. recover indices from one-hot matrices
    extract_idx_kernel<<<BE / 8, 256>>>(Rr, recv);
    extract_idx_kernel<<<BE / 8, 256>>>(Rs, send);

    // 2. node encoder (M=4096): 32->128->128->128, relu each
    gemm32_kernel<<<BN / 32, 256>>>(x,  32,  neW0, neb0, nullptr, tA, 1);
    gemm32_kernel<<<BN / 32, 256>>>(tA, 128, neW1, neb1, nullptr, tB, 1);
    gemm32_kernel<<<BN / 32, 256>>>(tB, 128, neW2, neb2, nullptr, node_enc, 1);

    // 3. edge encoder (M=32768): gather [x_r|x_s] then 64->128->128->128
    gather_xcat_kernel<<<(BE * 16 + 255) / 256, 256>>>(x, recv, send, xcat);
    gemm128_kernel<<<BE / 128, 256>>>(xcat, 64,  eeW0, eeb0, nullptr, tE, 1);
    gemm128_kernel<<<BE / 128, 256>>>(tE,   128, eeW1, eeb1, nullptr, tE2, 1);
    gemm128_kernel<<<BE / 128, 256>>>(tE2,  128, eeW2, eeb2, nullptr, edge_enc, 1);

    // 4. propagation, pstep = 2 (ping-pong node_effect)
    const float* eff_in = node_enc;   // node_effect starts as node_encode
    float* eff_out = node_eff;
    for (int step = 0; step < 2; step++) {
        gather_edge_in_kernel<<<(BE * 96 + 255) / 256, 256>>>(edge_enc, eff_in, recv, send, edge_in);
        gemm128_kernel<<<BE / 128, 256>>>(edge_in, 384, epW, epb, nullptr, edge_eff, 1);
        cudaMemsetAsync(agg, 0, (size_t)BN * Hh * sizeof(float));
        scatter_add_kernel<<<(BE * Hh + 255) / 256, 256>>>(edge_eff, recv, agg);
        concat2_kernel<<<(BN * 64 + 255) / 256, 256>>>(node_enc, agg, node_in, BN);
        gemm32_kernel<<<BN / 32, 256>>>(node_in, 256, npW, npb, eff_in, eff_out, 1);
        eff_in = eff_out;
        eff_out = node_eff2;
    }

    // 5. predictor: [node_enc | node_effect] -> 128 -> 128 -> 3
    concat2_kernel<<<(BN * 64 + 255) / 256, 256>>>(node_enc, eff_in, pcat, BN);
    gemm32_kernel<<<BN / 32, 256>>>(pcat, 256, ppW0, ppb0, nullptr, ph1, 1);
    gemm32_kernel<<<BN / 32, 256>>>(ph1,  128, ppW1, ppb1, nullptr, ph2, 1);
    gemm_out3_kernel<<<(BN * 3 + 255) / 256, 256>>>(ph2, ppW2, ppb2, out);
}

// round 3
// speedup vs baseline: 1.1577x; 1.1577x over previous
#include <cuda_runtime.h>
#include <cuda_bf16.h>
#include <cstdint>

// ---------------- problem dims ----------------
#define Nn 1024
#define Ee 8192
#define BN 4096    // B*N
#define BE 32768   // B*E

// ---------------- device scratch ----------------
// bfp = packed bf16 pair per element: low 16 = hi, high 16 = lo
#define OFF_XB    ((size_t)0)                       // [BN,32] bfp
#define OFF_TA    (OFF_XB + (size_t)BN*32)          // [BN,128] bfp
#define OFF_TB    (OFF_TA + (size_t)BN*128)
#define OFF_NEB   (OFF_TB + (size_t)BN*128)         // node_enc bfp
#define OFF_NEF   (OFF_NEB + (size_t)BN*128)        // node_enc f32
#define OFF_NF0B  (OFF_NEF + (size_t)BN*128)        // node_eff bfp ping
#define OFF_NF1B  (OFF_NF0B + (size_t)BN*128)
#define OFF_NF0F  (OFF_NF1B + (size_t)BN*128)       // node_eff f32 ping
#define OFF_NF1F  (OFF_NF0F + (size_t)BN*128)
#define OFF_AGG   (OFF_NF1F + (size_t)BN*128)       // f32
#define OFF_PH1   (OFF_AGG + (size_t)BN*128)        // bfp
#define OFF_PH2   (OFF_PH1 + (size_t)BN*128)        // f32
#define OFF_TE    (OFF_PH2 + (size_t)BN*128)        // [BE,128] bfp
#define OFF_TE2   (OFF_TE + (size_t)BE*128)
#define OFF_EEB   (OFF_TE2 + (size_t)BE*128)        // edge_enc bfp
#define OFF_EEFF  (OFF_EEB + (size_t)BE*128)        // edge_eff f32
#define ARENA_U32 (OFF_EEFF + (size_t)BE*128)

__device__ uint32_t g_arena[ARENA_U32];
__device__ int g_recv[BE];
__device__ int g_send[BE];

// transposed/split weights: [n][kpad] bf16
// Kp: ne0:64 ne1:128 ne2:128 ee0:64 ee1:128 ee2:128 np:256 ep:384 pp0:256 pp1:128
#define WT_TOTAL (1664*128)
__device__ __nv_bfloat16 g_whi[WT_TOTAL];
__device__ __nv_bfloat16 g_wlo[WT_TOTAL];

// ---------------- helpers ----------------
__device__ __forceinline__ uint32_t smem_u32(const void* p) {
    uint32_t a;
    asm("{ .reg .u64 t; cvta.to.shared.u64 t, %1; cvt.u32.u64 %0, t; }" : "=r"(a) : "l"(p));
    return a;
}

#define LDMX4(r, ad) \
    asm volatile("ldmatrix.sync.aligned.m8n8.x4.shared.b16 {%0,%1,%2,%3}, [%4];" \
        : "=r"((r)[0]), "=r"((r)[1]), "=r"((r)[2]), "=r"((r)[3]) : "r"(ad))

#define MMA16816(d, av, bv) \
    asm volatile("mma.sync.aligned.m16n8k16.row.col.f32.bf16.bf16.f32 " \
        "{%0,%1,%2,%3},{%4,%5,%6,%7},{%8,%9},{%0,%1,%2,%3};" \
        : "+f"((d)[0]), "+f"((d)[1]), "+f"((d)[2]), "+f"((d)[3]) \
        : "r"((av)[0]), "r"((av)[1]), "r"((av)[2]), "r"((av)[3]), \
          "r"((bv)[0]), "r"((bv)[1]))

__device__ __forceinline__ uint32_t packbfp(float v) {
    __nv_bfloat16 h = __float2bfloat16(v);
    float hf = __bfloat162float(h);
    __nv_bfloat16 l = __float2bfloat16(v - hf);
    return (uint32_t)__bfloat16_as_ushort(h) | ((uint32_t)__bfloat16_as_ushort(l) << 16);
}

// ---------------- aux kernels ----------------
__global__ void extract_idx_kernel(const float* __restrict__ R, int* __restrict__ idx)
{
    int row = blockIdx.x * 8 + (threadIdx.x >> 5);
    if (row >= BE) return;
    int lane = threadIdx.x & 31;
    const float4* p = (const float4*)(R + (size_t)row * Nn);
    int found = 0;
    #pragma unroll
    for (int i = 0; i < 8; i++) {
        int q = lane + i * 32;
        float4 v = p[q];
        if (v.x > 0.5f) found = q * 4 + 0;
        if (v.y > 0.5f) found = q * 4 + 1;
        if (v.z > 0.5f) found = q * 4 + 2;
        if (v.w > 0.5f) found = q * 4 + 3;
    }
    #pragma unroll
    for (int o = 16; o; o >>= 1) found = max(found, __shfl_xor_sync(0xFFFFFFFFu, found, o));
    if (lane == 0) idx[row] = found;
}

__global__ void xconv_kernel(const float* __restrict__ x, uint32_t* __restrict__ xb)
{
    int t = blockIdx.x * blockDim.x + threadIdx.x;
    if (t < BN * 32) xb[t] = packbfp(x[t]);
}

struct PArg { const float* W[10]; };
__global__ void prep_weights(PArg a, __nv_bfloat16* __restrict__ hi, __nv_bfloat16* __restrict__ lo)
{
    const int Ks[10]   = {32, 128, 128, 64, 128, 128, 256, 384, 256, 128};
    const int Kps[10]  = {64, 128, 128, 64, 128, 128, 256, 384, 256, 128};
    const int offs[10] = {0, 8192, 24576, 40960, 49152, 65536, 81920, 114688, 163840, 196608};
    int mid = blockIdx.x;
    int K = Ks[mid], Kp = Kps[mid];
    const float* W = a.W[mid];
    __nv_bfloat16* dh = hi + offs[mid];
    __nv_bfloat16* dl = lo + offs[mid];
    int total = Kp * 128;
    for (int i = threadIdx.x; i < total; i += blockDim.x) {
        int n = i / Kp, k = i - n * Kp;
        float v = (k < K) ? W[(size_t)k * 128 + n] : 0.f;
        __nv_bfloat16 h = __float2bfloat16(v);
        dh[i] = h;
        dl[i] = __float2bfloat16(v - __bfloat162float(h));
    }
}

__global__ void scatter_add_kernel(const float* __restrict__ ee,
                                   const int* __restrict__ recv,
                                   float* __restrict__ agg)
{
    int t = blockIdx.x * blockDim.x + threadIdx.x;
    if (t >= BE * 128) return;
    int e = t >> 7, h = t & 127;
    int n = recv[e] + ((e >> 13) << 10);
    atomicAdd(&agg[(size_t)n * 128 + h], ee[t]);
}

__global__ void gemm_out3_kernel(const float* __restrict__ A,
                                 const float* __restrict__ W,
                                 const float* __restrict__ b,
                                 float* __restrict__ out)
{
    int t = blockIdx.x * blockDim.x + threadIdx.x;
    if (t >= BN * 3) return;
    int m = t / 3, n = t - m * 3;
    const float* a = A + (size_t)m * 128;
    float s = b[n];
    #pragma unroll 16
    for (int k = 0; k < 128; k++) s += a[k] * W[k * 3 + n];
    out[t] = s;
}

// ---------------- HMMA GEMM: C[M,128] = act(A @ W + bias (+resid)) ----------------
// A assembled per-row from up to 3 segments:
//   mode 0: zeros   mode 1: bfp direct   mode 2: bfp indexed (edge->node)   mode 3: f32 direct
struct Seg { const void* p; const int* idx; int start; int mode; int rs; };
struct GArg {
    Seg s0, s1, s2;
    int K;                              // padded K, multiple of 64
    const __nv_bfloat16 *Bhi, *Blo;     // [128][K]
    const float* bias;
    const float* resid;                 // f32 [M,128] or null
    float* outf;                        // f32 out or null
    uint32_t* outb;                     // bfp out or null
    int relu;
};

// smem layout (bytes), row stride 144B (72 halves = 9 x 16B: aligned + conflict-free)
// A hi [RT][64], A lo, B hi [128][64], B lo
template<int MTILES>
__global__ __launch_bounds__(256) void hgemm(GArg a)
{
    constexpr int RT = MTILES * 32;           // CTA rows
    constexpr int AHI = 0;
    constexpr int ALO = RT * 144;
    constexpr int BHI = 2 * RT * 144;
    constexpr int BLO = BHI + 128 * 144;
    extern __shared__ char smem[];
    const uint32_t sb = smem_u32(smem);
    const int tid = threadIdx.x;
    const int wid = tid >> 5, lane = tid & 31;
    const int wm = wid & 1, wn = wid >> 1;    // 2 x 4 warp grid
    const int m0 = blockIdx.x * RT;

    float acc[MTILES][4][4];
    #pragma unroll
    for (int mt = 0; mt < MTILES; mt++)
        #pragma unroll
        for (int nt = 0; nt < 4; nt++)
            #pragma unroll
            for (int r = 0; r < 4; r++) acc[mt][nt][r] = 0.f;

    const int nchunks = a.K >> 6;
    for (int c = 0; c < nchunks; c++) {
        const int k0 = c << 6;
        // ---- A tile assembly (hi/lo planes), RT x 64 ----
        #pragma unroll
        for (int it = 0; it < MTILES * 2; it++) {
            int item = tid + (it << 8);          // RT*16 items, 4 cols each
            int r = item >> 4, g = item & 15;
            int kc = k0 + (g << 2);
            int m = m0 + r;
            uint32_t p0, p1, p2, p3;
            Seg sg = (kc >= a.s2.start) ? a.s2 : ((kc >= a.s1.start) ? a.s1 : a.s0);
            if (sg.mode == 0) {
                p0 = p1 = p2 = p3 = 0u;
            } else {
                long row = (sg.mode == 2) ? ((long)sg.idx[m] + (long)((m >> 13) << 10)) : (long)m;
                long base = row * (long)sg.rs + (kc - sg.start);
                if (sg.mode == 3) {
                    float4 v = *((const float4*)sg.p + (base >> 2));
                    p0 = packbfp(v.x); p1 = packbfp(v.y); p2 = packbfp(v.z); p3 = packbfp(v.w);
                } else {
                    uint4 v = *((const uint4*)sg.p + (base >> 2));
                    p0 = v.x; p1 = v.y; p2 = v.z; p3 = v.w;
                }
            }
            uint32_t hi01 = (p0 & 0xffffu) | (p1 << 16);
            uint32_t hi23 = (p2 & 0xffffu) | (p3 << 16);
            uint32_t lo01 = (p0 >> 16) | (p1 & 0xffff0000u);
            uint32_t lo23 = (p2 >> 16) | (p3 & 0xffff0000u);
            int off = r * 144 + g * 8;
            *(uint2*)(smem + AHI + off) = make_uint2(hi01, hi23);
            *(uint2*)(smem + ALO + off) = make_uint2(lo01, lo23);
        }
        // ---- B tiles: 128 n-rows x 64 k ----
        #pragma unroll
        for (int it = 0; it < 4; it++) {
            int item = tid + (it << 8);          // 1024 items, 8 halves each
            int n = item >> 3, g = item & 7;
            size_t goff = (size_t)n * a.K + k0 + (g << 3);
            int off = n * 144 + g * 16;
            *(uint4*)(smem + BHI + off) = *(const uint4*)(a.Bhi + goff);
            *(uint4*)(smem + BLO + off) = *(const uint4*)(a.Blo + goff);
        }
        __syncthreads();

        #pragma unroll
        for (int ks = 0; ks < 4; ks++) {
            // B fragments: 4 n-tiles of 8, fetched as 2 ldmatrix.x4 per plane
            uint32_t bh[8], bl[8];
            #pragma unroll
            for (int np = 0; np < 2; np++) {
                int n = wn * 32 + np * 16 + ((lane >> 4) << 3) + (lane & 7);
                int koff = ((lane >> 3) & 1) << 3;
                uint32_t ad = sb + BHI + n * 144 + (ks * 16 + koff) * 2;
                LDMX4(&bh[np * 4], ad);
                LDMX4(&bl[np * 4], ad + (BLO - BHI));
            }
            #pragma unroll
            for (int mt = 0; mt < MTILES; mt++) {
                int r = wm * MTILES * 16 + mt * 16 + (lane & 15);
                int koff = (lane >> 4) << 3;
                uint32_t ad = sb + AHI + r * 144 + (ks * 16 + koff) * 2;
                uint32_t ah[4], al[4];
                LDMX4(ah, ad);
                LDMX4(al, ad + ALO);
                #pragma unroll
                for (int nt = 0; nt < 4; nt++) {
                    MMA16816(acc[mt][nt], ah, &bh[nt * 2]);
                    MMA16816(acc[mt][nt], ah, &bl[nt * 2]);
                    MMA16816(acc[mt][nt], al, &bh[nt * 2]);
                }
            }
        }
        __syncthreads();
    }

    // ---- epilogue from registers ----
    #pragma unroll
    for (int mt = 0; mt < MTILES; mt++) {
        int row0 = m0 + wm * MTILES * 16 + mt * 16 + (lane >> 2);
        #pragma unroll
        for (int nt = 0; nt < 4; nt++) {
            int n = wn * 32 + nt * 8 + ((lane & 3) << 1);
            float b0 = __ldg(a.bias + n), b1 = __ldg(a.bias + n + 1);
            #pragma unroll
            for (int h = 0; h < 2; h++) {
                int m = row0 + h * 8;
                float s0 = acc[mt][nt][h * 2 + 0] + b0;
                float s1 = acc[mt][nt][h * 2 + 1] + b1;
                if (a.resid) {
                    float2 rv = *(const float2*)(a.resid + (size_t)m * 128 + n);
                    s0 += rv.x; s1 += rv.y;
                }
                if (a.relu) { s0 = fmaxf(s0, 0.f); s1 = fmaxf(s1, 0.f); }
                if (a.outf) *(float2*)(a.outf + (size_t)m * 128 + n) = make_float2(s0, s1);
                if (a.outb) *(uint2*)(a.outb + (size_t)m * 128 + n) = make_uint2(packbfp(s0), packbfp(s1));
            }
        }
    }
}

// smem sizes
#define SMEM_BIG   (2*128*144 + 2*128*144)   // 73728
#define SMEM_SMALL (2*32*144 + 2*128*144)    // 46080

// ---------------- launch ----------------
static inline Seg segd(const void* p, int start, int mode, int rs, const int* idx = nullptr) {
    Seg s; s.p = p; s.idx = idx; s.start = start; s.mode = mode; s.rs = rs; return s;
}
static inline Seg segnone() { return segd(nullptr, 0x40000000, 0, 0); }

extern "C" void kernel_launch(void* const* d_in, const int* in_sizes, int n_in,
                              void* d_out, int out_size)
{
    const float* x    = (const float*)d_in[0];
    const float* Rr   = (const float*)d_in[1];
    const float* Rs   = (const float*)d_in[2];
    const float* neW0 = (const float*)d_in[4];  const float* neb0 = (const float*)d_in[5];
    const float* neW1 = (const float*)d_in[6];  const float* neb1 = (const float*)d_in[7];
    const float* neW2 = (const float*)d_in[8];  const float* neb2 = (const float*)d_in[9];
    const float* eeW0 = (const float*)d_in[10]; const float* eeb0 = (const float*)d_in[11];
    const float* eeW1 = (const float*)d_in[12]; const float* eeb1 = (const float*)d_in[13];
    const float* eeW2 = (const float*)d_in[14]; const float* eeb2 = (const float*)d_in[15];
    const float* npW  = (const float*)d_in[16]; const float* npb  = (const float*)d_in[17];
    const float* epW  = (const float*)d_in[18]; const float* epb  = (const float*)d_in[19];
    const float* ppW0 = (const float*)d_in[20]; const float* ppb0 = (const float*)d_in[21];
    const float* ppW1 = (const float*)d_in[22]; const float* ppb1 = (const float*)d_in[23];
    const float* ppW2 = (const float*)d_in[24]; const float* ppb2 = (const float*)d_in[25];
    float* out = (float*)d_out;

    uint32_t* arena; cudaGetSymbolAddress((void**)&arena, g_arena);
    int* recv; cudaGetSymbolAddress((void**)&recv, g_recv);
    int* send; cudaGetSymbolAddress((void**)&send, g_send);
    __nv_bfloat16* whi; cudaGetSymbolAddress((void**)&whi, g_whi);
    __nv_bfloat16* wlo; cudaGetSymbolAddress((void**)&wlo, g_wlo);

    uint32_t* xb   = arena + OFF_XB;
    uint32_t* tA   = arena + OFF_TA;
    uint32_t* tB   = arena + OFF_TB;
    uint32_t* neb  = arena + OFF_NEB;
    float*    nef  = (float*)(arena + OFF_NEF);
    uint32_t* nf0b = arena + OFF_NF0B;
    uint32_t* nf1b = arena + OFF_NF1B;
    float*    nf0f = (float*)(arena + OFF_NF0F);
    float*    nf1f = (float*)(arena + OFF_NF1F);
    float*    agg  = (float*)(arena + OFF_AGG);
    uint32_t* ph1  = arena + OFF_PH1;
    float*    ph2  = (float*)(arena + OFF_PH2);
    uint32_t* tE   = arena + OFF_TE;
    uint32_t* tE2  = arena + OFF_TE2;
    uint32_t* eeb_ = arena + OFF_EEB;
    float*    eeff = (float*)(arena + OFF_EEFF);

    // weight offsets (elems): ne0,ne1,ne2,ee0,ee1,ee2,np,ep,pp0,pp1
    const int WO[10] = {0, 8192, 24576, 40960, 49152, 65536, 81920, 114688, 163840, 196608};

    cudaFuncSetAttribute(hgemm<4>, cudaFuncAttributeMaxDynamicSharedMemorySize, SMEM_BIG);
    cudaFuncSetAttribute(hgemm<1>, cudaFuncAttributeMaxDynamicSharedMemorySize, SMEM_SMALL);

    // 0. prep
    PArg pa;
    pa.W[0] = neW0; pa.W[1] = neW1; pa.W[2] = neW2;
    pa.W[3] = eeW0; pa.W[4] = eeW1; pa.W[5] = eeW2;
    pa.W[6] = npW;  pa.W[7] = epW;  pa.W[8] = ppW0; pa.W[9] = ppW1;
    prep_weights<<<10, 256>>>(pa, whi, wlo);
    extract_idx_kernel<<<BE / 8, 256>>>(Rr, recv);
    extract_idx_kernel<<<BE / 8, 256>>>(Rs, send);
    xconv_kernel<<<(BN * 32 + 255) / 256, 256>>>(x, xb);

    GArg a;
    a.resid = nullptr; a.outf = nullptr; a.outb = nullptr; a.relu = 1;

    // 1. node encoder (M=4096): 32(pad64)->128->128->128
    a.s0 = segd(xb, 0, 1, 32); a.s1 = segd(nullptr, 32, 0, 0); a.s2 = segnone();
    a.K = 64; a.Bhi = whi + WO[0]; a.Blo = wlo + WO[0]; a.bias = neb0; a.outb = tA; a.outf = nullptr;
    hgemm<1><<<BN / 32, 256, SMEM_SMALL>>>(a);

    a.s0 = segd(tA, 0, 1, 128); a.s1 = segnone();
    a.K = 128; a.Bhi = whi + WO[1]; a.Blo = wlo + WO[1]; a.bias = neb1; a.outb = tB;
    hgemm<1><<<BN / 32, 256, SMEM_SMALL>>>(a);

    a.s0 = segd(tB, 0, 1, 128);
    a.K = 128; a.Bhi = whi + WO[2]; a.Blo = wlo + WO[2]; a.bias = neb2; a.outb = neb; a.outf = nef;
    hgemm<1><<<BN / 32, 256, SMEM_SMALL>>>(a);
    a.outf = nullptr;

    // 2. edge encoder (M=32768), gathers fused into A loader
    a.s0 = segd(xb, 0, 2, 32, recv); a.s1 = segd(xb, 32, 2, 32, send); a.s2 = segnone();
    a.K = 64; a.Bhi = whi + WO[3]; a.Blo = wlo + WO[3]; a.bias = eeb0; a.outb = tE;
    hgemm<4><<<BE / 128, 256, SMEM_BIG>>>(a);

    a.s0 = segd(tE, 0, 1, 128); a.s1 = segnone();
    a.K = 128; a.Bhi = whi + WO[4]; a.Blo = wlo + WO[4]; a.bias = eeb1; a.outb = tE2;
    hgemm<4><<<BE / 128, 256, SMEM_BIG>>>(a);

    a.s0 = segd(tE2, 0, 1, 128);
    a.K = 128; a.Bhi = whi + WO[5]; a.Blo = wlo + WO[5]; a.bias = eeb2; a.outb = eeb_;
    hgemm<4><<<BE / 128, 256, SMEM_BIG>>>(a);

    // 3. propagation, pstep = 2
    const uint32_t* curb = neb; const float* curf = nef;
    uint32_t* nxtb = nf0b;      float* nxtf = nf0f;
    for (int step = 0; step < 2; step++) {
        // edge effect: A = [edge_enc | nf[recv] | nf[send]], K=384
        a.s0 = segd(eeb_, 0, 1, 128);
        a.s1 = segd(curb, 128, 2, 128, recv);
        a.s2 = segd(curb, 256, 2, 128, send);
        a.K = 384; a.Bhi = whi + WO[7]; a.Blo = wlo + WO[7]; a.bias = epb;
        a.outb = nullptr; a.outf = eeff; a.resid = nullptr; a.relu = 1;
        hgemm<4><<<BE / 128, 256, SMEM_BIG>>>(a);

        cudaMemsetAsync(agg, 0, (size_t)BN * 128 * sizeof(float));
        scatter_add_kernel<<<(BE * 128 + 255) / 256, 256>>>(eeff, recv, agg);

        // node update: A = [node_enc | agg], resid = node_effect
        a.s0 = segd(neb, 0, 1, 128);
        a.s1 = segd(agg, 128, 3, 128);
        a.s2 = segnone();
        a.K = 256; a.Bhi = whi + WO[6]; a.Blo = wlo + WO[6]; a.bias = npb;
        a.resid = curf; a.outf = nxtf; a.outb = nxtb; a.relu = 1;
        hgemm<1><<<BN / 32, 256, SMEM_SMALL>>>(a);
        a.resid = nullptr;

        curb = nxtb; curf = nxtf;
        nxtb = nf1b; nxtf = nf1f;
    }

    // 4. predictor
    a.s0 = segd(neb, 0, 1, 128); a.s1 = segd(curb, 128, 1, 128); a.s2 = segnone();
    a.K = 256; a.Bhi = whi + WO[8]; a.Blo = wlo + WO[8]; a.bias = ppb0;
    a.outf = nullptr; a.outb = ph1; a.relu = 1;
    hgemm<1><<<BN / 32, 256, SMEM_SMALL>>>(a);

    a.s0 = segd(ph1, 0, 1, 128); a.s1 = segnone();
    a.K = 128; a.Bhi = whi + WO[9]; a.Blo = wlo + WO[9]; a.bias = ppb1;
    a.outf = ph2; a.outb = nullptr; a.relu = 1;
    hgemm<1><<<BN / 32, 256, SMEM_SMALL>>>(a);

    gemm_out3_kernel<<<(BN * 3 + 255) / 256, 256>>>(ph2, ppW2, ppb2, out);
}

// round 4
// speedup vs baseline: 1.7520x; 1.5133x over previous
#include <cuda_runtime.h>
#include <cuda_bf16.h>
#include <cstdint>

// ---------------- problem dims ----------------
#define Nn 1024
#define Ee 8192
#define BN 4096    // B*N
#define BE 32768   // B*E

// ---------------- device scratch ----------------
// bfp = packed bf16 pair: low 16 = hi, high 16 = lo
#define OFF_XB    ((size_t)0)                       // [BN,32] bfp
#define OFF_TA    (OFF_XB + (size_t)BN*32)          // [BN,128] bfp
#define OFF_TB    (OFF_TA + (size_t)BN*128)
#define OFF_NEB   (OFF_TB + (size_t)BN*128)         // node_enc bfp
#define OFF_NEF   (OFF_NEB + (size_t)BN*128)        // node_enc f32
#define OFF_NF0B  (OFF_NEF + (size_t)BN*128)
#define OFF_NF1B  (OFF_NF0B + (size_t)BN*128)
#define OFF_NF0F  (OFF_NF1B + (size_t)BN*128)
#define OFF_NF1F  (OFF_NF0F + (size_t)BN*128)
#define OFF_AGG   (OFF_NF1F + (size_t)BN*128)       // f32
#define OFF_PH1   (OFF_AGG + (size_t)BN*128)        // bfp
#define OFF_PH2   (OFF_PH1 + (size_t)BN*128)        // f32
#define OFF_PR    (OFF_PH2 + (size_t)BN*128)        // x@Wr f32
#define OFF_PS    (OFF_PR + (size_t)BN*128)         // x@Ws f32
#define OFF_PRP   (OFF_PS + (size_t)BN*128)         // nf@ep_r f32
#define OFF_PSP   (OFF_PRP + (size_t)BN*128)        // nf@ep_s f32
#define OFF_E0    (OFF_PSP + (size_t)BN*128)        // [BE,128] bfp
#define OFF_TE2   (OFF_E0 + (size_t)BE*128)
#define OFF_EEB   (OFF_TE2 + (size_t)BE*128)        // edge_enc bfp
#define OFF_EC    (OFF_EEB + (size_t)BE*128)        // edge_enc@ep_e f32
#define ARENA_U32 (OFF_EC + (size_t)BE*128)

__device__ uint32_t g_arena[ARENA_U32];
__device__ int g_recv[BE];
__device__ int g_send[BE];
__device__ float g_zero[128];   // zero-init, never written: zero bias

// transposed/split weights [n][kpad] bf16, 13 matrices
#define WT_TOTAL (1728*128)
__device__ __nv_bfloat16 g_whi[WT_TOTAL];
__device__ __nv_bfloat16 g_wlo[WT_TOTAL];

// ---------------- helpers ----------------
__device__ __forceinline__ uint32_t smem_u32(const void* p) {
    uint32_t a;
    asm("{ .reg .u64 t; cvta.to.shared.u64 t, %1; cvt.u32.u64 %0, t; }" : "=r"(a) : "l"(p));
    return a;
}

#define LDMX4(r, ad) \
    asm volatile("ldmatrix.sync.aligned.m8n8.x4.shared.b16 {%0,%1,%2,%3}, [%4];" \
        : "=r"((r)[0]), "=r"((r)[1]), "=r"((r)[2]), "=r"((r)[3]) : "r"(ad))

#define MMA16816(d, av, bv) \
    asm volatile("mma.sync.aligned.m16n8k16.row.col.f32.bf16.bf16.f32 " \
        "{%0,%1,%2,%3},{%4,%5,%6,%7},{%8,%9},{%0,%1,%2,%3};" \
        : "+f"((d)[0]), "+f"((d)[1]), "+f"((d)[2]), "+f"((d)[3]) \
        : "r"((av)[0]), "r"((av)[1]), "r"((av)[2]), "r"((av)[3]), \
          "r"((bv)[0]), "r"((bv)[1]))

__device__ __forceinline__ uint32_t packbfp(float v) {
    __nv_bfloat16 h = __float2bfloat16(v);
    float hf = __bfloat162float(h);
    __nv_bfloat16 l = __float2bfloat16(v - hf);
    return (uint32_t)__bfloat16_as_ushort(h) | ((uint32_t)__bfloat16_as_ushort(l) << 16);
}

// ---------------- aux kernels ----------------
// merged Rr+Rs one-hot index extraction: rows [0,BE)=Rr, [BE,2BE)=Rs
__global__ void extract_idx2_kernel(const float* __restrict__ Rr,
                                    const float* __restrict__ Rs,
                                    int* __restrict__ recv, int* __restrict__ send)
{
    int row = blockIdx.x * 8 + (threadIdx.x >> 5);
    int lane = threadIdx.x & 31;
    const float* R = (row < BE) ? Rr : Rs;
    int r = (row < BE) ? row : row - BE;
    const float4* p = (const float4*)(R + (size_t)r * Nn);
    int found = 0;
    #pragma unroll
    for (int i = 0; i < 8; i++) {
        int q = lane + i * 32;
        float4 v = p[q];
        if (v.x > 0.5f) found = q * 4 + 0;
        if (v.y > 0.5f) found = q * 4 + 1;
        if (v.z > 0.5f) found = q * 4 + 2;
        if (v.w > 0.5f) found = q * 4 + 3;
    }
    #pragma unroll
    for (int o = 16; o; o >>= 1) found = max(found, __shfl_xor_sync(0xFFFFFFFFu, found, o));
    if (lane == 0) {
        if (row < BE) recv[r] = found; else send[r] = found;
    }
}

__global__ void xconv_kernel(const float* __restrict__ x, uint32_t* __restrict__ xb)
{
    int t = blockIdx.x * blockDim.x + threadIdx.x;
    if (t < BN * 32) xb[t] = packbfp(x[t]);
}

struct PArg { const float* W[13]; };
// matrices: 0 ne0  1 ne1  2 ne2  3 eer  4 ees  5 ee1  6 ee2
//           7 ep_e 8 ep_r 9 ep_s 10 np  11 pp0 12 pp1
__constant__ int c_Ks[13]  = {32,128,128, 32, 32,128,128,128,128,128,256,256,128};
__constant__ int c_Kps[13] = {64,128,128, 64, 64,128,128,128,128,128,256,256,128};
__constant__ int c_r0[13]  = { 0,  0,  0,  0, 32,  0,  0,  0,128,256,  0,  0,  0};
__constant__ int c_off[13] = {0,8192,24576,40960,49152,57344,73728,90112,106496,122880,139264,172032,204800};

__global__ void prep_weights(PArg a, __nv_bfloat16* __restrict__ hi, __nv_bfloat16* __restrict__ lo)
{
    int mid = blockIdx.x;
    int K = c_Ks[mid], Kp = c_Kps[mid], r0 = c_r0[mid];
    const float* W = a.W[mid];
    __nv_bfloat16* dh = hi + c_off[mid];
    __nv_bfloat16* dl = lo + c_off[mid];
    int total = Kp * 128;
    for (int i = threadIdx.x; i < total; i += blockDim.x) {
        int n = i / Kp, k = i - n * Kp;
        float v = (k < K) ? W[(size_t)(r0 + k) * 128 + n] : 0.f;
        __nv_bfloat16 h = __float2bfloat16(v);
        dh[i] = h;
        dl[i] = __float2bfloat16(v - __bfloat162float(h));
    }
}

// edge layer0: out_bfp[e,h] = packbfp(relu(Pr[recv[e]] + Ps[send[e]] + b))
__global__ void fused_edge0_kernel(const float* __restrict__ Pr,
                                   const float* __restrict__ Ps,
                                   const int* __restrict__ recv,
                                   const int* __restrict__ send,
                                   const float* __restrict__ bias,
                                   uint32_t* __restrict__ out)
{
    int t = blockIdx.x * blockDim.x + threadIdx.x;
    if (t >= BE * 128) return;
    int e = t >> 7, h = t & 127;
    int bo = (e >> 13) << 10;
    int r = __ldg(recv + e) + bo, s = __ldg(send + e) + bo;
    float v = Pr[(size_t)r * 128 + h] + Ps[(size_t)s * 128 + h] + __ldg(bias + h);
    out[t] = packbfp(fmaxf(v, 0.f));
}

// edge effect + scatter: v = relu(ec[e] + prp[recv] + psp[send] + b); agg[recv] += v
__global__ void fused_scatter_kernel(const float* __restrict__ ec,
                                     const float* __restrict__ prp,
                                     const float* __restrict__ psp,
                                     const int* __restrict__ recv,
                                     const int* __restrict__ send,
                                     const float* __restrict__ bias,
                                     float* __restrict__ agg)
{
    int t = blockIdx.x * blockDim.x + threadIdx.x;
    if (t >= BE * 128) return;
    int e = t >> 7, h = t & 127;
    int bo = (e >> 13) << 10;
    int r = __ldg(recv + e) + bo, s = __ldg(send + e) + bo;
    float v = ec[t] + prp[(size_t)r * 128 + h] + psp[(size_t)s * 128 + h] + __ldg(bias + h);
    v = fmaxf(v, 0.f);
    atomicAdd(&agg[(size_t)r * 128 + h], v);
}

__global__ void gemm_out3_kernel(const float* __restrict__ A,
                                 const float* __restrict__ W,
                                 const float* __restrict__ b,
                                 float* __restrict__ out)
{
    int t = blockIdx.x * blockDim.x + threadIdx.x;
    if (t >= BN * 3) return;
    int m = t / 3, n = t - m * 3;
    const float* a = A + (size_t)m * 128;
    float s = b[n];
    #pragma unroll 16
    for (int k = 0; k < 128; k++) s += a[k] * W[k * 3 + n];
    out[t] = s;
}

// ---------------- HMMA GEMM: C[M,128] = act(A @ W + bias (+resid)) ----------------
struct Seg { const void* p; const int* idx; int start; int mode; int rs; };
struct GArg {
    Seg s0, s1, s2;
    int K;
    const __nv_bfloat16 *Bhi, *Blo;
    const float* bias;
    const float* resid;
    float* outf;
    uint32_t* outb;
    int relu;
};

template<int MTILES>
__global__ __launch_bounds__(256) void hgemm(GArg a)
{
    constexpr int RT = MTILES * 32;
    constexpr int AHI = 0;
    constexpr int ALO = RT * 144;
    constexpr int BHI = 2 * RT * 144;
    constexpr int BLO = BHI + 128 * 144;
    extern __shared__ char smem[];
    const uint32_t sb = smem_u32(smem);
    const int tid = threadIdx.x;
    const int wid = tid >> 5, lane = tid & 31;
    const int wm = wid & 1, wn = wid >> 1;
    const int m0 = blockIdx.x * RT;

    float acc[MTILES][4][4];
    #pragma unroll
    for (int mt = 0; mt < MTILES; mt++)
        #pragma unroll
        for (int nt = 0; nt < 4; nt++)
            #pragma unroll
            for (int r = 0; r < 4; r++) acc[mt][nt][r] = 0.f;

    const int nchunks = a.K >> 6;
    for (int c = 0; c < nchunks; c++) {
        const int k0 = c << 6;
        #pragma unroll
        for (int it = 0; it < MTILES * 2; it++) {
            int item = tid + (it << 8);
            int r = item >> 4, g = item & 15;
            int kc = k0 + (g << 2);
            int m = m0 + r;
            uint32_t p0, p1, p2, p3;
            Seg sg = (kc >= a.s2.start) ? a.s2 : ((kc >= a.s1.start) ? a.s1 : a.s0);
            if (sg.mode == 0) {
                p0 = p1 = p2 = p3 = 0u;
            } else {
                long row = (sg.mode == 2) ? ((long)sg.idx[m] + (long)((m >> 13) << 10)) : (long)m;
                long base = row * (long)sg.rs + (kc - sg.start);
                if (sg.mode == 3) {
                    float4 v = *((const float4*)sg.p + (base >> 2));
                    p0 = packbfp(v.x); p1 = packbfp(v.y); p2 = packbfp(v.z); p3 = packbfp(v.w);
                } else {
                    uint4 v = *((const uint4*)sg.p + (base >> 2));
                    p0 = v.x; p1 = v.y; p2 = v.z; p3 = v.w;
                }
            }
            uint32_t hi01 = (p0 & 0xffffu) | (p1 << 16);
            uint32_t hi23 = (p2 & 0xffffu) | (p3 << 16);
            uint32_t lo01 = (p0 >> 16) | (p1 & 0xffff0000u);
            uint32_t lo23 = (p2 >> 16) | (p3 & 0xffff0000u);
            int off = r * 144 + g * 8;
            *(uint2*)(smem + AHI + off) = make_uint2(hi01, hi23);
            *(uint2*)(smem + ALO + off) = make_uint2(lo01, lo23);
        }
        #pragma unroll
        for (int it = 0; it < 4; it++) {
            int item = tid + (it << 8);
            int n = item >> 3, g = item & 7;
            size_t goff = (size_t)n * a.K + k0 + (g << 3);
            int off = n * 144 + g * 16;
            *(uint4*)(smem + BHI + off) = *(const uint4*)(a.Bhi + goff);
            *(uint4*)(smem + BLO + off) = *(const uint4*)(a.Blo + goff);
        }
        __syncthreads();

        #pragma unroll
        for (int ks = 0; ks < 4; ks++) {
            uint32_t bh[8], bl[8];
            #pragma unroll
            for (int np = 0; np < 2; np++) {
                int n = wn * 32 + np * 16 + ((lane >> 4) << 3) + (lane & 7);
                int koff = ((lane >> 3) & 1) << 3;
                uint32_t ad = sb + BHI + n * 144 + (ks * 16 + koff) * 2;
                LDMX4(&bh[np * 4], ad);
                LDMX4(&bl[np * 4], ad + (BLO - BHI));
            }
            #pragma unroll
            for (int mt = 0; mt < MTILES; mt++) {
                int r = wm * MTILES * 16 + mt * 16 + (lane & 15);
                int koff = (lane >> 4) << 3;
                uint32_t ad = sb + AHI + r * 144 + (ks * 16 + koff) * 2;
                uint32_t ah[4], al[4];
                LDMX4(ah, ad);
                LDMX4(al, ad + ALO);
                #pragma unroll
                for (int nt = 0; nt < 4; nt++) {
                    MMA16816(acc[mt][nt], ah, &bh[nt * 2]);
                    MMA16816(acc[mt][nt], ah, &bl[nt * 2]);
                    MMA16816(acc[mt][nt], al, &bh[nt * 2]);
                }
            }
        }
        __syncthreads();
    }

    #pragma unroll
    for (int mt = 0; mt < MTILES; mt++) {
        int row0 = m0 + wm * MTILES * 16 + mt * 16 + (lane >> 2);
        #pragma unroll
        for (int nt = 0; nt < 4; nt++) {
            int n = wn * 32 + nt * 8 + ((lane & 3) << 1);
            float b0 = __ldg(a.bias + n), b1 = __ldg(a.bias + n + 1);
            #pragma unroll
            for (int h = 0; h < 2; h++) {
                int m = row0 + h * 8;
                float s0 = acc[mt][nt][h * 2 + 0] + b0;
                float s1 = acc[mt][nt][h * 2 + 1] + b1;
                if (a.resid) {
                    float2 rv = *(const float2*)(a.resid + (size_t)m * 128 + n);
                    s0 += rv.x; s1 += rv.y;
                }
                if (a.relu) { s0 = fmaxf(s0, 0.f); s1 = fmaxf(s1, 0.f); }
                if (a.outf) *(float2*)(a.outf + (size_t)m * 128 + n) = make_float2(s0, s1);
                if (a.outb) *(uint2*)(a.outb + (size_t)m * 128 + n) = make_uint2(packbfp(s0), packbfp(s1));
            }
        }
    }
}

#define SMEM_M2 (2*64*144 + 2*128*144)   // 55296  (edge GEMMs, RT=64)
#define SMEM_M1 (2*32*144 + 2*128*144)   // 46080  (node GEMMs, RT=32)

// ---------------- launch ----------------
static inline Seg segd(const void* p, int start, int mode, int rs, const int* idx = nullptr) {
    Seg s; s.p = p; s.idx = idx; s.start = start; s.mode = mode; s.rs = rs; return s;
}
static inline Seg segnone() { return segd(nullptr, 0x40000000, 0, 0); }

extern "C" void kernel_launch(void* const* d_in, const int* in_sizes, int n_in,
                              void* d_out, int out_size)
{
    const float* x    = (const float*)d_in[0];
    const float* Rr   = (const float*)d_in[1];
    const float* Rs   = (const float*)d_in[2];
    const float* neW0 = (const float*)d_in[4];  const float* neb0 = (const float*)d_in[5];
    const float* neW1 = (const float*)d_in[6];  const float* neb1 = (const float*)d_in[7];
    const float* neW2 = (const float*)d_in[8];  const float* neb2 = (const float*)d_in[9];
    const float* eeW0 = (const float*)d_in[10]; const float* eeb0 = (const float*)d_in[11];
    const float* eeW1 = (const float*)d_in[12]; const float* eeb1 = (const float*)d_in[13];
    const float* eeW2 = (const float*)d_in[14]; const float* eeb2 = (const float*)d_in[15];
    const float* npW  = (const float*)d_in[16]; const float* npb  = (const float*)d_in[17];
    const float* epW  = (const float*)d_in[18]; const float* epb  = (const float*)d_in[19];
    const float* ppW0 = (const float*)d_in[20]; const float* ppb0 = (const float*)d_in[21];
    const float* ppW1 = (const float*)d_in[22]; const float* ppb1 = (const float*)d_in[23];
    const float* ppW2 = (const float*)d_in[24]; const float* ppb2 = (const float*)d_in[25];
    float* out = (float*)d_out;

    uint32_t* arena; cudaGetSymbolAddress((void**)&arena, g_arena);
    int* recv; cudaGetSymbolAddress((void**)&recv, g_recv);
    int* send; cudaGetSymbolAddress((void**)&send, g_send);
    __nv_bfloat16* whi; cudaGetSymbolAddress((void**)&whi, g_whi);
    __nv_bfloat16* wlo; cudaGetSymbolAddress((void**)&wlo, g_wlo);
    float* zb; cudaGetSymbolAddress((void**)&zb, g_zero);

    uint32_t* xb   = arena + OFF_XB;
    uint32_t* tA   = arena + OFF_TA;
    uint32_t* tB   = arena + OFF_TB;
    uint32_t* neb  = arena + OFF_NEB;
    float*    nef  = (float*)(arena + OFF_NEF);
    uint32_t* nf0b = arena + OFF_NF0B;
    uint32_t* nf1b = arena + OFF_NF1B;
    float*    nf0f = (float*)(arena + OFF_NF0F);
    float*    nf1f = (float*)(arena + OFF_NF1F);
    float*    agg  = (float*)(arena + OFF_AGG);
    uint32_t* ph1  = arena + OFF_PH1;
    float*    ph2  = (float*)(arena + OFF_PH2);
    float*    Pr   = (float*)(arena + OFF_PR);
    float*    Ps   = (float*)(arena + OFF_PS);
    float*    prp  = (float*)(arena + OFF_PRP);
    float*    psp  = (float*)(arena + OFF_PSP);
    uint32_t* e0   = arena + OFF_E0;
    uint32_t* tE2  = arena + OFF_TE2;
    uint32_t* eeb_ = arena + OFF_EEB;
    float*    ec   = (float*)(arena + OFF_EC);

    // weight offsets: 0 ne0  1 ne1  2 ne2  3 eer  4 ees  5 ee1  6 ee2
    //                 7 ep_e 8 ep_r 9 ep_s 10 np  11 pp0 12 pp1
    const int WO[13] = {0,8192,24576,40960,49152,57344,73728,90112,106496,122880,139264,172032,204800};

    cudaFuncSetAttribute(hgemm<2>, cudaFuncAttributeMaxDynamicSharedMemorySize, SMEM_M2);
    cudaFuncSetAttribute(hgemm<1>, cudaFuncAttributeMaxDynamicSharedMemorySize, SMEM_M1);

    // 0. prep
    PArg pa;
    pa.W[0] = neW0; pa.W[1] = neW1; pa.W[2] = neW2;
    pa.W[3] = eeW0; pa.W[4] = eeW0; pa.W[5] = eeW1; pa.W[6] = eeW2;
    pa.W[7] = epW;  pa.W[8] = epW;  pa.W[9] = epW;
    pa.W[10] = npW; pa.W[11] = ppW0; pa.W[12] = ppW1;
    prep_weights<<<13, 256>>>(pa, whi, wlo);
    extract_idx2_kernel<<<2 * BE / 8, 256>>>(Rr, Rs, recv, send);
    xconv_kernel<<<(BN * 32 + 255) / 256, 256>>>(x, xb);

    GArg a;
    a.resid = nullptr; a.outf = nullptr; a.outb = nullptr; a.relu = 1;

    // 1. node encoder (M=4096): 32(pad64)->128->128->128
    a.s0 = segd(xb, 0, 1, 32); a.s1 = segd(nullptr, 32, 0, 0); a.s2 = segnone();
    a.K = 64; a.Bhi = whi + WO[0]; a.Blo = wlo + WO[0]; a.bias = neb0; a.outb = tA;
    hgemm<1><<<BN / 32, 256, SMEM_M1>>>(a);

    a.s0 = segd(tA, 0, 1, 128); a.s1 = segnone();
    a.K = 128; a.Bhi = whi + WO[1]; a.Blo = wlo + WO[1]; a.bias = neb1; a.outb = tB;
    hgemm<1><<<BN / 32, 256, SMEM_M1>>>(a);

    a.s0 = segd(tB, 0, 1, 128);
    a.K = 128; a.Bhi = whi + WO[2]; a.Blo = wlo + WO[2]; a.bias = neb2; a.outb = neb; a.outf = nef;
    hgemm<1><<<BN / 32, 256, SMEM_M1>>>(a);
    a.outf = nullptr;

    // 2. edge encoder: per-node projections, fused gather layer0, then 2 edge GEMMs
    a.s0 = segd(xb, 0, 1, 32); a.s1 = segd(nullptr, 32, 0, 0); a.s2 = segnone();
    a.K = 64; a.Bhi = whi + WO[3]; a.Blo = wlo + WO[3]; a.bias = zb; a.relu = 0;
    a.outb = nullptr; a.outf = Pr;
    hgemm<1><<<BN / 32, 256, SMEM_M1>>>(a);
    a.Bhi = whi + WO[4]; a.Blo = wlo + WO[4]; a.outf = Ps;
    hgemm<1><<<BN / 32, 256, SMEM_M1>>>(a);
    a.relu = 1; a.outf = nullptr;

    fused_edge0_kernel<<<BE * 128 / 256, 256>>>(Pr, Ps, recv, send, eeb0, e0);

    a.s0 = segd(e0, 0, 1, 128); a.s1 = segnone();
    a.K = 128; a.Bhi = whi + WO[5]; a.Blo = wlo + WO[5]; a.bias = eeb1; a.outb = tE2;
    hgemm<2><<<BE / 64, 256, SMEM_M2>>>(a);

    a.s0 = segd(tE2, 0, 1, 128);
    a.Bhi = whi + WO[6]; a.Blo = wlo + WO[6]; a.bias = eeb2; a.outb = eeb_;
    hgemm<2><<<BE / 64, 256, SMEM_M2>>>(a);

    // 3. ec = edge_enc @ ep_e (step-invariant, no bias/relu)
    a.s0 = segd(eeb_, 0, 1, 128);
    a.Bhi = whi + WO[7]; a.Blo = wlo + WO[7]; a.bias = zb; a.relu = 0;
    a.outb = nullptr; a.outf = ec;
    hgemm<2><<<BE / 64, 256, SMEM_M2>>>(a);
    a.outf = nullptr;

    // 4. propagation, pstep = 2
    const uint32_t* curb = neb; const float* curf = nef;
    uint32_t* nxtb = nf0b;      float* nxtf = nf0f;
    for (int step = 0; step < 2; step++) {
        // node-side projections of current node_effect
        a.s0 = segd(curb, 0, 1, 128); a.s1 = segnone(); a.s2 = segnone();
        a.K = 128; a.bias = zb; a.relu = 0; a.outb = nullptr;
        a.Bhi = whi + WO[8]; a.Blo = wlo + WO[8]; a.outf = prp;
        hgemm<1><<<BN / 32, 256, SMEM_M1>>>(a);
        a.Bhi = whi + WO[9]; a.Blo = wlo + WO[9]; a.outf = psp;
        hgemm<1><<<BN / 32, 256, SMEM_M1>>>(a);
        a.outf = nullptr;

        cudaMemsetAsync(agg, 0, (size_t)BN * 128 * sizeof(float));
        fused_scatter_kernel<<<BE * 128 / 256, 256>>>(ec, prp, psp, recv, send, epb, agg);

        // node update: A = [node_enc | agg], resid = node_effect
        a.s0 = segd(neb, 0, 1, 128);
        a.s1 = segd(agg, 128, 3, 128);
        a.s2 = segnone();
        a.K = 256; a.Bhi = whi + WO[10]; a.Blo = wlo + WO[10]; a.bias = npb;
        a.resid = curf; a.outf = nxtf; a.outb = nxtb; a.relu = 1;
        hgemm<1><<<BN / 32, 256, SMEM_M1>>>(a);
        a.resid = nullptr; a.outf = nullptr;

        curb = nxtb; curf = nxtf;
        nxtb = nf1b; nxtf = nf1f;
    }

    // 5. predictor
    a.s0 = segd(neb, 0, 1, 128); a.s1 = segd(curb, 128, 1, 128); a.s2 = segnone();
    a.K = 256; a.Bhi = whi + WO[11]; a.Blo = wlo + WO[11]; a.bias = ppb0;
    a.outb = ph1; a.relu = 1;
    hgemm<1><<<BN / 32, 256, SMEM_M1>>>(a);

    a.s0 = segd(ph1, 0, 1, 128); a.s1 = segnone();
    a.K = 128; a.Bhi = whi + WO[12]; a.Blo = wlo + WO[12]; a.bias = ppb1;
    a.outf = ph2; a.outb = nullptr; a.relu = 1;
    hgemm<1><<<BN / 32, 256, SMEM_M1>>>(a);

    gemm_out3_kernel<<<(BN * 3 + 255) / 256, 256>>>(ph2, ppW2, ppb2, out);
}

// round 5
// speedup vs baseline: 1.8905x; 1.0790x over previous
#include <cuda_runtime.h>
#include <cuda_bf16.h>
#include <cstdint>

// ---------------- problem dims ----------------
#define Nn 1024
#define Ee 8192
#define BN 4096    // B*N
#define BE 32768   // B*E

// ---------------- device scratch ----------------
#define OFF_TA    ((size_t)0)                       // [BN,128] bfp
#define OFF_TB    (OFF_TA + (size_t)BN*128)
#define OFF_NEB   (OFF_TB + (size_t)BN*128)         // node_enc bfp
#define OFF_NEF   (OFF_NEB + (size_t)BN*128)        // node_enc f32
#define OFF_NF0B  (OFF_NEF + (size_t)BN*128)
#define OFF_NF1B  (OFF_NF0B + (size_t)BN*128)
#define OFF_NF0F  (OFF_NF1B + (size_t)BN*128)
#define OFF_NF1F  (OFF_NF0F + (size_t)BN*128)
#define OFF_AGG   (OFF_NF1F + (size_t)BN*128)       // f32
#define OFF_PH1   (OFF_AGG + (size_t)BN*128)        // bfp
#define OFF_PH2   (OFF_PH1 + (size_t)BN*128)        // f32
#define OFF_PRS   (OFF_PH2 + (size_t)BN*128)        // [BN,256] f32 (x@Wr | x@Ws)
#define OFF_PRPSP (OFF_PRS + (size_t)BN*256)        // [BN,256] f32 (nf@ep_r | nf@ep_s)
#define OFF_TE2   (OFF_PRPSP + (size_t)BN*256)      // [BE,128] bfp
#define OFF_EEB   (OFF_TE2 + (size_t)BE*128)        // edge_enc bfp
#define OFF_EC    (OFF_EEB + (size_t)BE*128)        // edge_enc@ep_e f32
#define ARENA_U32 (OFF_EC + (size_t)BE*128)

__device__ uint32_t g_arena[ARENA_U32];
__device__ int g_recv[BE];
__device__ int g_send[BE];
__device__ float g_zero[256];   // zero-init: zero bias

// split/transposed weights [n][kpad] bf16, 11 matrices (some N=256 packed)
#define WT_TOTAL 221184
__device__ __nv_bfloat16 g_whi[WT_TOTAL];
__device__ __nv_bfloat16 g_wlo[WT_TOTAL];

// ---------------- helpers ----------------
__device__ __forceinline__ uint32_t smem_u32(const void* p) {
    uint32_t a;
    asm("{ .reg .u64 t; cvta.to.shared.u64 t, %1; cvt.u32.u64 %0, t; }" : "=r"(a) : "l"(p));
    return a;
}

#define LDMX4(r, ad) \
    asm volatile("ldmatrix.sync.aligned.m8n8.x4.shared.b16 {%0,%1,%2,%3}, [%4];" \
        : "=r"((r)[0]), "=r"((r)[1]), "=r"((r)[2]), "=r"((r)[3]) : "r"(ad))

#define MMA16816(d, av, bv) \
    asm volatile("mma.sync.aligned.m16n8k16.row.col.f32.bf16.bf16.f32 " \
        "{%0,%1,%2,%3},{%4,%5,%6,%7},{%8,%9},{%0,%1,%2,%3};" \
        : "+f"((d)[0]), "+f"((d)[1]), "+f"((d)[2]), "+f"((d)[3]) \
        : "r"((av)[0]), "r"((av)[1]), "r"((av)[2]), "r"((av)[3]), \
          "r"((bv)[0]), "r"((bv)[1]))

__device__ __forceinline__ uint32_t packbfp(float v) {
    __nv_bfloat16 h = __float2bfloat16(v);
    float hf = __bfloat162float(h);
    __nv_bfloat16 l = __float2bfloat16(v - hf);
    return (uint32_t)__bfloat16_as_ushort(h) | ((uint32_t)__bfloat16_as_ushort(l) << 16);
}

// ---------------- aux kernels ----------------
__global__ void extract_idx2_kernel(const float* __restrict__ Rr,
                                    const float* __restrict__ Rs,
                                    int* __restrict__ recv, int* __restrict__ send)
{
    int row = blockIdx.x * 8 + (threadIdx.x >> 5);
    int lane = threadIdx.x & 31;
    const float* R = (row < BE) ? Rr : Rs;
    int r = (row < BE) ? row : row - BE;
    const float4* p = (const float4*)(R + (size_t)r * Nn);
    int found = 0;
    #pragma unroll
    for (int i = 0; i < 8; i++) {
        int q = lane + i * 32;
        float4 v = p[q];
        if (v.x > 0.5f) found = q * 4 + 0;
        if (v.y > 0.5f) found = q * 4 + 1;
        if (v.z > 0.5f) found = q * 4 + 2;
        if (v.w > 0.5f) found = q * 4 + 3;
    }
    #pragma unroll
    for (int o = 16; o; o >>= 1) found = max(found, __shfl_xor_sync(0xFFFFFFFFu, found, o));
    if (lane == 0) {
        if (row < BE) recv[r] = found; else send[r] = found;
    }
}

// matrices: 0 ne0  1 ne1  2 ne2  3 eers(256)  4 ee1  5 ee2
//           6 ep_e 7 ep_rs(256) 8 np 9 pp0 10 pp1
struct PArg { const float* W[11]; };
__constant__ int c_Ks[11]  = {32,128,128, 32,128,128,128,128,256,256,128};
__constant__ int c_Kps[11] = {64,128,128, 64,128,128,128,128,256,256,128};
__constant__ int c_Rs[11]  = {128,128,128,256,128,128,128,256,128,128,128};
__constant__ int c_r0a[11] = {0,0,0,0,0,0,0,128,0,0,0};
__constant__ int c_r0b[11] = {0,0,0,32,0,0,0,256,0,0,0};
__constant__ int c_off[11] = {0,8192,24576,40960,57344,73728,90112,106496,139264,172032,204800};

__global__ void prep_weights(PArg a, __nv_bfloat16* __restrict__ hi, __nv_bfloat16* __restrict__ lo)
{
    int mid = blockIdx.x;
    int K = c_Ks[mid], Kp = c_Kps[mid], R = c_Rs[mid];
    int r0a = c_r0a[mid], r0b = c_r0b[mid];
    const float* W = a.W[mid];
    __nv_bfloat16* dh = hi + c_off[mid];
    __nv_bfloat16* dl = lo + c_off[mid];
    int total = R * Kp;
    for (int i = threadIdx.x; i < total; i += blockDim.x) {
        int n = i / Kp, k = i - n * Kp;
        int col = n & 127;
        int r0 = (n >> 7) ? r0b : r0a;
        float v = (k < K) ? W[(size_t)(r0 + k) * 128 + col] : 0.f;
        __nv_bfloat16 h = __float2bfloat16(v);
        dh[i] = h;
        dl[i] = __float2bfloat16(v - __bfloat162float(h));
    }
}

// edge effect + scatter: v = relu(ec[e] + prp[recv] + psp[send] + b); agg[recv] += v
__global__ void fused_scatter_kernel(const float* __restrict__ ec,
                                     const float* __restrict__ prpsp,
                                     const int* __restrict__ recv,
                                     const int* __restrict__ send,
                                     const float* __restrict__ bias,
                                     float* __restrict__ agg)
{
    int t = blockIdx.x * blockDim.x + threadIdx.x;
    if (t >= BE * 128) return;
    int e = t >> 7, h = t & 127;
    int bo = (e >> 13) << 10;
    int r = __ldg(recv + e) + bo, s = __ldg(send + e) + bo;
    float v = ec[t] + prpsp[(size_t)r * 256 + h] + prpsp[(size_t)s * 256 + 128 + h] + __ldg(bias + h);
    v = fmaxf(v, 0.f);
    atomicAdd(&agg[(size_t)r * 128 + h], v);
}

__global__ void gemm_out3_kernel(const float* __restrict__ A,
                                 const float* __restrict__ W,
                                 const float* __restrict__ b,
                                 float* __restrict__ out)
{
    int t = blockIdx.x * blockDim.x + threadIdx.x;
    if (t >= BN * 3) return;
    int m = t / 3, n = t - m * 3;
    const float* a = A + (size_t)m * 128;
    float s = b[n];
    #pragma unroll 16
    for (int k = 0; k < 128; k++) s += a[k] * W[k * 3 + n];
    out[t] = s;
}

// ---------------- HMMA GEMM ----------------
// A segment modes: 0 zeros  1 bfp direct  3 f32 direct  4 edge-layer0 compute
struct Seg { const void* p; const int* idx; const int* idx2; const float* ebias;
             int start; int mode; int rs; };
struct GArg {
    Seg s0, s1, s2;
    int K;                           // full K (multiple of KCH)
    const __nv_bfloat16 *Bhi, *Blo;  // [NT*128][K]
    const float* bias;               // [NT*128]
    const float* resid;              // f32 [M,128] or null (ld 128)
    float* outf;                     // f32 out or null
    uint32_t* outb;                  // bfp out or null
    int ldo;                         // out row stride (elems)
    int relu;
};

template<int MT, int NT, int KCH>
__global__ __launch_bounds__(256) void hgemm(GArg a)
{
    constexpr int RT = MT * 32;
    constexpr int STRIDE = KCH * 2 + 16;
    constexpr int ALO = RT * STRIDE;
    constexpr int BHI = 2 * RT * STRIDE;
    constexpr int BPL = NT * 128 * STRIDE;   // B plane size
    extern __shared__ char smem[];
    const uint32_t sb = smem_u32(smem);
    const int tid = threadIdx.x;
    const int wid = tid >> 5, lane = tid & 31;
    const int wm = wid & 1, wn = wid >> 1;
    const int m0 = blockIdx.x * RT;

    float acc[MT][NT * 4][4];
    #pragma unroll
    for (int mt = 0; mt < MT; mt++)
        #pragma unroll
        for (int st = 0; st < NT * 4; st++)
            #pragma unroll
            for (int r = 0; r < 4; r++) acc[mt][st][r] = 0.f;

    const int nchunks = a.K / KCH;
    for (int c = 0; c < nchunks; c++) {
        const int k0 = c * KCH;
        // ---- A tile (hi/lo), RT x KCH ----
        #pragma unroll
        for (int it = 0; it < MT * KCH / 32; it++) {
            int item = tid + (it << 8);
            int r = item / (KCH / 4), g = item % (KCH / 4);
            int kc = k0 + (g << 2);
            int m = m0 + r;
            uint32_t p0, p1, p2, p3;
            Seg sg = (kc >= a.s2.start) ? a.s2 : ((kc >= a.s1.start) ? a.s1 : a.s0);
            if (sg.mode == 0) {
                p0 = p1 = p2 = p3 = 0u;
            } else if (sg.mode == 4) {
                int bo = (m >> 13) << 10;
                int rr = __ldg(sg.idx + m) + bo, ss = __ldg(sg.idx2 + m) + bo;
                int kk = kc - sg.start;
                float4 pr = *(const float4*)((const float*)sg.p + (size_t)rr * 256 + kk);
                float4 ps = *(const float4*)((const float*)sg.p + (size_t)ss * 256 + 128 + kk);
                float4 bb = *(const float4*)(sg.ebias + kk);
                p0 = packbfp(fmaxf(pr.x + ps.x + bb.x, 0.f));
                p1 = packbfp(fmaxf(pr.y + ps.y + bb.y, 0.f));
                p2 = packbfp(fmaxf(pr.z + ps.z + bb.z, 0.f));
                p3 = packbfp(fmaxf(pr.w + ps.w + bb.w, 0.f));
            } else {
                long base = (long)m * sg.rs + (kc - sg.start);
                if (sg.mode == 3) {
                    float4 v = *((const float4*)sg.p + (base >> 2));
                    p0 = packbfp(v.x); p1 = packbfp(v.y); p2 = packbfp(v.z); p3 = packbfp(v.w);
                } else {
                    uint4 v = *((const uint4*)sg.p + (base >> 2));
                    p0 = v.x; p1 = v.y; p2 = v.z; p3 = v.w;
                }
            }
            uint32_t hi01 = (p0 & 0xffffu) | (p1 << 16);
            uint32_t hi23 = (p2 & 0xffffu) | (p3 << 16);
            uint32_t lo01 = (p0 >> 16) | (p1 & 0xffff0000u);
            uint32_t lo23 = (p2 >> 16) | (p3 & 0xffff0000u);
            int off = r * STRIDE + g * 8;
            *(uint2*)(smem + off) = make_uint2(hi01, hi23);
            *(uint2*)(smem + ALO + off) = make_uint2(lo01, lo23);
        }
        // ---- B tiles: NT*128 rows x KCH ----
        #pragma unroll
        for (int it = 0; it < NT * KCH / 16; it++) {
            int item = tid + (it << 8);
            int n = item / (KCH / 8), g = item % (KCH / 8);
            size_t goff = (size_t)n * a.K + k0 + (g << 3);
            int off = n * STRIDE + g * 16;
            *(uint4*)(smem + BHI + off) = *(const uint4*)(a.Bhi + goff);
            *(uint4*)(smem + BHI + BPL + off) = *(const uint4*)(a.Blo + goff);
        }
        __syncthreads();

        #pragma unroll
        for (int ks = 0; ks < KCH / 16; ks++) {
            uint32_t bh[NT * 8], bl[NT * 8];
            #pragma unroll
            for (int t2 = 0; t2 < NT; t2++)
                #pragma unroll
                for (int np = 0; np < 2; np++) {
                    int n = t2 * 128 + wn * 32 + np * 16 + ((lane >> 4) << 3) + (lane & 7);
                    int koff = ((lane >> 3) & 1) << 3;
                    uint32_t ad = sb + BHI + n * STRIDE + (ks * 16 + koff) * 2;
                    LDMX4(&bh[(t2 * 2 + np) * 4], ad);
                    LDMX4(&bl[(t2 * 2 + np) * 4], ad + BPL);
                }
            #pragma unroll
            for (int mt = 0; mt < MT; mt++) {
                int r = wm * MT * 16 + mt * 16 + (lane & 15);
                int koff = (lane >> 4) << 3;
                uint32_t ad = sb + r * STRIDE + (ks * 16 + koff) * 2;
                uint32_t ah[4], al[4];
                LDMX4(ah, ad);
                LDMX4(al, ad + ALO);
                #pragma unroll
                for (int st = 0; st < NT * 4; st++) {
                    MMA16816(acc[mt][st], ah, &bh[st * 2]);
                    MMA16816(acc[mt][st], ah, &bl[st * 2]);
                    MMA16816(acc[mt][st], al, &bh[st * 2]);
                }
            }
        }
        __syncthreads();
    }

    // ---- epilogue ----
    #pragma unroll
    for (int mt = 0; mt < MT; mt++) {
        int row0 = m0 + wm * MT * 16 + mt * 16 + (lane >> 2);
        #pragma unroll
        for (int st = 0; st < NT * 4; st++) {
            int n = (st >> 2) * 128 + wn * 32 + (st & 3) * 8 + ((lane & 3) << 1);
            float b0 = __ldg(a.bias + n), b1 = __ldg(a.bias + n + 1);
            #pragma unroll
            for (int h = 0; h < 2; h++) {
                int m = row0 + h * 8;
                float s0 = acc[mt][st][h * 2 + 0] + b0;
                float s1 = acc[mt][st][h * 2 + 1] + b1;
                if (a.resid) {
                    float2 rv = *(const float2*)(a.resid + (size_t)m * 128 + n);
                    s0 += rv.x; s1 += rv.y;
                }
                if (a.relu) { s0 = fmaxf(s0, 0.f); s1 = fmaxf(s1, 0.f); }
                if (a.outf) *(float2*)(a.outf + (size_t)m * a.ldo + n) = make_float2(s0, s1);
                if (a.outb) *(uint2*)(a.outb + (size_t)m * a.ldo + n) = make_uint2(packbfp(s0), packbfp(s1));
            }
        }
    }
}

constexpr int smem_sz(int MT, int NT, int KCH) {
    return (2 * MT * 32 + 2 * NT * 128) * (KCH * 2 + 16);
}

// ---------------- launch ----------------
static inline Seg segd(const void* p, int start, int mode, int rs,
                       const int* idx = nullptr, const int* idx2 = nullptr,
                       const float* eb = nullptr) {
    Seg s; s.p = p; s.idx = idx; s.idx2 = idx2; s.ebias = eb;
    s.start = start; s.mode = mode; s.rs = rs; return s;
}
static inline Seg segnone() { return segd(nullptr, 0x40000000, 0, 0); }

extern "C" void kernel_launch(void* const* d_in, const int* in_sizes, int n_in,
                              void* d_out, int out_size)
{
    const float* x    = (const float*)d_in[0];
    const float* Rr   = (const float*)d_in[1];
    const float* Rs   = (const float*)d_in[2];
    const float* neW0 = (const float*)d_in[4];  const float* neb0 = (const float*)d_in[5];
    const float* neW1 = (const float*)d_in[6];  const float* neb1 = (const float*)d_in[7];
    const float* neW2 = (const float*)d_in[8];  const float* neb2 = (const float*)d_in[9];
    const float* eeW0 = (const float*)d_in[10]; const float* eeb0 = (const float*)d_in[11];
    const float* eeW1 = (const float*)d_in[12]; const float* eeb1 = (const float*)d_in[13];
    const float* eeW2 = (const float*)d_in[14]; const float* eeb2 = (const float*)d_in[15];
    const float* npW  = (const float*)d_in[16]; const float* npb  = (const float*)d_in[17];
    const float* epW  = (const float*)d_in[18]; const float* epb  = (const float*)d_in[19];
    const float* ppW0 = (const float*)d_in[20]; const float* ppb0 = (const float*)d_in[21];
    const float* ppW1 = (const float*)d_in[22]; const float* ppb1 = (const float*)d_in[23];
    const float* ppW2 = (const float*)d_in[24]; const float* ppb2 = (const float*)d_in[25];
    float* out = (float*)d_out;

    uint32_t* arena; cudaGetSymbolAddress((void**)&arena, g_arena);
    int* recv; cudaGetSymbolAddress((void**)&recv, g_recv);
    int* send; cudaGetSymbolAddress((void**)&send, g_send);
    __nv_bfloat16* whi; cudaGetSymbolAddress((void**)&whi, g_whi);
    __nv_bfloat16* wlo; cudaGetSymbolAddress((void**)&wlo, g_wlo);
    float* zb; cudaGetSymbolAddress((void**)&zb, g_zero);

    uint32_t* tA    = arena + OFF_TA;
    uint32_t* tB    = arena + OFF_TB;
    uint32_t* neb   = arena + OFF_NEB;
    float*    nef   = (float*)(arena + OFF_NEF);
    uint32_t* nf0b  = arena + OFF_NF0B;
    uint32_t* nf1b  = arena + OFF_NF1B;
    float*    nf0f  = (float*)(arena + OFF_NF0F);
    float*    nf1f  = (float*)(arena + OFF_NF1F);
    float*    agg   = (float*)(arena + OFF_AGG);
    uint32_t* ph1   = arena + OFF_PH1;
    float*    ph2   = (float*)(arena + OFF_PH2);
    float*    prs   = (float*)(arena + OFF_PRS);
    float*    prpsp = (float*)(arena + OFF_PRPSP);
    uint32_t* tE2   = arena + OFF_TE2;
    uint32_t* eeb_  = arena + OFF_EEB;
    float*    ec    = (float*)(arena + OFF_EC);

    // weight offsets: 0 ne0 1 ne1 2 ne2 3 eers 4 ee1 5 ee2 6 ep_e 7 ep_rs 8 np 9 pp0 10 pp1
    const int WO[11] = {0,8192,24576,40960,57344,73728,90112,106496,139264,172032,204800};

    cudaFuncSetAttribute(hgemm<1,1,64>,  cudaFuncAttributeMaxDynamicSharedMemorySize, smem_sz(1,1,64));
    cudaFuncSetAttribute(hgemm<1,1,128>, cudaFuncAttributeMaxDynamicSharedMemorySize, smem_sz(1,1,128));
    cudaFuncSetAttribute(hgemm<1,2,64>,  cudaFuncAttributeMaxDynamicSharedMemorySize, smem_sz(1,2,64));
    cudaFuncSetAttribute(hgemm<1,2,128>, cudaFuncAttributeMaxDynamicSharedMemorySize, smem_sz(1,2,128));
    cudaFuncSetAttribute(hgemm<2,1,128>, cudaFuncAttributeMaxDynamicSharedMemorySize, smem_sz(2,1,128));

    // 0. prep
    PArg pa;
    pa.W[0] = neW0; pa.W[1] = neW1; pa.W[2] = neW2;
    pa.W[3] = eeW0; pa.W[4] = eeW1; pa.W[5] = eeW2;
    pa.W[6] = epW;  pa.W[7] = epW;
    pa.W[8] = npW;  pa.W[9] = ppW0; pa.W[10] = ppW1;
    prep_weights<<<11, 256>>>(pa, whi, wlo);
    extract_idx2_kernel<<<2 * BE / 8, 256>>>(Rr, Rs, recv, send);

    GArg a;
    a.resid = nullptr; a.outf = nullptr; a.outb = nullptr; a.relu = 1; a.ldo = 128;

    // 1. node encoder (M=4096): x(f32,K32 pad64)->128->128->128
    a.s0 = segd(x, 0, 3, 32); a.s1 = segd(nullptr, 32, 0, 0); a.s2 = segnone();
    a.K = 64; a.Bhi = whi + WO[0]; a.Blo = wlo + WO[0]; a.bias = neb0; a.outb = tA;
    hgemm<1,1,64><<<BN / 32, 256, smem_sz(1,1,64)>>>(a);

    a.s0 = segd(tA, 0, 1, 128); a.s1 = segnone();
    a.K = 128; a.Bhi = whi + WO[1]; a.Blo = wlo + WO[1]; a.bias = neb1; a.outb = tB;
    hgemm<1,1,128><<<BN / 32, 256, smem_sz(1,1,128)>>>(a);

    a.s0 = segd(tB, 0, 1, 128);
    a.Bhi = whi + WO[2]; a.Blo = wlo + WO[2]; a.bias = neb2; a.outb = neb; a.outf = nef;
    hgemm<1,1,128><<<BN / 32, 256, smem_sz(1,1,128)>>>(a);
    a.outf = nullptr;

    // 2. PrPs: x @ [eer|ees] -> prs [BN,256] (no relu, zero bias)
    a.s0 = segd(x, 0, 3, 32); a.s1 = segd(nullptr, 32, 0, 0); a.s2 = segnone();
    a.K = 64; a.Bhi = whi + WO[3]; a.Blo = wlo + WO[3]; a.bias = zb; a.relu = 0;
    a.outb = nullptr; a.outf = prs; a.ldo = 256;
    hgemm<1,2,64><<<BN / 32, 256, smem_sz(1,2,64)>>>(a);
    a.relu = 1; a.outf = nullptr; a.ldo = 128;

    // 3. edge encoder: ee1 (A computed on the fly from prs), then ee2
    a.s0 = segd(prs, 0, 4, 256, recv, send, eeb0); a.s1 = segnone(); a.s2 = segnone();
    a.K = 128; a.Bhi = whi + WO[4]; a.Blo = wlo + WO[4]; a.bias = eeb1; a.outb = tE2;
    hgemm<2,1,128><<<BE / 64, 256, smem_sz(2,1,128)>>>(a);

    a.s0 = segd(tE2, 0, 1, 128);
    a.Bhi = whi + WO[5]; a.Blo = wlo + WO[5]; a.bias = eeb2; a.outb = eeb_;
    hgemm<2,1,128><<<BE / 64, 256, smem_sz(2,1,128)>>>(a);

    // 4. ec = edge_enc @ ep_e (step-invariant)
    a.s0 = segd(eeb_, 0, 1, 128);
    a.Bhi = whi + WO[6]; a.Blo = wlo + WO[6]; a.bias = zb; a.relu = 0;
    a.outb = nullptr; a.outf = ec;
    hgemm<2,1,128><<<BE / 64, 256, smem_sz(2,1,128)>>>(a);
    a.outf = nullptr; a.relu = 1;

    // 5. propagation, pstep = 2
    const uint32_t* curb = neb; const float* curf = nef;
    uint32_t* nxtb = nf0b;      float* nxtf = nf0f;
    for (int step = 0; step < 2; step++) {
        // prpsp = nf @ [ep_r|ep_s] -> [BN,256]
        a.s0 = segd(curb, 0, 1, 128); a.s1 = segnone(); a.s2 = segnone();
        a.K = 128; a.Bhi = whi + WO[7]; a.Blo = wlo + WO[7]; a.bias = zb;
        a.relu = 0; a.outb = nullptr; a.outf = prpsp; a.ldo = 256;
        hgemm<1,2,128><<<BN / 32, 256, smem_sz(1,2,128)>>>(a);
        a.relu = 1; a.outf = nullptr; a.ldo = 128;

        cudaMemsetAsync(agg, 0, (size_t)BN * 128 * sizeof(float));
        fused_scatter_kernel<<<BE * 128 / 256, 256>>>(ec, prpsp, recv, send, epb, agg);

        // node update: A = [node_enc | agg], resid = node_effect
        a.s0 = segd(neb, 0, 1, 128);
        a.s1 = segd(agg, 128, 3, 128);
        a.s2 = segnone();
        a.K = 256; a.Bhi = whi + WO[8]; a.Blo = wlo + WO[8]; a.bias = npb;
        a.resid = curf; a.outf = nxtf; a.outb = nxtb;
        hgemm<1,1,128><<<BN / 32, 256, smem_sz(1,1,128)>>>(a);
        a.resid = nullptr; a.outf = nullptr;

        curb = nxtb; curf = nxtf;
        nxtb = nf1b; nxtf = nf1f;
    }

    // 6. predictor
    a.s0 = segd(neb, 0, 1, 128); a.s1 = segd(curb, 128, 1, 128); a.s2 = segnone();
    a.K = 256; a.Bhi = whi + WO[9]; a.Blo = wlo + WO[9]; a.bias = ppb0;
    a.outb = ph1;
    hgemm<1,1,128><<<BN / 32, 256, smem_sz(1,1,128)>>>(a);

    a.s0 = segd(ph1, 0, 1, 128); a.s1 = segnone();
    a.K = 128; a.Bhi = whi + WO[10]; a.Blo = wlo + WO[10]; a.bias = ppb1;
    a.outf = ph2; a.outb = nullptr;
    hgemm<1,1,128><<<BN / 32, 256, smem_sz(1,1,128)>>>(a);

    gemm_out3_kernel<<<(BN * 3 + 255) / 256, 256>>>(ph2, ppW2, ppb2, out);
}

// round 7
// speedup vs baseline: 2.3033x; 1.2184x over previous
#include <cuda_runtime.h>
#include <cuda_bf16.h>
#include <cstdint>

// ---------------- problem dims ----------------
#define Nn 1024
#define Ee 8192
#define BN 4096    // B*N
#define BE 32768   // B*E

// ---------------- device scratch ----------------
#define OFF_TA    ((size_t)0)                       // [BN,128] bfp
#define OFF_TB    (OFF_TA + (size_t)BN*128)
#define OFF_NEB   (OFF_TB + (size_t)BN*128)         // node_enc bfp
#define OFF_NEF   (OFF_NEB + (size_t)BN*128)        // node_enc f32
#define OFF_NF0B  (OFF_NEF + (size_t)BN*128)
#define OFF_NF1B  (OFF_NF0B + (size_t)BN*128)
#define OFF_NF0F  (OFF_NF1B + (size_t)BN*128)
#define OFF_NF1F  (OFF_NF0F + (size_t)BN*128)
#define OFF_AGG0  (OFF_NF1F + (size_t)BN*128)       // f32
#define OFF_AGG1  (OFF_AGG0 + (size_t)BN*128)       // f32
#define OFF_PH1   (OFF_AGG1 + (size_t)BN*128)       // bfp
#define OFF_PH2   (OFF_PH1 + (size_t)BN*128)        // f32
#define OFF_PRS   (OFF_PH2 + (size_t)BN*128)        // [BN,256] f32 (x@Wr | x@Ws)
#define OFF_PRPSP (OFF_PRS + (size_t)BN*256)        // [BN,256] f32 (nf@ep_r | nf@ep_s)
#define OFF_TE2   (OFF_PRPSP + (size_t)BN*256)      // [BE,128] bfp
#define OFF_EC    (OFF_TE2 + (size_t)BE*128)        // f32
#define ARENA_U32 (OFF_EC + (size_t)BE*128)

__device__ uint32_t g_arena[ARENA_U32];
__device__ int g_recv[BE];
__device__ int g_send[BE];
__device__ float g_zero[256];   // zero-init: zero bias

// split/transposed weights [n][kpad] bf16, 11 matrices (some N=256 packed)
#define WT_TOTAL 221184
__device__ __nv_bfloat16 g_whi[WT_TOTAL];
__device__ __nv_bfloat16 g_wlo[WT_TOTAL];

// ---------------- helpers ----------------
__device__ __forceinline__ uint32_t smem_u32(const void* p) {
    uint32_t a;
    asm("{ .reg .u64 t; cvta.to.shared.u64 t, %1; cvt.u32.u64 %0, t; }" : "=r"(a) : "l"(p));
    return a;
}

#define LDMX4(r, ad) \
    asm volatile("ldmatrix.sync.aligned.m8n8.x4.shared.b16 {%0,%1,%2,%3}, [%4];" \
        : "=r"((r)[0]), "=r"((r)[1]), "=r"((r)[2]), "=r"((r)[3]) : "r"(ad))

#define MMA16816(d, av, bv) \
    asm volatile("mma.sync.aligned.m16n8k16.row.col.f32.bf16.bf16.f32 " \
        "{%0,%1,%2,%3},{%4,%5,%6,%7},{%8,%9},{%0,%1,%2,%3};" \
        : "+f"((d)[0]), "+f"((d)[1]), "+f"((d)[2]), "+f"((d)[3]) \
        : "r"((av)[0]), "r"((av)[1]), "r"((av)[2]), "r"((av)[3]), \
          "r"((bv)[0]), "r"((bv)[1]))

__device__ __forceinline__ uint32_t packbfp(float v) {
    __nv_bfloat16 h = __float2bfloat16(v);
    float hf = __bfloat162float(h);
    __nv_bfloat16 l = __float2bfloat16(v - hf);
    return (uint32_t)__bfloat16_as_ushort(h) | ((uint32_t)__bfloat16_as_ushort(l) << 16);
}

// ---------------- aux kernels ----------------
__global__ void extract_idx2_kernel(const float* __restrict__ Rr,
                                    const float* __restrict__ Rs,
                                    int* __restrict__ recv, int* __restrict__ send)
{
    int row = blockIdx.x * 8 + (threadIdx.x >> 5);
    int lane = threadIdx.x & 31;
    const float* R = (row < BE) ? Rr : Rs;
    int r = (row < BE) ? row : row - BE;
    const float4* p = (const float4*)(R + (size_t)r * Nn);
    int found = 0;
    #pragma unroll
    for (int i = 0; i < 8; i++) {
        int q = lane + i * 32;
        float4 v = p[q];
        if (v.x > 0.5f) found = q * 4 + 0;
        if (v.y > 0.5f) found = q * 4 + 1;
        if (v.z > 0.5f) found = q * 4 + 2;
        if (v.w > 0.5f) found = q * 4 + 3;
    }
    #pragma unroll
    for (int o = 16; o; o >>= 1) found = max(found, __shfl_xor_sync(0xFFFFFFFFu, found, o));
    if (lane == 0) {
        if (row < BE) recv[r] = found; else send[r] = found;
    }
}

// matrices: 0 ne0  1 ne1  2 ne2  3 eers(256)  4 ee1  5 ee2
//           6 ep_e 7 ep_rs(256) 8 np 9 pp0 10 pp1
struct PArg { const float* W[11]; };
__constant__ int c_Ks[11]  = {32,128,128, 32,128,128,128,128,256,256,128};
__constant__ int c_Kps[11] = {64,128,128, 64,128,128,128,128,256,256,128};
__constant__ int c_Rs[11]  = {128,128,128,256,128,128,128,256,128,128,128};
__constant__ int c_r0a[11] = {0,0,0,0,0,0,0,128,0,0,0};
__constant__ int c_r0b[11] = {0,0,0,32,0,0,0,256,0,0,0};
__constant__ int c_off[11] = {0,8192,24576,40960,57344,73728,90112,106496,139264,172032,204800};

__global__ void prep_weights(PArg a, __nv_bfloat16* __restrict__ hi, __nv_bfloat16* __restrict__ lo)
{
    int mid = blockIdx.x;
    int K = c_Ks[mid], Kp = c_Kps[mid], R = c_Rs[mid];
    int r0a = c_r0a[mid], r0b = c_r0b[mid];
    const float* W = a.W[mid];
    __nv_bfloat16* dh = hi + c_off[mid];
    __nv_bfloat16* dl = lo + c_off[mid];
    int total = R * Kp;
    for (int i = threadIdx.x + blockIdx.y * blockDim.x; i < total; i += blockDim.x * gridDim.y) {
        int n = i / Kp, k = i - n * Kp;
        int col = n & 127;
        int r0 = (n >> 7) ? r0b : r0a;
        float v = (k < K) ? W[(size_t)(r0 + k) * 128 + col] : 0.f;
        __nv_bfloat16 h = __float2bfloat16(v);
        dh[i] = h;
        dl[i] = __float2bfloat16(v - __bfloat162float(h));
    }
}

// edge effect + scatter: v = relu(ec[e] + prp[recv] + psp[send] + b); agg[recv] += v
__global__ void fused_scatter_kernel(const float* __restrict__ ec,
                                     const float* __restrict__ prpsp,
                                     const int* __restrict__ recv,
                                     const int* __restrict__ send,
                                     const float* __restrict__ bias,
                                     float* __restrict__ agg)
{
    int t = blockIdx.x * blockDim.x + threadIdx.x;
    if (t >= BE * 128) return;
    int e = t >> 7, h = t & 127;
    int bo = (e >> 13) << 10;
    int r = __ldg(recv + e) + bo, s = __ldg(send + e) + bo;
    float v = ec[t] + prpsp[(size_t)r * 256 + h] + prpsp[(size_t)s * 256 + 128 + h] + __ldg(bias + h);
    v = fmaxf(v, 0.f);
    atomicAdd(&agg[(size_t)r * 128 + h], v);
}

__global__ void gemm_out3_kernel(const float* __restrict__ A,
                                 const float* __restrict__ W,
                                 const float* __restrict__ b,
                                 float* __restrict__ out)
{
    int t = blockIdx.x * blockDim.x + threadIdx.x;
    if (t >= BN * 3) return;
    int m = t / 3, n = t - m * 3;
    const float* a = A + (size_t)m * 128;
    float s = b[n];
    #pragma unroll 16
    for (int k = 0; k < 128; k++) s += a[k] * W[k * 3 + n];
    out[t] = s;
}

// ---------------- HMMA GEMM ----------------
// A segment modes: 0 zeros  1 bfp direct  3 f32 direct  4 edge-layer0 compute
struct Seg { const void* p; const int* idx; const int* idx2; const float* ebias;
             int start; int mode; int rs; };
struct GArg {
    Seg s0, s1, s2;
    int K;
    const __nv_bfloat16 *Bhi, *Blo;
    const float* bias;
    const float* resid;
    float* outf;
    uint32_t* outb;
    int ldo;
    int relu;
};

template<int MT, int NT, int KCH>
__global__ __launch_bounds__(256) void hgemm(GArg a)
{
    constexpr int RT = MT * 32;
    constexpr int STRIDE = KCH * 2 + 16;
    constexpr int ALO = RT * STRIDE;
    constexpr int BHI = 2 * RT * STRIDE;
    constexpr int BPL = NT * 128 * STRIDE;
    extern __shared__ char smem[];
    const uint32_t sb = smem_u32(smem);
    const int tid = threadIdx.x;
    const int wid = tid >> 5, lane = tid & 31;
    const int wm = wid & 1, wn = wid >> 1;
    const int m0 = blockIdx.x * RT;

    float acc[MT][NT * 4][4];
    #pragma unroll
    for (int mt = 0; mt < MT; mt++)
        #pragma unroll
        for (int st = 0; st < NT * 4; st++)
            #pragma unroll
            for (int r = 0; r < 4; r++) acc[mt][st][r] = 0.f;

    const int nchunks = a.K / KCH;
    for (int c = 0; c < nchunks; c++) {
        const int k0 = c * KCH;
        #pragma unroll
        for (int it = 0; it < MT * KCH / 32; it++) {
            int item = tid + (it << 8);
            int r = item / (KCH / 4), g = item % (KCH / 4);
            int kc = k0 + (g << 2);
            int m = m0 + r;
            uint32_t p0, p1, p2, p3;
            Seg sg = (kc >= a.s2.start) ? a.s2 : ((kc >= a.s1.start) ? a.s1 : a.s0);
            if (sg.mode == 0) {
                p0 = p1 = p2 = p3 = 0u;
            } else if (sg.mode == 4) {
                int bo = (m >> 13) << 10;
                int rr = __ldg(sg.idx + m) + bo, ss = __ldg(sg.idx2 + m) + bo;
                int kk = kc - sg.start;
                float4 pr = *(const float4*)((const float*)sg.p + (size_t)rr * 256 + kk);
                float4 ps = *(const float4*)((const float*)sg.p + (size_t)ss * 256 + 128 + kk);
                float4 bb = *(const float4*)(sg.ebias + kk);
                p0 = packbfp(fmaxf(pr.x + ps.x + bb.x, 0.f));
                p1 = packbfp(fmaxf(pr.y + ps.y + bb.y, 0.f));
                p2 = packbfp(fmaxf(pr.z + ps.z + bb.z, 0.f));
                p3 = packbfp(fmaxf(pr.w + ps.w + bb.w, 0.f));
            } else {
                long base = (long)m * sg.rs + (kc - sg.start);
                if (sg.mode == 3) {
                    float4 v = *((const float4*)sg.p + (base >> 2));
                    p0 = packbfp(v.x); p1 = packbfp(v.y); p2 = packbfp(v.z); p3 = packbfp(v.w);
                } else {
                    uint4 v = *((const uint4*)sg.p + (base >> 2));
                    p0 = v.x; p1 = v.y; p2 = v.z; p3 = v.w;
                }
            }
            uint32_t hi01 = (p0 & 0xffffu) | (p1 << 16);
            uint32_t hi23 = (p2 & 0xffffu) | (p3 << 16);
            uint32_t lo01 = (p0 >> 16) | (p1 & 0xffff0000u);
            uint32_t lo23 = (p2 >> 16) | (p3 & 0xffff0000u);
            int off = r * STRIDE + g * 8;
            *(uint2*)(smem + off) = make_uint2(hi01, hi23);
            *(uint2*)(smem + ALO + off) = make_uint2(lo01, lo23);
        }
        #pragma unroll
        for (int it = 0; it < NT * KCH / 16; it++) {
            int item = tid + (it << 8);
            int n = item / (KCH / 8), g = item % (KCH / 8);
            size_t goff = (size_t)n * a.K + k0 + (g << 3);
            int off = n * STRIDE + g * 16;
            *(uint4*)(smem + BHI + off) = *(const uint4*)(a.Bhi + goff);
            *(uint4*)(smem + BHI + BPL + off) = *(const uint4*)(a.Blo + goff);
        }
        __syncthreads();

        #pragma unroll
        for (int ks = 0; ks < KCH / 16; ks++) {
            uint32_t bh[NT * 8], bl[NT * 8];
            #pragma unroll
            for (int t2 = 0; t2 < NT; t2++)
                #pragma unroll
                for (int np = 0; np < 2; np++) {
                    int n = t2 * 128 + wn * 32 + np * 16 + ((lane >> 4) << 3) + (lane & 7);
                    int koff = ((lane >> 3) & 1) << 3;
                    uint32_t ad = sb + BHI + n * STRIDE + (ks * 16 + koff) * 2;
                    LDMX4(&bh[(t2 * 2 + np) * 4], ad);
                    LDMX4(&bl[(t2 * 2 + np) * 4], ad + BPL);
                }
            #pragma unroll
            for (int mt = 0; mt < MT; mt++) {
                int r = wm * MT * 16 + mt * 16 + (lane & 15);
                int koff = (lane >> 4) << 3;
                uint32_t ad = sb + r * STRIDE + (ks * 16 + koff) * 2;
                uint32_t ah[4], al[4];
                LDMX4(ah, ad);
                LDMX4(al, ad + ALO);
                #pragma unroll
                for (int st = 0; st < NT * 4; st++) {
                    MMA16816(acc[mt][st], ah, &bh[st * 2]);
                    MMA16816(acc[mt][st], ah, &bl[st * 2]);
                    MMA16816(acc[mt][st], al, &bh[st * 2]);
                }
            }
        }
        __syncthreads();
    }

    #pragma unroll
    for (int mt = 0; mt < MT; mt++) {
        int row0 = m0 + wm * MT * 16 + mt * 16 + (lane >> 2);
        #pragma unroll
        for (int st = 0; st < NT * 4; st++) {
            int n = (st >> 2) * 128 + wn * 32 + (st & 3) * 8 + ((lane & 3) << 1);
            float b0 = __ldg(a.bias + n), b1 = __ldg(a.bias + n + 1);
            #pragma unroll
            for (int h = 0; h < 2; h++) {
                int m = row0 + h * 8;
                float s0 = acc[mt][st][h * 2 + 0] + b0;
                float s1 = acc[mt][st][h * 2 + 1] + b1;
                if (a.resid) {
                    float2 rv = *(const float2*)(a.resid + (size_t)m * 128 + n);
                    s0 += rv.x; s1 += rv.y;
                }
                if (a.relu) { s0 = fmaxf(s0, 0.f); s1 = fmaxf(s1, 0.f); }
                if (a.outf) *(float2*)(a.outf + (size_t)m * a.ldo + n) = make_float2(s0, s1);
                if (a.outb) *(uint2*)(a.outb + (size_t)m * a.ldo + n) = make_uint2(packbfp(s0), packbfp(s1));
            }
        }
    }
}

constexpr int smem_sz(int MT, int NT, int KCH) {
    return (2 * MT * 32 + 2 * NT * 128) * (KCH * 2 + 16);
}

// ---------------- fused ee2 + ec kernel ----------------
// per 64-row edge tile: h = relu(A @ W1 + b1); ec_out = h @ W2 (no bias/relu)
#define EESTRIDE 272
#define EE_ALO   (64 * EESTRIDE)                 // 17408
#define EE_B1HI  (2 * EE_ALO)                    // 34816
#define EE_BPL   (128 * EESTRIDE)                // 34816
#define EE_SMEM  (EE_B1HI + 4 * EE_BPL)          // 174080

__global__ __launch_bounds__(256) void hgemm_ee2ec(
    const uint32_t* __restrict__ Abfp,
    const __nv_bfloat16* __restrict__ B1hi, const __nv_bfloat16* __restrict__ B1lo,
    const float* __restrict__ b1,
    const __nv_bfloat16* __restrict__ B2hi, const __nv_bfloat16* __restrict__ B2lo,
    float* __restrict__ outf)
{
    extern __shared__ char smem[];
    const uint32_t sb = smem_u32(smem);
    const int tid = threadIdx.x;
    const int wid = tid >> 5, lane = tid & 31;
    const int wm = wid & 1, wn = wid >> 1;
    const int m0 = blockIdx.x * 64;

    float acc[2][4][4];
    #pragma unroll
    for (int mt = 0; mt < 2; mt++)
        #pragma unroll
        for (int st = 0; st < 4; st++)
            #pragma unroll
            for (int r = 0; r < 4; r++) acc[mt][st][r] = 0.f;

    // load A tile (bfp direct)
    #pragma unroll
    for (int it = 0; it < 8; it++) {
        int item = tid + (it << 8);
        int r = item >> 5, g = item & 31;
        uint4 v = *((const uint4*)Abfp + ((((size_t)(m0 + r) << 7) + (g << 2)) >> 2));
        uint32_t hi01 = (v.x & 0xffffu) | (v.y << 16);
        uint32_t hi23 = (v.z & 0xffffu) | (v.w << 16);
        uint32_t lo01 = (v.x >> 16) | (v.y & 0xffff0000u);
        uint32_t lo23 = (v.z >> 16) | (v.w & 0xffff0000u);
        int off = r * EESTRIDE + g * 8;
        *(uint2*)(smem + off) = make_uint2(hi01, hi23);
        *(uint2*)(smem + EE_ALO + off) = make_uint2(lo01, lo23);
    }
    // load both weight sets
    #pragma unroll
    for (int it = 0; it < 8; it++) {
        int item = tid + (it << 8);
        int n = item >> 4, g = item & 15;
        size_t goff = ((size_t)n << 7) + (g << 3);
        int off = n * EESTRIDE + g * 16;
        *(uint4*)(smem + EE_B1HI + off)              = *(const uint4*)(B1hi + goff);
        *(uint4*)(smem + EE_B1HI + EE_BPL + off)     = *(const uint4*)(B1lo + goff);
        *(uint4*)(smem + EE_B1HI + 2 * EE_BPL + off) = *(const uint4*)(B2hi + goff);
        *(uint4*)(smem + EE_B1HI + 3 * EE_BPL + off) = *(const uint4*)(B2lo + goff);
    }
    __syncthreads();

    // ---- phase 1 & 2 mma ----
    #pragma unroll
    for (int phase = 0; phase < 2; phase++) {
        const uint32_t bbase = sb + EE_B1HI + (phase ? 2 * EE_BPL : 0);
        #pragma unroll
        for (int ks = 0; ks < 8; ks++) {
            uint32_t bh[8], bl[8];
            #pragma unroll
            for (int np = 0; np < 2; np++) {
                int n = wn * 32 + np * 16 + ((lane >> 4) << 3) + (lane & 7);
                int koff = ((lane >> 3) & 1) << 3;
                uint32_t ad = bbase + n * EESTRIDE + (ks * 16 + koff) * 2;
                LDMX4(&bh[np * 4], ad);
                LDMX4(&bl[np * 4], ad + EE_BPL);
            }
            #pragma unroll
            for (int mt = 0; mt < 2; mt++) {
                int r = wm * 32 + mt * 16 + (lane & 15);
                int koff = (lane >> 4) << 3;
                uint32_t ad = sb + r * EESTRIDE + (ks * 16 + koff) * 2;
                uint32_t ah[4], al[4];
                LDMX4(ah, ad);
                LDMX4(al, ad + EE_ALO);
                #pragma unroll
                for (int st = 0; st < 4; st++) {
                    MMA16816(acc[mt][st], ah, &bh[st * 2]);
                    MMA16816(acc[mt][st], ah, &bl[st * 2]);
                    MMA16816(acc[mt][st], al, &bh[st * 2]);
                }
            }
        }
        if (phase == 0) {
            // epilogue 1: relu(acc+b1) -> repack bfp into A planes
            __syncthreads();
            #pragma unroll
            for (int mt = 0; mt < 2; mt++) {
                int r0 = wm * 32 + mt * 16 + (lane >> 2);
                #pragma unroll
                for (int st = 0; st < 4; st++) {
                    int n = wn * 32 + st * 8 + ((lane & 3) << 1);
                    float c0 = __ldg(b1 + n), c1 = __ldg(b1 + n + 1);
                    #pragma unroll
                    for (int h = 0; h < 2; h++) {
                        int r = r0 + h * 8;
                        float s0 = fmaxf(acc[mt][st][h * 2 + 0] + c0, 0.f);
                        float s1 = fmaxf(acc[mt][st][h * 2 + 1] + c1, 0.f);
                        uint32_t p0 = packbfp(s0), p1 = packbfp(s1);
                        int off = r * EESTRIDE + n * 2;
                        *(uint32_t*)(smem + off) = (p0 & 0xffffu) | (p1 << 16);
                        *(uint32_t*)(smem + EE_ALO + off) = (p0 >> 16) | (p1 & 0xffff0000u);
                        acc[mt][st][h * 2 + 0] = 0.f;
                        acc[mt][st][h * 2 + 1] = 0.f;
                    }
                }
            }
            __syncthreads();
        }
    }

    // epilogue 2: write ec (f32, no bias/relu)
    #pragma unroll
    for (int mt = 0; mt < 2; mt++) {
        int row0 = m0 + wm * 32 + mt * 16 + (lane >> 2);
        #pragma unroll
        for (int st = 0; st < 4; st++) {
            int n = wn * 32 + st * 8 + ((lane & 3) << 1);
            #pragma unroll
            for (int h = 0; h < 2; h++) {
                int m = row0 + h * 8;
                *(float2*)(outf + ((size_t)m << 7) + n) =
                    make_float2(acc[mt][st][h * 2 + 0], acc[mt][st][h * 2 + 1]);
            }
        }
    }
}

// ---------------- launch ----------------
static inline Seg segd(const void* p, int start, int mode, int rs,
                       const int* idx = nullptr, const int* idx2 = nullptr,
                       const float* eb = nullptr) {
    Seg s; s.p = p; s.idx = idx; s.idx2 = idx2; s.ebias = eb;
    s.start = start; s.mode = mode; s.rs = rs; return s;
}
static inline Seg segnone() { return segd(nullptr, 0x40000000, 0, 0); }

extern "C" void kernel_launch(void* const* d_in, const int* in_sizes, int n_in,
                              void* d_out, int out_size)
{
    const float* x    = (const float*)d_in[0];
    const float* Rr   = (const float*)d_in[1];
    const float* Rs   = (const float*)d_in[2];
    const float* neW0 = (const float*)d_in[4];  const float* neb0 = (const float*)d_in[5];
    const float* neW1 = (const float*)d_in[6];  const float* neb1 = (const float*)d_in[7];
    const float* neW2 = (const float*)d_in[8];  const float* neb2 = (const float*)d_in[9];
    const float* eeW0 = (const float*)d_in[10]; const float* eeb0 = (const float*)d_in[11];
    const float* eeW1 = (const float*)d_in[12]; const float* eeb1 = (const float*)d_in[13];
    const float* eeW2 = (const float*)d_in[14]; const float* eeb2 = (const float*)d_in[15];
    const float* npW  = (const float*)d_in[16]; const float* npb  = (const float*)d_in[17];
    const float* epW  = (const float*)d_in[18]; const float* epb  = (const float*)d_in[19];
    const float* ppW0 = (const float*)d_in[20]; const float* ppb0 = (const float*)d_in[21];
    const float* ppW1 = (const float*)d_in[22]; const float* ppb1 = (const float*)d_in[23];
    const float* ppW2 = (const float*)d_in[24]; const float* ppb2 = (const float*)d_in[25];
    float* out = (float*)d_out;

    uint32_t* arena; cudaGetSymbolAddress((void**)&arena, g_arena);
    int* recv; cudaGetSymbolAddress((void**)&recv, g_recv);
    int* send; cudaGetSymbolAddress((void**)&send, g_send);
    __nv_bfloat16* whi; cudaGetSymbolAddress((void**)&whi, g_whi);
    __nv_bfloat16* wlo; cudaGetSymbolAddress((void**)&wlo, g_wlo);
    float* zb; cudaGetSymbolAddress((void**)&zb, g_zero);

    uint32_t* tA    = arena + OFF_TA;
    uint32_t* tB    = arena + OFF_TB;
    uint32_t* neb   = arena + OFF_NEB;
    float*    nef   = (float*)(arena + OFF_NEF);
    uint32_t* nf0b  = arena + OFF_NF0B;
    uint32_t* nf1b  = arena + OFF_NF1B;
    float*    nf0f  = (float*)(arena + OFF_NF0F);
    float*    nf1f  = (float*)(arena + OFF_NF1F);
    float*    agg0  = (float*)(arena + OFF_AGG0);
    float*    agg1  = (float*)(arena + OFF_AGG1);
    uint32_t* ph1   = arena + OFF_PH1;
    float*    ph2   = (float*)(arena + OFF_PH2);
    float*    prs   = (float*)(arena + OFF_PRS);
    float*    prpsp = (float*)(arena + OFF_PRPSP);
    uint32_t* tE2   = arena + OFF_TE2;
    float*    ec    = (float*)(arena + OFF_EC);

    const int WO[11] = {0,8192,24576,40960,57344,73728,90112,106496,139264,172032,204800};

    // one-time host-side setup (first call is the un-captured correctness run;
    // device work per call is identical regardless)
    static bool s_init = false;
    static cudaStream_t s1, s2;
    static cudaEvent_t evRoot, evS1, evNE;
    if (!s_init) {
        cudaStreamCreateWithFlags(&s1, cudaStreamNonBlocking);
        cudaStreamCreateWithFlags(&s2, cudaStreamNonBlocking);
        cudaEventCreateWithFlags(&evRoot, cudaEventDisableTiming);
        cudaEventCreateWithFlags(&evS1,   cudaEventDisableTiming);
        cudaEventCreateWithFlags(&evNE,   cudaEventDisableTiming);
        cudaFuncSetAttribute(hgemm<1,1,64>,  cudaFuncAttributeMaxDynamicSharedMemorySize, smem_sz(1,1,64));
        cudaFuncSetAttribute(hgemm<1,1,128>, cudaFuncAttributeMaxDynamicSharedMemorySize, smem_sz(1,1,128));
        cudaFuncSetAttribute(hgemm<1,2,64>,  cudaFuncAttributeMaxDynamicSharedMemorySize, smem_sz(1,2,64));
        cudaFuncSetAttribute(hgemm<1,2,128>, cudaFuncAttributeMaxDynamicSharedMemorySize, smem_sz(1,2,128));
        cudaFuncSetAttribute(hgemm<2,1,128>, cudaFuncAttributeMaxDynamicSharedMemorySize, smem_sz(2,1,128));
        cudaFuncSetAttribute(hgemm_ee2ec,    cudaFuncAttributeMaxDynamicSharedMemorySize, EE_SMEM);
        s_init = true;
    }

    // ---- origin stream: weight prep, then fork ----
    PArg pa;
    pa.W[0] = neW0; pa.W[1] = neW1; pa.W[2] = neW2;
    pa.W[3] = eeW0; pa.W[4] = eeW1; pa.W[5] = eeW2;
    pa.W[6] = epW;  pa.W[7] = epW;
    pa.W[8] = npW;  pa.W[9] = ppW0; pa.W[10] = ppW1;
    prep_weights<<<dim3(11, 8), 256>>>(pa, whi, wlo);
    cudaEventRecord(evRoot, 0);

    // fork: s1 and s2 branch from the capture origin
    cudaStreamWaitEvent(s1, evRoot, 0);
    cudaStreamWaitEvent(s2, evRoot, 0);

    // s1: index extraction + agg pre-zero
    extract_idx2_kernel<<<2 * BE / 8, 256, 0, s1>>>(Rr, Rs, recv, send);
    cudaMemsetAsync(agg0, 0, (size_t)BN * 128 * sizeof(float), s1);
    cudaMemsetAsync(agg1, 0, (size_t)BN * 128 * sizeof(float), s1);
    cudaEventRecord(evS1, s1);

    // s2: node encoder chain
    {
        GArg a;
        a.resid = nullptr; a.outf = nullptr; a.outb = nullptr; a.relu = 1; a.ldo = 128;
        a.s0 = segd(x, 0, 3, 32); a.s1 = segd(nullptr, 32, 0, 0); a.s2 = segnone();
        a.K = 64; a.Bhi = whi + WO[0]; a.Blo = wlo + WO[0]; a.bias = neb0; a.outb = tA;
        hgemm<1,1,64><<<BN / 32, 256, smem_sz(1,1,64), s2>>>(a);

        a.s0 = segd(tA, 0, 1, 128); a.s1 = segnone();
        a.K = 128; a.Bhi = whi + WO[1]; a.Blo = wlo + WO[1]; a.bias = neb1; a.outb = tB;
        hgemm<1,1,128><<<BN / 32, 256, smem_sz(1,1,128), s2>>>(a);

        a.s0 = segd(tB, 0, 1, 128);
        a.Bhi = whi + WO[2]; a.Blo = wlo + WO[2]; a.bias = neb2; a.outb = neb; a.outf = nef;
        hgemm<1,1,128><<<BN / 32, 256, smem_sz(1,1,128), s2>>>(a);
    }
    cudaEventRecord(evNE, s2);

    GArg a;
    a.resid = nullptr; a.outf = nullptr; a.outb = nullptr; a.relu = 1; a.ldo = 128;

    // origin: PrPs = x @ [eer|ees]
    a.s0 = segd(x, 0, 3, 32); a.s1 = segd(nullptr, 32, 0, 0); a.s2 = segnone();
    a.K = 64; a.Bhi = whi + WO[3]; a.Blo = wlo + WO[3]; a.bias = zb; a.relu = 0;
    a.outb = nullptr; a.outf = prs; a.ldo = 256;
    hgemm<1,2,64><<<BN / 32, 256, smem_sz(1,2,64)>>>(a);
    a.relu = 1; a.outf = nullptr; a.ldo = 128;

    // join: indices ready
    cudaStreamWaitEvent(0, evS1, 0);

    // ee1: A computed on the fly from prs via recv/send
    a.s0 = segd(prs, 0, 4, 256, recv, send, eeb0); a.s1 = segnone(); a.s2 = segnone();
    a.K = 128; a.Bhi = whi + WO[4]; a.Blo = wlo + WO[4]; a.bias = eeb1; a.outb = tE2;
    hgemm<2,1,128><<<BE / 64, 256, smem_sz(2,1,128)>>>(a);

    // fused ee2 + ec
    hgemm_ee2ec<<<BE / 64, 256, EE_SMEM>>>(tE2,
        whi + WO[5], wlo + WO[5], eeb2, whi + WO[6], wlo + WO[6], ec);

    // join: node encoder ready
    cudaStreamWaitEvent(0, evNE, 0);

    // propagation, pstep = 2
    const uint32_t* curb = neb; const float* curf = nef;
    uint32_t* nxtb = nf0b;      float* nxtf = nf0f;
    float* aggs[2] = {agg0, agg1};
    for (int step = 0; step < 2; step++) {
        a.s0 = segd(curb, 0, 1, 128); a.s1 = segnone(); a.s2 = segnone();
        a.K = 128; a.Bhi = whi + WO[7]; a.Blo = wlo + WO[7]; a.bias = zb;
        a.relu = 0; a.outb = nullptr; a.outf = prpsp; a.ldo = 256;
        hgemm<1,2,128><<<BN / 32, 256, smem_sz(1,2,128)>>>(a);
        a.relu = 1; a.outf = nullptr; a.ldo = 128;

        fused_scatter_kernel<<<BE * 128 / 256, 256>>>(ec, prpsp, recv, send, epb, aggs[step]);

        a.s0 = segd(neb, 0, 1, 128);
        a.s1 = segd(aggs[step], 128, 3, 128);
        a.s2 = segnone();
        a.K = 256; a.Bhi = whi + WO[8]; a.Blo = wlo + WO[8]; a.bias = npb;
        a.resid = curf; a.outf = nxtf; a.outb = nxtb;
        hgemm<1,1,128><<<BN / 32, 256, smem_sz(1,1,128)>>>(a);
        a.resid = nullptr; a.outf = nullptr;

        curb = nxtb; curf = nxtf;
        nxtb = nf1b; nxtf = nf1f;
    }

    // predictor
    a.s0 = segd(neb, 0, 1, 128); a.s1 = segd(curb, 128, 1, 128); a.s2 = segnone();
    a.K = 256; a.Bhi = whi + WO[9]; a.Blo = wlo + WO[9]; a.bias = ppb0;
    a.outb = ph1;
    hgemm<1,1,128><<<BN / 32, 256, smem_sz(1,1,128)>>>(a);

    a.s0 = segd(ph1, 0, 1, 128); a.s1 = segnone();
    a.K = 128; a.Bhi = whi + WO[10]; a.Blo = wlo + WO[10]; a.bias = ppb1;
    a.outf = ph2; a.outb = nullptr;
    hgemm<1,1,128><<<BN / 32, 256, smem_sz(1,1,128)>>>(a);

    gemm_out3_kernel<<<(BN * 3 + 255) / 256, 256>>>(ph2, ppW2, ppb2, out);
}

// round 8
// speedup vs baseline: 2.3315x; 1.0122x over previous
#include <cuda_runtime.h>
#include <cuda_bf16.h>
#include <cstdint>

// ---------------- problem dims ----------------
#define Nn 1024
#define Ee 8192
#define BN 4096    // B*N
#define BE 32768   // B*E

// ---------------- device scratch ----------------
#define OFF_TA     ((size_t)0)                       // [BN,128] bfp
#define OFF_TB     (OFF_TA + (size_t)BN*128)
#define OFF_NEB    (OFF_TB + (size_t)BN*128)         // node_enc bfp
#define OFF_NEF    (OFF_NEB + (size_t)BN*128)        // node_enc f32
#define OFF_NF1F   (OFF_NEF + (size_t)BN*128)        // nf1 f32
#define OFF_PC     (OFF_NF1F + (size_t)BN*128)       // neb@pp0a f32
#define OFF_AGG0   (OFF_PC + (size_t)BN*128)
#define OFF_AGG1   (OFF_AGG0 + (size_t)BN*128)
#define OFF_PRS    (OFF_AGG1 + (size_t)BN*128)       // [BN,256] f32 (x@Wr | x@Ws)
#define OFF_PRPSPA (OFF_PRS + (size_t)BN*256)        // [BN,256] f32 step0
#define OFF_PRPSPB (OFF_PRPSPA + (size_t)BN*256)     // [BN,256] f32 step1
#define OFF_TE2    (OFF_PRPSPB + (size_t)BN*256)     // [BE,128] bfp
#define OFF_EC     (OFF_TE2 + (size_t)BE*128)        // f32
#define ARENA_U32  (OFF_EC + (size_t)BE*128)

__device__ uint32_t g_arena[ARENA_U32];
__device__ int g_recv[BE];
__device__ int g_send[BE];
__device__ float g_zero[256];

// split/transposed weights [n][kpad] bf16, 12 matrices
#define WT_TOTAL 221184
__device__ __nv_bfloat16 g_whi[WT_TOTAL];
__device__ __nv_bfloat16 g_wlo[WT_TOTAL];

// ---------------- helpers ----------------
__device__ __forceinline__ uint32_t smem_u32(const void* p) {
    uint32_t a;
    asm("{ .reg .u64 t; cvta.to.shared.u64 t, %1; cvt.u32.u64 %0, t; }" : "=r"(a) : "l"(p));
    return a;
}

#define LDMX4(r, ad) \
    asm volatile("ldmatrix.sync.aligned.m8n8.x4.shared.b16 {%0,%1,%2,%3}, [%4];" \
        : "=r"((r)[0]), "=r"((r)[1]), "=r"((r)[2]), "=r"((r)[3]) : "r"(ad))

#define MMA16816(d, av, bv) \
    asm volatile("mma.sync.aligned.m16n8k16.row.col.f32.bf16.bf16.f32 " \
        "{%0,%1,%2,%3},{%4,%5,%6,%7},{%8,%9},{%0,%1,%2,%3};" \
        : "+f"((d)[0]), "+f"((d)[1]), "+f"((d)[2]), "+f"((d)[3]) \
        : "r"((av)[0]), "r"((av)[1]), "r"((av)[2]), "r"((av)[3]), \
          "r"((bv)[0]), "r"((bv)[1]))

__device__ __forceinline__ uint32_t packbfp(float v) {
    __nv_bfloat16 h = __float2bfloat16(v);
    float hf = __bfloat162float(h);
    __nv_bfloat16 l = __float2bfloat16(v - hf);
    return (uint32_t)__bfloat16_as_ushort(h) | ((uint32_t)__bfloat16_as_ushort(l) << 16);
}

// 3-pass emulated MMA over one K-span. A: one 16-row tile per warp half (wm).
// acc has NT*4 n-tiles. Strides in bytes.
template<int NT>
__device__ __forceinline__ void mma_span(
    uint32_t aHi, uint32_t aLo, uint32_t bHi, uint32_t bLo,
    int astr, int bstr, int nk, float (*acc)[4], int wm, int wn, int lane)
{
    for (int ks = 0; ks < nk; ks++) {
        uint32_t bh[NT * 8], bl[NT * 8];
        #pragma unroll
        for (int t2 = 0; t2 < NT; t2++)
            #pragma unroll
            for (int np = 0; np < 2; np++) {
                int n = t2 * 128 + wn * 32 + np * 16 + ((lane >> 4) << 3) + (lane & 7);
                int koff = ((lane >> 3) & 1) << 3;
                uint32_t ad = bHi + n * bstr + (ks * 16 + koff) * 2;
                LDMX4(&bh[(t2 * 2 + np) * 4], ad);
                LDMX4(&bl[(t2 * 2 + np) * 4], ad + (bLo - bHi));
            }
        int r = wm * 16 + (lane & 15);
        int koff = (lane >> 4) << 3;
        uint32_t ad = aHi + r * astr + (ks * 16 + koff) * 2;
        uint32_t ah[4], al[4];
        LDMX4(ah, ad);
        LDMX4(al, ad + (aLo - aHi));
        #pragma unroll
        for (int st = 0; st < NT * 4; st++) {
            MMA16816(acc[st], ah, &bh[st * 2]);
            MMA16816(acc[st], ah, &bl[st * 2]);
            MMA16816(acc[st], al, &bh[st * 2]);
        }
    }
}

// load both weight planes into smem
__device__ __forceinline__ void load_Bw(char* smem, int base, int plane,
    const __nv_bfloat16* Bhi, const __nv_bfloat16* Blo,
    int nrows, int kcols, int bstr, int tid)
{
    int kg = kcols >> 3;
    int per = nrows * kg;
    for (int item = tid; item < per; item += 256) {
        int n = item / kg, g = item - n * kg;
        size_t goff = (size_t)n * kcols + (g << 3);
        int so = base + n * bstr + (g << 4);
        *(uint4*)(smem + so) = *(const uint4*)(Bhi + goff);
        *(uint4*)(smem + so + plane) = *(const uint4*)(Blo + goff);
    }
}

// ---------------- aux kernels ----------------
__global__ void extract_idx2_kernel(const float* __restrict__ Rr,
                                    const float* __restrict__ Rs,
                                    int* __restrict__ recv, int* __restrict__ send)
{
    int row = blockIdx.x * 8 + (threadIdx.x >> 5);
    int lane = threadIdx.x & 31;
    const float* R = (row < BE) ? Rr : Rs;
    int r = (row < BE) ? row : row - BE;
    const float4* p = (const float4*)(R + (size_t)r * Nn);
    int found = 0;
    #pragma unroll
    for (int i = 0; i < 8; i++) {
        int q = lane + i * 32;
        float4 v = p[q];
        if (v.x > 0.5f) found = q * 4 + 0;
        if (v.y > 0.5f) found = q * 4 + 1;
        if (v.z > 0.5f) found = q * 4 + 2;
        if (v.w > 0.5f) found = q * 4 + 3;
    }
    #pragma unroll
    for (int o = 16; o; o >>= 1) found = max(found, __shfl_xor_sync(0xFFFFFFFFu, found, o));
    if (lane == 0) {
        if (row < BE) recv[r] = found; else send[r] = found;
    }
}

// matrices: 0 ne0 1 ne1 2 ne2 3 eers(R256) 4 ee1 5 ee2 6 ep_e 7 ep_rs(R256)
//           8 np(K256) 9 pp0a 10 pp0b 11 pp1
struct PArg { const float* W[12]; };
__constant__ int c_Ks[12]  = {32,128,128, 32,128,128,128,128,256,128,128,128};
__constant__ int c_Kps[12] = {64,128,128, 64,128,128,128,128,256,128,128,128};
__constant__ int c_Rs[12]  = {128,128,128,256,128,128,128,256,128,128,128,128};
__constant__ int c_r0a[12] = {0,0,0,0,0,0,0,128,0,0,128,0};
__constant__ int c_r0b[12] = {0,0,0,32,0,0,0,256,0,0,0,0};
__constant__ int c_off[12] = {0,8192,24576,40960,57344,73728,90112,106496,139264,172032,188416,204800};

__global__ void prep_weights(PArg a, __nv_bfloat16* __restrict__ hi, __nv_bfloat16* __restrict__ lo)
{
    int mid = blockIdx.x;
    int K = c_Ks[mid], Kp = c_Kps[mid], R = c_Rs[mid];
    int r0a = c_r0a[mid], r0b = c_r0b[mid];
    const float* W = a.W[mid];
    __nv_bfloat16* dh = hi + c_off[mid];
    __nv_bfloat16* dl = lo + c_off[mid];
    int total = R * Kp;
    for (int i = threadIdx.x + blockIdx.y * blockDim.x; i < total; i += blockDim.x * gridDim.y) {
        int n = i / Kp, k = i - n * Kp;
        int col = n & 127;
        int r0 = (n >> 7) ? r0b : r0a;
        float v = (k < K) ? W[(size_t)(r0 + k) * 128 + col] : 0.f;
        __nv_bfloat16 h = __float2bfloat16(v);
        dh[i] = h;
        dl[i] = __float2bfloat16(v - __bfloat162float(h));
    }
}

// step-1 scatter: v = relu(ec[e] + prp[recv] + psp[send] + b); agg[recv] += v
__global__ void fused_scatter_kernel(const float* __restrict__ ec,
                                     const float* __restrict__ prpsp,
                                     const int* __restrict__ recv,
                                     const int* __restrict__ send,
                                     const float* __restrict__ bias,
                                     float* __restrict__ agg)
{
    int t = blockIdx.x * blockDim.x + threadIdx.x;
    if (t >= BE * 128) return;
    int e = t >> 7, h = t & 127;
    int bo = (e >> 13) << 10;
    int r = __ldg(recv + e) + bo, s = __ldg(send + e) + bo;
    float v = ec[t] + prpsp[(size_t)r * 256 + h] + prpsp[(size_t)s * 256 + 128 + h] + __ldg(bias + h);
    v = fmaxf(v, 0.f);
    atomicAdd(&agg[(size_t)r * 128 + h], v);
}

// ---------------- generic HMMA GEMM (unchanged core) ----------------
struct Seg { const void* p; const int* idx; const int* idx2; const float* ebias;
             int start; int mode; int rs; };
struct GArg {
    Seg s0, s1, s2;
    int K;
    const __nv_bfloat16 *Bhi, *Blo;
    const float* bias;
    const float* resid;
    float* outf;
    uint32_t* outb;
    int ldo;
    int relu;
};

template<int MT, int NT, int KCH>
__global__ __launch_bounds__(256) void hgemm(GArg a)
{
    constexpr int RT = MT * 32;
    constexpr int STRIDE = KCH * 2 + 16;
    constexpr int ALO = RT * STRIDE;
    constexpr int BHI = 2 * RT * STRIDE;
    constexpr int BPL = NT * 128 * STRIDE;
    extern __shared__ char smem[];
    const uint32_t sb = smem_u32(smem);
    const int tid = threadIdx.x;
    const int wid = tid >> 5, lane = tid & 31;
    const int wm = wid & 1, wn = wid >> 1;
    const int m0 = blockIdx.x * RT;

    float acc[MT][NT * 4][4];
    #pragma unroll
    for (int mt = 0; mt < MT; mt++)
        #pragma unroll
        for (int st = 0; st < NT * 4; st++)
            #pragma unroll
            for (int r = 0; r < 4; r++) acc[mt][st][r] = 0.f;

    const int nchunks = a.K / KCH;
    for (int c = 0; c < nchunks; c++) {
        const int k0 = c * KCH;
        #pragma unroll
        for (int it = 0; it < MT * KCH / 32; it++) {
            int item = tid + (it << 8);
            int r = item / (KCH / 4), g = item % (KCH / 4);
            int kc = k0 + (g << 2);
            int m = m0 + r;
            uint32_t p0, p1, p2, p3;
            Seg sg = (kc >= a.s2.start) ? a.s2 : ((kc >= a.s1.start) ? a.s1 : a.s0);
            if (sg.mode == 0) {
                p0 = p1 = p2 = p3 = 0u;
            } else if (sg.mode == 4) {
                int bo = (m >> 13) << 10;
                int rr = __ldg(sg.idx + m) + bo, ss = __ldg(sg.idx2 + m) + bo;
                int kk = kc - sg.start;
                float4 pr = *(const float4*)((const float*)sg.p + (size_t)rr * 256 + kk);
                float4 ps = *(const float4*)((const float*)sg.p + (size_t)ss * 256 + 128 + kk);
                float4 bb = *(const float4*)(sg.ebias + kk);
                p0 = packbfp(fmaxf(pr.x + ps.x + bb.x, 0.f));
                p1 = packbfp(fmaxf(pr.y + ps.y + bb.y, 0.f));
                p2 = packbfp(fmaxf(pr.z + ps.z + bb.z, 0.f));
                p3 = packbfp(fmaxf(pr.w + ps.w + bb.w, 0.f));
            } else {
                long base = (long)m * sg.rs + (kc - sg.start);
                if (sg.mode == 3) {
                    float4 v = *((const float4*)sg.p + (base >> 2));
                    p0 = packbfp(v.x); p1 = packbfp(v.y); p2 = packbfp(v.z); p3 = packbfp(v.w);
                } else {
                    uint4 v = *((const uint4*)sg.p + (base >> 2));
                    p0 = v.x; p1 = v.y; p2 = v.z; p3 = v.w;
                }
            }
            uint32_t hi01 = (p0 & 0xffffu) | (p1 << 16);
            uint32_t hi23 = (p2 & 0xffffu) | (p3 << 16);
            uint32_t lo01 = (p0 >> 16) | (p1 & 0xffff0000u);
            uint32_t lo23 = (p2 >> 16) | (p3 & 0xffff0000u);
            int off = r * STRIDE + g * 8;
            *(uint2*)(smem + off) = make_uint2(hi01, hi23);
            *(uint2*)(smem + ALO + off) = make_uint2(lo01, lo23);
        }
        #pragma unroll
        for (int it = 0; it < NT * KCH / 16; it++) {
            int item = tid + (it << 8);
            int n = item / (KCH / 8), g = item % (KCH / 8);
            size_t goff = (size_t)n * a.K + k0 + (g << 3);
            int off = n * STRIDE + g * 16;
            *(uint4*)(smem + BHI + off) = *(const uint4*)(a.Bhi + goff);
            *(uint4*)(smem + BHI + BPL + off) = *(const uint4*)(a.Blo + goff);
        }
        __syncthreads();
        #pragma unroll
        for (int mt = 0; mt < MT; mt++)
            mma_span<NT>(sb + mt * 0, sb + ALO, sb + BHI, sb + BHI + BPL,
                         STRIDE, STRIDE, KCH / 16,
                         acc[mt], wm * MT + mt, wn, lane);
        __syncthreads();
    }

    #pragma unroll
    for (int mt = 0; mt < MT; mt++) {
        int row0 = m0 + (wm * MT + mt) * 16 + (lane >> 2);
        #pragma unroll
        for (int st = 0; st < NT * 4; st++) {
            int n = (st >> 2) * 128 + wn * 32 + (st & 3) * 8 + ((lane & 3) << 1);
            float b0 = __ldg(a.bias + n), b1 = __ldg(a.bias + n + 1);
            #pragma unroll
            for (int h = 0; h < 2; h++) {
                int m = row0 + h * 8;
                float s0 = acc[mt][st][h * 2 + 0] + b0;
                float s1 = acc[mt][st][h * 2 + 1] + b1;
                if (a.resid) {
                    float2 rv = *(const float2*)(a.resid + (size_t)m * 128 + n);
                    s0 += rv.x; s1 += rv.y;
                }
                if (a.relu) { s0 = fmaxf(s0, 0.f); s1 = fmaxf(s1, 0.f); }
                if (a.outf) *(float2*)(a.outf + (size_t)m * a.ldo + n) = make_float2(s0, s1);
                if (a.outb) *(uint2*)(a.outb + (size_t)m * a.ldo + n) = make_uint2(packbfp(s0), packbfp(s1));
            }
        }
    }
}

constexpr int smem_sz(int MT, int NT, int KCH) {
    return (2 * MT * 32 + 2 * NT * 128) * (KCH * 2 + 16);
}

// ---------------- fused ee2 + ec + step0-scatter ----------------
#define EESTRIDE 272
#define EE_ALO   (64 * EESTRIDE)
#define EE_B1HI  (2 * EE_ALO)
#define EE_BPL   (128 * EESTRIDE)
#define EE_SMEM  (EE_B1HI + 4 * EE_BPL)          // 174080

__global__ __launch_bounds__(256) void hgemm_ee2ec_sc(
    const uint32_t* __restrict__ Abfp,
    const __nv_bfloat16* __restrict__ B1hi, const __nv_bfloat16* __restrict__ B1lo,
    const float* __restrict__ b1,
    const __nv_bfloat16* __restrict__ B2hi, const __nv_bfloat16* __restrict__ B2lo,
    const float* __restrict__ prpsp,
    const int* __restrict__ recv, const int* __restrict__ send,
    const float* __restrict__ epb,
    float* __restrict__ ec_out, float* __restrict__ agg)
{
    extern __shared__ char smem[];
    const uint32_t sb = smem_u32(smem);
    const int tid = threadIdx.x;
    const int wid = tid >> 5, lane = tid & 31;
    const int wm = wid & 1, wn = wid >> 1;
    const int m0 = blockIdx.x * 64;

    float acc[2][4][4];
    #pragma unroll
    for (int mt = 0; mt < 2; mt++)
        #pragma unroll
        for (int st = 0; st < 4; st++)
            #pragma unroll
            for (int r = 0; r < 4; r++) acc[mt][st][r] = 0.f;

    #pragma unroll
    for (int it = 0; it < 8; it++) {
        int item = tid + (it << 8);
        int r = item >> 5, g = item & 31;
        uint4 v = *((const uint4*)Abfp + ((((size_t)(m0 + r) << 7) + (g << 2)) >> 2));
        uint32_t hi01 = (v.x & 0xffffu) | (v.y << 16);
        uint32_t hi23 = (v.z & 0xffffu) | (v.w << 16);
        uint32_t lo01 = (v.x >> 16) | (v.y & 0xffff0000u);
        uint32_t lo23 = (v.z >> 16) | (v.w & 0xffff0000u);
        int off = r * EESTRIDE + g * 8;
        *(uint2*)(smem + off) = make_uint2(hi01, hi23);
        *(uint2*)(smem + EE_ALO + off) = make_uint2(lo01, lo23);
    }
    load_Bw(smem, EE_B1HI, EE_BPL, B1hi, B1lo, 128, 128, EESTRIDE, tid);
    load_Bw(smem, EE_B1HI + 2 * EE_BPL, EE_BPL, B2hi, B2lo, 128, 128, EESTRIDE, tid);
    __syncthreads();

    #pragma unroll
    for (int phase = 0; phase < 2; phase++) {
        const uint32_t bbase = sb + EE_B1HI + (phase ? 2 * EE_BPL : 0);
        #pragma unroll
        for (int mt = 0; mt < 2; mt++)
            mma_span<1>(sb, sb + EE_ALO, bbase, bbase + EE_BPL,
                        EESTRIDE, EESTRIDE, 8, acc[mt], wm * 2 + mt, wn, lane);
        if (phase == 0) {
            __syncthreads();
            #pragma unroll
            for (int mt = 0; mt < 2; mt++) {
                int r0 = (wm * 2 + mt) * 16 + (lane >> 2);
                #pragma unroll
                for (int st = 0; st < 4; st++) {
                    int n = wn * 32 + st * 8 + ((lane & 3) << 1);
                    float c0 = __ldg(b1 + n), c1 = __ldg(b1 + n + 1);
                    #pragma unroll
                    for (int h = 0; h < 2; h++) {
                        int r = r0 + h * 8;
                        float s0 = fmaxf(acc[mt][st][h * 2 + 0] + c0, 0.f);
                        float s1 = fmaxf(acc[mt][st][h * 2 + 1] + c1, 0.f);
                        uint32_t p0 = packbfp(s0), p1 = packbfp(s1);
                        int off = r * EESTRIDE + n * 2;
                        *(uint32_t*)(smem + off) = (p0 & 0xffffu) | (p1 << 16);
                        *(uint32_t*)(smem + EE_ALO + off) = (p0 >> 16) | (p1 & 0xffff0000u);
                        acc[mt][st][h * 2 + 0] = 0.f;
                        acc[mt][st][h * 2 + 1] = 0.f;
                    }
                }
            }
            __syncthreads();
        }
    }

    // epilogue: write ec + fused step-0 edge-effect scatter
    #pragma unroll
    for (int mt = 0; mt < 2; mt++) {
        int row0 = m0 + (wm * 2 + mt) * 16 + (lane >> 2);
        #pragma unroll
        for (int st = 0; st < 4; st++) {
            int n = wn * 32 + st * 8 + ((lane & 3) << 1);
            float e0b = __ldg(epb + n), e1b = __ldg(epb + n + 1);
            #pragma unroll
            for (int h = 0; h < 2; h++) {
                int m = row0 + h * 8;
                float e0 = acc[mt][st][h * 2 + 0];
                float e1 = acc[mt][st][h * 2 + 1];
                *(float2*)(ec_out + ((size_t)m << 7) + n) = make_float2(e0, e1);
                int bo = (m >> 13) << 10;
                int r_ = __ldg(recv + m) + bo, s_ = __ldg(send + m) + bo;
                float2 pr = *(const float2*)(prpsp + (size_t)r_ * 256 + n);
                float2 ps = *(const float2*)(prpsp + (size_t)s_ * 256 + 128 + n);
                float v0 = fmaxf(e0 + pr.x + ps.x + e0b, 0.f);
                float v1 = fmaxf(e1 + pr.y + ps.y + e1b, 0.f);
                atomicAdd(&agg[(size_t)r_ * 128 + n], v0);
                atomicAdd(&agg[(size_t)r_ * 128 + n + 1], v1);
            }
        }
    }
}

// ---------------- fused node kernels (32-row tiles) ----------------
#define NSTR   528                       // A row stride (K=256 capable)
#define N_ALO  (32 * NSTR)               // 16896
#define N_B0   (2 * N_ALO)               // 33792
#define NP_SMEM (N_B0 + 2 * 256 * 272)   // 173056 (phase B: 256n x 272)
#define TL_SMEM (N_B0 + 2 * 128 * NSTR)  // 168960 (phase A: 128n x 528)

// phase-A A assembly: [neb bfp | agg f32], 32 rows x 256 cols
__device__ __forceinline__ void load_A_npagg(char* smem, int m0,
    const uint32_t* neb, const float* agg, int tid)
{
    #pragma unroll
    for (int it = 0; it < 8; it++) {
        int item = tid + (it << 8);
        int r = item >> 6, g = item & 63;
        int kc = g << 2;
        int m = m0 + r;
        uint32_t p0, p1, p2, p3;
        if (kc < 128) {
            uint4 v = *(const uint4*)(neb + ((size_t)m << 7) + kc);
            p0 = v.x; p1 = v.y; p2 = v.z; p3 = v.w;
        } else {
            float4 v = *(const float4*)(agg + ((size_t)m << 7) + (kc - 128));
            p0 = packbfp(v.x); p1 = packbfp(v.y); p2 = packbfp(v.z); p3 = packbfp(v.w);
        }
        uint32_t hi01 = (p0 & 0xffffu) | (p1 << 16);
        uint32_t hi23 = (p2 & 0xffffu) | (p3 << 16);
        uint32_t lo01 = (p0 >> 16) | (p1 & 0xffff0000u);
        uint32_t lo23 = (p2 >> 16) | (p3 & 0xffff0000u);
        int off = r * NSTR + g * 8;
        *(uint2*)(smem + off) = make_uint2(hi01, hi23);
        *(uint2*)(smem + N_ALO + off) = make_uint2(lo01, lo23);
    }
}

// epilogue: s = acc + bias + resid; relu; repack into A smem (K=128), optional f32 out
__device__ __forceinline__ void epi_repack(char* smem, float (*acc)[4], int m0,
    const float* bias, const float* resid, float* outf, int wm, int wn, int lane)
{
    #pragma unroll
    for (int st = 0; st < 4; st++) {
        int n = wn * 32 + st * 8 + ((lane & 3) << 1);
        float b0 = __ldg(bias + n), b1 = __ldg(bias + n + 1);
        int r0 = wm * 16 + (lane >> 2);
        #pragma unroll
        for (int h = 0; h < 2; h++) {
            int r = r0 + h * 8;
            float s0 = acc[st][h * 2 + 0] + b0;
            float s1 = acc[st][h * 2 + 1] + b1;
            if (resid) {
                float2 rv = *(const float2*)(resid + (((size_t)(m0 + r)) << 7) + n);
                s0 += rv.x; s1 += rv.y;
            }
            s0 = fmaxf(s0, 0.f); s1 = fmaxf(s1, 0.f);
            if (outf) *(float2*)(outf + (((size_t)(m0 + r)) << 7) + n) = make_float2(s0, s1);
            uint32_t p0 = packbfp(s0), p1 = packbfp(s1);
            int off = r * NSTR + n * 2;
            *(uint32_t*)(smem + off) = (p0 & 0xffffu) | (p1 << 16);
            *(uint32_t*)(smem + N_ALO + off) = (p0 >> 16) | (p1 & 0xffff0000u);
            acc[st][h * 2 + 0] = 0.f;
            acc[st][h * 2 + 1] = 0.f;
        }
    }
}

// np + prpsp: nf = relu([neb|agg]@npW + npb + nf_cur); prpsp = nf@ep_rs
__global__ __launch_bounds__(256) void np_prpsp_kernel(
    const uint32_t* __restrict__ neb, const float* __restrict__ agg,
    const float* __restrict__ resid,
    const __nv_bfloat16* __restrict__ npHi, const __nv_bfloat16* __restrict__ npLo,
    const float* __restrict__ npb,
    const __nv_bfloat16* __restrict__ epHi, const __nv_bfloat16* __restrict__ epLo,
    float* __restrict__ nf_out, float* __restrict__ prpsp_out)
{
    extern __shared__ char smem[];
    const uint32_t sb = smem_u32(smem);
    const int tid = threadIdx.x;
    const int wid = tid >> 5, lane = tid & 31;
    const int wm = wid & 1, wn = wid >> 1;
    const int m0 = blockIdx.x * 32;

    float acc[8][4];
    #pragma unroll
    for (int st = 0; st < 8; st++)
        #pragma unroll
        for (int r = 0; r < 4; r++) acc[st][r] = 0.f;

    load_A_npagg(smem, m0, neb, agg, tid);
    load_Bw(smem, N_B0, 128 * NSTR, npHi, npLo, 128, 256, NSTR, tid);
    __syncthreads();
    mma_span<1>(sb, sb + N_ALO, sb + N_B0, sb + N_B0 + 128 * NSTR,
                NSTR, NSTR, 16, acc, wm, wn, lane);
    __syncthreads();
    epi_repack(smem, acc, m0, npb, resid, nf_out, wm, wn, lane);
    load_Bw(smem, N_B0, 256 * 272, epHi, epLo, 256, 128, 272, tid);
    __syncthreads();
    mma_span<2>(sb, sb + N_ALO, sb + N_B0, sb + N_B0 + 256 * 272,
                NSTR, 272, 8, acc, wm, wn, lane);
    // write prpsp (no bias/relu), ldo 256
    #pragma unroll
    for (int st = 0; st < 8; st++) {
        int n = (st >> 2) * 128 + wn * 32 + (st & 3) * 8 + ((lane & 3) << 1);
        int r0 = wm * 16 + (lane >> 2);
        #pragma unroll
        for (int h = 0; h < 2; h++) {
            int m = m0 + r0 + h * 8;
            *(float2*)(prpsp_out + (size_t)m * 256 + n) =
                make_float2(acc[st][h * 2 + 0], acc[st][h * 2 + 1]);
        }
    }
}

// tail: nf2 = relu([neb|agg1]@npW+npb+nf1); h1 = relu(pc + nf2@pp0b + ppb0);
//       h2 = relu(h1@pp1 + ppb1); out = h2@ppW2 + ppb2
__global__ __launch_bounds__(256) void tail_kernel(
    const uint32_t* __restrict__ neb, const float* __restrict__ agg1,
    const float* __restrict__ nf1,
    const __nv_bfloat16* __restrict__ npHi, const __nv_bfloat16* __restrict__ npLo,
    const float* __restrict__ npb,
    const float* __restrict__ pc,
    const __nv_bfloat16* __restrict__ p0bHi, const __nv_bfloat16* __restrict__ p0bLo,
    const float* __restrict__ ppb0,
    const __nv_bfloat16* __restrict__ p1Hi, const __nv_bfloat16* __restrict__ p1Lo,
    const float* __restrict__ ppb1,
    const float* __restrict__ ppW2, const float* __restrict__ ppb2,
    float* __restrict__ out)
{
    extern __shared__ char smem[];
    const uint32_t sb = smem_u32(smem);
    const int tid = threadIdx.x;
    const int wid = tid >> 5, lane = tid & 31;
    const int wm = wid & 1, wn = wid >> 1;
    const int m0 = blockIdx.x * 32;

    float acc[4][4];
    #pragma unroll
    for (int st = 0; st < 4; st++)
        #pragma unroll
        for (int r = 0; r < 4; r++) acc[st][r] = 0.f;

    // phase A: np step 1
    load_A_npagg(smem, m0, neb, agg1, tid);
    load_Bw(smem, N_B0, 128 * NSTR, npHi, npLo, 128, 256, NSTR, tid);
    __syncthreads();
    mma_span<1>(sb, sb + N_ALO, sb + N_B0, sb + N_B0 + 128 * NSTR,
                NSTR, NSTR, 16, acc, wm, wn, lane);
    __syncthreads();
    epi_repack(smem, acc, m0, npb, nf1, nullptr, wm, wn, lane);
    // phase B: pp0 (bottom half) + pc
    load_Bw(smem, N_B0, 128 * 272, p0bHi, p0bLo, 128, 128, 272, tid);
    __syncthreads();
    mma_span<1>(sb, sb + N_ALO, sb + N_B0, sb + N_B0 + 128 * 272,
                NSTR, 272, 8, acc, wm, wn, lane);
    __syncthreads();
    epi_repack(smem, acc, m0, ppb0, pc, nullptr, wm, wn, lane);
    // phase C: pp1
    load_Bw(smem, N_B0, 128 * 272, p1Hi, p1Lo, 128, 128, 272, tid);
    __syncthreads();
    mma_span<1>(sb, sb + N_ALO, sb + N_B0, sb + N_B0 + 128 * 272,
                NSTR, 272, 8, acc, wm, wn, lane);
    __syncthreads();
    // stage h2 as f32 into B region (stride 132 floats)
    float* stage = (float*)(smem + N_B0);
    #pragma unroll
    for (int st = 0; st < 4; st++) {
        int n = wn * 32 + st * 8 + ((lane & 3) << 1);
        float b0 = __ldg(ppb1 + n), b1 = __ldg(ppb1 + n + 1);
        int r0 = wm * 16 + (lane >> 2);
        #pragma unroll
        for (int h = 0; h < 2; h++) {
            int r = r0 + h * 8;
            stage[r * 132 + n]     = fmaxf(acc[st][h * 2 + 0] + b0, 0.f);
            stage[r * 132 + n + 1] = fmaxf(acc[st][h * 2 + 1] + b1, 0.f);
        }
    }
    __syncthreads();
    // phase D: 128 -> 3
    if (tid < 96) {
        int m = tid / 3, n = tid - (tid / 3) * 3;
        const float* a = stage + m * 132;
        float s = __ldg(ppb2 + n);
        #pragma unroll 16
        for (int k = 0; k < 128; k++) s += a[k] * __ldg(ppW2 + k * 3 + n);
        out[(size_t)(m0 + m) * 3 + n] = s;
    }
}

// ---------------- launch ----------------
static inline Seg segd(const void* p, int start, int mode, int rs,
                       const int* idx = nullptr, const int* idx2 = nullptr,
                       const float* eb = nullptr) {
    Seg s; s.p = p; s.idx = idx; s.idx2 = idx2; s.ebias = eb;
    s.start = start; s.mode = mode; s.rs = rs; return s;
}
static inline Seg segnone() { return segd(nullptr, 0x40000000, 0, 0); }

extern "C" void kernel_launch(void* const* d_in, const int* in_sizes, int n_in,
                              void* d_out, int out_size)
{
    const float* x    = (const float*)d_in[0];
    const float* Rr   = (const float*)d_in[1];
    const float* Rs   = (const float*)d_in[2];
    const float* neW0 = (const float*)d_in[4];  const float* neb0 = (const float*)d_in[5];
    const float* neW1 = (const float*)d_in[6];  const float* neb1 = (const float*)d_in[7];
    const float* neW2 = (const float*)d_in[8];  const float* neb2 = (const float*)d_in[9];
    const float* eeW0 = (const float*)d_in[10]; const float* eeb0 = (const float*)d_in[11];
    const float* eeW1 = (const float*)d_in[12]; const float* eeb1 = (const float*)d_in[13];
    const float* eeW2 = (const float*)d_in[14]; const float* eeb2 = (const float*)d_in[15];
    const float* npW  = (const float*)d_in[16]; const float* npb  = (const float*)d_in[17];
    const float* epW  = (const float*)d_in[18]; const float* epb  = (const float*)d_in[19];
    const float* ppW0 = (const float*)d_in[20]; const float* ppb0 = (const float*)d_in[21];
    const float* ppW1 = (const float*)d_in[22]; const float* ppb1 = (const float*)d_in[23];
    const float* ppW2 = (const float*)d_in[24]; const float* ppb2 = (const float*)d_in[25];
    float* out = (float*)d_out;

    uint32_t* arena; cudaGetSymbolAddress((void**)&arena, g_arena);
    int* recv; cudaGetSymbolAddress((void**)&recv, g_recv);
    int* send; cudaGetSymbolAddress((void**)&send, g_send);
    __nv_bfloat16* whi; cudaGetSymbolAddress((void**)&whi, g_whi);
    __nv_bfloat16* wlo; cudaGetSymbolAddress((void**)&wlo, g_wlo);
    float* zb; cudaGetSymbolAddress((void**)&zb, g_zero);

    uint32_t* tA     = arena + OFF_TA;
    uint32_t* tB     = arena + OFF_TB;
    uint32_t* neb    = arena + OFF_NEB;
    float*    nef    = (float*)(arena + OFF_NEF);
    float*    nf1f   = (float*)(arena + OFF_NF1F);
    float*    pc     = (float*)(arena + OFF_PC);
    float*    agg0   = (float*)(arena + OFF_AGG0);
    float*    agg1   = (float*)(arena + OFF_AGG1);
    float*    prs    = (float*)(arena + OFF_PRS);
    float*    prpspA = (float*)(arena + OFF_PRPSPA);
    float*    prpspB = (float*)(arena + OFF_PRPSPB);
    uint32_t* tE2    = arena + OFF_TE2;
    float*    ec     = (float*)(arena + OFF_EC);

    // 0 ne0 1 ne1 2 ne2 3 eers 4 ee1 5 ee2 6 ep_e 7 ep_rs 8 np 9 pp0a 10 pp0b 11 pp1
    const int WO[12] = {0,8192,24576,40960,57344,73728,90112,106496,139264,172032,188416,204800};

    static bool s_init = false;
    static cudaStream_t s1, s2;
    static cudaEvent_t evStart, evPrep, evS1, evNE;
    if (!s_init) {
        cudaStreamCreateWithFlags(&s1, cudaStreamNonBlocking);
        cudaStreamCreateWithFlags(&s2, cudaStreamNonBlocking);
        cudaEventCreateWithFlags(&evStart, cudaEventDisableTiming);
        cudaEventCreateWithFlags(&evPrep,  cudaEventDisableTiming);
        cudaEventCreateWithFlags(&evS1,    cudaEventDisableTiming);
        cudaEventCreateWithFlags(&evNE,    cudaEventDisableTiming);
        cudaFuncSetAttribute(hgemm<1,1,64>,  cudaFuncAttributeMaxDynamicSharedMemorySize, smem_sz(1,1,64));
        cudaFuncSetAttribute(hgemm<1,1,128>, cudaFuncAttributeMaxDynamicSharedMemorySize, smem_sz(1,1,128));
        cudaFuncSetAttribute(hgemm<1,2,64>,  cudaFuncAttributeMaxDynamicSharedMemorySize, smem_sz(1,2,64));
        cudaFuncSetAttribute(hgemm<1,2,128>, cudaFuncAttributeMaxDynamicSharedMemorySize, smem_sz(1,2,128));
        cudaFuncSetAttribute(hgemm<2,1,128>, cudaFuncAttributeMaxDynamicSharedMemorySize, smem_sz(2,1,128));
        cudaFuncSetAttribute(hgemm_ee2ec_sc, cudaFuncAttributeMaxDynamicSharedMemorySize, EE_SMEM);
        cudaFuncSetAttribute(np_prpsp_kernel, cudaFuncAttributeMaxDynamicSharedMemorySize, NP_SMEM);
        cudaFuncSetAttribute(tail_kernel,     cudaFuncAttributeMaxDynamicSharedMemorySize, TL_SMEM);
        s_init = true;
    }

    // ---- fork at graph root: extract starts immediately on s1 ----
    cudaEventRecord(evStart, 0);
    cudaStreamWaitEvent(s1, evStart, 0);
    extract_idx2_kernel<<<2 * BE / 8, 256, 0, s1>>>(Rr, Rs, recv, send);
    cudaMemsetAsync(agg0, 0, (size_t)BN * 128 * sizeof(float), s1);
    cudaMemsetAsync(agg1, 0, (size_t)BN * 128 * sizeof(float), s1);
    cudaEventRecord(evS1, s1);

    // ---- origin: weight prep ----
    PArg pa;
    pa.W[0] = neW0; pa.W[1] = neW1; pa.W[2] = neW2;
    pa.W[3] = eeW0; pa.W[4] = eeW1; pa.W[5] = eeW2;
    pa.W[6] = epW;  pa.W[7] = epW;  pa.W[8] = npW;
    pa.W[9] = ppW0; pa.W[10] = ppW0; pa.W[11] = ppW1;
    prep_weights<<<dim3(12, 8), 256>>>(pa, whi, wlo);
    cudaEventRecord(evPrep, 0);
    cudaStreamWaitEvent(s2, evPrep, 0);

    // ---- s2: node encoder chain + step-invariant node projections ----
    {
        GArg a;
        a.resid = nullptr; a.outf = nullptr; a.outb = nullptr; a.relu = 1; a.ldo = 128;
        a.s0 = segd(x, 0, 3, 32); a.s1 = segd(nullptr, 32, 0, 0); a.s2 = segnone();
        a.K = 64; a.Bhi = whi + WO[0]; a.Blo = wlo + WO[0]; a.bias = neb0; a.outb = tA;
        hgemm<1,1,64><<<BN / 32, 256, smem_sz(1,1,64), s2>>>(a);

        a.s0 = segd(tA, 0, 1, 128); a.s1 = segnone();
        a.K = 128; a.Bhi = whi + WO[1]; a.Blo = wlo + WO[1]; a.bias = neb1; a.outb = tB;
        hgemm<1,1,128><<<BN / 32, 256, smem_sz(1,1,128), s2>>>(a);

        a.s0 = segd(tB, 0, 1, 128);
        a.Bhi = whi + WO[2]; a.Blo = wlo + WO[2]; a.bias = neb2; a.outb = neb; a.outf = nef;
        hgemm<1,1,128><<<BN / 32, 256, smem_sz(1,1,128), s2>>>(a);
        a.outf = nullptr;

        // prpsp0 = node_enc @ [ep_r|ep_s]
        a.s0 = segd(neb, 0, 1, 128);
        a.K = 128; a.Bhi = whi + WO[7]; a.Blo = wlo + WO[7]; a.bias = zb;
        a.relu = 0; a.outb = nullptr; a.outf = prpspA; a.ldo = 256;
        hgemm<1,2,128><<<BN / 32, 256, smem_sz(1,2,128), s2>>>(a);

        // pc = node_enc @ pp0a
        a.Bhi = whi + WO[9]; a.Blo = wlo + WO[9]; a.outf = pc; a.ldo = 128;
        hgemm<1,1,128><<<BN / 32, 256, smem_sz(1,1,128), s2>>>(a);
    }
    cudaEventRecord(evNE, s2);

    GArg a;
    a.resid = nullptr; a.outf = nullptr; a.outb = nullptr; a.relu = 1; a.ldo = 128;

    // ---- origin: PrPs = x @ [eer|ees] ----
    a.s0 = segd(x, 0, 3, 32); a.s1 = segd(nullptr, 32, 0, 0); a.s2 = segnone();
    a.K = 64; a.Bhi = whi + WO[3]; a.Blo = wlo + WO[3]; a.bias = zb; a.relu = 0;
    a.outb = nullptr; a.outf = prs; a.ldo = 256;
    hgemm<1,2,64><<<BN / 32, 256, smem_sz(1,2,64)>>>(a);
    a.relu = 1; a.outf = nullptr; a.ldo = 128;

    // join: indices + agg zeros ready
    cudaStreamWaitEvent(0, evS1, 0);

    // ee1: edge layer0 computed on the fly, then layer1
    a.s0 = segd(prs, 0, 4, 256, recv, send, eeb0); a.s1 = segnone(); a.s2 = segnone();
    a.K = 128; a.Bhi = whi + WO[4]; a.Blo = wlo + WO[4]; a.bias = eeb1; a.outb = tE2;
    hgemm<2,1,128><<<BE / 64, 256, smem_sz(2,1,128)>>>(a);

    // join: node-side projections ready
    cudaStreamWaitEvent(0, evNE, 0);

    // fused ee2 + ec + step-0 scatter
    hgemm_ee2ec_sc<<<BE / 64, 256, EE_SMEM>>>(tE2,
        whi + WO[5], wlo + WO[5], eeb2, whi + WO[6], wlo + WO[6],
        prpspA, recv, send, epb, ec, agg0);

    // fused np(step0) + prpsp(step1)
    np_prpsp_kernel<<<BN / 32, 256, NP_SMEM>>>(neb, agg0, nef,
        whi + WO[8], wlo + WO[8], npb, whi + WO[7], wlo + WO[7],
        nf1f, prpspB);

    // step-1 scatter
    fused_scatter_kernel<<<BE * 128 / 256, 256>>>(ec, prpspB, recv, send, epb, agg1);

    // fused np(step1) + predictor + output
    tail_kernel<<<BN / 32, 256, TL_SMEM>>>(neb, agg1, nf1f,
        whi + WO[8], wlo + WO[8], npb, pc,
        whi + WO[10], wlo + WO[10], ppb0,
        whi + WO[11], wlo + WO[11], ppb1,
        ppW2, ppb2, out);
}

// round 9
// speedup vs baseline: 2.6838x; 1.1511x over previous
#include <cuda_runtime.h>
#include <cuda_bf16.h>
#include <cstdint>

// ---------------- problem dims ----------------
#define Nn 1024
#define Ee 8192
#define BN 4096    // B*N
#define BE 32768   // B*E

// ---------------- device scratch ----------------
#define OFF_NEB    ((size_t)0)                       // node_enc bfp
#define OFF_NEF    (OFF_NEB + (size_t)BN*128)        // node_enc f32
#define OFF_NF1F   (OFF_NEF + (size_t)BN*128)        // nf1 f32
#define OFF_PC     (OFF_NF1F + (size_t)BN*128)       // neb@pp0a f32
#define OFF_AGG0   (OFF_PC + (size_t)BN*128)
#define OFF_AGG1   (OFF_AGG0 + (size_t)BN*128)
#define OFF_PRS    (OFF_AGG1 + (size_t)BN*128)       // [BN,256] f32 (x@Wr | x@Ws)
#define OFF_PRPSPA (OFF_PRS + (size_t)BN*256)        // [BN,256] f32 step0
#define OFF_PRPSPB (OFF_PRPSPA + (size_t)BN*256)     // [BN,256] f32 step1
#define OFF_EC     (OFF_PRPSPB + (size_t)BN*256)     // [BE,128] f32
#define ARENA_U32  (OFF_EC + (size_t)BE*128)

__device__ uint32_t g_arena[ARENA_U32];
__device__ int g_recv[BE];
__device__ int g_send[BE];
__device__ float g_zero[256];

// split/transposed weights [n][kpad] bf16, 12 matrices
#define WT_TOTAL 221184
__device__ __nv_bfloat16 g_whi[WT_TOTAL];
__device__ __nv_bfloat16 g_wlo[WT_TOTAL];

// ---------------- helpers ----------------
__device__ __forceinline__ uint32_t smem_u32(const void* p) {
    uint32_t a;
    asm("{ .reg .u64 t; cvta.to.shared.u64 t, %1; cvt.u32.u64 %0, t; }" : "=r"(a) : "l"(p));
    return a;
}

#define LDMX4(r, ad) \
    asm volatile("ldmatrix.sync.aligned.m8n8.x4.shared.b16 {%0,%1,%2,%3}, [%4];" \
        : "=r"((r)[0]), "=r"((r)[1]), "=r"((r)[2]), "=r"((r)[3]) : "r"(ad))

#define MMA16816(d, av, bv) \
    asm volatile("mma.sync.aligned.m16n8k16.row.col.f32.bf16.bf16.f32 " \
        "{%0,%1,%2,%3},{%4,%5,%6,%7},{%8,%9},{%0,%1,%2,%3};" \
        : "+f"((d)[0]), "+f"((d)[1]), "+f"((d)[2]), "+f"((d)[3]) \
        : "r"((av)[0]), "r"((av)[1]), "r"((av)[2]), "r"((av)[3]), \
          "r"((bv)[0]), "r"((bv)[1]))

__device__ __forceinline__ uint32_t packbfp(float v) {
    __nv_bfloat16 h = __float2bfloat16(v);
    float hf = __bfloat162float(h);
    __nv_bfloat16 l = __float2bfloat16(v - hf);
    return (uint32_t)__bfloat16_as_ushort(h) | ((uint32_t)__bfloat16_as_ushort(l) << 16);
}

// 3-pass emulated MMA over one K-span. tile = m-tile index (16 rows each).
template<int NT>
__device__ __forceinline__ void mma_span(
    uint32_t aHi, uint32_t aLo, uint32_t bHi, uint32_t bLo,
    int astr, int bstr, int nk, float (*acc)[4], int tile, int wn, int lane)
{
    for (int ks = 0; ks < nk; ks++) {
        uint32_t bh[NT * 8], bl[NT * 8];
        #pragma unroll
        for (int t2 = 0; t2 < NT; t2++)
            #pragma unroll
            for (int np = 0; np < 2; np++) {
                int n = t2 * 128 + wn * 32 + np * 16 + ((lane >> 4) << 3) + (lane & 7);
                int koff = ((lane >> 3) & 1) << 3;
                uint32_t ad = bHi + n * bstr + (ks * 16 + koff) * 2;
                LDMX4(&bh[(t2 * 2 + np) * 4], ad);
                LDMX4(&bl[(t2 * 2 + np) * 4], ad + (bLo - bHi));
            }
        int r = tile * 16 + (lane & 15);
        int koff = (lane >> 4) << 3;
        uint32_t ad = aHi + r * astr + (ks * 16 + koff) * 2;
        uint32_t ah[4], al[4];
        LDMX4(ah, ad);
        LDMX4(al, ad + (aLo - aHi));
        #pragma unroll
        for (int st = 0; st < NT * 4; st++) {
            MMA16816(acc[st], ah, &bh[st * 2]);
            MMA16816(acc[st], ah, &bl[st * 2]);
            MMA16816(acc[st], al, &bh[st * 2]);
        }
    }
}

// load both weight planes into smem
__device__ __forceinline__ void load_Bw(char* smem, int base, int plane,
    const __nv_bfloat16* Bhi, const __nv_bfloat16* Blo,
    int nrows, int kcols, int bstr, int tid)
{
    int kg = kcols >> 3;
    int per = nrows * kg;
    for (int item = tid; item < per; item += 256) {
        int n = item / kg, g = item - n * kg;
        size_t goff = (size_t)n * kcols + (g << 3);
        int so = base + n * bstr + (g << 4);
        *(uint4*)(smem + so) = *(const uint4*)(Bhi + goff);
        *(uint4*)(smem + so + plane) = *(const uint4*)(Blo + goff);
    }
}

// epilogue: s = acc + bias (+resid); relu; repack into A smem planes; optional outf/outb
__device__ __forceinline__ void epi_repack2(char* smem, int astr, int aplane,
    float (*acc)[4], int m0, int tile,
    const float* bias, const float* resid, float* outf, uint32_t* outb,
    int wn, int lane)
{
    #pragma unroll
    for (int st = 0; st < 4; st++) {
        int n = wn * 32 + st * 8 + ((lane & 3) << 1);
        float b0 = __ldg(bias + n), b1 = __ldg(bias + n + 1);
        int r0 = tile * 16 + (lane >> 2);
        #pragma unroll
        for (int h = 0; h < 2; h++) {
            int r = r0 + h * 8;
            float s0 = acc[st][h * 2 + 0] + b0;
            float s1 = acc[st][h * 2 + 1] + b1;
            if (resid) {
                float2 rv = *(const float2*)(resid + (((size_t)(m0 + r)) << 7) + n);
                s0 += rv.x; s1 += rv.y;
            }
            s0 = fmaxf(s0, 0.f); s1 = fmaxf(s1, 0.f);
            if (outf) *(float2*)(outf + (((size_t)(m0 + r)) << 7) + n) = make_float2(s0, s1);
            uint32_t p0 = packbfp(s0), p1 = packbfp(s1);
            if (outb) *(uint2*)(outb + (((size_t)(m0 + r)) << 7) + n) = make_uint2(p0, p1);
            int off = r * astr + n * 2;
            *(uint32_t*)(smem + off) = (p0 & 0xffffu) | (p1 << 16);
            *(uint32_t*)(smem + aplane + off) = (p0 >> 16) | (p1 & 0xffff0000u);
            acc[st][h * 2 + 0] = 0.f;
            acc[st][h * 2 + 1] = 0.f;
        }
    }
}

// write acc (f32, no bias/relu) to out[m][nbase+n], zero acc
__device__ __forceinline__ void write_accf(float (*acc)[4], int m0, int tile,
    int wn, int lane, float* out, int nbase, int ldo)
{
    #pragma unroll
    for (int st = 0; st < 4; st++) {
        int n = nbase + wn * 32 + st * 8 + ((lane & 3) << 1);
        int r0 = tile * 16 + (lane >> 2);
        #pragma unroll
        for (int h = 0; h < 2; h++) {
            int m = m0 + r0 + h * 8;
            *(float2*)(out + (size_t)m * ldo + n) =
                make_float2(acc[st][h * 2 + 0], acc[st][h * 2 + 1]);
            acc[st][h * 2 + 0] = 0.f;
            acc[st][h * 2 + 1] = 0.f;
        }
    }
}

// ---------------- aux kernels ----------------
__global__ void extract_idx2_kernel(const float* __restrict__ Rr,
                                    const float* __restrict__ Rs,
                                    int* __restrict__ recv, int* __restrict__ send)
{
    int row = blockIdx.x * 8 + (threadIdx.x >> 5);
    int lane = threadIdx.x & 31;
    const float* R = (row < BE) ? Rr : Rs;
    int r = (row < BE) ? row : row - BE;
    const float4* p = (const float4*)(R + (size_t)r * Nn);
    int found = 0;
    #pragma unroll
    for (int i = 0; i < 8; i++) {
        int q = lane + i * 32;
        float4 v = p[q];
        if (v.x > 0.5f) found = q * 4 + 0;
        if (v.y > 0.5f) found = q * 4 + 1;
        if (v.z > 0.5f) found = q * 4 + 2;
        if (v.w > 0.5f) found = q * 4 + 3;
    }
    #pragma unroll
    for (int o = 16; o; o >>= 1) found = max(found, __shfl_xor_sync(0xFFFFFFFFu, found, o));
    if (lane == 0) {
        if (row < BE) recv[r] = found; else send[r] = found;
    }
}

// matrices: 0 ne0 1 ne1 2 ne2 3 eers(R256) 4 ee1 5 ee2 6 ep_e 7 ep_rs(R256)
//           8 np(K256) 9 pp0a 10 pp0b 11 pp1
struct PArg { const float* W[12]; };
__constant__ int c_Ks[12]  = {32,128,128, 32,128,128,128,128,256,128,128,128};
__constant__ int c_Kps[12] = {64,128,128, 64,128,128,128,128,256,128,128,128};
__constant__ int c_Rs[12]  = {128,128,128,256,128,128,128,256,128,128,128,128};
__constant__ int c_r0a[12] = {0,0,0,0,0,0,0,128,0,0,128,0};
__constant__ int c_r0b[12] = {0,0,0,32,0,0,0,256,0,0,0,0};
__constant__ int c_off[12] = {0,8192,24576,40960,57344,73728,90112,106496,139264,172032,188416,204800};

__global__ void prep_weights(PArg a, __nv_bfloat16* __restrict__ hi, __nv_bfloat16* __restrict__ lo)
{
    int mid = blockIdx.x;
    int K = c_Ks[mid], Kp = c_Kps[mid], R = c_Rs[mid];
    int r0a = c_r0a[mid], r0b = c_r0b[mid];
    const float* W = a.W[mid];
    __nv_bfloat16* dh = hi + c_off[mid];
    __nv_bfloat16* dl = lo + c_off[mid];
    int total = R * Kp;
    for (int i = threadIdx.x + blockIdx.y * blockDim.x; i < total; i += blockDim.x * gridDim.y) {
        int n = i / Kp, k = i - n * Kp;
        int col = n & 127;
        int r0 = (n >> 7) ? r0b : r0a;
        float v = (k < K) ? W[(size_t)(r0 + k) * 128 + col] : 0.f;
        __nv_bfloat16 h = __float2bfloat16(v);
        dh[i] = h;
        dl[i] = __float2bfloat16(v - __bfloat162float(h));
    }
}

// step-1 scatter
__global__ void fused_scatter_kernel(const float* __restrict__ ec,
                                     const float* __restrict__ prpsp,
                                     const int* __restrict__ recv,
                                     const int* __restrict__ send,
                                     const float* __restrict__ bias,
                                     float* __restrict__ agg)
{
    int t = blockIdx.x * blockDim.x + threadIdx.x;
    if (t >= BE * 128) return;
    int e = t >> 7, h = t & 127;
    int bo = (e >> 13) << 10;
    int r = __ldg(recv + e) + bo, s = __ldg(send + e) + bo;
    float v = ec[t] + prpsp[(size_t)r * 256 + h] + prpsp[(size_t)s * 256 + 128 + h] + __ldg(bias + h);
    v = fmaxf(v, 0.f);
    atomicAdd(&agg[(size_t)r * 128 + h], v);
}

// ---------------- generic HMMA GEMM (PrPs only) ----------------
struct Seg { const void* p; int start; int mode; int rs; };
struct GArg {
    Seg s0, s1;
    int K;
    const __nv_bfloat16 *Bhi, *Blo;
    const float* bias;
    float* outf;
    int ldo;
};

template<int NT, int KCH>
__global__ __launch_bounds__(256) void hgemm(GArg a)
{
    constexpr int STRIDE = KCH * 2 + 16;
    constexpr int ALO = 32 * STRIDE;
    constexpr int BHI = 2 * ALO;
    constexpr int BPL = NT * 128 * STRIDE;
    extern __shared__ char smem[];
    const uint32_t sb = smem_u32(smem);
    const int tid = threadIdx.x;
    const int wid = tid >> 5, lane = tid & 31;
    const int wm = wid & 1, wn = wid >> 1;
    const int m0 = blockIdx.x * 32;

    float acc[NT * 4][4];
    #pragma unroll
    for (int st = 0; st < NT * 4; st++)
        #pragma unroll
        for (int r = 0; r < 4; r++) acc[st][r] = 0.f;

    const int nchunks = a.K / KCH;
    for (int c = 0; c < nchunks; c++) {
        const int k0 = c * KCH;
        #pragma unroll
        for (int it = 0; it < KCH / 32; it++) {
            int item = tid + (it << 8);
            int r = item / (KCH / 4), g = item % (KCH / 4);
            int kc = k0 + (g << 2);
            int m = m0 + r;
            uint32_t p0, p1, p2, p3;
            const Seg& sg = (kc >= a.s1.start) ? a.s1 : a.s0;
            if (sg.mode == 0) {
                p0 = p1 = p2 = p3 = 0u;
            } else {
                long base = (long)m * sg.rs + (kc - sg.start);
                float4 v = *((const float4*)sg.p + (base >> 2));
                p0 = packbfp(v.x); p1 = packbfp(v.y); p2 = packbfp(v.z); p3 = packbfp(v.w);
            }
            uint32_t hi01 = (p0 & 0xffffu) | (p1 << 16);
            uint32_t hi23 = (p2 & 0xffffu) | (p3 << 16);
            uint32_t lo01 = (p0 >> 16) | (p1 & 0xffff0000u);
            uint32_t lo23 = (p2 >> 16) | (p3 & 0xffff0000u);
            int off = r * STRIDE + g * 8;
            *(uint2*)(smem + off) = make_uint2(hi01, hi23);
            *(uint2*)(smem + ALO + off) = make_uint2(lo01, lo23);
        }
        #pragma unroll
        for (int it = 0; it < NT * KCH / 16; it++) {
            int item = tid + (it << 8);
            int n = item / (KCH / 8), g = item % (KCH / 8);
            size_t goff = (size_t)n * a.K + k0 + (g << 3);
            int off = n * STRIDE + g * 16;
            *(uint4*)(smem + BHI + off) = *(const uint4*)(a.Bhi + goff);
            *(uint4*)(smem + BHI + BPL + off) = *(const uint4*)(a.Blo + goff);
        }
        __syncthreads();
        mma_span<NT>(sb, sb + ALO, sb + BHI, sb + BHI + BPL,
                     STRIDE, STRIDE, KCH / 16, acc, wm, wn, lane);
        __syncthreads();
    }
    #pragma unroll
    for (int t2 = 0; t2 < NT; t2++) {
        float (*accp)[4] = acc + t2 * 4;
        write_accf(accp, m0, wm, wn, lane, a.outf, t2 * 128, a.ldo);
    }
}

constexpr int smem_hg(int NT, int KCH) {
    return (2 * 32 + 2 * NT * 128) * (KCH * 2 + 16);
}

// ---------------- node_mega: ne0->ne1->ne2->prpsp_r->prpsp_s->pc ----------------
#define NM_STR   272
#define NM_ALO   (32 * NM_STR)             // 8704
#define NM_B0    (2 * NM_ALO)              // 17408
#define NM_BPL   (128 * NM_STR)            // 34816
#define NM_SMEM  (NM_B0 + 2 * NM_BPL)      // 87040

struct NodeArg {
    const float* x;
    const __nv_bfloat16 *w0h,*w0l,*w1h,*w1l,*w2h,*w2l,*eprh,*eprl,*epsh,*epsl,*pqh,*pql;
    const float *b0,*b1,*b2;
    uint32_t* neb; float* nef; float* prpsp; float* pc;
};

__global__ __launch_bounds__(256) void node_mega(NodeArg a)
{
    extern __shared__ char smem[];
    const uint32_t sb = smem_u32(smem);
    const int tid = threadIdx.x;
    const int wid = tid >> 5, lane = tid & 31;
    const int wm = wid & 1, wn = wid >> 1;
    const int m0 = blockIdx.x * 32;

    float acc[4][4];
    #pragma unroll
    for (int st = 0; st < 4; st++)
        #pragma unroll
        for (int r = 0; r < 4; r++) acc[st][r] = 0.f;

    // A <- x (K=32 pad 64)
    #pragma unroll
    for (int it = 0; it < 2; it++) {
        int item = tid + (it << 8);
        int r = item >> 4, g = item & 15;
        int kc = g << 2;
        uint32_t p0 = 0, p1 = 0, p2 = 0, p3 = 0;
        if (kc < 32) {
            float4 v = *(const float4*)(a.x + (size_t)(m0 + r) * 32 + kc);
            p0 = packbfp(v.x); p1 = packbfp(v.y); p2 = packbfp(v.z); p3 = packbfp(v.w);
        }
        uint32_t hi01 = (p0 & 0xffffu) | (p1 << 16);
        uint32_t hi23 = (p2 & 0xffffu) | (p3 << 16);
        uint32_t lo01 = (p0 >> 16) | (p1 & 0xffff0000u);
        uint32_t lo23 = (p2 >> 16) | (p3 & 0xffff0000u);
        int off = r * NM_STR + g * 8;
        *(uint2*)(smem + off) = make_uint2(hi01, hi23);
        *(uint2*)(smem + NM_ALO + off) = make_uint2(lo01, lo23);
    }
    load_Bw(smem, NM_B0, NM_BPL, a.w0h, a.w0l, 128, 64, NM_STR, tid);
    __syncthreads();
    mma_span<1>(sb, sb + NM_ALO, sb + NM_B0, sb + NM_B0 + NM_BPL, NM_STR, NM_STR, 4, acc, wm, wn, lane);
    __syncthreads();
    epi_repack2(smem, NM_STR, NM_ALO, acc, m0, wm, a.b0, nullptr, nullptr, nullptr, wn, lane);
    load_Bw(smem, NM_B0, NM_BPL, a.w1h, a.w1l, 128, 128, NM_STR, tid);
    __syncthreads();
    mma_span<1>(sb, sb + NM_ALO, sb + NM_B0, sb + NM_B0 + NM_BPL, NM_STR, NM_STR, 8, acc, wm, wn, lane);
    __syncthreads();
    epi_repack2(smem, NM_STR, NM_ALO, acc, m0, wm, a.b1, nullptr, nullptr, nullptr, wn, lane);
    load_Bw(smem, NM_B0, NM_BPL, a.w2h, a.w2l, 128, 128, NM_STR, tid);
    __syncthreads();
    mma_span<1>(sb, sb + NM_ALO, sb + NM_B0, sb + NM_B0 + NM_BPL, NM_STR, NM_STR, 8, acc, wm, wn, lane);
    __syncthreads();
    epi_repack2(smem, NM_STR, NM_ALO, acc, m0, wm, a.b2, nullptr, a.nef, a.neb, wn, lane);
    // prpsp_r
    load_Bw(smem, NM_B0, NM_BPL, a.eprh, a.eprl, 128, 128, NM_STR, tid);
    __syncthreads();
    mma_span<1>(sb, sb + NM_ALO, sb + NM_B0, sb + NM_B0 + NM_BPL, NM_STR, NM_STR, 8, acc, wm, wn, lane);
    __syncthreads();
    write_accf(acc, m0, wm, wn, lane, a.prpsp, 0, 256);
    // prpsp_s
    load_Bw(smem, NM_B0, NM_BPL, a.epsh, a.epsl, 128, 128, NM_STR, tid);
    __syncthreads();
    mma_span<1>(sb, sb + NM_ALO, sb + NM_B0, sb + NM_B0 + NM_BPL, NM_STR, NM_STR, 8, acc, wm, wn, lane);
    __syncthreads();
    write_accf(acc, m0, wm, wn, lane, a.prpsp, 128, 256);
    // pc
    load_Bw(smem, NM_B0, NM_BPL, a.pqh, a.pql, 128, 128, NM_STR, tid);
    __syncthreads();
    mma_span<1>(sb, sb + NM_ALO, sb + NM_B0, sb + NM_B0 + NM_BPL, NM_STR, NM_STR, 8, acc, wm, wn, lane);
    __syncthreads();
    write_accf(acc, m0, wm, wn, lane, a.pc, 0, 128);
}

// ---------------- edge_mega: ee1 -> ee2 -> ec -> scatter0 ----------------
#define EM_STR   272
#define EM_ALO   (64 * EM_STR)             // 17408
#define EM_B0    (2 * EM_ALO)              // 34816
#define EM_BPL   (128 * EM_STR)            // 34816
#define EM_SMEM  (EM_B0 + 2 * EM_BPL)      // 104448

struct EdgeArg {
    const float* prs; const int* recv; const int* send; const float* eeb0;
    const __nv_bfloat16 *w1h,*w1l,*w2h,*w2l,*weh,*wel;
    const float *b1,*b2;
    const float* prpsp; const float* epb;
    float* ec; float* agg;
};

__global__ __launch_bounds__(256, 2) void edge_mega(EdgeArg a)
{
    extern __shared__ char smem[];
    const uint32_t sb = smem_u32(smem);
    const int tid = threadIdx.x;
    const int wid = tid >> 5, lane = tid & 31;
    const int wm = wid & 1, wn = wid >> 1;
    const int m0 = blockIdx.x * 64;

    float acc[2][4][4];
    #pragma unroll
    for (int mt = 0; mt < 2; mt++)
        #pragma unroll
        for (int st = 0; st < 4; st++)
            #pragma unroll
            for (int r = 0; r < 4; r++) acc[mt][st][r] = 0.f;

    // A <- edge layer0 on the fly: relu(Pr[recv]+Ps[send]+b0)
    #pragma unroll
    for (int it = 0; it < 8; it++) {
        int item = tid + (it << 8);
        int r = item >> 5, g = item & 31;
        int kc = g << 2;
        int m = m0 + r;
        int bo = (m >> 13) << 10;
        int rr = __ldg(a.recv + m) + bo, ss = __ldg(a.send + m) + bo;
        float4 pr = *(const float4*)(a.prs + (size_t)rr * 256 + kc);
        float4 ps = *(const float4*)(a.prs + (size_t)ss * 256 + 128 + kc);
        float4 bb = *(const float4*)(a.eeb0 + kc);
        uint32_t p0 = packbfp(fmaxf(pr.x + ps.x + bb.x, 0.f));
        uint32_t p1 = packbfp(fmaxf(pr.y + ps.y + bb.y, 0.f));
        uint32_t p2 = packbfp(fmaxf(pr.z + ps.z + bb.z, 0.f));
        uint32_t p3 = packbfp(fmaxf(pr.w + ps.w + bb.w, 0.f));
        uint32_t hi01 = (p0 & 0xffffu) | (p1 << 16);
        uint32_t hi23 = (p2 & 0xffffu) | (p3 << 16);
        uint32_t lo01 = (p0 >> 16) | (p1 & 0xffff0000u);
        uint32_t lo23 = (p2 >> 16) | (p3 & 0xffff0000u);
        int off = r * EM_STR + g * 8;
        *(uint2*)(smem + off) = make_uint2(hi01, hi23);
        *(uint2*)(smem + EM_ALO + off) = make_uint2(lo01, lo23);
    }
    load_Bw(smem, EM_B0, EM_BPL, a.w1h, a.w1l, 128, 128, EM_STR, tid);
    __syncthreads();
    #pragma unroll
    for (int mt = 0; mt < 2; mt++)
        mma_span<1>(sb, sb + EM_ALO, sb + EM_B0, sb + EM_B0 + EM_BPL,
                    EM_STR, EM_STR, 8, acc[mt], wm * 2 + mt, wn, lane);
    __syncthreads();
    #pragma unroll
    for (int mt = 0; mt < 2; mt++)
        epi_repack2(smem, EM_STR, EM_ALO, acc[mt], m0, wm * 2 + mt, a.b1,
                    nullptr, nullptr, nullptr, wn, lane);
    load_Bw(smem, EM_B0, EM_BPL, a.w2h, a.w2l, 128, 128, EM_STR, tid);
    __syncthreads();
    #pragma unroll
    for (int mt = 0; mt < 2; mt++)
        mma_span<1>(sb, sb + EM_ALO, sb + EM_B0, sb + EM_B0 + EM_BPL,
                    EM_STR, EM_STR, 8, acc[mt], wm * 2 + mt, wn, lane);
    __syncthreads();
    #pragma unroll
    for (int mt = 0; mt < 2; mt++)
        epi_repack2(smem, EM_STR, EM_ALO, acc[mt], m0, wm * 2 + mt, a.b2,
                    nullptr, nullptr, nullptr, wn, lane);
    load_Bw(smem, EM_B0, EM_BPL, a.weh, a.wel, 128, 128, EM_STR, tid);
    __syncthreads();
    #pragma unroll
    for (int mt = 0; mt < 2; mt++)
        mma_span<1>(sb, sb + EM_ALO, sb + EM_B0, sb + EM_B0 + EM_BPL,
                    EM_STR, EM_STR, 8, acc[mt], wm * 2 + mt, wn, lane);

    // epilogue: write ec + fused step-0 scatter
    #pragma unroll
    for (int mt = 0; mt < 2; mt++) {
        int row0 = m0 + (wm * 2 + mt) * 16 + (lane >> 2);
        #pragma unroll
        for (int st = 0; st < 4; st++) {
            int n = wn * 32 + st * 8 + ((lane & 3) << 1);
            float e0b = __ldg(a.epb + n), e1b = __ldg(a.epb + n + 1);
            #pragma unroll
            for (int h = 0; h < 2; h++) {
                int m = row0 + h * 8;
                float e0 = acc[mt][st][h * 2 + 0];
                float e1 = acc[mt][st][h * 2 + 1];
                *(float2*)(a.ec + ((size_t)m << 7) + n) = make_float2(e0, e1);
                int bo = (m >> 13) << 10;
                int r_ = __ldg(a.recv + m) + bo, s_ = __ldg(a.send + m) + bo;
                float2 pr = *(const float2*)(a.prpsp + (size_t)r_ * 256 + n);
                float2 ps = *(const float2*)(a.prpsp + (size_t)s_ * 256 + 128 + n);
                float v0 = fmaxf(e0 + pr.x + ps.x + e0b, 0.f);
                float v1 = fmaxf(e1 + pr.y + ps.y + e1b, 0.f);
                atomicAdd(&a.agg[(size_t)r_ * 128 + n], v0);
                atomicAdd(&a.agg[(size_t)r_ * 128 + n + 1], v1);
            }
        }
    }
}

// ---------------- np_prpsp / tail (32-row tiles, K=256 capable) ----------------
#define NSTR   528
#define N_ALO  (32 * NSTR)
#define N_B0   (2 * N_ALO)
#define NP_SMEM (N_B0 + 2 * 256 * 272)   // 173056
#define TL_SMEM (N_B0 + 2 * 128 * NSTR)  // 168960

__device__ __forceinline__ void load_A_npagg(char* smem, int m0,
    const uint32_t* neb, const float* agg, int tid)
{
    #pragma unroll
    for (int it = 0; it < 8; it++) {
        int item = tid + (it << 8);
        int r = item >> 6, g = item & 63;
        int kc = g << 2;
        int m = m0 + r;
        uint32_t p0, p1, p2, p3;
        if (kc < 128) {
            uint4 v = *(const uint4*)(neb + ((size_t)m << 7) + kc);
            p0 = v.x; p1 = v.y; p2 = v.z; p3 = v.w;
        } else {
            float4 v = *(const float4*)(agg + ((size_t)m << 7) + (kc - 128));
            p0 = packbfp(v.x); p1 = packbfp(v.y); p2 = packbfp(v.z); p3 = packbfp(v.w);
        }
        uint32_t hi01 = (p0 & 0xffffu) | (p1 << 16);
        uint32_t hi23 = (p2 & 0xffffu) | (p3 << 16);
        uint32_t lo01 = (p0 >> 16) | (p1 & 0xffff0000u);
        uint32_t lo23 = (p2 >> 16) | (p3 & 0xffff0000u);
        int off = r * NSTR + g * 8;
        *(uint2*)(smem + off) = make_uint2(hi01, hi23);
        *(uint2*)(smem + N_ALO + off) = make_uint2(lo01, lo23);
    }
}

__global__ __launch_bounds__(256) void np_prpsp_kernel(
    const uint32_t* __restrict__ neb, const float* __restrict__ agg,
    const float* __restrict__ resid,
    const __nv_bfloat16* __restrict__ npHi, const __nv_bfloat16* __restrict__ npLo,
    const float* __restrict__ npb,
    const __nv_bfloat16* __restrict__ epHi, const __nv_bfloat16* __restrict__ epLo,
    float* __restrict__ nf_out, float* __restrict__ prpsp_out)
{
    extern __shared__ char smem[];
    const uint32_t sb = smem_u32(smem);
    const int tid = threadIdx.x;
    const int wid = tid >> 5, lane = tid & 31;
    const int wm = wid & 1, wn = wid >> 1;
    const int m0 = blockIdx.x * 32;

    float acc[8][4];
    #pragma unroll
    for (int st = 0; st < 8; st++)
        #pragma unroll
        for (int r = 0; r < 4; r++) acc[st][r] = 0.f;

    load_A_npagg(smem, m0, neb, agg, tid);
    load_Bw(smem, N_B0, 128 * NSTR, npHi, npLo, 128, 256, NSTR, tid);
    __syncthreads();
    mma_span<1>(sb, sb + N_ALO, sb + N_B0, sb + N_B0 + 128 * NSTR,
                NSTR, NSTR, 16, acc, wm, wn, lane);
    __syncthreads();
    epi_repack2(smem, NSTR, N_ALO, acc, m0, wm, npb, resid, nf_out, nullptr, wn, lane);
    load_Bw(smem, N_B0, 256 * 272, epHi, epLo, 256, 128, 272, tid);
    __syncthreads();
    mma_span<2>(sb, sb + N_ALO, sb + N_B0, sb + N_B0 + 256 * 272,
                NSTR, 272, 8, acc, wm, wn, lane);
    #pragma unroll
    for (int t2 = 0; t2 < 2; t2++) {
        float (*accp)[4] = acc + t2 * 4;
        write_accf(accp, m0, wm, wn, lane, prpsp_out, t2 * 128, 256);
    }
}

__global__ __launch_bounds__(256) void tail_kernel(
    const uint32_t* __restrict__ neb, const float* __restrict__ agg1,
    const float* __restrict__ nf1,
    const __nv_bfloat16* __restrict__ npHi, const __nv_bfloat16* __restrict__ npLo,
    const float* __restrict__ npb,
    const float* __restrict__ pc,
    const __nv_bfloat16* __restrict__ p0bHi, const __nv_bfloat16* __restrict__ p0bLo,
    const float* __restrict__ ppb0,
    const __nv_bfloat16* __restrict__ p1Hi, const __nv_bfloat16* __restrict__ p1Lo,
    const float* __restrict__ ppb1,
    const float* __restrict__ ppW2, const float* __restrict__ ppb2,
    float* __restrict__ out)
{
    extern __shared__ char smem[];
    const uint32_t sb = smem_u32(smem);
    const int tid = threadIdx.x;
    const int wid = tid >> 5, lane = tid & 31;
    const int wm = wid & 1, wn = wid >> 1;
    const int m0 = blockIdx.x * 32;

    float acc[4][4];
    #pragma unroll
    for (int st = 0; st < 4; st++)
        #pragma unroll
        for (int r = 0; r < 4; r++) acc[st][r] = 0.f;

    load_A_npagg(smem, m0, neb, agg1, tid);
    load_Bw(smem, N_B0, 128 * NSTR, npHi, npLo, 128, 256, NSTR, tid);
    __syncthreads();
    mma_span<1>(sb, sb + N_ALO, sb + N_B0, sb + N_B0 + 128 * NSTR,
                NSTR, NSTR, 16, acc, wm, wn, lane);
    __syncthreads();
    epi_repack2(smem, NSTR, N_ALO, acc, m0, wm, npb, nf1, nullptr, nullptr, wn, lane);
    load_Bw(smem, N_B0, 128 * 272, p0bHi, p0bLo, 128, 128, 272, tid);
    __syncthreads();
    mma_span<1>(sb, sb + N_ALO, sb + N_B0, sb + N_B0 + 128 * 272,
                NSTR, 272, 8, acc, wm, wn, lane);
    __syncthreads();
    epi_repack2(smem, NSTR, N_ALO, acc, m0, wm, ppb0, pc, nullptr, nullptr, wn, lane);
    load_Bw(smem, N_B0, 128 * 272, p1Hi, p1Lo, 128, 128, 272, tid);
    __syncthreads();
    mma_span<1>(sb, sb + N_ALO, sb + N_B0, sb + N_B0 + 128 * 272,
                NSTR, 272, 8, acc, wm, wn, lane);
    __syncthreads();
    float* stage = (float*)(smem + N_B0);
    #pragma unroll
    for (int st = 0; st < 4; st++) {
        int n = wn * 32 + st * 8 + ((lane & 3) << 1);
        float b0 = __ldg(ppb1 + n), b1 = __ldg(ppb1 + n + 1);
        int r0 = wm * 16 + (lane >> 2);
        #pragma unroll
        for (int h = 0; h < 2; h++) {
            int r = r0 + h * 8;
            stage[r * 132 + n]     = fmaxf(acc[st][h * 2 + 0] + b0, 0.f);
            stage[r * 132 + n + 1] = fmaxf(acc[st][h * 2 + 1] + b1, 0.f);
        }
    }
    __syncthreads();
    if (tid < 96) {
        int m = tid / 3, n = tid - (tid / 3) * 3;
        const float* aa = stage + m * 132;
        float s = __ldg(ppb2 + n);
        #pragma unroll 16
        for (int k = 0; k < 128; k++) s += aa[k] * __ldg(ppW2 + k * 3 + n);
        out[(size_t)(m0 + m) * 3 + n] = s;
    }
}

// ---------------- launch ----------------
extern "C" void kernel_launch(void* const* d_in, const int* in_sizes, int n_in,
                              void* d_out, int out_size)
{
    const float* x    = (const float*)d_in[0];
    const float* Rr   = (const float*)d_in[1];
    const float* Rs   = (const float*)d_in[2];
    const float* neW0 = (const float*)d_in[4];  const float* neb0 = (const float*)d_in[5];
    const float* neW1 = (const float*)d_in[6];  const float* neb1 = (const float*)d_in[7];
    const float* neW2 = (const float*)d_in[8];  const float* neb2 = (const float*)d_in[9];
    const float* eeW0 = (const float*)d_in[10]; const float* eeb0 = (const float*)d_in[11];
    const float* eeW1 = (const float*)d_in[12]; const float* eeb1 = (const float*)d_in[13];
    const float* eeW2 = (const float*)d_in[14]; const float* eeb2 = (const float*)d_in[15];
    const float* npW  = (const float*)d_in[16]; const float* npb  = (const float*)d_in[17];
    const float* epW  = (const float*)d_in[18]; const float* epb  = (const float*)d_in[19];
    const float* ppW0 = (const float*)d_in[20]; const float* ppb0 = (const float*)d_in[21];
    const float* ppW1 = (const float*)d_in[22]; const float* ppb1 = (const float*)d_in[23];
    const float* ppW2 = (const float*)d_in[24]; const float* ppb2 = (const float*)d_in[25];
    float* out = (float*)d_out;

    uint32_t* arena; cudaGetSymbolAddress((void**)&arena, g_arena);
    int* recv; cudaGetSymbolAddress((void**)&recv, g_recv);
    int* send; cudaGetSymbolAddress((void**)&send, g_send);
    __nv_bfloat16* whi; cudaGetSymbolAddress((void**)&whi, g_whi);
    __nv_bfloat16* wlo; cudaGetSymbolAddress((void**)&wlo, g_wlo);
    float* zb; cudaGetSymbolAddress((void**)&zb, g_zero);

    uint32_t* neb    = arena + OFF_NEB;
    float*    nef    = (float*)(arena + OFF_NEF);
    float*    nf1f   = (float*)(arena + OFF_NF1F);
    float*    pc     = (float*)(arena + OFF_PC);
    float*    agg0   = (float*)(arena + OFF_AGG0);
    float*    agg1   = (float*)(arena + OFF_AGG1);
    float*    prs    = (float*)(arena + OFF_PRS);
    float*    prpspA = (float*)(arena + OFF_PRPSPA);
    float*    prpspB = (float*)(arena + OFF_PRPSPB);
    float*    ec     = (float*)(arena + OFF_EC);

    const int WO[12] = {0,8192,24576,40960,57344,73728,90112,106496,139264,172032,188416,204800};

    static bool s_init = false;
    static cudaStream_t s1, s2;
    static cudaEvent_t evStart, evPrep, evS1, evNE;
    if (!s_init) {
        cudaStreamCreateWithFlags(&s1, cudaStreamNonBlocking);
        cudaStreamCreateWithFlags(&s2, cudaStreamNonBlocking);
        cudaEventCreateWithFlags(&evStart, cudaEventDisableTiming);
        cudaEventCreateWithFlags(&evPrep,  cudaEventDisableTiming);
        cudaEventCreateWithFlags(&evS1,    cudaEventDisableTiming);
        cudaEventCreateWithFlags(&evNE,    cudaEventDisableTiming);
        cudaFuncSetAttribute(hgemm<2,64>,   cudaFuncAttributeMaxDynamicSharedMemorySize, smem_hg(2,64));
        cudaFuncSetAttribute(node_mega,     cudaFuncAttributeMaxDynamicSharedMemorySize, NM_SMEM);
        cudaFuncSetAttribute(edge_mega,     cudaFuncAttributeMaxDynamicSharedMemorySize, EM_SMEM);
        cudaFuncSetAttribute(np_prpsp_kernel, cudaFuncAttributeMaxDynamicSharedMemorySize, NP_SMEM);
        cudaFuncSetAttribute(tail_kernel,     cudaFuncAttributeMaxDynamicSharedMemorySize, TL_SMEM);
        s_init = true;
    }

    // fork at root: extract + agg zeros on s1
    cudaEventRecord(evStart, 0);
    cudaStreamWaitEvent(s1, evStart, 0);
    extract_idx2_kernel<<<2 * BE / 8, 256, 0, s1>>>(Rr, Rs, recv, send);
    cudaMemsetAsync(agg0, 0, (size_t)BN * 128 * sizeof(float), s1);
    cudaMemsetAsync(agg1, 0, (size_t)BN * 128 * sizeof(float), s1);
    cudaEventRecord(evS1, s1);

    // origin: weight prep
    PArg pa;
    pa.W[0] = neW0; pa.W[1] = neW1; pa.W[2] = neW2;
    pa.W[3] = eeW0; pa.W[4] = eeW1; pa.W[5] = eeW2;
    pa.W[6] = epW;  pa.W[7] = epW;  pa.W[8] = npW;
    pa.W[9] = ppW0; pa.W[10] = ppW0; pa.W[11] = ppW1;
    prep_weights<<<dim3(12, 8), 256>>>(pa, whi, wlo);
    cudaEventRecord(evPrep, 0);
    cudaStreamWaitEvent(s2, evPrep, 0);

    // s2: fused node encoder + step-invariant projections
    {
        NodeArg na;
        na.x = x;
        na.w0h = whi + WO[0]; na.w0l = wlo + WO[0];
        na.w1h = whi + WO[1]; na.w1l = wlo + WO[1];
        na.w2h = whi + WO[2]; na.w2l = wlo + WO[2];
        na.eprh = whi + WO[7];          na.eprl = wlo + WO[7];
        na.epsh = whi + WO[7] + 16384;  na.epsl = wlo + WO[7] + 16384;
        na.pqh = whi + WO[9];  na.pql = wlo + WO[9];
        na.b0 = neb0; na.b1 = neb1; na.b2 = neb2;
        na.neb = neb; na.nef = nef; na.prpsp = prpspA; na.pc = pc;
        node_mega<<<BN / 32, 256, NM_SMEM, s2>>>(na);
    }
    cudaEventRecord(evNE, s2);

    // origin: PrPs = x @ [eer|ees]
    {
        GArg a;
        a.s0.p = x; a.s0.start = 0; a.s0.mode = 3; a.s0.rs = 32;
        a.s1.p = nullptr; a.s1.start = 32; a.s1.mode = 0; a.s1.rs = 0;
        a.K = 64; a.Bhi = whi + WO[3]; a.Blo = wlo + WO[3];
        a.bias = zb; a.outf = prs; a.ldo = 256;
        hgemm<2,64><<<BN / 32, 256, smem_hg(2,64)>>>(a);
    }

    // join: indices + node projections
    cudaStreamWaitEvent(0, evS1, 0);
    cudaStreamWaitEvent(0, evNE, 0);

    // fused edge chain + step-0 scatter
    {
        EdgeArg ea;
        ea.prs = prs; ea.recv = recv; ea.send = send; ea.eeb0 = eeb0;
        ea.w1h = whi + WO[4]; ea.w1l = wlo + WO[4];
        ea.w2h = whi + WO[5]; ea.w2l = wlo + WO[5];
        ea.weh = whi + WO[6]; ea.wel = wlo + WO[6];
        ea.b1 = eeb1; ea.b2 = eeb2;
        ea.prpsp = prpspA; ea.epb = epb;
        ea.ec = ec; ea.agg = agg0;
        edge_mega<<<BE / 64, 256, EM_SMEM>>>(ea);
    }

    // fused np(step0) + prpsp(step1)
    np_prpsp_kernel<<<BN / 32, 256, NP_SMEM>>>(neb, agg0, nef,
        whi + WO[8], wlo + WO[8], npb, whi + WO[7], wlo + WO[7],
        nf1f, prpspB);

    // step-1 scatter
    fused_scatter_kernel<<<BE * 128 / 256, 256>>>(ec, prpspB, recv, send, epb, agg1);

    // fused np(step1) + predictor + output
    tail_kernel<<<BN / 32, 256, TL_SMEM>>>(neb, agg1, nf1f,
        whi + WO[8], wlo + WO[8], npb, pc,
        whi + WO[10], wlo + WO[10], ppb0,
        whi + WO[11], wlo + WO[11], ppb1,
        ppW2, ppb2, out);
}

// round 10
// speedup vs baseline: 2.9752x; 1.1086x over previous
#include <cuda_runtime.h>
#include <cuda_bf16.h>
#include <cstdint>

// ---------------- problem dims ----------------
#define Nn 1024
#define Ee 8192
#define BN 4096    // B*N
#define BE 32768   // B*E

// ---------------- device scratch ----------------
#define OFF_NEB    ((size_t)0)                       // node_enc bfp
#define OFF_NEF    (OFF_NEB + (size_t)BN*128)        // node_enc f32
#define OFF_NF1F   (OFF_NEF + (size_t)BN*128)        // nf1 f32
#define OFF_PC     (OFF_NF1F + (size_t)BN*128)       // neb@pp0a f32
#define OFF_AGG0   (OFF_PC + (size_t)BN*128)
#define OFF_AGG1   (OFF_AGG0 + (size_t)BN*128)
#define OFF_PRS    (OFF_AGG1 + (size_t)BN*128)       // [BN,256] f32 (x@Wr | x@Ws)
#define OFF_PRPSPA (OFF_PRS + (size_t)BN*256)        // [BN,256] f32 step0
#define OFF_PRPSPB (OFF_PRPSPA + (size_t)BN*256)     // [BN,256] f32 step1
#define OFF_EC     (OFF_PRPSPB + (size_t)BN*256)     // [BE,128] f32
#define ARENA_U32  (OFF_EC + (size_t)BE*128)

__device__ uint32_t g_arena[ARENA_U32];
__device__ int g_recv[BE];
__device__ int g_send[BE];
__device__ float g_zero[256];

// split/transposed weights [n][kpad] bf16, 12 matrices
#define WT_TOTAL 221184
__device__ __nv_bfloat16 g_whi[WT_TOTAL];
__device__ __nv_bfloat16 g_wlo[WT_TOTAL];

// ---------------- helpers ----------------
__device__ __forceinline__ uint32_t smem_u32(const void* p) {
    uint32_t a;
    asm("{ .reg .u64 t; cvta.to.shared.u64 t, %1; cvt.u32.u64 %0, t; }" : "=r"(a) : "l"(p));
    return a;
}

#define LDMX4(r, ad) \
    asm volatile("ldmatrix.sync.aligned.m8n8.x4.shared.b16 {%0,%1,%2,%3}, [%4];" \
        : "=r"((r)[0]), "=r"((r)[1]), "=r"((r)[2]), "=r"((r)[3]) : "r"(ad))

#define MMA16816(d, av, bv) \
    asm volatile("mma.sync.aligned.m16n8k16.row.col.f32.bf16.bf16.f32 " \
        "{%0,%1,%2,%3},{%4,%5,%6,%7},{%8,%9},{%0,%1,%2,%3};" \
        : "+f"((d)[0]), "+f"((d)[1]), "+f"((d)[2]), "+f"((d)[3]) \
        : "r"((av)[0]), "r"((av)[1]), "r"((av)[2]), "r"((av)[3]), \
          "r"((bv)[0]), "r"((bv)[1]))

#define CP_ASYNC16(sa, gp) \
    asm volatile("cp.async.cg.shared.global [%0], [%1], 16;" :: "r"(sa), "l"(gp))
#define CP_COMMIT()  asm volatile("cp.async.commit_group;" ::: "memory")
#define CP_WAIT1()   asm volatile("cp.async.wait_group 1;" ::: "memory")
#define CP_WAIT0()   asm volatile("cp.async.wait_group 0;" ::: "memory")

__device__ __forceinline__ uint32_t packbfp(float v) {
    __nv_bfloat16 h = __float2bfloat16(v);
    float hf = __bfloat162float(h);
    __nv_bfloat16 l = __float2bfloat16(v - hf);
    return (uint32_t)__bfloat16_as_ushort(h) | ((uint32_t)__bfloat16_as_ushort(l) << 16);
}

// 3-pass emulated MMA over one K-span. tile = m-tile index (16 rows each).
template<int NT>
__device__ __forceinline__ void mma_span(
    uint32_t aHi, uint32_t aLo, uint32_t bHi, uint32_t bLo,
    int astr, int bstr, int nk, float (*acc)[4], int tile, int wn, int lane)
{
    for (int ks = 0; ks < nk; ks++) {
        uint32_t bh[NT * 8], bl[NT * 8];
        #pragma unroll
        for (int t2 = 0; t2 < NT; t2++)
            #pragma unroll
            for (int np = 0; np < 2; np++) {
                int n = t2 * 128 + wn * 32 + np * 16 + ((lane >> 4) << 3) + (lane & 7);
                int koff = ((lane >> 3) & 1) << 3;
                uint32_t ad = bHi + n * bstr + (ks * 16 + koff) * 2;
                LDMX4(&bh[(t2 * 2 + np) * 4], ad);
                LDMX4(&bl[(t2 * 2 + np) * 4], ad + (bLo - bHi));
            }
        int r = tile * 16 + (lane & 15);
        int koff = (lane >> 4) << 3;
        uint32_t ad = aHi + r * astr + (ks * 16 + koff) * 2;
        uint32_t ah[4], al[4];
        LDMX4(ah, ad);
        LDMX4(al, ad + (aLo - aHi));
        #pragma unroll
        for (int st = 0; st < NT * 4; st++) {
            MMA16816(acc[st], ah, &bh[st * 2]);
            MMA16816(acc[st], ah, &bl[st * 2]);
            MMA16816(acc[st], al, &bh[st * 2]);
        }
    }
}

// synchronous weight load (LDG+STS)
__device__ __forceinline__ void load_Bw(char* smem, int base, int plane,
    const __nv_bfloat16* Bhi, const __nv_bfloat16* Blo,
    int nrows, int kcols, int bstr, int tid)
{
    int kg = kcols >> 3;
    int per = nrows * kg;
    for (int item = tid; item < per; item += 256) {
        int n = item / kg, g = item - n * kg;
        size_t goff = (size_t)n * kcols + (g << 3);
        int so = base + n * bstr + (g << 4);
        *(uint4*)(smem + so) = *(const uint4*)(Bhi + goff);
        *(uint4*)(smem + so + plane) = *(const uint4*)(Blo + goff);
    }
}

// async weight load (cp.async, caller commits/waits)
__device__ __forceinline__ void load_Bw_cp(uint32_t sbase, int plane,
    const __nv_bfloat16* Bhi, const __nv_bfloat16* Blo,
    int nrows, int kcols, int bstr, int tid)
{
    int kg = kcols >> 3;
    int per = nrows * kg;
    for (int item = tid; item < per; item += 256) {
        int n = item / kg, g = item - n * kg;
        size_t goff = (size_t)n * kcols + (g << 3);
        uint32_t so = sbase + n * bstr + (g << 4);
        CP_ASYNC16(so, Bhi + goff);
        CP_ASYNC16(so + plane, Blo + goff);
    }
}

// epilogue: s = acc + bias (+resid); relu; repack into A smem planes; optional outf/outb
__device__ __forceinline__ void epi_repack2(char* smem, int astr, int aplane,
    float (*acc)[4], int m0, int tile,
    const float* bias, const float* resid, float* outf, uint32_t* outb,
    int wn, int lane)
{
    #pragma unroll
    for (int st = 0; st < 4; st++) {
        int n = wn * 32 + st * 8 + ((lane & 3) << 1);
        float b0 = __ldg(bias + n), b1 = __ldg(bias + n + 1);
        int r0 = tile * 16 + (lane >> 2);
        #pragma unroll
        for (int h = 0; h < 2; h++) {
            int r = r0 + h * 8;
            float s0 = acc[st][h * 2 + 0] + b0;
            float s1 = acc[st][h * 2 + 1] + b1;
            if (resid) {
                float2 rv = *(const float2*)(resid + (((size_t)(m0 + r)) << 7) + n);
                s0 += rv.x; s1 += rv.y;
            }
            s0 = fmaxf(s0, 0.f); s1 = fmaxf(s1, 0.f);
            if (outf) *(float2*)(outf + (((size_t)(m0 + r)) << 7) + n) = make_float2(s0, s1);
            uint32_t p0 = packbfp(s0), p1 = packbfp(s1);
            if (outb) *(uint2*)(outb + (((size_t)(m0 + r)) << 7) + n) = make_uint2(p0, p1);
            int off = r * astr + n * 2;
            *(uint32_t*)(smem + off) = (p0 & 0xffffu) | (p1 << 16);
            *(uint32_t*)(smem + aplane + off) = (p0 >> 16) | (p1 & 0xffff0000u);
            acc[st][h * 2 + 0] = 0.f;
            acc[st][h * 2 + 1] = 0.f;
        }
    }
}

// write acc (f32, no bias/relu) to out[m][nbase+n], zero acc
__device__ __forceinline__ void write_accf(float (*acc)[4], int m0, int tile,
    int wn, int lane, float* out, int nbase, int ldo)
{
    #pragma unroll
    for (int st = 0; st < 4; st++) {
        int n = nbase + wn * 32 + st * 8 + ((lane & 3) << 1);
        int r0 = tile * 16 + (lane >> 2);
        #pragma unroll
        for (int h = 0; h < 2; h++) {
            int m = m0 + r0 + h * 8;
            *(float2*)(out + (size_t)m * ldo + n) =
                make_float2(acc[st][h * 2 + 0], acc[st][h * 2 + 1]);
            acc[st][h * 2 + 0] = 0.f;
            acc[st][h * 2 + 1] = 0.f;
        }
    }
}

// ---------------- aux kernels ----------------
// one-hot argmax with two-batch early exit (expected 0.75x traffic)
__global__ void extract_idx2_kernel(const float* __restrict__ Rr,
                                    const float* __restrict__ Rs,
                                    int* __restrict__ recv, int* __restrict__ send)
{
    int row = blockIdx.x * 8 + (threadIdx.x >> 5);
    int lane = threadIdx.x & 31;
    const float* R = (row < BE) ? Rr : Rs;
    int r = (row < BE) ? row : row - BE;
    const float4* p = (const float4*)(R + (size_t)r * Nn);
    int found = -1;
    #pragma unroll
    for (int i = 0; i < 4; i++) {
        int q = lane + i * 32;
        float4 v = p[q];
        if (v.x > 0.5f) found = q * 4 + 0;
        if (v.y > 0.5f) found = q * 4 + 1;
        if (v.z > 0.5f) found = q * 4 + 2;
        if (v.w > 0.5f) found = q * 4 + 3;
    }
    if (__ballot_sync(0xFFFFFFFFu, found >= 0) == 0u) {
        #pragma unroll
        for (int i = 4; i < 8; i++) {
            int q = lane + i * 32;
            float4 v = p[q];
            if (v.x > 0.5f) found = q * 4 + 0;
            if (v.y > 0.5f) found = q * 4 + 1;
            if (v.z > 0.5f) found = q * 4 + 2;
            if (v.w > 0.5f) found = q * 4 + 3;
        }
    }
    #pragma unroll
    for (int o = 16; o; o >>= 1) found = max(found, __shfl_xor_sync(0xFFFFFFFFu, found, o));
    if (lane == 0) {
        found = max(found, 0);
        if (row < BE) recv[r] = found; else send[r] = found;
    }
}

// matrices: 0 ne0 1 ne1 2 ne2 3 eers(R256) 4 ee1 5 ee2 6 ep_e 7 ep_rs(R256)
//           8 np(K256) 9 pp0a 10 pp0b 11 pp1
struct PArg { const float* W[12]; };
__constant__ int c_Ks[12]  = {32,128,128, 32,128,128,128,128,256,128,128,128};
__constant__ int c_Kps[12] = {64,128,128, 64,128,128,128,128,256,128,128,128};
__constant__ int c_Rs[12]  = {128,128,128,256,128,128,128,256,128,128,128,128};
__constant__ int c_r0a[12] = {0,0,0,0,0,0,0,128,0,0,128,0};
__constant__ int c_r0b[12] = {0,0,0,32,0,0,0,256,0,0,0,0};
__constant__ int c_off[12] = {0,8192,24576,40960,57344,73728,90112,106496,139264,172032,188416,204800};

__global__ void prep_weights(PArg a, __nv_bfloat16* __restrict__ hi, __nv_bfloat16* __restrict__ lo)
{
    int mid = blockIdx.x;
    int K = c_Ks[mid], Kp = c_Kps[mid], R = c_Rs[mid];
    int r0a = c_r0a[mid], r0b = c_r0b[mid];
    const float* W = a.W[mid];
    __nv_bfloat16* dh = hi + c_off[mid];
    __nv_bfloat16* dl = lo + c_off[mid];
    int total = R * Kp;
    for (int i = threadIdx.x + blockIdx.y * blockDim.x; i < total; i += blockDim.x * gridDim.y) {
        int n = i / Kp, k = i - n * Kp;
        int col = n & 127;
        int r0 = (n >> 7) ? r0b : r0a;
        float v = (k < K) ? W[(size_t)(r0 + k) * 128 + col] : 0.f;
        __nv_bfloat16 h = __float2bfloat16(v);
        dh[i] = h;
        dl[i] = __float2bfloat16(v - __bfloat162float(h));
    }
}

// step-1 scatter
__global__ void fused_scatter_kernel(const float* __restrict__ ec,
                                     const float* __restrict__ prpsp,
                                     const int* __restrict__ recv,
                                     const int* __restrict__ send,
                                     const float* __restrict__ bias,
                                     float* __restrict__ agg)
{
    int t = blockIdx.x * blockDim.x + threadIdx.x;
    if (t >= BE * 128) return;
    int e = t >> 7, h = t & 127;
    int bo = (e >> 13) << 10;
    int r = __ldg(recv + e) + bo, s = __ldg(send + e) + bo;
    float v = ec[t] + prpsp[(size_t)r * 256 + h] + prpsp[(size_t)s * 256 + 128 + h] + __ldg(bias + h);
    v = fmaxf(v, 0.f);
    atomicAdd(&agg[(size_t)r * 128 + h], v);
}

// ---------------- generic HMMA GEMM (PrPs only) ----------------
struct Seg { const void* p; int start; int mode; int rs; };
struct GArg {
    Seg s0, s1;
    int K;
    const __nv_bfloat16 *Bhi, *Blo;
    const float* bias;
    float* outf;
    int ldo;
};

template<int NT, int KCH>
__global__ __launch_bounds__(256) void hgemm(GArg a)
{
    constexpr int STRIDE = KCH * 2 + 16;
    constexpr int ALO = 32 * STRIDE;
    constexpr int BHI = 2 * ALO;
    constexpr int BPL = NT * 128 * STRIDE;
    extern __shared__ char smem[];
    const uint32_t sb = smem_u32(smem);
    const int tid = threadIdx.x;
    const int wid = tid >> 5, lane = tid & 31;
    const int wm = wid & 1, wn = wid >> 1;
    const int m0 = blockIdx.x * 32;

    float acc[NT * 4][4];
    #pragma unroll
    for (int st = 0; st < NT * 4; st++)
        #pragma unroll
        for (int r = 0; r < 4; r++) acc[st][r] = 0.f;

    const int nchunks = a.K / KCH;
    for (int c = 0; c < nchunks; c++) {
        const int k0 = c * KCH;
        #pragma unroll
        for (int it = 0; it < KCH / 32; it++) {
            int item = tid + (it << 8);
            int r = item / (KCH / 4), g = item % (KCH / 4);
            int kc = k0 + (g << 2);
            int m = m0 + r;
            uint32_t p0, p1, p2, p3;
            const Seg& sg = (kc >= a.s1.start) ? a.s1 : a.s0;
            if (sg.mode == 0) {
                p0 = p1 = p2 = p3 = 0u;
            } else {
                long base = (long)m * sg.rs + (kc - sg.start);
                float4 v = *((const float4*)sg.p + (base >> 2));
                p0 = packbfp(v.x); p1 = packbfp(v.y); p2 = packbfp(v.z); p3 = packbfp(v.w);
            }
            uint32_t hi01 = (p0 & 0xffffu) | (p1 << 16);
            uint32_t hi23 = (p2 & 0xffffu) | (p3 << 16);
            uint32_t lo01 = (p0 >> 16) | (p1 & 0xffff0000u);
            uint32_t lo23 = (p2 >> 16) | (p3 & 0xffff0000u);
            int off = r * STRIDE + g * 8;
            *(uint2*)(smem + off) = make_uint2(hi01, hi23);
            *(uint2*)(smem + ALO + off) = make_uint2(lo01, lo23);
        }
        #pragma unroll
        for (int it = 0; it < NT * KCH / 16; it++) {
            int item = tid + (it << 8);
            int n = item / (KCH / 8), g = item % (KCH / 8);
            size_t goff = (size_t)n * a.K + k0 + (g << 3);
            int off = n * STRIDE + g * 16;
            *(uint4*)(smem + BHI + off) = *(const uint4*)(a.Bhi + goff);
            *(uint4*)(smem + BHI + BPL + off) = *(const uint4*)(a.Blo + goff);
        }
        __syncthreads();
        mma_span<NT>(sb, sb + ALO, sb + BHI, sb + BHI + BPL,
                     STRIDE, STRIDE, KCH / 16, acc, wm, wn, lane);
        __syncthreads();
    }
    #pragma unroll
    for (int t2 = 0; t2 < NT; t2++) {
        float (*accp)[4] = acc + t2 * 4;
        write_accf(accp, m0, wm, wn, lane, a.outf, t2 * 128, a.ldo);
    }
}

constexpr int smem_hg(int NT, int KCH) {
    return (2 * 32 + 2 * NT * 128) * (KCH * 2 + 16);
}

// ---------------- node_mega: ne0->ne1->ne2->prpsp_r->prpsp_s->pc ----------------
// cp.async ping-pong weight slots: loads hidden behind MMA phases
#define NM_STR   272
#define NM_ALO   (32 * NM_STR)             // 8704
#define NM_B0    (2 * NM_ALO)              // 17408
#define NM_BPL   (128 * NM_STR)            // 34816
#define NM_SLOT  (2 * NM_BPL)              // 69632
#define NM_SMEM  (NM_B0 + 2 * NM_SLOT)     // 156672

struct NodeArg {
    const float* x;
    const __nv_bfloat16 *w0h,*w0l,*w1h,*w1l,*w2h,*w2l,*eprh,*eprl,*epsh,*epsl,*pqh,*pql;
    const float *b0,*b1,*b2;
    uint32_t* neb; float* nef; float* prpsp; float* pc;
};

__global__ __launch_bounds__(256) void node_mega(NodeArg a)
{
    extern __shared__ char smem[];
    const uint32_t sb = smem_u32(smem);
    const int tid = threadIdx.x;
    const int wid = tid >> 5, lane = tid & 31;
    const int wm = wid & 1, wn = wid >> 1;
    const int m0 = blockIdx.x * 32;

    const uint32_t sA = sb + NM_B0;
    const uint32_t sB = sb + NM_B0 + NM_SLOT;

    float acc[4][4];
    #pragma unroll
    for (int st = 0; st < 4; st++)
        #pragma unroll
        for (int r = 0; r < 4; r++) acc[st][r] = 0.f;

    // prefetch W0 and W1
    load_Bw_cp(sA, NM_BPL, a.w0h, a.w0l, 128, 64, NM_STR, tid);  CP_COMMIT();
    load_Bw_cp(sB, NM_BPL, a.w1h, a.w1l, 128, 128, NM_STR, tid); CP_COMMIT();

    // A <- x (K=32 pad 64)
    #pragma unroll
    for (int it = 0; it < 2; it++) {
        int item = tid + (it << 8);
        int r = item >> 4, g = item & 15;
        int kc = g << 2;
        uint32_t p0 = 0, p1 = 0, p2 = 0, p3 = 0;
        if (kc < 32) {
            float4 v = *(const float4*)(a.x + (size_t)(m0 + r) * 32 + kc);
            p0 = packbfp(v.x); p1 = packbfp(v.y); p2 = packbfp(v.z); p3 = packbfp(v.w);
        }
        uint32_t hi01 = (p0 & 0xffffu) | (p1 << 16);
        uint32_t hi23 = (p2 & 0xffffu) | (p3 << 16);
        uint32_t lo01 = (p0 >> 16) | (p1 & 0xffff0000u);
        uint32_t lo23 = (p2 >> 16) | (p3 & 0xffff0000u);
        int off = r * NM_STR + g * 8;
        *(uint2*)(smem + off) = make_uint2(hi01, hi23);
        *(uint2*)(smem + NM_ALO + off) = make_uint2(lo01, lo23);
    }

    // P0: ne0 (W0 in sA), prefetch W2 after
    CP_WAIT1(); __syncthreads();
    mma_span<1>(sb, sb + NM_ALO, sA, sA + NM_BPL, NM_STR, NM_STR, 4, acc, wm, wn, lane);
    __syncthreads();
    epi_repack2(smem, NM_STR, NM_ALO, acc, m0, wm, a.b0, nullptr, nullptr, nullptr, wn, lane);
    load_Bw_cp(sA, NM_BPL, a.w2h, a.w2l, 128, 128, NM_STR, tid); CP_COMMIT();

    // P1: ne1 (W1 in sB), prefetch epr
    CP_WAIT1(); __syncthreads();
    mma_span<1>(sb, sb + NM_ALO, sB, sB + NM_BPL, NM_STR, NM_STR, 8, acc, wm, wn, lane);
    __syncthreads();
    epi_repack2(smem, NM_STR, NM_ALO, acc, m0, wm, a.b1, nullptr, nullptr, nullptr, wn, lane);
    load_Bw_cp(sB, NM_BPL, a.eprh, a.eprl, 128, 128, NM_STR, tid); CP_COMMIT();

    // P2: ne2 (W2 in sA) -> writes neb/nef, prefetch eps
    CP_WAIT1(); __syncthreads();
    mma_span<1>(sb, sb + NM_ALO, sA, sA + NM_BPL, NM_STR, NM_STR, 8, acc, wm, wn, lane);
    __syncthreads();
    epi_repack2(smem, NM_STR, NM_ALO, acc, m0, wm, a.b2, nullptr, a.nef, a.neb, wn, lane);
    load_Bw_cp(sA, NM_BPL, a.epsh, a.epsl, 128, 128, NM_STR, tid); CP_COMMIT();

    // P3: prpsp_r (epr in sB), prefetch pq
    CP_WAIT1(); __syncthreads();
    mma_span<1>(sb, sb + NM_ALO, sB, sB + NM_BPL, NM_STR, NM_STR, 8, acc, wm, wn, lane);
    __syncthreads();
    write_accf(acc, m0, wm, wn, lane, a.prpsp, 0, 256);
    load_Bw_cp(sB, NM_BPL, a.pqh, a.pql, 128, 128, NM_STR, tid); CP_COMMIT();

    // P4: prpsp_s (eps in sA)
    CP_WAIT1(); __syncthreads();
    mma_span<1>(sb, sb + NM_ALO, sA, sA + NM_BPL, NM_STR, NM_STR, 8, acc, wm, wn, lane);
    __syncthreads();
    write_accf(acc, m0, wm, wn, lane, a.prpsp, 128, 256);

    // P5: pc (pq in sB)
    CP_WAIT0(); __syncthreads();
    mma_span<1>(sb, sb + NM_ALO, sB, sB + NM_BPL, NM_STR, NM_STR, 8, acc, wm, wn, lane);
    __syncthreads();
    write_accf(acc, m0, wm, wn, lane, a.pc, 0, 128);
}

// ---------------- edge_mega: ee1 -> ee2 -> ec -> scatter0 ----------------
#define EM_STR   272
#define EM_ALO   (64 * EM_STR)             // 17408
#define EM_B0    (2 * EM_ALO)              // 34816
#define EM_BPL   (128 * EM_STR)            // 34816
#define EM_SMEM  (EM_B0 + 2 * EM_BPL)      // 104448

struct EdgeArg {
    const float* prs; const int* recv; const int* send; const float* eeb0;
    const __nv_bfloat16 *w1h,*w1l,*w2h,*w2l,*weh,*wel;
    const float *b1,*b2;
    const float* prpsp; const float* epb;
    float* ec; float* agg;
};

__global__ __launch_bounds__(256, 2) void edge_mega(EdgeArg a)
{
    extern __shared__ char smem[];
    const uint32_t sb = smem_u32(smem);
    const int tid = threadIdx.x;
    const int wid = tid >> 5, lane = tid & 31;
    const int wm = wid & 1, wn = wid >> 1;
    const int m0 = blockIdx.x * 64;

    float acc[2][4][4];
    #pragma unroll
    for (int mt = 0; mt < 2; mt++)
        #pragma unroll
        for (int st = 0; st < 4; st++)
            #pragma unroll
            for (int r = 0; r < 4; r++) acc[mt][st][r] = 0.f;

    // A <- edge layer0 on the fly: relu(Pr[recv]+Ps[send]+b0)
    #pragma unroll
    for (int it = 0; it < 8; it++) {
        int item = tid + (it << 8);
        int r = item >> 5, g = item & 31;
        int kc = g << 2;
        int m = m0 + r;
        int bo = (m >> 13) << 10;
        int rr = __ldg(a.recv + m) + bo, ss = __ldg(a.send + m) + bo;
        float4 pr = *(const float4*)(a.prs + (size_t)rr * 256 + kc);
        float4 ps = *(const float4*)(a.prs + (size_t)ss * 256 + 128 + kc);
        float4 bb = *(const float4*)(a.eeb0 + kc);
        uint32_t p0 = packbfp(fmaxf(pr.x + ps.x + bb.x, 0.f));
        uint32_t p1 = packbfp(fmaxf(pr.y + ps.y + bb.y, 0.f));
        uint32_t p2 = packbfp(fmaxf(pr.z + ps.z + bb.z, 0.f));
        uint32_t p3 = packbfp(fmaxf(pr.w + ps.w + bb.w, 0.f));
        uint32_t hi01 = (p0 & 0xffffu) | (p1 << 16);
        uint32_t hi23 = (p2 & 0xffffu) | (p3 << 16);
        uint32_t lo01 = (p0 >> 16) | (p1 & 0xffff0000u);
        uint32_t lo23 = (p2 >> 16) | (p3 & 0xffff0000u);
        int off = r * EM_STR + g * 8;
        *(uint2*)(smem + off) = make_uint2(hi01, hi23);
        *(uint2*)(smem + EM_ALO + off) = make_uint2(lo01, lo23);
    }
    load_Bw(smem, EM_B0, EM_BPL, a.w1h, a.w1l, 128, 128, EM_STR, tid);
    __syncthreads();
    #pragma unroll
    for (int mt = 0; mt < 2; mt++)
        mma_span<1>(sb, sb + EM_ALO, sb + EM_B0, sb + EM_B0 + EM_BPL,
                    EM_STR, EM_STR, 8, acc[mt], wm * 2 + mt, wn, lane);
    __syncthreads();
    #pragma unroll
    for (int mt = 0; mt < 2; mt++)
        epi_repack2(smem, EM_STR, EM_ALO, acc[mt], m0, wm * 2 + mt, a.b1,
                    nullptr, nullptr, nullptr, wn, lane);
    load_Bw(smem, EM_B0, EM_BPL, a.w2h, a.w2l, 128, 128, EM_STR, tid);
    __syncthreads();
    #pragma unroll
    for (int mt = 0; mt < 2; mt++)
        mma_span<1>(sb, sb + EM_ALO, sb + EM_B0, sb + EM_B0 + EM_BPL,
                    EM_STR, EM_STR, 8, acc[mt], wm * 2 + mt, wn, lane);
    __syncthreads();
    #pragma unroll
    for (int mt = 0; mt < 2; mt++)
        epi_repack2(smem, EM_STR, EM_ALO, acc[mt], m0, wm * 2 + mt, a.b2,
                    nullptr, nullptr, nullptr, wn, lane);
    load_Bw(smem, EM_B0, EM_BPL, a.weh, a.wel, 128, 128, EM_STR, tid);
    __syncthreads();
    #pragma unroll
    for (int mt = 0; mt < 2; mt++)
        mma_span<1>(sb, sb + EM_ALO, sb + EM_B0, sb + EM_B0 + EM_BPL,
                    EM_STR, EM_STR, 8, acc[mt], wm * 2 + mt, wn, lane);

    // epilogue: write ec + fused step-0 scatter
    #pragma unroll
    for (int mt = 0; mt < 2; mt++) {
        int row0 = m0 + (wm * 2 + mt) * 16 + (lane >> 2);
        #pragma unroll
        for (int st = 0; st < 4; st++) {
            int n = wn * 32 + st * 8 + ((lane & 3) << 1);
            float e0b = __ldg(a.epb + n), e1b = __ldg(a.epb + n + 1);
            #pragma unroll
            for (int h = 0; h < 2; h++) {
                int m = row0 + h * 8;
                float e0 = acc[mt][st][h * 2 + 0];
                float e1 = acc[mt][st][h * 2 + 1];
                *(float2*)(a.ec + ((size_t)m << 7) + n) = make_float2(e0, e1);
                int bo = (m >> 13) << 10;
                int r_ = __ldg(a.recv + m) + bo, s_ = __ldg(a.send + m) + bo;
                float2 pr = *(const float2*)(a.prpsp + (size_t)r_ * 256 + n);
                float2 ps = *(const float2*)(a.prpsp + (size_t)s_ * 256 + 128 + n);
                float v0 = fmaxf(e0 + pr.x + ps.x + e0b, 0.f);
                float v1 = fmaxf(e1 + pr.y + ps.y + e1b, 0.f);
                atomicAdd(&a.agg[(size_t)r_ * 128 + n], v0);
                atomicAdd(&a.agg[(size_t)r_ * 128 + n + 1], v1);
            }
        }
    }
}

// ---------------- np_prpsp / tail (32-row tiles, K=256 capable) ----------------
#define NSTR   528
#define N_ALO  (32 * NSTR)
#define N_B0   (2 * N_ALO)
#define NP_SMEM (N_B0 + 2 * 256 * 272)   // 173056
#define TL_SMEM (N_B0 + 2 * 128 * NSTR)  // 168960

__device__ __forceinline__ void load_A_npagg(char* smem, int m0,
    const uint32_t* neb, const float* agg, int tid)
{
    #pragma unroll
    for (int it = 0; it < 8; it++) {
        int item = tid + (it << 8);
        int r = item >> 6, g = item & 63;
        int kc = g << 2;
        int m = m0 + r;
        uint32_t p0, p1, p2, p3;
        if (kc < 128) {
            uint4 v = *(const uint4*)(neb + ((size_t)m << 7) + kc);
            p0 = v.x; p1 = v.y; p2 = v.z; p3 = v.w;
        } else {
            float4 v = *(const float4*)(agg + ((size_t)m << 7) + (kc - 128));
            p0 = packbfp(v.x); p1 = packbfp(v.y); p2 = packbfp(v.z); p3 = packbfp(v.w);
        }
        uint32_t hi01 = (p0 & 0xffffu) | (p1 << 16);
        uint32_t hi23 = (p2 & 0xffffu) | (p3 << 16);
        uint32_t lo01 = (p0 >> 16) | (p1 & 0xffff0000u);
        uint32_t lo23 = (p2 >> 16) | (p3 & 0xffff0000u);
        int off = r * NSTR + g * 8;
        *(uint2*)(smem + off) = make_uint2(hi01, hi23);
        *(uint2*)(smem + N_ALO + off) = make_uint2(lo01, lo23);
    }
}

__global__ __launch_bounds__(256) void np_prpsp_kernel(
    const uint32_t* __restrict__ neb, const float* __restrict__ agg,
    const float* __restrict__ resid,
    const __nv_bfloat16* __restrict__ npHi, const __nv_bfloat16* __restrict__ npLo,
    const float* __restrict__ npb,
    const __nv_bfloat16* __restrict__ epHi, const __nv_bfloat16* __restrict__ epLo,
    float* __restrict__ nf_out, float* __restrict__ prpsp_out)
{
    extern __shared__ char smem[];
    const uint32_t sb = smem_u32(smem);
    const int tid = threadIdx.x;
    const int wid = tid >> 5, lane = tid & 31;
    const int wm = wid & 1, wn = wid >> 1;
    const int m0 = blockIdx.x * 32;

    float acc[8][4];
    #pragma unroll
    for (int st = 0; st < 8; st++)
        #pragma unroll
        for (int r = 0; r < 4; r++) acc[st][r] = 0.f;

    load_A_npagg(smem, m0, neb, agg, tid);
    load_Bw(smem, N_B0, 128 * NSTR, npHi, npLo, 128, 256, NSTR, tid);
    __syncthreads();
    mma_span<1>(sb, sb + N_ALO, sb + N_B0, sb + N_B0 + 128 * NSTR,
                NSTR, NSTR, 16, acc, wm, wn, lane);
    __syncthreads();
    epi_repack2(smem, NSTR, N_ALO, acc, m0, wm, npb, resid, nf_out, nullptr, wn, lane);
    load_Bw(smem, N_B0, 256 * 272, epHi, epLo, 256, 128, 272, tid);
    __syncthreads();
    mma_span<2>(sb, sb + N_ALO, sb + N_B0, sb + N_B0 + 256 * 272,
                NSTR, 272, 8, acc, wm, wn, lane);
    #pragma unroll
    for (int t2 = 0; t2 < 2; t2++) {
        float (*accp)[4] = acc + t2 * 4;
        write_accf(accp, m0, wm, wn, lane, prpsp_out, t2 * 128, 256);
    }
}

__global__ __launch_bounds__(256) void tail_kernel(
    const uint32_t* __restrict__ neb, const float* __restrict__ agg1,
    const float* __restrict__ nf1,
    const __nv_bfloat16* __restrict__ npHi, const __nv_bfloat16* __restrict__ npLo,
    const float* __restrict__ npb,
    const float* __restrict__ pc,
    const __nv_bfloat16* __restrict__ p0bHi, const __nv_bfloat16* __restrict__ p0bLo,
    const float* __restrict__ ppb0,
    const __nv_bfloat16* __restrict__ p1Hi, const __nv_bfloat16* __restrict__ p1Lo,
    const float* __restrict__ ppb1,
    const float* __restrict__ ppW2, const float* __restrict__ ppb2,
    float* __restrict__ out)
{
    extern __shared__ char smem[];
    const uint32_t sb = smem_u32(smem);
    const int tid = threadIdx.x;
    const int wid = tid >> 5, lane = tid & 31;
    const int wm = wid & 1, wn = wid >> 1;
    const int m0 = blockIdx.x * 32;

    float acc[4][4];
    #pragma unroll
    for (int st = 0; st < 4; st++)
        #pragma unroll
        for (int r = 0; r < 4; r++) acc[st][r] = 0.f;

    load_A_npagg(smem, m0, neb, agg1, tid);
    load_Bw(smem, N_B0, 128 * NSTR, npHi, npLo, 128, 256, NSTR, tid);
    __syncthreads();
    mma_span<1>(sb, sb + N_ALO, sb + N_B0, sb + N_B0 + 128 * NSTR,
                NSTR, NSTR, 16, acc, wm, wn, lane);
    __syncthreads();
    epi_repack2(smem, NSTR, N_ALO, acc, m0, wm, npb, nf1, nullptr, nullptr, wn, lane);
    load_Bw(smem, N_B0, 128 * 272, p0bHi, p0bLo, 128, 128, 272, tid);
    __syncthreads();
    mma_span<1>(sb, sb + N_ALO, sb + N_B0, sb + N_B0 + 128 * 272,
                NSTR, 272, 8, acc, wm, wn, lane);
    __syncthreads();
    epi_repack2(smem, NSTR, N_ALO, acc, m0, wm, ppb0, pc, nullptr, nullptr, wn, lane);
    load_Bw(smem, N_B0, 128 * 272, p1Hi, p1Lo, 128, 128, 272, tid);
    __syncthreads();
    mma_span<1>(sb, sb + N_ALO, sb + N_B0, sb + N_B0 + 128 * 272,
                NSTR, 272, 8, acc, wm, wn, lane);
    __syncthreads();
    float* stage = (float*)(smem + N_B0);
    #pragma unroll
    for (int st = 0; st < 4; st++) {
        int n = wn * 32 + st * 8 + ((lane & 3) << 1);
        float b0 = __ldg(ppb1 + n), b1 = __ldg(ppb1 + n + 1);
        int r0 = wm * 16 + (lane >> 2);
        #pragma unroll
        for (int h = 0; h < 2; h++) {
            int r = r0 + h * 8;
            stage[r * 132 + n]     = fmaxf(acc[st][h * 2 + 0] + b0, 0.f);
            stage[r * 132 + n + 1] = fmaxf(acc[st][h * 2 + 1] + b1, 0.f);
        }
    }
    __syncthreads();
    if (tid < 96) {
        int m = tid / 3, n = tid - (tid / 3) * 3;
        const float* aa = stage + m * 132;
        float s = __ldg(ppb2 + n);
        #pragma unroll 16
        for (int k = 0; k < 128; k++) s += aa[k] * __ldg(ppW2 + k * 3 + n);
        out[(size_t)(m0 + m) * 3 + n] = s;
    }
}

// ---------------- launch ----------------
extern "C" void kernel_launch(void* const* d_in, const int* in_sizes, int n_in,
                              void* d_out, int out_size)
{
    const float* x    = (const float*)d_in[0];
    const float* Rr   = (const float*)d_in[1];
    const float* Rs   = (const float*)d_in[2];
    const float* neW0 = (const float*)d_in[4];  const float* neb0 = (const float*)d_in[5];
    const float* neW1 = (const float*)d_in[6];  const float* neb1 = (const float*)d_in[7];
    const float* neW2 = (const float*)d_in[8];  const float* neb2 = (const float*)d_in[9];
    const float* eeW0 = (const float*)d_in[10]; const float* eeb0 = (const float*)d_in[11];
    const float* eeW1 = (const float*)d_in[12]; const float* eeb1 = (const float*)d_in[13];
    const float* eeW2 = (const float*)d_in[14]; const float* eeb2 = (const float*)d_in[15];
    const float* npW  = (const float*)d_in[16]; const float* npb  = (const float*)d_in[17];
    const float* epW  = (const float*)d_in[18]; const float* epb  = (const float*)d_in[19];
    const float* ppW0 = (const float*)d_in[20]; const float* ppb0 = (const float*)d_in[21];
    const float* ppW1 = (const float*)d_in[22]; const float* ppb1 = (const float*)d_in[23];
    const float* ppW2 = (const float*)d_in[24]; const float* ppb2 = (const float*)d_in[25];
    float* out = (float*)d_out;

    uint32_t* arena; cudaGetSymbolAddress((void**)&arena, g_arena);
    int* recv; cudaGetSymbolAddress((void**)&recv, g_recv);
    int* send; cudaGetSymbolAddress((void**)&send, g_send);
    __nv_bfloat16* whi; cudaGetSymbolAddress((void**)&whi, g_whi);
    __nv_bfloat16* wlo; cudaGetSymbolAddress((void**)&wlo, g_wlo);
    float* zb; cudaGetSymbolAddress((void**)&zb, g_zero);

    uint32_t* neb    = arena + OFF_NEB;
    float*    nef    = (float*)(arena + OFF_NEF);
    float*    nf1f   = (float*)(arena + OFF_NF1F);
    float*    pc     = (float*)(arena + OFF_PC);
    float*    agg0   = (float*)(arena + OFF_AGG0);
    float*    agg1   = (float*)(arena + OFF_AGG1);
    float*    prs    = (float*)(arena + OFF_PRS);
    float*    prpspA = (float*)(arena + OFF_PRPSPA);
    float*    prpspB = (float*)(arena + OFF_PRPSPB);
    float*    ec     = (float*)(arena + OFF_EC);

    const int WO[12] = {0,8192,24576,40960,57344,73728,90112,106496,139264,172032,188416,204800};

    static bool s_init = false;
    static cudaStream_t s1, s2;
    static cudaEvent_t evStart, evPrep, evS1, evNE;
    if (!s_init) {
        cudaStreamCreateWithFlags(&s1, cudaStreamNonBlocking);
        cudaStreamCreateWithFlags(&s2, cudaStreamNonBlocking);
        cudaEventCreateWithFlags(&evStart, cudaEventDisableTiming);
        cudaEventCreateWithFlags(&evPrep,  cudaEventDisableTiming);
        cudaEventCreateWithFlags(&evS1,    cudaEventDisableTiming);
        cudaEventCreateWithFlags(&evNE,    cudaEventDisableTiming);
        cudaFuncSetAttribute(hgemm<2,64>,   cudaFuncAttributeMaxDynamicSharedMemorySize, smem_hg(2,64));
        cudaFuncSetAttribute(node_mega,     cudaFuncAttributeMaxDynamicSharedMemorySize, NM_SMEM);
        cudaFuncSetAttribute(edge_mega,     cudaFuncAttributeMaxDynamicSharedMemorySize, EM_SMEM);
        cudaFuncSetAttribute(np_prpsp_kernel, cudaFuncAttributeMaxDynamicSharedMemorySize, NP_SMEM);
        cudaFuncSetAttribute(tail_kernel,     cudaFuncAttributeMaxDynamicSharedMemorySize, TL_SMEM);
        s_init = true;
    }

    // fork at root: extract + agg zeros on s1
    cudaEventRecord(evStart, 0);
    cudaStreamWaitEvent(s1, evStart, 0);
    extract_idx2_kernel<<<2 * BE / 8, 256, 0, s1>>>(Rr, Rs, recv, send);
    cudaMemsetAsync(agg0, 0, (size_t)BN * 128 * sizeof(float), s1);
    cudaMemsetAsync(agg1, 0, (size_t)BN * 128 * sizeof(float), s1);
    cudaEventRecord(evS1, s1);

    // origin: weight prep
    PArg pa;
    pa.W[0] = neW0; pa.W[1] = neW1; pa.W[2] = neW2;
    pa.W[3] = eeW0; pa.W[4] = eeW1; pa.W[5] = eeW2;
    pa.W[6] = epW;  pa.W[7] = epW;  pa.W[8] = npW;
    pa.W[9] = ppW0; pa.W[10] = ppW0; pa.W[11] = ppW1;
    prep_weights<<<dim3(12, 8), 256>>>(pa, whi, wlo);
    cudaEventRecord(evPrep, 0);
    cudaStreamWaitEvent(s2, evPrep, 0);

    // s2: fused node encoder + step-invariant projections
    {
        NodeArg na;
        na.x = x;
        na.w0h = whi + WO[0]; na.w0l = wlo + WO[0];
        na.w1h = whi + WO[1]; na.w1l = wlo + WO[1];
        na.w2h = whi + WO[2]; na.w2l = wlo + WO[2];
        na.eprh = whi + WO[7];          na.eprl = wlo + WO[7];
        na.epsh = whi + WO[7] + 16384;  na.epsl = wlo + WO[7] + 16384;
        na.pqh = whi + WO[9];  na.pql = wlo + WO[9];
        na.b0 = neb0; na.b1 = neb1; na.b2 = neb2;
        na.neb = neb; na.nef = nef; na.prpsp = prpspA; na.pc = pc;
        node_mega<<<BN / 32, 256, NM_SMEM, s2>>>(na);
    }
    cudaEventRecord(evNE, s2);

    // origin: PrPs = x @ [eer|ees]
    {
        GArg a;
        a.s0.p = x; a.s0.start = 0; a.s0.mode = 3; a.s0.rs = 32;
        a.s1.p = nullptr; a.s1.start = 32; a.s1.mode = 0; a.s1.rs = 0;
        a.K = 64; a.Bhi = whi + WO[3]; a.Blo = wlo + WO[3];
        a.bias = zb; a.outf = prs; a.ldo = 256;
        hgemm<2,64><<<BN / 32, 256, smem_hg(2,64)>>>(a);
    }

    // join: indices + node projections
    cudaStreamWaitEvent(0, evS1, 0);
    cudaStreamWaitEvent(0, evNE, 0);

    // fused edge chain + step-0 scatter
    {
        EdgeArg ea;
        ea.prs = prs; ea.recv = recv; ea.send = send; ea.eeb0 = eeb0;
        ea.w1h = whi + WO[4]; ea.w1l = wlo + WO[4];
        ea.w2h = whi + WO[5]; ea.w2l = wlo + WO[5];
        ea.weh = whi + WO[6]; ea.wel = wlo + WO[6];
        ea.b1 = eeb1; ea.b2 = eeb2;
        ea.prpsp = prpspA; ea.epb = epb;
        ea.ec = ec; ea.agg = agg0;
        edge_mega<<<BE / 64, 256, EM_SMEM>>>(ea);
    }

    // fused np(step0) + prpsp(step1)
    np_prpsp_kernel<<<BN / 32, 256, NP_SMEM>>>(neb, agg0, nef,
        whi + WO[8], wlo + WO[8], npb, whi + WO[7], wlo + WO[7],
        nf1f, prpspB);

    // step-1 scatter
    fused_scatter_kernel<<<BE * 128 / 256, 256>>>(ec, prpspB, recv, send, epb, agg1);

    // fused np(step1) + predictor + output
    tail_kernel<<<BN / 32, 256, TL_SMEM>>>(neb, agg1, nf1f,
        whi + WO[8], wlo + WO[8], npb, pc,
        whi + WO[10], wlo + WO[10], ppb0,
        whi + WO[11], wlo + WO[11], ppb1,
        ppW2, ppb2, out);
}

// round 11
// speedup vs baseline: 3.0114x; 1.0122x over previous
#include <cuda_runtime.h>
#include <cuda_bf16.h>
#include <cstdint>

// ---------------- problem dims ----------------
#define Nn 1024
#define Ee 8192
#define BN 4096    // B*N
#define BE 32768   // B*E

// ---------------- device scratch ----------------
#define OFF_NEB    ((size_t)0)                       // node_enc bfp
#define OFF_NEF    (OFF_NEB + (size_t)BN*128)        // node_enc f32
#define OFF_NF1F   (OFF_NEF + (size_t)BN*128)        // nf1 f32
#define OFF_PC     (OFF_NF1F + (size_t)BN*128)       // neb@pp0a f32
#define OFF_AGG0   (OFF_PC + (size_t)BN*128)
#define OFF_AGG1   (OFF_AGG0 + (size_t)BN*128)
#define OFF_PRS    (OFF_AGG1 + (size_t)BN*128)       // [BN,256] f32 (x@Wr | x@Ws)
#define OFF_PRPSPA (OFF_PRS + (size_t)BN*256)        // [BN,256] f32 step0
#define OFF_PRPSPB (OFF_PRPSPA + (size_t)BN*256)     // [BN,256] f32 step1
#define OFF_EC     (OFF_PRPSPB + (size_t)BN*256)     // [BE,128] f32
#define ARENA_U32  (OFF_EC + (size_t)BE*128)

__device__ uint32_t g_arena[ARENA_U32];
__device__ int g_recv[BE];
__device__ int g_send[BE];
__device__ float g_zero[256];

// split/transposed weights [n][kpad] bf16, 12 matrices
#define WT_TOTAL 221184
__device__ __nv_bfloat16 g_whi[WT_TOTAL];
__device__ __nv_bfloat16 g_wlo[WT_TOTAL];

// ---------------- helpers ----------------
__device__ __forceinline__ uint32_t smem_u32(const void* p) {
    uint32_t a;
    asm("{ .reg .u64 t; cvta.to.shared.u64 t, %1; cvt.u32.u64 %0, t; }" : "=r"(a) : "l"(p));
    return a;
}

#define LDMX4(r, ad) \
    asm volatile("ldmatrix.sync.aligned.m8n8.x4.shared.b16 {%0,%1,%2,%3}, [%4];" \
        : "=r"((r)[0]), "=r"((r)[1]), "=r"((r)[2]), "=r"((r)[3]) : "r"(ad))

#define MMA16816(d, av, bv) \
    asm volatile("mma.sync.aligned.m16n8k16.row.col.f32.bf16.bf16.f32 " \
        "{%0,%1,%2,%3},{%4,%5,%6,%7},{%8,%9},{%0,%1,%2,%3};" \
        : "+f"((d)[0]), "+f"((d)[1]), "+f"((d)[2]), "+f"((d)[3]) \
        : "r"((av)[0]), "r"((av)[1]), "r"((av)[2]), "r"((av)[3]), \
          "r"((bv)[0]), "r"((bv)[1]))

#define CP_ASYNC16(sa, gp) \
    asm volatile("cp.async.cg.shared.global [%0], [%1], 16;" :: "r"(sa), "l"(gp))
#define CP_COMMIT()  asm volatile("cp.async.commit_group;" ::: "memory")
#define CP_WAIT1()   asm volatile("cp.async.wait_group 1;" ::: "memory")
#define CP_WAIT0()   asm volatile("cp.async.wait_group 0;" ::: "memory")

__device__ __forceinline__ uint32_t packbfp(float v) {
    __nv_bfloat16 h = __float2bfloat16(v);
    float hf = __bfloat162float(h);
    __nv_bfloat16 l = __float2bfloat16(v - hf);
    return (uint32_t)__bfloat16_as_ushort(h) | ((uint32_t)__bfloat16_as_ushort(l) << 16);
}

// ---- 32-col-warp 3-pass MMA (256-thread kernels) ----
template<int NT>
__device__ __forceinline__ void mma_span(
    uint32_t aHi, uint32_t aLo, uint32_t bHi, uint32_t bLo,
    int astr, int bstr, int nk, float (*acc)[4], int tile, int wn, int lane)
{
    for (int ks = 0; ks < nk; ks++) {
        uint32_t bh[NT * 8], bl[NT * 8];
        #pragma unroll
        for (int t2 = 0; t2 < NT; t2++)
            #pragma unroll
            for (int np = 0; np < 2; np++) {
                int n = t2 * 128 + wn * 32 + np * 16 + ((lane >> 4) << 3) + (lane & 7);
                int koff = ((lane >> 3) & 1) << 3;
                uint32_t ad = bHi + n * bstr + (ks * 16 + koff) * 2;
                LDMX4(&bh[(t2 * 2 + np) * 4], ad);
                LDMX4(&bl[(t2 * 2 + np) * 4], ad + (bLo - bHi));
            }
        int r = tile * 16 + (lane & 15);
        int koff = (lane >> 4) << 3;
        uint32_t ad = aHi + r * astr + (ks * 16 + koff) * 2;
        uint32_t ah[4], al[4];
        LDMX4(ah, ad);
        LDMX4(al, ad + (aLo - aHi));
        #pragma unroll
        for (int st = 0; st < NT * 4; st++) {
            MMA16816(acc[st], ah, &bh[st * 2]);
            MMA16816(acc[st], ah, &bl[st * 2]);
            MMA16816(acc[st], al, &bh[st * 2]);
        }
    }
}

// ---- 16-col-warp 3-pass MMA (512-thread kernels): wn in 0..7, 16 cols/warp ----
template<int NT>
__device__ __forceinline__ void mma_span16(
    uint32_t aHi, uint32_t aLo, uint32_t bHi, uint32_t bLo,
    int astr, int bstr, int nk, float (*acc)[4], int tile, int wn, int lane)
{
    for (int ks = 0; ks < nk; ks++) {
        uint32_t bh[NT * 4], bl[NT * 4];
        #pragma unroll
        for (int t2 = 0; t2 < NT; t2++) {
            int n = t2 * 128 + wn * 16 + ((lane >> 4) << 3) + (lane & 7);
            int koff = ((lane >> 3) & 1) << 3;
            uint32_t ad = bHi + n * bstr + (ks * 16 + koff) * 2;
            LDMX4(&bh[t2 * 4], ad);
            LDMX4(&bl[t2 * 4], ad + (bLo - bHi));
        }
        int r = tile * 16 + (lane & 15);
        int koff = (lane >> 4) << 3;
        uint32_t ad = aHi + r * astr + (ks * 16 + koff) * 2;
        uint32_t ah[4], al[4];
        LDMX4(ah, ad);
        LDMX4(al, ad + (aLo - aHi));
        #pragma unroll
        for (int st = 0; st < NT * 2; st++) {
            MMA16816(acc[st], ah, &bh[st * 2]);
            MMA16816(acc[st], ah, &bl[st * 2]);
            MMA16816(acc[st], al, &bh[st * 2]);
        }
    }
}

// synchronous weight load (LDG+STS)
__device__ __forceinline__ void load_Bw(char* smem, int base, int plane,
    const __nv_bfloat16* Bhi, const __nv_bfloat16* Blo,
    int nrows, int kcols, int bstr, int tid, int nth)
{
    int kg = kcols >> 3;
    int per = nrows * kg;
    for (int item = tid; item < per; item += nth) {
        int n = item / kg, g = item - n * kg;
        size_t goff = (size_t)n * kcols + (g << 3);
        int so = base + n * bstr + (g << 4);
        *(uint4*)(smem + so) = *(const uint4*)(Bhi + goff);
        *(uint4*)(smem + so + plane) = *(const uint4*)(Blo + goff);
    }
}

// async weight load (cp.async, caller commits/waits)
__device__ __forceinline__ void load_Bw_cp(uint32_t sbase, int plane,
    const __nv_bfloat16* Bhi, const __nv_bfloat16* Blo,
    int nrows, int kcols, int bstr, int tid, int nth)
{
    int kg = kcols >> 3;
    int per = nrows * kg;
    for (int item = tid; item < per; item += nth) {
        int n = item / kg, g = item - n * kg;
        size_t goff = (size_t)n * kcols + (g << 3);
        uint32_t so = sbase + n * bstr + (g << 4);
        CP_ASYNC16(so, Bhi + goff);
        CP_ASYNC16(so + plane, Blo + goff);
    }
}

// 32-col-warp epilogue
__device__ __forceinline__ void epi_repack2(char* smem, int astr, int aplane,
    float (*acc)[4], int m0, int tile,
    const float* bias, const float* resid, float* outf, uint32_t* outb,
    int wn, int lane)
{
    #pragma unroll
    for (int st = 0; st < 4; st++) {
        int n = wn * 32 + st * 8 + ((lane & 3) << 1);
        float b0 = __ldg(bias + n), b1 = __ldg(bias + n + 1);
        int r0 = tile * 16 + (lane >> 2);
        #pragma unroll
        for (int h = 0; h < 2; h++) {
            int r = r0 + h * 8;
            float s0 = acc[st][h * 2 + 0] + b0;
            float s1 = acc[st][h * 2 + 1] + b1;
            if (resid) {
                float2 rv = *(const float2*)(resid + (((size_t)(m0 + r)) << 7) + n);
                s0 += rv.x; s1 += rv.y;
            }
            s0 = fmaxf(s0, 0.f); s1 = fmaxf(s1, 0.f);
            if (outf) *(float2*)(outf + (((size_t)(m0 + r)) << 7) + n) = make_float2(s0, s1);
            uint32_t p0 = packbfp(s0), p1 = packbfp(s1);
            if (outb) *(uint2*)(outb + (((size_t)(m0 + r)) << 7) + n) = make_uint2(p0, p1);
            int off = r * astr + n * 2;
            *(uint32_t*)(smem + off) = (p0 & 0xffffu) | (p1 << 16);
            *(uint32_t*)(smem + aplane + off) = (p0 >> 16) | (p1 & 0xffff0000u);
            acc[st][h * 2 + 0] = 0.f;
            acc[st][h * 2 + 1] = 0.f;
        }
    }
}

// 16-col-warp epilogue
__device__ __forceinline__ void epi_repack16(char* smem, int astr, int aplane,
    float (*acc)[4], int m0, int tile,
    const float* bias, const float* resid, float* outf, uint32_t* outb,
    int wn, int lane)
{
    #pragma unroll
    for (int st = 0; st < 2; st++) {
        int n = wn * 16 + st * 8 + ((lane & 3) << 1);
        float b0 = __ldg(bias + n), b1 = __ldg(bias + n + 1);
        int r0 = tile * 16 + (lane >> 2);
        #pragma unroll
        for (int h = 0; h < 2; h++) {
            int r = r0 + h * 8;
            float s0 = acc[st][h * 2 + 0] + b0;
            float s1 = acc[st][h * 2 + 1] + b1;
            if (resid) {
                float2 rv = *(const float2*)(resid + (((size_t)(m0 + r)) << 7) + n);
                s0 += rv.x; s1 += rv.y;
            }
            s0 = fmaxf(s0, 0.f); s1 = fmaxf(s1, 0.f);
            if (outf) *(float2*)(outf + (((size_t)(m0 + r)) << 7) + n) = make_float2(s0, s1);
            uint32_t p0 = packbfp(s0), p1 = packbfp(s1);
            if (outb) *(uint2*)(outb + (((size_t)(m0 + r)) << 7) + n) = make_uint2(p0, p1);
            int off = r * astr + n * 2;
            *(uint32_t*)(smem + off) = (p0 & 0xffffu) | (p1 << 16);
            *(uint32_t*)(smem + aplane + off) = (p0 >> 16) | (p1 & 0xffff0000u);
            acc[st][h * 2 + 0] = 0.f;
            acc[st][h * 2 + 1] = 0.f;
        }
    }
}

// write acc f32 (32-col warps)
__device__ __forceinline__ void write_accf(float (*acc)[4], int m0, int tile,
    int wn, int lane, float* out, int nbase, int ldo)
{
    #pragma unroll
    for (int st = 0; st < 4; st++) {
        int n = nbase + wn * 32 + st * 8 + ((lane & 3) << 1);
        int r0 = tile * 16 + (lane >> 2);
        #pragma unroll
        for (int h = 0; h < 2; h++) {
            int m = m0 + r0 + h * 8;
            *(float2*)(out + (size_t)m * ldo + n) =
                make_float2(acc[st][h * 2 + 0], acc[st][h * 2 + 1]);
            acc[st][h * 2 + 0] = 0.f;
            acc[st][h * 2 + 1] = 0.f;
        }
    }
}

// write acc f32 (16-col warps)
__device__ __forceinline__ void write_accf16(float (*acc)[4], int m0, int tile,
    int wn, int lane, float* out, int nbase, int ldo)
{
    #pragma unroll
    for (int st = 0; st < 2; st++) {
        int n = nbase + wn * 16 + st * 8 + ((lane & 3) << 1);
        int r0 = tile * 16 + (lane >> 2);
        #pragma unroll
        for (int h = 0; h < 2; h++) {
            int m = m0 + r0 + h * 8;
            *(float2*)(out + (size_t)m * ldo + n) =
                make_float2(acc[st][h * 2 + 0], acc[st][h * 2 + 1]);
            acc[st][h * 2 + 0] = 0.f;
            acc[st][h * 2 + 1] = 0.f;
        }
    }
}

// ---------------- aux kernels ----------------
__global__ void extract_idx2_kernel(const float* __restrict__ Rr,
                                    const float* __restrict__ Rs,
                                    int* __restrict__ recv, int* __restrict__ send)
{
    int row = blockIdx.x * 8 + (threadIdx.x >> 5);
    int lane = threadIdx.x & 31;
    const float* R = (row < BE) ? Rr : Rs;
    int r = (row < BE) ? row : row - BE;
    const float4* p = (const float4*)(R + (size_t)r * Nn);
    int found = -1;
    #pragma unroll
    for (int i = 0; i < 4; i++) {
        int q = lane + i * 32;
        float4 v = p[q];
        if (v.x > 0.5f) found = q * 4 + 0;
        if (v.y > 0.5f) found = q * 4 + 1;
        if (v.z > 0.5f) found = q * 4 + 2;
        if (v.w > 0.5f) found = q * 4 + 3;
    }
    if (__ballot_sync(0xFFFFFFFFu, found >= 0) == 0u) {
        #pragma unroll
        for (int i = 4; i < 8; i++) {
            int q = lane + i * 32;
            float4 v = p[q];
            if (v.x > 0.5f) found = q * 4 + 0;
            if (v.y > 0.5f) found = q * 4 + 1;
            if (v.z > 0.5f) found = q * 4 + 2;
            if (v.w > 0.5f) found = q * 4 + 3;
        }
    }
    #pragma unroll
    for (int o = 16; o; o >>= 1) found = max(found, __shfl_xor_sync(0xFFFFFFFFu, found, o));
    if (lane == 0) {
        found = max(found, 0);
        if (row < BE) recv[r] = found; else send[r] = found;
    }
}

// matrices: 0 ne0 1 ne1 2 ne2 3 eers(R256) 4 ee1 5 ee2 6 ep_e 7 ep_rs(R256)
//           8 np(K256) 9 pp0a 10 pp0b 11 pp1
struct PArg { const float* W[12]; };
__constant__ int c_Ks[12]  = {32,128,128, 32,128,128,128,128,256,128,128,128};
__constant__ int c_Kps[12] = {64,128,128, 64,128,128,128,128,256,128,128,128};
__constant__ int c_Rs[12]  = {128,128,128,256,128,128,128,256,128,128,128,128};
__constant__ int c_r0a[12] = {0,0,0,0,0,0,0,128,0,0,128,0};
__constant__ int c_r0b[12] = {0,0,0,32,0,0,0,256,0,0,0,0};
__constant__ int c_off[12] = {0,8192,24576,40960,57344,73728,90112,106496,139264,172032,188416,204800};

__global__ void prep_weights(PArg a, __nv_bfloat16* __restrict__ hi, __nv_bfloat16* __restrict__ lo)
{
    int mid = blockIdx.x;
    int K = c_Ks[mid], Kp = c_Kps[mid], R = c_Rs[mid];
    int r0a = c_r0a[mid], r0b = c_r0b[mid];
    const float* W = a.W[mid];
    __nv_bfloat16* dh = hi + c_off[mid];
    __nv_bfloat16* dl = lo + c_off[mid];
    int total = R * Kp;
    for (int i = threadIdx.x + blockIdx.y * blockDim.x; i < total; i += blockDim.x * gridDim.y) {
        int n = i / Kp, k = i - n * Kp;
        int col = n & 127;
        int r0 = (n >> 7) ? r0b : r0a;
        float v = (k < K) ? W[(size_t)(r0 + k) * 128 + col] : 0.f;
        __nv_bfloat16 h = __float2bfloat16(v);
        dh[i] = h;
        dl[i] = __float2bfloat16(v - __bfloat162float(h));
    }
}

// step-1 scatter
__global__ void fused_scatter_kernel(const float* __restrict__ ec,
                                     const float* __restrict__ prpsp,
                                     const int* __restrict__ recv,
                                     const int* __restrict__ send,
                                     const float* __restrict__ bias,
                                     float* __restrict__ agg)
{
    int t = blockIdx.x * blockDim.x + threadIdx.x;
    if (t >= BE * 128) return;
    int e = t >> 7, h = t & 127;
    int bo = (e >> 13) << 10;
    int r = __ldg(recv + e) + bo, s = __ldg(send + e) + bo;
    float v = ec[t] + prpsp[(size_t)r * 256 + h] + prpsp[(size_t)s * 256 + 128 + h] + __ldg(bias + h);
    v = fmaxf(v, 0.f);
    atomicAdd(&agg[(size_t)r * 128 + h], v);
}

// ---------------- generic HMMA GEMM (PrPs only, 256 threads) ----------------
struct Seg { const void* p; int start; int mode; int rs; };
struct GArg {
    Seg s0, s1;
    int K;
    const __nv_bfloat16 *Bhi, *Blo;
    const float* bias;
    float* outf;
    int ldo;
};

template<int NT, int KCH>
__global__ __launch_bounds__(256) void hgemm(GArg a)
{
    constexpr int STRIDE = KCH * 2 + 16;
    constexpr int ALO = 32 * STRIDE;
    constexpr int BHI = 2 * ALO;
    constexpr int BPL = NT * 128 * STRIDE;
    extern __shared__ char smem[];
    const uint32_t sb = smem_u32(smem);
    const int tid = threadIdx.x;
    const int wid = tid >> 5, lane = tid & 31;
    const int wm = wid & 1, wn = wid >> 1;
    const int m0 = blockIdx.x * 32;

    float acc[NT * 4][4];
    #pragma unroll
    for (int st = 0; st < NT * 4; st++)
        #pragma unroll
        for (int r = 0; r < 4; r++) acc[st][r] = 0.f;

    const int nchunks = a.K / KCH;
    for (int c = 0; c < nchunks; c++) {
        const int k0 = c * KCH;
        #pragma unroll
        for (int it = 0; it < KCH / 32; it++) {
            int item = tid + (it << 8);
            int r = item / (KCH / 4), g = item % (KCH / 4);
            int kc = k0 + (g << 2);
            int m = m0 + r;
            uint32_t p0, p1, p2, p3;
            const Seg& sg = (kc >= a.s1.start) ? a.s1 : a.s0;
            if (sg.mode == 0) {
                p0 = p1 = p2 = p3 = 0u;
            } else {
                long base = (long)m * sg.rs + (kc - sg.start);
                float4 v = *((const float4*)sg.p + (base >> 2));
                p0 = packbfp(v.x); p1 = packbfp(v.y); p2 = packbfp(v.z); p3 = packbfp(v.w);
            }
            uint32_t hi01 = (p0 & 0xffffu) | (p1 << 16);
            uint32_t hi23 = (p2 & 0xffffu) | (p3 << 16);
            uint32_t lo01 = (p0 >> 16) | (p1 & 0xffff0000u);
            uint32_t lo23 = (p2 >> 16) | (p3 & 0xffff0000u);
            int off = r * STRIDE + g * 8;
            *(uint2*)(smem + off) = make_uint2(hi01, hi23);
            *(uint2*)(smem + ALO + off) = make_uint2(lo01, lo23);
        }
        #pragma unroll
        for (int it = 0; it < NT * KCH / 16; it++) {
            int item = tid + (it << 8);
            int n = item / (KCH / 8), g = item % (KCH / 8);
            size_t goff = (size_t)n * a.K + k0 + (g << 3);
            int off = n * STRIDE + g * 16;
            *(uint4*)(smem + BHI + off) = *(const uint4*)(a.Bhi + goff);
            *(uint4*)(smem + BHI + BPL + off) = *(const uint4*)(a.Blo + goff);
        }
        __syncthreads();
        mma_span<NT>(sb, sb + ALO, sb + BHI, sb + BHI + BPL,
                     STRIDE, STRIDE, KCH / 16, acc, wm, wn, lane);
        __syncthreads();
    }
    #pragma unroll
    for (int t2 = 0; t2 < NT; t2++) {
        float (*accp)[4] = acc + t2 * 4;
        write_accf(accp, m0, wm, wn, lane, a.outf, t2 * 128, a.ldo);
    }
}

constexpr int smem_hg(int NT, int KCH) {
    return (2 * 32 + 2 * NT * 128) * (KCH * 2 + 16);
}

// ---------------- node_mega (256 threads, cp.async ping-pong) ----------------
#define NM_STR   272
#define NM_ALO   (32 * NM_STR)
#define NM_B0    (2 * NM_ALO)
#define NM_BPL   (128 * NM_STR)
#define NM_SLOT  (2 * NM_BPL)
#define NM_SMEM  (NM_B0 + 2 * NM_SLOT)     // 156672

struct NodeArg {
    const float* x;
    const __nv_bfloat16 *w0h,*w0l,*w1h,*w1l,*w2h,*w2l,*eprh,*eprl,*epsh,*epsl,*pqh,*pql;
    const float *b0,*b1,*b2;
    uint32_t* neb; float* nef; float* prpsp; float* pc;
};

__global__ __launch_bounds__(256) void node_mega(NodeArg a)
{
    extern __shared__ char smem[];
    const uint32_t sb = smem_u32(smem);
    const int tid = threadIdx.x;
    const int wid = tid >> 5, lane = tid & 31;
    const int wm = wid & 1, wn = wid >> 1;
    const int m0 = blockIdx.x * 32;

    const uint32_t sA = sb + NM_B0;
    const uint32_t sB = sb + NM_B0 + NM_SLOT;

    float acc[4][4];
    #pragma unroll
    for (int st = 0; st < 4; st++)
        #pragma unroll
        for (int r = 0; r < 4; r++) acc[st][r] = 0.f;

    load_Bw_cp(sA, NM_BPL, a.w0h, a.w0l, 128, 64, NM_STR, tid, 256);  CP_COMMIT();
    load_Bw_cp(sB, NM_BPL, a.w1h, a.w1l, 128, 128, NM_STR, tid, 256); CP_COMMIT();

    #pragma unroll
    for (int it = 0; it < 2; it++) {
        int item = tid + (it << 8);
        int r = item >> 4, g = item & 15;
        int kc = g << 2;
        uint32_t p0 = 0, p1 = 0, p2 = 0, p3 = 0;
        if (kc < 32) {
            float4 v = *(const float4*)(a.x + (size_t)(m0 + r) * 32 + kc);
            p0 = packbfp(v.x); p1 = packbfp(v.y); p2 = packbfp(v.z); p3 = packbfp(v.w);
        }
        uint32_t hi01 = (p0 & 0xffffu) | (p1 << 16);
        uint32_t hi23 = (p2 & 0xffffu) | (p3 << 16);
        uint32_t lo01 = (p0 >> 16) | (p1 & 0xffff0000u);
        uint32_t lo23 = (p2 >> 16) | (p3 & 0xffff0000u);
        int off = r * NM_STR + g * 8;
        *(uint2*)(smem + off) = make_uint2(hi01, hi23);
        *(uint2*)(smem + NM_ALO + off) = make_uint2(lo01, lo23);
    }

    CP_WAIT1(); __syncthreads();
    mma_span<1>(sb, sb + NM_ALO, sA, sA + NM_BPL, NM_STR, NM_STR, 4, acc, wm, wn, lane);
    __syncthreads();
    epi_repack2(smem, NM_STR, NM_ALO, acc, m0, wm, a.b0, nullptr, nullptr, nullptr, wn, lane);
    load_Bw_cp(sA, NM_BPL, a.w2h, a.w2l, 128, 128, NM_STR, tid, 256); CP_COMMIT();

    CP_WAIT1(); __syncthreads();
    mma_span<1>(sb, sb + NM_ALO, sB, sB + NM_BPL, NM_STR, NM_STR, 8, acc, wm, wn, lane);
    __syncthreads();
    epi_repack2(smem, NM_STR, NM_ALO, acc, m0, wm, a.b1, nullptr, nullptr, nullptr, wn, lane);
    load_Bw_cp(sB, NM_BPL, a.eprh, a.eprl, 128, 128, NM_STR, tid, 256); CP_COMMIT();

    CP_WAIT1(); __syncthreads();
    mma_span<1>(sb, sb + NM_ALO, sA, sA + NM_BPL, NM_STR, NM_STR, 8, acc, wm, wn, lane);
    __syncthreads();
    epi_repack2(smem, NM_STR, NM_ALO, acc, m0, wm, a.b2, nullptr, a.nef, a.neb, wn, lane);
    load_Bw_cp(sA, NM_BPL, a.epsh, a.epsl, 128, 128, NM_STR, tid, 256); CP_COMMIT();

    CP_WAIT1(); __syncthreads();
    mma_span<1>(sb, sb + NM_ALO, sB, sB + NM_BPL, NM_STR, NM_STR, 8, acc, wm, wn, lane);
    __syncthreads();
    write_accf(acc, m0, wm, wn, lane, a.prpsp, 0, 256);
    load_Bw_cp(sB, NM_BPL, a.pqh, a.pql, 128, 128, NM_STR, tid, 256); CP_COMMIT();

    CP_WAIT1(); __syncthreads();
    mma_span<1>(sb, sb + NM_ALO, sA, sA + NM_BPL, NM_STR, NM_STR, 8, acc, wm, wn, lane);
    __syncthreads();
    write_accf(acc, m0, wm, wn, lane, a.prpsp, 128, 256);

    CP_WAIT0(); __syncthreads();
    mma_span<1>(sb, sb + NM_ALO, sB, sB + NM_BPL, NM_STR, NM_STR, 8, acc, wm, wn, lane);
    __syncthreads();
    write_accf(acc, m0, wm, wn, lane, a.pc, 0, 128);
}

// ---------------- edge_mega: 512 threads, cp.async ping-pong ----------------
#define EM_STR   272
#define EM_ALO   (64 * EM_STR)             // 17408
#define EM_B0    (2 * EM_ALO)              // 34816
#define EM_BPL   (128 * EM_STR)            // 34816
#define EM_SLOT  (2 * EM_BPL)              // 69632
#define EM_SMEM  (EM_B0 + 2 * EM_SLOT)     // 174080

struct EdgeArg {
    const float* prs; const int* recv; const int* send; const float* eeb0;
    const __nv_bfloat16 *w1h,*w1l,*w2h,*w2l,*weh,*wel;
    const float *b1,*b2;
    const float* prpsp; const float* epb;
    float* ec; float* agg;
};

__global__ __launch_bounds__(512, 1) void edge_mega(EdgeArg a)
{
    extern __shared__ char smem[];
    const uint32_t sb = smem_u32(smem);
    const int tid = threadIdx.x;
    const int wid = tid >> 5, lane = tid & 31;
    const int wm = wid & 1, wn = wid >> 1;      // 2 x 8 warp grid, 16 cols/warp
    const int m0 = blockIdx.x * 64;

    const uint32_t sA = sb + EM_B0;
    const uint32_t sB = sb + EM_B0 + EM_SLOT;

    float acc[2][2][4];
    #pragma unroll
    for (int mt = 0; mt < 2; mt++)
        #pragma unroll
        for (int st = 0; st < 2; st++)
            #pragma unroll
            for (int r = 0; r < 4; r++) acc[mt][st][r] = 0.f;

    // prefetch W1 (sA) and W2 (sB)
    load_Bw_cp(sA, EM_BPL, a.w1h, a.w1l, 128, 128, EM_STR, tid, 512); CP_COMMIT();
    load_Bw_cp(sB, EM_BPL, a.w2h, a.w2l, 128, 128, EM_STR, tid, 512); CP_COMMIT();

    // A <- edge layer0 on the fly: relu(Pr[recv]+Ps[send]+b0)
    #pragma unroll
    for (int it = 0; it < 4; it++) {
        int item = tid + (it << 9);
        int r = item >> 5, g = item & 31;
        int kc = g << 2;
        int m = m0 + r;
        int bo = (m >> 13) << 10;
        int rr = __ldg(a.recv + m) + bo, ss = __ldg(a.send + m) + bo;
        float4 pr = *(const float4*)(a.prs + (size_t)rr * 256 + kc);
        float4 ps = *(const float4*)(a.prs + (size_t)ss * 256 + 128 + kc);
        float4 bb = *(const float4*)(a.eeb0 + kc);
        uint32_t p0 = packbfp(fmaxf(pr.x + ps.x + bb.x, 0.f));
        uint32_t p1 = packbfp(fmaxf(pr.y + ps.y + bb.y, 0.f));
        uint32_t p2 = packbfp(fmaxf(pr.z + ps.z + bb.z, 0.f));
        uint32_t p3 = packbfp(fmaxf(pr.w + ps.w + bb.w, 0.f));
        uint32_t hi01 = (p0 & 0xffffu) | (p1 << 16);
        uint32_t hi23 = (p2 & 0xffffu) | (p3 << 16);
        uint32_t lo01 = (p0 >> 16) | (p1 & 0xffff0000u);
        uint32_t lo23 = (p2 >> 16) | (p3 & 0xffff0000u);
        int off = r * EM_STR + g * 8;
        *(uint2*)(smem + off) = make_uint2(hi01, hi23);
        *(uint2*)(smem + EM_ALO + off) = make_uint2(lo01, lo23);
    }

    // phase 1: ee1 (W1 in sA)
    CP_WAIT1(); __syncthreads();
    #pragma unroll
    for (int mt = 0; mt < 2; mt++)
        mma_span16<1>(sb, sb + EM_ALO, sA, sA + EM_BPL,
                      EM_STR, EM_STR, 8, acc[mt], wm * 2 + mt, wn, lane);
    __syncthreads();
    #pragma unroll
    for (int mt = 0; mt < 2; mt++)
        epi_repack16(smem, EM_STR, EM_ALO, acc[mt], m0, wm * 2 + mt, a.b1,
                     nullptr, nullptr, nullptr, wn, lane);
    load_Bw_cp(sA, EM_BPL, a.weh, a.wel, 128, 128, EM_STR, tid, 512); CP_COMMIT();

    // phase 2: ee2 (W2 in sB)
    CP_WAIT1(); __syncthreads();
    #pragma unroll
    for (int mt = 0; mt < 2; mt++)
        mma_span16<1>(sb, sb + EM_ALO, sB, sB + EM_BPL,
                      EM_STR, EM_STR, 8, acc[mt], wm * 2 + mt, wn, lane);
    __syncthreads();
    #pragma unroll
    for (int mt = 0; mt < 2; mt++)
        epi_repack16(smem, EM_STR, EM_ALO, acc[mt], m0, wm * 2 + mt, a.b2,
                     nullptr, nullptr, nullptr, wn, lane);

    // phase 3: ec (We in sA)
    CP_WAIT0(); __syncthreads();
    #pragma unroll
    for (int mt = 0; mt < 2; mt++)
        mma_span16<1>(sb, sb + EM_ALO, sA, sA + EM_BPL,
                      EM_STR, EM_STR, 8, acc[mt], wm * 2 + mt, wn, lane);

    // epilogue: write ec + fused step-0 scatter
    #pragma unroll
    for (int mt = 0; mt < 2; mt++) {
        int row0 = m0 + (wm * 2 + mt) * 16 + (lane >> 2);
        #pragma unroll
        for (int st = 0; st < 2; st++) {
            int n = wn * 16 + st * 8 + ((lane & 3) << 1);
            float e0b = __ldg(a.epb + n), e1b = __ldg(a.epb + n + 1);
            #pragma unroll
            for (int h = 0; h < 2; h++) {
                int m = row0 + h * 8;
                float e0 = acc[mt][st][h * 2 + 0];
                float e1 = acc[mt][st][h * 2 + 1];
                *(float2*)(a.ec + ((size_t)m << 7) + n) = make_float2(e0, e1);
                int bo = (m >> 13) << 10;
                int r_ = __ldg(a.recv + m) + bo, s_ = __ldg(a.send + m) + bo;
                float2 pr = *(const float2*)(a.prpsp + (size_t)r_ * 256 + n);
                float2 ps = *(const float2*)(a.prpsp + (size_t)s_ * 256 + 128 + n);
                float v0 = fmaxf(e0 + pr.x + ps.x + e0b, 0.f);
                float v1 = fmaxf(e1 + pr.y + ps.y + e1b, 0.f);
                atomicAdd(&a.agg[(size_t)r_ * 128 + n], v0);
                atomicAdd(&a.agg[(size_t)r_ * 128 + n + 1], v1);
            }
        }
    }
}

// ---------------- np_prpsp / tail (512 threads, 32-row tiles) ----------------
#define NSTR   528
#define N_ALO  (32 * NSTR)
#define N_B0   (2 * N_ALO)
#define NP_SMEM (N_B0 + 2 * 256 * 272)   // 173056
#define TL_SMEM (N_B0 + 2 * 128 * NSTR)  // 168960

__device__ __forceinline__ void load_A_npagg(char* smem, int m0,
    const uint32_t* neb, const float* agg, int tid)
{
    #pragma unroll
    for (int it = 0; it < 4; it++) {
        int item = tid + (it << 9);
        int r = item >> 6, g = item & 63;
        int kc = g << 2;
        int m = m0 + r;
        uint32_t p0, p1, p2, p3;
        if (kc < 128) {
            uint4 v = *(const uint4*)(neb + ((size_t)m << 7) + kc);
            p0 = v.x; p1 = v.y; p2 = v.z; p3 = v.w;
        } else {
            float4 v = *(const float4*)(agg + ((size_t)m << 7) + (kc - 128));
            p0 = packbfp(v.x); p1 = packbfp(v.y); p2 = packbfp(v.z); p3 = packbfp(v.w);
        }
        uint32_t hi01 = (p0 & 0xffffu) | (p1 << 16);
        uint32_t hi23 = (p2 & 0xffffu) | (p3 << 16);
        uint32_t lo01 = (p0 >> 16) | (p1 & 0xffff0000u);
        uint32_t lo23 = (p2 >> 16) | (p3 & 0xffff0000u);
        int off = r * NSTR + g * 8;
        *(uint2*)(smem + off) = make_uint2(hi01, hi23);
        *(uint2*)(smem + N_ALO + off) = make_uint2(lo01, lo23);
    }
}

__global__ __launch_bounds__(512, 1) void np_prpsp_kernel(
    const uint32_t* __restrict__ neb, const float* __restrict__ agg,
    const float* __restrict__ resid,
    const __nv_bfloat16* __restrict__ npHi, const __nv_bfloat16* __restrict__ npLo,
    const float* __restrict__ npb,
    const __nv_bfloat16* __restrict__ epHi, const __nv_bfloat16* __restrict__ epLo,
    float* __restrict__ nf_out, float* __restrict__ prpsp_out)
{
    extern __shared__ char smem[];
    const uint32_t sb = smem_u32(smem);
    const int tid = threadIdx.x;
    const int wid = tid >> 5, lane = tid & 31;
    const int wm = wid & 1, wn = wid >> 1;
    const int m0 = blockIdx.x * 32;

    float acc[4][4];
    #pragma unroll
    for (int st = 0; st < 4; st++)
        #pragma unroll
        for (int r = 0; r < 4; r++) acc[st][r] = 0.f;

    load_A_npagg(smem, m0, neb, agg, tid);
    load_Bw(smem, N_B0, 128 * NSTR, npHi, npLo, 128, 256, NSTR, tid, 512);
    __syncthreads();
    mma_span16<1>(sb, sb + N_ALO, sb + N_B0, sb + N_B0 + 128 * NSTR,
                  NSTR, NSTR, 16, acc, wm, wn, lane);
    __syncthreads();
    epi_repack16(smem, NSTR, N_ALO, acc, m0, wm, npb, resid, nf_out, nullptr, wn, lane);
    load_Bw(smem, N_B0, 256 * 272, epHi, epLo, 256, 128, 272, tid, 512);
    __syncthreads();
    mma_span16<2>(sb, sb + N_ALO, sb + N_B0, sb + N_B0 + 256 * 272,
                  NSTR, 272, 8, acc, wm, wn, lane);
    #pragma unroll
    for (int t2 = 0; t2 < 2; t2++) {
        float (*accp)[4] = acc + t2 * 2;
        write_accf16(accp, m0, wm, wn, lane, prpsp_out, t2 * 128, 256);
    }
}

__global__ __launch_bounds__(512, 1) void tail_kernel(
    const uint32_t* __restrict__ neb, const float* __restrict__ agg1,
    const float* __restrict__ nf1,
    const __nv_bfloat16* __restrict__ npHi, const __nv_bfloat16* __restrict__ npLo,
    const float* __restrict__ npb,
    const float* __restrict__ pc,
    const __nv_bfloat16* __restrict__ p0bHi, const __nv_bfloat16* __restrict__ p0bLo,
    const float* __restrict__ ppb0,
    const __nv_bfloat16* __restrict__ p1Hi, const __nv_bfloat16* __restrict__ p1Lo,
    const float* __restrict__ ppb1,
    const float* __restrict__ ppW2, const float* __restrict__ ppb2,
    float* __restrict__ out)
{
    extern __shared__ char smem[];
    const uint32_t sb = smem_u32(smem);
    const int tid = threadIdx.x;
    const int wid = tid >> 5, lane = tid & 31;
    const int wm = wid & 1, wn = wid >> 1;
    const int m0 = blockIdx.x * 32;

    float acc[2][4];
    #pragma unroll
    for (int st = 0; st < 2; st++)
        #pragma unroll
        for (int r = 0; r < 4; r++) acc[st][r] = 0.f;

    load_A_npagg(smem, m0, neb, agg1, tid);
    load_Bw(smem, N_B0, 128 * NSTR, npHi, npLo, 128, 256, NSTR, tid, 512);
    __syncthreads();
    mma_span16<1>(sb, sb + N_ALO, sb + N_B0, sb + N_B0 + 128 * NSTR,
                  NSTR, NSTR, 16, acc, wm, wn, lane);
    __syncthreads();
    epi_repack16(smem, NSTR, N_ALO, acc, m0, wm, npb, nf1, nullptr, nullptr, wn, lane);
    load_Bw(smem, N_B0, 128 * 272, p0bHi, p0bLo, 128, 128, 272, tid, 512);
    __syncthreads();
    mma_span16<1>(sb, sb + N_ALO, sb + N_B0, sb + N_B0 + 128 * 272,
                  NSTR, 272, 8, acc, wm, wn, lane);
    __syncthreads();
    epi_repack16(smem, NSTR, N_ALO, acc, m0, wm, ppb0, pc, nullptr, nullptr, wn, lane);
    load_Bw(smem, N_B0, 128 * 272, p1Hi, p1Lo, 128, 128, 272, tid, 512);
    __syncthreads();
    mma_span16<1>(sb, sb + N_ALO, sb + N_B0, sb + N_B0 + 128 * 272,
                  NSTR, 272, 8, acc, wm, wn, lane);
    __syncthreads();
    float* stage = (float*)(smem + N_B0);
    #pragma unroll
    for (int st = 0; st < 2; st++) {
        int n = wn * 16 + st * 8 + ((lane & 3) << 1);
        float b0 = __ldg(ppb1 + n), b1 = __ldg(ppb1 + n + 1);
        int r0 = wm * 16 + (lane >> 2);
        #pragma unroll
        for (int h = 0; h < 2; h++) {
            int r = r0 + h * 8;
            stage[r * 132 + n]     = fmaxf(acc[st][h * 2 + 0] + b0, 0.f);
            stage[r * 132 + n + 1] = fmaxf(acc[st][h * 2 + 1] + b1, 0.f);
        }
    }
    __syncthreads();
    if (tid < 96) {
        int m = tid / 3, n = tid - (tid / 3) * 3;
        const float* aa = stage + m * 132;
        float s = __ldg(ppb2 + n);
        #pragma unroll 16
        for (int k = 0; k < 128; k++) s += aa[k] * __ldg(ppW2 + k * 3 + n);
        out[(size_t)(m0 + m) * 3 + n] = s;
    }
}

// ---------------- launch ----------------
extern "C" void kernel_launch(void* const* d_in, const int* in_sizes, int n_in,
                              void* d_out, int out_size)
{
    const float* x    = (const float*)d_in[0];
    const float* Rr   = (const float*)d_in[1];
    const float* Rs   = (const float*)d_in[2];
    const float* neW0 = (const float*)d_in[4];  const float* neb0 = (const float*)d_in[5];
    const float* neW1 = (const float*)d_in[6];  const float* neb1 = (const float*)d_in[7];
    const float* neW2 = (const float*)d_in[8];  const float* neb2 = (const float*)d_in[9];
    const float* eeW0 = (const float*)d_in[10]; const float* eeb0 = (const float*)d_in[11];
    const float* eeW1 = (const float*)d_in[12]; const float* eeb1 = (const float*)d_in[13];
    const float* eeW2 = (const float*)d_in[14]; const float* eeb2 = (const float*)d_in[15];
    const float* npW  = (const float*)d_in[16]; const float* npb  = (const float*)d_in[17];
    const float* epW  = (const float*)d_in[18]; const float* epb  = (const float*)d_in[19];
    const float* ppW0 = (const float*)d_in[20]; const float* ppb0 = (const float*)d_in[21];
    const float* ppW1 = (const float*)d_in[22]; const float* ppb1 = (const float*)d_in[23];
    const float* ppW2 = (const float*)d_in[24]; const float* ppb2 = (const float*)d_in[25];
    float* out = (float*)d_out;

    uint32_t* arena; cudaGetSymbolAddress((void**)&arena, g_arena);
    int* recv; cudaGetSymbolAddress((void**)&recv, g_recv);
    int* send; cudaGetSymbolAddress((void**)&send, g_send);
    __nv_bfloat16* whi; cudaGetSymbolAddress((void**)&whi, g_whi);
    __nv_bfloat16* wlo; cudaGetSymbolAddress((void**)&wlo, g_wlo);
    float* zb; cudaGetSymbolAddress((void**)&zb, g_zero);

    uint32_t* neb    = arena + OFF_NEB;
    float*    nef    = (float*)(arena + OFF_NEF);
    float*    nf1f   = (float*)(arena + OFF_NF1F);
    float*    pc     = (float*)(arena + OFF_PC);
    float*    agg0   = (float*)(arena + OFF_AGG0);
    float*    agg1   = (float*)(arena + OFF_AGG1);
    float*    prs    = (float*)(arena + OFF_PRS);
    float*    prpspA = (float*)(arena + OFF_PRPSPA);
    float*    prpspB = (float*)(arena + OFF_PRPSPB);
    float*    ec     = (float*)(arena + OFF_EC);

    const int WO[12] = {0,8192,24576,40960,57344,73728,90112,106496,139264,172032,188416,204800};

    static bool s_init = false;
    static cudaStream_t s1, s2;
    static cudaEvent_t evStart, evPrep, evS1, evNE;
    if (!s_init) {
        cudaStreamCreateWithFlags(&s1, cudaStreamNonBlocking);
        cudaStreamCreateWithFlags(&s2, cudaStreamNonBlocking);
        cudaEventCreateWithFlags(&evStart, cudaEventDisableTiming);
        cudaEventCreateWithFlags(&evPrep,  cudaEventDisableTiming);
        cudaEventCreateWithFlags(&evS1,    cudaEventDisableTiming);
        cudaEventCreateWithFlags(&evNE,    cudaEventDisableTiming);
        cudaFuncSetAttribute(hgemm<2,64>,   cudaFuncAttributeMaxDynamicSharedMemorySize, smem_hg(2,64));
        cudaFuncSetAttribute(node_mega,     cudaFuncAttributeMaxDynamicSharedMemorySize, NM_SMEM);
        cudaFuncSetAttribute(edge_mega,     cudaFuncAttributeMaxDynamicSharedMemorySize, EM_SMEM);
        cudaFuncSetAttribute(np_prpsp_kernel, cudaFuncAttributeMaxDynamicSharedMemorySize, NP_SMEM);
        cudaFuncSetAttribute(tail_kernel,     cudaFuncAttributeMaxDynamicSharedMemorySize, TL_SMEM);
        s_init = true;
    }

    // fork at root: extract + agg zeros on s1
    cudaEventRecord(evStart, 0);
    cudaStreamWaitEvent(s1, evStart, 0);
    extract_idx2_kernel<<<2 * BE / 8, 256, 0, s1>>>(Rr, Rs, recv, send);
    cudaMemsetAsync(agg0, 0, (size_t)BN * 128 * sizeof(float), s1);
    cudaMemsetAsync(agg1, 0, (size_t)BN * 128 * sizeof(float), s1);
    cudaEventRecord(evS1, s1);

    // origin: weight prep
    PArg pa;
    pa.W[0] = neW0; pa.W[1] = neW1; pa.W[2] = neW2;
    pa.W[3] = eeW0; pa.W[4] = eeW1; pa.W[5] = eeW2;
    pa.W[6] = epW;  pa.W[7] = epW;  pa.W[8] = npW;
    pa.W[9] = ppW0; pa.W[10] = ppW0; pa.W[11] = ppW1;
    prep_weights<<<dim3(12, 8), 256>>>(pa, whi, wlo);
    cudaEventRecord(evPrep, 0);
    cudaStreamWaitEvent(s2, evPrep, 0);

    // s2: fused node encoder + step-invariant projections
    {
        NodeArg na;
        na.x = x;
        na.w0h = whi + WO[0]; na.w0l = wlo + WO[0];
        na.w1h = whi + WO[1]; na.w1l = wlo + WO[1];
        na.w2h = whi + WO[2]; na.w2l = wlo + WO[2];
        na.eprh = whi + WO[7];          na.eprl = wlo + WO[7];
        na.epsh = whi + WO[7] + 16384;  na.epsl = wlo + WO[7] + 16384;
        na.pqh = whi + WO[9];  na.pql = wlo + WO[9];
        na.b0 = neb0; na.b1 = neb1; na.b2 = neb2;
        na.neb = neb; na.nef = nef; na.prpsp = prpspA; na.pc = pc;
        node_mega<<<BN / 32, 256, NM_SMEM, s2>>>(na);
    }
    cudaEventRecord(evNE, s2);

    // origin: PrPs = x @ [eer|ees]
    {
        GArg a;
        a.s0.p = x; a.s0.start = 0; a.s0.mode = 3; a.s0.rs = 32;
        a.s1.p = nullptr; a.s1.start = 32; a.s1.mode = 0; a.s1.rs = 0;
        a.K = 64; a.Bhi = whi + WO[3]; a.Blo = wlo + WO[3];
        a.bias = zb; a.outf = prs; a.ldo = 256;
        hgemm<2,64><<<BN / 32, 256, smem_hg(2,64)>>>(a);
    }

    // join: indices + node projections
    cudaStreamWaitEvent(0, evS1, 0);
    cudaStreamWaitEvent(0, evNE, 0);

    // fused edge chain + step-0 scatter (512 threads, ping-pong weights)
    {
        EdgeArg ea;
        ea.prs = prs; ea.recv = recv; ea.send = send; ea.eeb0 = eeb0;
        ea.w1h = whi + WO[4]; ea.w1l = wlo + WO[4];
        ea.w2h = whi + WO[5]; ea.w2l = wlo + WO[5];
        ea.weh = whi + WO[6]; ea.wel = wlo + WO[6];
        ea.b1 = eeb1; ea.b2 = eeb2;
        ea.prpsp = prpspA; ea.epb = epb;
        ea.ec = ec; ea.agg = agg0;
        edge_mega<<<BE / 64, 512, EM_SMEM>>>(ea);
    }

    // fused np(step0) + prpsp(step1)
    np_prpsp_kernel<<<BN / 32, 512, NP_SMEM>>>(neb, agg0, nef,
        whi + WO[8], wlo + WO[8], npb, whi + WO[7], wlo + WO[7],
        nf1f, prpspB);

    // step-1 scatter
    fused_scatter_kernel<<<BE * 128 / 256, 256>>>(ec, prpspB, recv, send, epb, agg1);

    // fused np(step1) + predictor + output
    tail_kernel<<<BN / 32, 512, TL_SMEM>>>(neb, agg1, nf1f,
        whi + WO[8], wlo + WO[8], npb, pc,
        whi + WO[10], wlo + WO[10], ppb0,
        whi + WO[11], wlo + WO[11], ppb1,
        ppW2, ppb2, out);
}

// round 12
// speedup vs baseline: 3.0474x; 1.0120x over previous
#include <cuda_runtime.h>
#include <cuda_bf16.h>
#include <cstdint>

// ---------------- problem dims ----------------
#define Nn 1024
#define Ee 8192
#define BN 4096    // B*N
#define BE 32768   // B*E

// ---------------- device scratch ----------------
#define OFF_NEB    ((size_t)0)                       // node_enc bfp
#define OFF_NEF    (OFF_NEB + (size_t)BN*128)        // node_enc f32
#define OFF_NF1F   (OFF_NEF + (size_t)BN*128)        // nf1 f32
#define OFF_PC     (OFF_NF1F + (size_t)BN*128)       // neb@pp0a f32
#define OFF_AGG0   (OFF_PC + (size_t)BN*128)
#define OFF_AGG1   (OFF_AGG0 + (size_t)BN*128)       // adjacent to agg0
#define OFF_PRS    (OFF_AGG1 + (size_t)BN*128)       // [BN,256] f32 (x@Wr | x@Ws)
#define OFF_PRPSPA (OFF_PRS + (size_t)BN*256)        // [BN,256] f32 step0
#define OFF_PRPSPB (OFF_PRPSPA + (size_t)BN*256)     // [BN,256] f32 step1
#define OFF_EC     (OFF_PRPSPB + (size_t)BN*256)     // [BE,128] f32
#define ARENA_U32  (OFF_EC + (size_t)BE*128)

__device__ uint32_t g_arena[ARENA_U32];
__device__ int g_recv[BE];
__device__ int g_send[BE];
__device__ float g_zero[256];

// split/transposed weights [n][kpad] bf16, 12 matrices
#define WT_TOTAL 221184
__device__ __nv_bfloat16 g_whi[WT_TOTAL];
__device__ __nv_bfloat16 g_wlo[WT_TOTAL];

// ---------------- helpers ----------------
__device__ __forceinline__ uint32_t smem_u32(const void* p) {
    uint32_t a;
    asm("{ .reg .u64 t; cvta.to.shared.u64 t, %1; cvt.u32.u64 %0, t; }" : "=r"(a) : "l"(p));
    return a;
}

#define LDMX4(r, ad) \
    asm volatile("ldmatrix.sync.aligned.m8n8.x4.shared.b16 {%0,%1,%2,%3}, [%4];" \
        : "=r"((r)[0]), "=r"((r)[1]), "=r"((r)[2]), "=r"((r)[3]) : "r"(ad))

#define MMA16816(d, av, bv) \
    asm volatile("mma.sync.aligned.m16n8k16.row.col.f32.bf16.bf16.f32 " \
        "{%0,%1,%2,%3},{%4,%5,%6,%7},{%8,%9},{%0,%1,%2,%3};" \
        : "+f"((d)[0]), "+f"((d)[1]), "+f"((d)[2]), "+f"((d)[3]) \
        : "r"((av)[0]), "r"((av)[1]), "r"((av)[2]), "r"((av)[3]), \
          "r"((bv)[0]), "r"((bv)[1]))

#define CP_ASYNC16(sa, gp) \
    asm volatile("cp.async.cg.shared.global [%0], [%1], 16;" :: "r"(sa), "l"(gp))
#define CP_COMMIT()  asm volatile("cp.async.commit_group;" ::: "memory")
#define CP_WAIT1()   asm volatile("cp.async.wait_group 1;" ::: "memory")
#define CP_WAIT0()   asm volatile("cp.async.wait_group 0;" ::: "memory")

__device__ __forceinline__ uint32_t packbfp(float v) {
    __nv_bfloat16 h = __float2bfloat16(v);
    float hf = __bfloat162float(h);
    __nv_bfloat16 l = __float2bfloat16(v - hf);
    return (uint32_t)__bfloat16_as_ushort(h) | ((uint32_t)__bfloat16_as_ushort(l) << 16);
}

// ---- 32-col-warp 3-pass MMA (256-thread kernels) ----
__device__ __forceinline__ void mma_span1(
    uint32_t aHi, uint32_t aLo, uint32_t bHi, uint32_t bLo,
    int astr, int bstr, int nk, float (*acc)[4], int tile, int wn, int lane)
{
    for (int ks = 0; ks < nk; ks++) {
        uint32_t bh[8], bl[8];
        #pragma unroll
        for (int np = 0; np < 2; np++) {
            int n = wn * 32 + np * 16 + ((lane >> 4) << 3) + (lane & 7);
            int koff = ((lane >> 3) & 1) << 3;
            uint32_t ad = bHi + n * bstr + (ks * 16 + koff) * 2;
            LDMX4(&bh[np * 4], ad);
            LDMX4(&bl[np * 4], ad + (bLo - bHi));
        }
        int r = tile * 16 + (lane & 15);
        int koff = (lane >> 4) << 3;
        uint32_t ad = aHi + r * astr + (ks * 16 + koff) * 2;
        uint32_t ah[4], al[4];
        LDMX4(ah, ad);
        LDMX4(al, ad + (aLo - aHi));
        #pragma unroll
        for (int st = 0; st < 4; st++) {
            MMA16816(acc[st], ah, &bh[st * 2]);
            MMA16816(acc[st], ah, &bl[st * 2]);
            MMA16816(acc[st], al, &bh[st * 2]);
        }
    }
}

// ---- 16-col-warp 3-pass MMA (512-thread kernels): wn in 0..7, 16 cols/warp ----
__device__ __forceinline__ void mma_span16(
    uint32_t aHi, uint32_t aLo, uint32_t bHi, uint32_t bLo,
    int astr, int bstr, int nk, float (*acc)[4], int tile, int wn, int lane)
{
    for (int ks = 0; ks < nk; ks++) {
        uint32_t bh[4], bl[4];
        int n = wn * 16 + ((lane >> 4) << 3) + (lane & 7);
        int koff = ((lane >> 3) & 1) << 3;
        uint32_t ad = bHi + n * bstr + (ks * 16 + koff) * 2;
        LDMX4(bh, ad);
        LDMX4(bl, ad + (bLo - bHi));
        int r = tile * 16 + (lane & 15);
        int koff2 = (lane >> 4) << 3;
        uint32_t ad2 = aHi + r * astr + (ks * 16 + koff2) * 2;
        uint32_t ah[4], al[4];
        LDMX4(ah, ad2);
        LDMX4(al, ad2 + (aLo - aHi));
        #pragma unroll
        for (int st = 0; st < 2; st++) {
            MMA16816(acc[st], ah, &bh[st * 2]);
            MMA16816(acc[st], ah, &bl[st * 2]);
            MMA16816(acc[st], al, &bh[st * 2]);
        }
    }
}

// async weight load with K-window (cp.async, caller commits/waits)
__device__ __forceinline__ void load_Bw_cp(uint32_t sbase, int plane,
    const __nv_bfloat16* Bhi, const __nv_bfloat16* Blo,
    int nrows, int kwin, int fullK, int k0, int bstr, int tid, int nth)
{
    int kg = kwin >> 3;
    int per = nrows * kg;
    for (int item = tid; item < per; item += nth) {
        int n = item / kg, g = item - n * kg;
        size_t goff = (size_t)n * fullK + k0 + (g << 3);
        uint32_t so = sbase + n * bstr + (g << 4);
        CP_ASYNC16(so, Bhi + goff);
        CP_ASYNC16(so + plane, Blo + goff);
    }
}

// 32-col-warp epilogue: relu(acc+bias(+resid)) -> repack A planes (+outf/outb)
__device__ __forceinline__ void epi_repack2(char* smem, int astr, int aplane,
    float (*acc)[4], int m0, int tile,
    const float* bias, const float* resid, float* outf, uint32_t* outb,
    int wn, int lane)
{
    #pragma unroll
    for (int st = 0; st < 4; st++) {
        int n = wn * 32 + st * 8 + ((lane & 3) << 1);
        float b0 = __ldg(bias + n), b1 = __ldg(bias + n + 1);
        int r0 = tile * 16 + (lane >> 2);
        #pragma unroll
        for (int h = 0; h < 2; h++) {
            int r = r0 + h * 8;
            float s0 = acc[st][h * 2 + 0] + b0;
            float s1 = acc[st][h * 2 + 1] + b1;
            if (resid) {
                float2 rv = *(const float2*)(resid + (((size_t)(m0 + r)) << 7) + n);
                s0 += rv.x; s1 += rv.y;
            }
            s0 = fmaxf(s0, 0.f); s1 = fmaxf(s1, 0.f);
            if (outf) *(float2*)(outf + (((size_t)(m0 + r)) << 7) + n) = make_float2(s0, s1);
            uint32_t p0 = packbfp(s0), p1 = packbfp(s1);
            if (outb) *(uint2*)(outb + (((size_t)(m0 + r)) << 7) + n) = make_uint2(p0, p1);
            int off = r * astr + n * 2;
            *(uint32_t*)(smem + off) = (p0 & 0xffffu) | (p1 << 16);
            *(uint32_t*)(smem + aplane + off) = (p0 >> 16) | (p1 & 0xffff0000u);
            acc[st][h * 2 + 0] = 0.f;
            acc[st][h * 2 + 1] = 0.f;
        }
    }
}

// 16-col-warp epilogue
__device__ __forceinline__ void epi_repack16(char* smem, int astr, int aplane,
    float (*acc)[4], int m0, int tile,
    const float* bias, const float* resid, float* outf,
    int wn, int lane)
{
    #pragma unroll
    for (int st = 0; st < 2; st++) {
        int n = wn * 16 + st * 8 + ((lane & 3) << 1);
        float b0 = __ldg(bias + n), b1 = __ldg(bias + n + 1);
        int r0 = tile * 16 + (lane >> 2);
        #pragma unroll
        for (int h = 0; h < 2; h++) {
            int r = r0 + h * 8;
            float s0 = acc[st][h * 2 + 0] + b0;
            float s1 = acc[st][h * 2 + 1] + b1;
            if (resid) {
                float2 rv = *(const float2*)(resid + (((size_t)(m0 + r)) << 7) + n);
                s0 += rv.x; s1 += rv.y;
            }
            s0 = fmaxf(s0, 0.f); s1 = fmaxf(s1, 0.f);
            if (outf) *(float2*)(outf + (((size_t)(m0 + r)) << 7) + n) = make_float2(s0, s1);
            uint32_t p0 = packbfp(s0), p1 = packbfp(s1);
            int off = r * astr + n * 2;
            *(uint32_t*)(smem + off) = (p0 & 0xffffu) | (p1 << 16);
            *(uint32_t*)(smem + aplane + off) = (p0 >> 16) | (p1 & 0xffff0000u);
            acc[st][h * 2 + 0] = 0.f;
            acc[st][h * 2 + 1] = 0.f;
        }
    }
}

// write acc f32 (32-col warps)
__device__ __forceinline__ void write_accf(float (*acc)[4], int m0, int tile,
    int wn, int lane, float* out, int nbase, int ldo)
{
    #pragma unroll
    for (int st = 0; st < 4; st++) {
        int n = nbase + wn * 32 + st * 8 + ((lane & 3) << 1);
        int r0 = tile * 16 + (lane >> 2);
        #pragma unroll
        for (int h = 0; h < 2; h++) {
            int m = m0 + r0 + h * 8;
            *(float2*)(out + (size_t)m * ldo + n) =
                make_float2(acc[st][h * 2 + 0], acc[st][h * 2 + 1]);
            acc[st][h * 2 + 0] = 0.f;
            acc[st][h * 2 + 1] = 0.f;
        }
    }
}

// write acc f32 (16-col warps)
__device__ __forceinline__ void write_accf16(float (*acc)[4], int m0, int tile,
    int wn, int lane, float* out, int nbase, int ldo)
{
    #pragma unroll
    for (int st = 0; st < 2; st++) {
        int n = nbase + wn * 16 + st * 8 + ((lane & 3) << 1);
        int r0 = tile * 16 + (lane >> 2);
        #pragma unroll
        for (int h = 0; h < 2; h++) {
            int m = m0 + r0 + h * 8;
            *(float2*)(out + (size_t)m * ldo + n) =
                make_float2(acc[st][h * 2 + 0], acc[st][h * 2 + 1]);
            acc[st][h * 2 + 0] = 0.f;
            acc[st][h * 2 + 1] = 0.f;
        }
    }
}

// ---------------- aux kernels ----------------
__global__ void extract_idx2_kernel(const float* __restrict__ Rr,
                                    const float* __restrict__ Rs,
                                    int* __restrict__ recv, int* __restrict__ send)
{
    int row = blockIdx.x * 8 + (threadIdx.x >> 5);
    int lane = threadIdx.x & 31;
    const float* R = (row < BE) ? Rr : Rs;
    int r = (row < BE) ? row : row - BE;
    const float4* p = (const float4*)(R + (size_t)r * Nn);
    int found = -1;
    #pragma unroll
    for (int i = 0; i < 4; i++) {
        int q = lane + i * 32;
        float4 v = p[q];
        if (v.x > 0.5f) found = q * 4 + 0;
        if (v.y > 0.5f) found = q * 4 + 1;
        if (v.z > 0.5f) found = q * 4 + 2;
        if (v.w > 0.5f) found = q * 4 + 3;
    }
    if (__ballot_sync(0xFFFFFFFFu, found >= 0) == 0u) {
        #pragma unroll
        for (int i = 4; i < 8; i++) {
            int q = lane + i * 32;
            float4 v = p[q];
            if (v.x > 0.5f) found = q * 4 + 0;
            if (v.y > 0.5f) found = q * 4 + 1;
            if (v.z > 0.5f) found = q * 4 + 2;
            if (v.w > 0.5f) found = q * 4 + 3;
        }
    }
    #pragma unroll
    for (int o = 16; o; o >>= 1) found = max(found, __shfl_xor_sync(0xFFFFFFFFu, found, o));
    if (lane == 0) {
        found = max(found, 0);
        if (row < BE) recv[r] = found; else send[r] = found;
    }
}

// matrices: 0 ne0 1 ne1 2 ne2 3 eers(R256) 4 ee1 5 ee2 6 ep_e 7 ep_rs(R256)
//           8 np(K256) 9 pp0a 10 pp0b 11 pp1
struct PArg { const float* W[12]; };
__constant__ int c_Ks[12]  = {32,128,128, 32,128,128,128,128,256,128,128,128};
__constant__ int c_Kps[12] = {64,128,128, 64,128,128,128,128,256,128,128,128};
__constant__ int c_Rs[12]  = {128,128,128,256,128,128,128,256,128,128,128,128};
__constant__ int c_r0a[12] = {0,0,0,0,0,0,0,128,0,0,128,0};
__constant__ int c_r0b[12] = {0,0,0,32,0,0,0,256,0,0,0,0};
__constant__ int c_off[12] = {0,8192,24576,40960,57344,73728,90112,106496,139264,172032,188416,204800};

__global__ void prep_weights(PArg a, __nv_bfloat16* __restrict__ hi, __nv_bfloat16* __restrict__ lo)
{
    int mid = blockIdx.x;
    int K = c_Ks[mid], Kp = c_Kps[mid], R = c_Rs[mid];
    int r0a = c_r0a[mid], r0b = c_r0b[mid];
    const float* W = a.W[mid];
    __nv_bfloat16* dh = hi + c_off[mid];
    __nv_bfloat16* dl = lo + c_off[mid];
    int total = R * Kp;
    for (int i = threadIdx.x + blockIdx.y * blockDim.x; i < total; i += blockDim.x * gridDim.y) {
        int n = i / Kp, k = i - n * Kp;
        int col = n & 127;
        int r0 = (n >> 7) ? r0b : r0a;
        float v = (k < K) ? W[(size_t)(r0 + k) * 128 + col] : 0.f;
        __nv_bfloat16 h = __float2bfloat16(v);
        dh[i] = h;
        dl[i] = __float2bfloat16(v - __bfloat162float(h));
    }
}

// step-1 scatter
__global__ void fused_scatter_kernel(const float* __restrict__ ec,
                                     const float* __restrict__ prpsp,
                                     const int* __restrict__ recv,
                                     const int* __restrict__ send,
                                     const float* __restrict__ bias,
                                     float* __restrict__ agg)
{
    int t = blockIdx.x * blockDim.x + threadIdx.x;
    if (t >= BE * 128) return;
    int e = t >> 7, h = t & 127;
    int bo = (e >> 13) << 10;
    int r = __ldg(recv + e) + bo, s = __ldg(send + e) + bo;
    float v = ec[t] + prpsp[(size_t)r * 256 + h] + prpsp[(size_t)s * 256 + 128 + h] + __ldg(bias + h);
    v = fmaxf(v, 0.f);
    atomicAdd(&agg[(size_t)r * 128 + h], v);
}

// ---------------- node_mega: eer,ees,ne0..ne2,epr,eps,pc (256 thr, ping-pong) ----------------
#define NM_STR   272
#define NM_ALO   (32 * NM_STR)
#define NM_B0    (2 * NM_ALO)
#define NM_BPL   (128 * NM_STR)
#define NM_SLOT  (2 * NM_BPL)
#define NM_SMEM  (NM_B0 + 2 * NM_SLOT)     // 156672

struct NodeArg {
    const float* x;
    const __nv_bfloat16 *eerh,*eerl,*eesh,*eesl;
    const __nv_bfloat16 *w0h,*w0l,*w1h,*w1l,*w2h,*w2l,*eprh,*eprl,*epsh,*epsl,*pqh,*pql;
    const float *b0,*b1,*b2;
    uint32_t* neb; float* nef; float* prs; float* prpsp; float* pc;
};

__global__ __launch_bounds__(256) void node_mega(NodeArg a)
{
    extern __shared__ char smem[];
    const uint32_t sb = smem_u32(smem);
    const int tid = threadIdx.x;
    const int wid = tid >> 5, lane = tid & 31;
    const int wm = wid & 1, wn = wid >> 1;
    const int m0 = blockIdx.x * 32;

    const uint32_t sA = sb + NM_B0;
    const uint32_t sB = sb + NM_B0 + NM_SLOT;

    float acc[4][4];
    #pragma unroll
    for (int st = 0; st < 4; st++)
        #pragma unroll
        for (int r = 0; r < 4; r++) acc[st][r] = 0.f;

    // prefetch eer (sA), ees (sB)
    load_Bw_cp(sA, NM_BPL, a.eerh, a.eerl, 128, 64, 64, 0, NM_STR, tid, 256); CP_COMMIT();
    load_Bw_cp(sB, NM_BPL, a.eesh, a.eesl, 128, 64, 64, 0, NM_STR, tid, 256); CP_COMMIT();

    // A <- x (K=32 pad 64)
    #pragma unroll
    for (int it = 0; it < 2; it++) {
        int item = tid + (it << 8);
        int r = item >> 4, g = item & 15;
        int kc = g << 2;
        uint32_t p0 = 0, p1 = 0, p2 = 0, p3 = 0;
        if (kc < 32) {
            float4 v = *(const float4*)(a.x + (size_t)(m0 + r) * 32 + kc);
            p0 = packbfp(v.x); p1 = packbfp(v.y); p2 = packbfp(v.z); p3 = packbfp(v.w);
        }
        uint32_t hi01 = (p0 & 0xffffu) | (p1 << 16);
        uint32_t hi23 = (p2 & 0xffffu) | (p3 << 16);
        uint32_t lo01 = (p0 >> 16) | (p1 & 0xffff0000u);
        uint32_t lo23 = (p2 >> 16) | (p3 & 0xffff0000u);
        int off = r * NM_STR + g * 8;
        *(uint2*)(smem + off) = make_uint2(hi01, hi23);
        *(uint2*)(smem + NM_ALO + off) = make_uint2(lo01, lo23);
    }

    // P0: eer -> prs[:,0:128]
    CP_WAIT1(); __syncthreads();
    mma_span1(sb, sb + NM_ALO, sA, sA + NM_BPL, NM_STR, NM_STR, 4, acc, wm, wn, lane);
    __syncthreads();
    write_accf(acc, m0, wm, wn, lane, a.prs, 0, 256);
    load_Bw_cp(sA, NM_BPL, a.w0h, a.w0l, 128, 64, 64, 0, NM_STR, tid, 256); CP_COMMIT();

    // P1: ees -> prs[:,128:256]
    CP_WAIT1(); __syncthreads();
    mma_span1(sb, sb + NM_ALO, sB, sB + NM_BPL, NM_STR, NM_STR, 4, acc, wm, wn, lane);
    __syncthreads();
    write_accf(acc, m0, wm, wn, lane, a.prs, 128, 256);
    load_Bw_cp(sB, NM_BPL, a.w1h, a.w1l, 128, 128, 128, 0, NM_STR, tid, 256); CP_COMMIT();

    // P2: ne0 (A <- h0)
    CP_WAIT1(); __syncthreads();
    mma_span1(sb, sb + NM_ALO, sA, sA + NM_BPL, NM_STR, NM_STR, 4, acc, wm, wn, lane);
    __syncthreads();
    epi_repack2(smem, NM_STR, NM_ALO, acc, m0, wm, a.b0, nullptr, nullptr, nullptr, wn, lane);
    load_Bw_cp(sA, NM_BPL, a.w2h, a.w2l, 128, 128, 128, 0, NM_STR, tid, 256); CP_COMMIT();

    // P3: ne1
    CP_WAIT1(); __syncthreads();
    mma_span1(sb, sb + NM_ALO, sB, sB + NM_BPL, NM_STR, NM_STR, 8, acc, wm, wn, lane);
    __syncthreads();
    epi_repack2(smem, NM_STR, NM_ALO, acc, m0, wm, a.b1, nullptr, nullptr, nullptr, wn, lane);
    load_Bw_cp(sB, NM_BPL, a.eprh, a.eprl, 128, 128, 128, 0, NM_STR, tid, 256); CP_COMMIT();

    // P4: ne2 -> neb/nef
    CP_WAIT1(); __syncthreads();
    mma_span1(sb, sb + NM_ALO, sA, sA + NM_BPL, NM_STR, NM_STR, 8, acc, wm, wn, lane);
    __syncthreads();
    epi_repack2(smem, NM_STR, NM_ALO, acc, m0, wm, a.b2, nullptr, a.nef, a.neb, wn, lane);
    load_Bw_cp(sA, NM_BPL, a.epsh, a.epsl, 128, 128, 128, 0, NM_STR, tid, 256); CP_COMMIT();

    // P5: epr -> prpspA[:,0:128]
    CP_WAIT1(); __syncthreads();
    mma_span1(sb, sb + NM_ALO, sB, sB + NM_BPL, NM_STR, NM_STR, 8, acc, wm, wn, lane);
    __syncthreads();
    write_accf(acc, m0, wm, wn, lane, a.prpsp, 0, 256);
    load_Bw_cp(sB, NM_BPL, a.pqh, a.pql, 128, 128, 128, 0, NM_STR, tid, 256); CP_COMMIT();

    // P6: eps -> prpspA[:,128:256]
    CP_WAIT1(); __syncthreads();
    mma_span1(sb, sb + NM_ALO, sA, sA + NM_BPL, NM_STR, NM_STR, 8, acc, wm, wn, lane);
    __syncthreads();
    write_accf(acc, m0, wm, wn, lane, a.prpsp, 128, 256);

    // P7: pc
    CP_WAIT0(); __syncthreads();
    mma_span1(sb, sb + NM_ALO, sB, sB + NM_BPL, NM_STR, NM_STR, 8, acc, wm, wn, lane);
    __syncthreads();
    write_accf(acc, m0, wm, wn, lane, a.pc, 0, 128);
}

// ---------------- edge_mega: 512 threads, cp.async ping-pong ----------------
#define EM_STR   272
#define EM_ALO   (64 * EM_STR)
#define EM_B0    (2 * EM_ALO)
#define EM_BPL   (128 * EM_STR)
#define EM_SLOT  (2 * EM_BPL)
#define EM_SMEM  (EM_B0 + 2 * EM_SLOT)     // 174080

struct EdgeArg {
    const float* prs; const int* recv; const int* send; const float* eeb0;
    const __nv_bfloat16 *w1h,*w1l,*w2h,*w2l,*weh,*wel;
    const float *b1,*b2;
    const float* prpsp; const float* epb;
    float* ec; float* agg;
};

__global__ __launch_bounds__(512, 1) void edge_mega(EdgeArg a)
{
    extern __shared__ char smem[];
    const uint32_t sb = smem_u32(smem);
    const int tid = threadIdx.x;
    const int wid = tid >> 5, lane = tid & 31;
    const int wm = wid & 1, wn = wid >> 1;
    const int m0 = blockIdx.x * 64;

    const uint32_t sA = sb + EM_B0;
    const uint32_t sB = sb + EM_B0 + EM_SLOT;

    float acc[2][2][4];
    #pragma unroll
    for (int mt = 0; mt < 2; mt++)
        #pragma unroll
        for (int st = 0; st < 2; st++)
            #pragma unroll
            for (int r = 0; r < 4; r++) acc[mt][st][r] = 0.f;

    load_Bw_cp(sA, EM_BPL, a.w1h, a.w1l, 128, 128, 128, 0, EM_STR, tid, 512); CP_COMMIT();
    load_Bw_cp(sB, EM_BPL, a.w2h, a.w2l, 128, 128, 128, 0, EM_STR, tid, 512); CP_COMMIT();

    // A <- edge layer0 on the fly: relu(Pr[recv]+Ps[send]+b0)
    #pragma unroll
    for (int it = 0; it < 4; it++) {
        int item = tid + (it << 9);
        int r = item >> 5, g = item & 31;
        int kc = g << 2;
        int m = m0 + r;
        int bo = (m >> 13) << 10;
        int rr = __ldg(a.recv + m) + bo, ss = __ldg(a.send + m) + bo;
        float4 pr = *(const float4*)(a.prs + (size_t)rr * 256 + kc);
        float4 ps = *(const float4*)(a.prs + (size_t)ss * 256 + 128 + kc);
        float4 bb = *(const float4*)(a.eeb0 + kc);
        uint32_t p0 = packbfp(fmaxf(pr.x + ps.x + bb.x, 0.f));
        uint32_t p1 = packbfp(fmaxf(pr.y + ps.y + bb.y, 0.f));
        uint32_t p2 = packbfp(fmaxf(pr.z + ps.z + bb.z, 0.f));
        uint32_t p3 = packbfp(fmaxf(pr.w + ps.w + bb.w, 0.f));
        uint32_t hi01 = (p0 & 0xffffu) | (p1 << 16);
        uint32_t hi23 = (p2 & 0xffffu) | (p3 << 16);
        uint32_t lo01 = (p0 >> 16) | (p1 & 0xffff0000u);
        uint32_t lo23 = (p2 >> 16) | (p3 & 0xffff0000u);
        int off = r * EM_STR + g * 8;
        *(uint2*)(smem + off) = make_uint2(hi01, hi23);
        *(uint2*)(smem + EM_ALO + off) = make_uint2(lo01, lo23);
    }

    // phase 1: ee1 (sA)
    CP_WAIT1(); __syncthreads();
    #pragma unroll
    for (int mt = 0; mt < 2; mt++)
        mma_span16(sb, sb + EM_ALO, sA, sA + EM_BPL,
                   EM_STR, EM_STR, 8, acc[mt], wm * 2 + mt, wn, lane);
    __syncthreads();
    #pragma unroll
    for (int mt = 0; mt < 2; mt++)
        epi_repack16(smem, EM_STR, EM_ALO, acc[mt], m0, wm * 2 + mt, a.b1,
                     nullptr, nullptr, wn, lane);
    load_Bw_cp(sA, EM_BPL, a.weh, a.wel, 128, 128, 128, 0, EM_STR, tid, 512); CP_COMMIT();

    // phase 2: ee2 (sB)
    CP_WAIT1(); __syncthreads();
    #pragma unroll
    for (int mt = 0; mt < 2; mt++)
        mma_span16(sb, sb + EM_ALO, sB, sB + EM_BPL,
                   EM_STR, EM_STR, 8, acc[mt], wm * 2 + mt, wn, lane);
    __syncthreads();
    #pragma unroll
    for (int mt = 0; mt < 2; mt++)
        epi_repack16(smem, EM_STR, EM_ALO, acc[mt], m0, wm * 2 + mt, a.b2,
                     nullptr, nullptr, wn, lane);

    // phase 3: ec (sA)
    CP_WAIT0(); __syncthreads();
    #pragma unroll
    for (int mt = 0; mt < 2; mt++)
        mma_span16(sb, sb + EM_ALO, sA, sA + EM_BPL,
                   EM_STR, EM_STR, 8, acc[mt], wm * 2 + mt, wn, lane);

    // epilogue: write ec + fused step-0 scatter
    #pragma unroll
    for (int mt = 0; mt < 2; mt++) {
        int row0 = m0 + (wm * 2 + mt) * 16 + (lane >> 2);
        #pragma unroll
        for (int st = 0; st < 2; st++) {
            int n = wn * 16 + st * 8 + ((lane & 3) << 1);
            float e0b = __ldg(a.epb + n), e1b = __ldg(a.epb + n + 1);
            #pragma unroll
            for (int h = 0; h < 2; h++) {
                int m = row0 + h * 8;
                float e0 = acc[mt][st][h * 2 + 0];
                float e1 = acc[mt][st][h * 2 + 1];
                *(float2*)(a.ec + ((size_t)m << 7) + n) = make_float2(e0, e1);
                int bo = (m >> 13) << 10;
                int r_ = __ldg(a.recv + m) + bo, s_ = __ldg(a.send + m) + bo;
                float2 pr = *(const float2*)(a.prpsp + (size_t)r_ * 256 + n);
                float2 ps = *(const float2*)(a.prpsp + (size_t)s_ * 256 + 128 + n);
                float v0 = fmaxf(e0 + pr.x + ps.x + e0b, 0.f);
                float v1 = fmaxf(e1 + pr.y + ps.y + e1b, 0.f);
                atomicAdd(&a.agg[(size_t)r_ * 128 + n], v0);
                atomicAdd(&a.agg[(size_t)r_ * 128 + n + 1], v1);
            }
        }
    }
}

// ---------------- np_prpsp / tail (512 threads, ping-pong, K-chunked np) ----------------
#define NSTR   528
#define N_ALO  (32 * NSTR)                 // 16896
#define N_B0   (2 * N_ALO)                 // 33792
#define N_BPL  (128 * 272)                 // 34816
#define N_SLOT (2 * N_BPL)                 // 69632
#define NT_SMEM (N_B0 + 2 * N_SLOT)        // 173056

__device__ __forceinline__ void load_A_npagg(char* smem, int m0,
    const uint32_t* neb, const float* agg, int tid)
{
    #pragma unroll
    for (int it = 0; it < 4; it++) {
        int item = tid + (it << 9);
        int r = item >> 6, g = item & 63;
        int kc = g << 2;
        int m = m0 + r;
        uint32_t p0, p1, p2, p3;
        if (kc < 128) {
            uint4 v = *(const uint4*)(neb + ((size_t)m << 7) + kc);
            p0 = v.x; p1 = v.y; p2 = v.z; p3 = v.w;
        } else {
            float4 v = *(const float4*)(agg + ((size_t)m << 7) + (kc - 128));
            p0 = packbfp(v.x); p1 = packbfp(v.y); p2 = packbfp(v.z); p3 = packbfp(v.w);
        }
        uint32_t hi01 = (p0 & 0xffffu) | (p1 << 16);
        uint32_t hi23 = (p2 & 0xffffu) | (p3 << 16);
        uint32_t lo01 = (p0 >> 16) | (p1 & 0xffff0000u);
        uint32_t lo23 = (p2 >> 16) | (p3 & 0xffff0000u);
        int off = r * NSTR + g * 8;
        *(uint2*)(smem + off) = make_uint2(hi01, hi23);
        *(uint2*)(smem + N_ALO + off) = make_uint2(lo01, lo23);
    }
}

__global__ __launch_bounds__(512, 1) void np_prpsp_kernel(
    const uint32_t* __restrict__ neb, const float* __restrict__ agg,
    const float* __restrict__ resid,
    const __nv_bfloat16* __restrict__ npHi, const __nv_bfloat16* __restrict__ npLo,
    const float* __restrict__ npb,
    const __nv_bfloat16* __restrict__ epHi, const __nv_bfloat16* __restrict__ epLo,
    float* __restrict__ nf_out, float* __restrict__ prpsp_out)
{
    extern __shared__ char smem[];
    const uint32_t sb = smem_u32(smem);
    const int tid = threadIdx.x;
    const int wid = tid >> 5, lane = tid & 31;
    const int wm = wid & 1, wn = wid >> 1;
    const int m0 = blockIdx.x * 32;

    const uint32_t sA = sb + N_B0;
    const uint32_t sB = sb + N_B0 + N_SLOT;

    float acc[2][4];
    #pragma unroll
    for (int st = 0; st < 2; st++)
        #pragma unroll
        for (int r = 0; r < 4; r++) acc[st][r] = 0.f;

    // prefetch np chunk0 (sA), chunk1 (sB)
    load_Bw_cp(sA, N_BPL, npHi, npLo, 128, 128, 256, 0,   272, tid, 512); CP_COMMIT();
    load_Bw_cp(sB, N_BPL, npHi, npLo, 128, 128, 256, 128, 272, tid, 512); CP_COMMIT();

    load_A_npagg(smem, m0, neb, agg, tid);

    // np chunk0
    CP_WAIT1(); __syncthreads();
    mma_span16(sb, sb + N_ALO, sA, sA + N_BPL, NSTR, 272, 8, acc, wm, wn, lane);
    __syncthreads();
    load_Bw_cp(sA, N_BPL, epHi, epLo, 128, 128, 128, 0, 272, tid, 512); CP_COMMIT();
    // np chunk1 (accumulate)
    CP_WAIT1(); __syncthreads();
    mma_span16(sb + 256, sb + N_ALO + 256, sB, sB + N_BPL, NSTR, 272, 8, acc, wm, wn, lane);
    __syncthreads();
    epi_repack16(smem, NSTR, N_ALO, acc, m0, wm, npb, resid, nf_out, wn, lane);
    load_Bw_cp(sB, N_BPL, epHi + 128 * 128, epLo + 128 * 128, 128, 128, 128, 0, 272, tid, 512); CP_COMMIT();

    // ep half0 -> prpsp[:,0:128]
    CP_WAIT1(); __syncthreads();
    mma_span16(sb, sb + N_ALO, sA, sA + N_BPL, NSTR, 272, 8, acc, wm, wn, lane);
    __syncthreads();
    write_accf16(acc, m0, wm, wn, lane, prpsp_out, 0, 256);

    // ep half1 -> prpsp[:,128:256]
    CP_WAIT0(); __syncthreads();
    mma_span16(sb, sb + N_ALO, sB, sB + N_BPL, NSTR, 272, 8, acc, wm, wn, lane);
    __syncthreads();
    write_accf16(acc, m0, wm, wn, lane, prpsp_out, 128, 256);
}

__global__ __launch_bounds__(512, 1) void tail_kernel(
    const uint32_t* __restrict__ neb, const float* __restrict__ agg1,
    const float* __restrict__ nf1,
    const __nv_bfloat16* __restrict__ npHi, const __nv_bfloat16* __restrict__ npLo,
    const float* __restrict__ npb,
    const float* __restrict__ pc,
    const __nv_bfloat16* __restrict__ p0bHi, const __nv_bfloat16* __restrict__ p0bLo,
    const float* __restrict__ ppb0,
    const __nv_bfloat16* __restrict__ p1Hi, const __nv_bfloat16* __restrict__ p1Lo,
    const float* __restrict__ ppb1,
    const float* __restrict__ ppW2, const float* __restrict__ ppb2,
    float* __restrict__ out)
{
    extern __shared__ char smem[];
    const uint32_t sb = smem_u32(smem);
    const int tid = threadIdx.x;
    const int wid = tid >> 5, lane = tid & 31;
    const int wm = wid & 1, wn = wid >> 1;
    const int m0 = blockIdx.x * 32;

    const uint32_t sA = sb + N_B0;
    const uint32_t sB = sb + N_B0 + N_SLOT;

    float acc[2][4];
    #pragma unroll
    for (int st = 0; st < 2; st++)
        #pragma unroll
        for (int r = 0; r < 4; r++) acc[st][r] = 0.f;

    load_Bw_cp(sA, N_BPL, npHi, npLo, 128, 128, 256, 0,   272, tid, 512); CP_COMMIT();
    load_Bw_cp(sB, N_BPL, npHi, npLo, 128, 128, 256, 128, 272, tid, 512); CP_COMMIT();

    load_A_npagg(smem, m0, neb, agg1, tid);

    // np chunk0
    CP_WAIT1(); __syncthreads();
    mma_span16(sb, sb + N_ALO, sA, sA + N_BPL, NSTR, 272, 8, acc, wm, wn, lane);
    __syncthreads();
    load_Bw_cp(sA, N_BPL, p0bHi, p0bLo, 128, 128, 128, 0, 272, tid, 512); CP_COMMIT();
    // np chunk1 (accumulate)
    CP_WAIT1(); __syncthreads();
    mma_span16(sb + 256, sb + N_ALO + 256, sB, sB + N_BPL, NSTR, 272, 8, acc, wm, wn, lane);
    __syncthreads();
    epi_repack16(smem, NSTR, N_ALO, acc, m0, wm, npb, nf1, nullptr, wn, lane);
    load_Bw_cp(sB, N_BPL, p1Hi, p1Lo, 128, 128, 128, 0, 272, tid, 512); CP_COMMIT();

    // pp0b (resid pc)
    CP_WAIT1(); __syncthreads();
    mma_span16(sb, sb + N_ALO, sA, sA + N_BPL, NSTR, 272, 8, acc, wm, wn, lane);
    __syncthreads();
    epi_repack16(smem, NSTR, N_ALO, acc, m0, wm, ppb0, pc, nullptr, wn, lane);

    // pp1
    CP_WAIT0(); __syncthreads();
    mma_span16(sb, sb + N_ALO, sB, sB + N_BPL, NSTR, 272, 8, acc, wm, wn, lane);
    __syncthreads();
    float* stage = (float*)(smem + N_B0);
    #pragma unroll
    for (int st = 0; st < 2; st++) {
        int n = wn * 16 + st * 8 + ((lane & 3) << 1);
        float b0 = __ldg(ppb1 + n), b1 = __ldg(ppb1 + n + 1);
        int r0 = wm * 16 + (lane >> 2);
        #pragma unroll
        for (int h = 0; h < 2; h++) {
            int r = r0 + h * 8;
            stage[r * 132 + n]     = fmaxf(acc[st][h * 2 + 0] + b0, 0.f);
            stage[r * 132 + n + 1] = fmaxf(acc[st][h * 2 + 1] + b1, 0.f);
        }
    }
    __syncthreads();
    if (tid < 96) {
        int m = tid / 3, n = tid - (tid / 3) * 3;
        const float* aa = stage + m * 132;
        float s = __ldg(ppb2 + n);
        #pragma unroll 16
        for (int k = 0; k < 128; k++) s += aa[k] * __ldg(ppW2 + k * 3 + n);
        out[(size_t)(m0 + m) * 3 + n] = s;
    }
}

// ---------------- launch ----------------
extern "C" void kernel_launch(void* const* d_in, const int* in_sizes, int n_in,
                              void* d_out, int out_size)
{
    const float* x    = (const float*)d_in[0];
    const float* Rr   = (const float*)d_in[1];
    const float* Rs   = (const float*)d_in[2];
    const float* neW0 = (const float*)d_in[4];  const float* neb0 = (const float*)d_in[5];
    const float* neW1 = (const float*)d_in[6];  const float* neb1 = (const float*)d_in[7];
    const float* neW2 = (const float*)d_in[8];  const float* neb2 = (const float*)d_in[9];
    const float* eeW0 = (const float*)d_in[10]; const float* eeb0 = (const float*)d_in[11];
    const float* eeW1 = (const float*)d_in[12]; const float* eeb1 = (const float*)d_in[13];
    const float* eeW2 = (const float*)d_in[14]; const float* eeb2 = (const float*)d_in[15];
    const float* npW  = (const float*)d_in[16]; const float* npb  = (const float*)d_in[17];
    const float* epW  = (const float*)d_in[18]; const float* epb  = (const float*)d_in[19];
    const float* ppW0 = (const float*)d_in[20]; const float* ppb0 = (const float*)d_in[21];
    const float* ppW1 = (const float*)d_in[22]; const float* ppb1 = (const float*)d_in[23];
    const float* ppW2 = (const float*)d_in[24]; const float* ppb2 = (const float*)d_in[25];
    float* out = (float*)d_out;

    uint32_t* arena; cudaGetSymbolAddress((void**)&arena, g_arena);
    int* recv; cudaGetSymbolAddress((void**)&recv, g_recv);
    int* send; cudaGetSymbolAddress((void**)&send, g_send);
    __nv_bfloat16* whi; cudaGetSymbolAddress((void**)&whi, g_whi);
    __nv_bfloat16* wlo; cudaGetSymbolAddress((void**)&wlo, g_wlo);

    uint32_t* neb    = arena + OFF_NEB;
    float*    nef    = (float*)(arena + OFF_NEF);
    float*    nf1f   = (float*)(arena + OFF_NF1F);
    float*    pc     = (float*)(arena + OFF_PC);
    float*    agg0   = (float*)(arena + OFF_AGG0);
    float*    agg1   = (float*)(arena + OFF_AGG1);
    float*    prs    = (float*)(arena + OFF_PRS);
    float*    prpspA = (float*)(arena + OFF_PRPSPA);
    float*    prpspB = (float*)(arena + OFF_PRPSPB);
    float*    ec     = (float*)(arena + OFF_EC);

    const int WO[12] = {0,8192,24576,40960,57344,73728,90112,106496,139264,172032,188416,204800};

    static bool s_init = false;
    static cudaStream_t s1, s2;
    static cudaEvent_t evStart, evPrep, evS1, evNE;
    if (!s_init) {
        cudaStreamCreateWithFlags(&s1, cudaStreamNonBlocking);
        cudaStreamCreateWithFlags(&s2, cudaStreamNonBlocking);
        cudaEventCreateWithFlags(&evStart, cudaEventDisableTiming);
        cudaEventCreateWithFlags(&evPrep,  cudaEventDisableTiming);
        cudaEventCreateWithFlags(&evS1,    cudaEventDisableTiming);
        cudaEventCreateWithFlags(&evNE,    cudaEventDisableTiming);
        cudaFuncSetAttribute(node_mega,       cudaFuncAttributeMaxDynamicSharedMemorySize, NM_SMEM);
        cudaFuncSetAttribute(edge_mega,       cudaFuncAttributeMaxDynamicSharedMemorySize, EM_SMEM);
        cudaFuncSetAttribute(np_prpsp_kernel, cudaFuncAttributeMaxDynamicSharedMemorySize, NT_SMEM);
        cudaFuncSetAttribute(tail_kernel,     cudaFuncAttributeMaxDynamicSharedMemorySize, NT_SMEM);
        s_init = true;
    }

    // fork at root: extract + agg zeros on s1
    cudaEventRecord(evStart, 0);
    cudaStreamWaitEvent(s1, evStart, 0);
    extract_idx2_kernel<<<2 * BE / 8, 256, 0, s1>>>(Rr, Rs, recv, send);
    cudaMemsetAsync(agg0, 0, (size_t)2 * BN * 128 * sizeof(float), s1);  // agg0 + agg1 (adjacent)
    cudaEventRecord(evS1, s1);

    // origin: weight prep
    PArg pa;
    pa.W[0] = neW0; pa.W[1] = neW1; pa.W[2] = neW2;
    pa.W[3] = eeW0; pa.W[4] = eeW1; pa.W[5] = eeW2;
    pa.W[6] = epW;  pa.W[7] = epW;  pa.W[8] = npW;
    pa.W[9] = ppW0; pa.W[10] = ppW0; pa.W[11] = ppW1;
    prep_weights<<<dim3(12, 8), 256>>>(pa, whi, wlo);
    cudaEventRecord(evPrep, 0);
    cudaStreamWaitEvent(s2, evPrep, 0);

    // s2: fused node mega-chain (PrPs + encoder + projections + pc)
    {
        NodeArg na;
        na.x = x;
        na.eerh = whi + WO[3];        na.eerl = wlo + WO[3];
        na.eesh = whi + WO[3] + 8192; na.eesl = wlo + WO[3] + 8192;
        na.w0h = whi + WO[0]; na.w0l = wlo + WO[0];
        na.w1h = whi + WO[1]; na.w1l = wlo + WO[1];
        na.w2h = whi + WO[2]; na.w2l = wlo + WO[2];
        na.eprh = whi + WO[7];          na.eprl = wlo + WO[7];
        na.epsh = whi + WO[7] + 16384;  na.epsl = wlo + WO[7] + 16384;
        na.pqh = whi + WO[9];  na.pql = wlo + WO[9];
        na.b0 = neb0; na.b1 = neb1; na.b2 = neb2;
        na.neb = neb; na.nef = nef; na.prs = prs; na.prpsp = prpspA; na.pc = pc;
        node_mega<<<BN / 32, 256, NM_SMEM, s2>>>(na);
    }
    cudaEventRecord(evNE, s2);

    // join: indices + node outputs
    cudaStreamWaitEvent(0, evS1, 0);
    cudaStreamWaitEvent(0, evNE, 0);

    // fused edge chain + step-0 scatter
    {
        EdgeArg ea;
        ea.prs = prs; ea.recv = recv; ea.send = send; ea.eeb0 = eeb0;
        ea.w1h = whi + WO[4]; ea.w1l = wlo + WO[4];
        ea.w2h = whi + WO[5]; ea.w2l = wlo + WO[5];
        ea.weh = whi + WO[6]; ea.wel = wlo + WO[6];
        ea.b1 = eeb1; ea.b2 = eeb2;
        ea.prpsp = prpspA; ea.epb = epb;
        ea.ec = ec; ea.agg = agg0;
        edge_mega<<<BE / 64, 512, EM_SMEM>>>(ea);
    }

    // fused np(step0) + prpsp(step1), pipelined weights
    np_prpsp_kernel<<<BN / 32, 512, NT_SMEM>>>(neb, agg0, nef,
        whi + WO[8], wlo + WO[8], npb, whi + WO[7], wlo + WO[7],
        nf1f, prpspB);

    // step-1 scatter
    fused_scatter_kernel<<<BE * 128 / 256, 256>>>(ec, prpspB, recv, send, epb, agg1);

    // fused np(step1) + predictor + output, pipelined weights
    tail_kernel<<<BN / 32, 512, NT_SMEM>>>(neb, agg1, nf1f,
        whi + WO[8], wlo + WO[8], npb, pc,
        whi + WO[10], wlo + WO[10], ppb0,
        whi + WO[11], wlo + WO[11], ppb1,
        ppW2, ppb2, out);
}

// round 13
// speedup vs baseline: 3.1652x; 1.0386x over previous
#include <cuda_runtime.h>
#include <cuda_bf16.h>
#include <cstdint>

// ---------------- problem dims ----------------
#define Nn 1024
#define Ee 8192
#define BN 4096    // B*N
#define BE 32768   // B*E

// ---------------- device scratch ----------------
#define OFF_NEB    ((size_t)0)                       // node_enc bfp
#define OFF_NEF    (OFF_NEB + (size_t)BN*128)        // node_enc f32
#define OFF_NF1F   (OFF_NEF + (size_t)BN*128)        // nf1 f32
#define OFF_PC     (OFF_NF1F + (size_t)BN*128)       // neb@pp0a f32
#define OFF_AGG0   (OFF_PC + (size_t)BN*128)
#define OFF_AGG1   (OFF_AGG0 + (size_t)BN*128)       // adjacent to agg0
#define OFF_PRS    (OFF_AGG1 + (size_t)BN*128)       // [BN,256] f32 (x@Wr | x@Ws)
#define OFF_PRPSPA (OFF_PRS + (size_t)BN*256)        // [BN,256] f32 step0
#define OFF_PRPSPB (OFF_PRPSPA + (size_t)BN*256)     // [BN,256] f32 step1
#define OFF_EC     (OFF_PRPSPB + (size_t)BN*256)     // [BE,128] f32
#define ARENA_U32  (OFF_EC + (size_t)BE*128)

__device__ uint32_t g_arena[ARENA_U32];
__device__ int g_recv[BE];
__device__ int g_send[BE];
__device__ float g_zero[256];

// split/transposed weights [n][kpad] bf16, 12 matrices
#define WT_TOTAL 221184
__device__ __nv_bfloat16 g_whi[WT_TOTAL];
__device__ __nv_bfloat16 g_wlo[WT_TOTAL];

// ---------------- helpers ----------------
__device__ __forceinline__ uint32_t smem_u32(const void* p) {
    uint32_t a;
    asm("{ .reg .u64 t; cvta.to.shared.u64 t, %1; cvt.u32.u64 %0, t; }" : "=r"(a) : "l"(p));
    return a;
}

#define LDMX4(r, ad) \
    asm volatile("ldmatrix.sync.aligned.m8n8.x4.shared.b16 {%0,%1,%2,%3}, [%4];" \
        : "=r"((r)[0]), "=r"((r)[1]), "=r"((r)[2]), "=r"((r)[3]) : "r"(ad))

#define MMA16816(d, av, bv) \
    asm volatile("mma.sync.aligned.m16n8k16.row.col.f32.bf16.bf16.f32 " \
        "{%0,%1,%2,%3},{%4,%5,%6,%7},{%8,%9},{%0,%1,%2,%3};" \
        : "+f"((d)[0]), "+f"((d)[1]), "+f"((d)[2]), "+f"((d)[3]) \
        : "r"((av)[0]), "r"((av)[1]), "r"((av)[2]), "r"((av)[3]), \
          "r"((bv)[0]), "r"((bv)[1]))

#define CP_ASYNC16(sa, gp) \
    asm volatile("cp.async.cg.shared.global [%0], [%1], 16;" :: "r"(sa), "l"(gp))
#define CP_COMMIT()  asm volatile("cp.async.commit_group;" ::: "memory")
#define CP_WAIT1()   asm volatile("cp.async.wait_group 1;" ::: "memory")
#define CP_WAIT0()   asm volatile("cp.async.wait_group 0;" ::: "memory")

__device__ __forceinline__ uint32_t packbfp(float v) {
    __nv_bfloat16 h = __float2bfloat16(v);
    float hf = __bfloat162float(h);
    __nv_bfloat16 l = __float2bfloat16(v - hf);
    return (uint32_t)__bfloat16_as_ushort(h) | ((uint32_t)__bfloat16_as_ushort(l) << 16);
}

// ---- 32-col-warp 3-pass MMA ----
__device__ __forceinline__ void mma_span1(
    uint32_t aHi, uint32_t aLo, uint32_t bHi, uint32_t bLo,
    int astr, int bstr, int nk, float (*acc)[4], int tile, int wn, int lane)
{
    for (int ks = 0; ks < nk; ks++) {
        uint32_t bh[8], bl[8];
        #pragma unroll
        for (int np = 0; np < 2; np++) {
            int n = wn * 32 + np * 16 + ((lane >> 4) << 3) + (lane & 7);
            int koff = ((lane >> 3) & 1) << 3;
            uint32_t ad = bHi + n * bstr + (ks * 16 + koff) * 2;
            LDMX4(&bh[np * 4], ad);
            LDMX4(&bl[np * 4], ad + (bLo - bHi));
        }
        int r = tile * 16 + (lane & 15);
        int koff = (lane >> 4) << 3;
        uint32_t ad = aHi + r * astr + (ks * 16 + koff) * 2;
        uint32_t ah[4], al[4];
        LDMX4(ah, ad);
        LDMX4(al, ad + (aLo - aHi));
        #pragma unroll
        for (int st = 0; st < 4; st++) {
            MMA16816(acc[st], ah, &bh[st * 2]);
            MMA16816(acc[st], ah, &bl[st * 2]);
            MMA16816(acc[st], al, &bh[st * 2]);
        }
    }
}

// ---- 32-col-warp, 2 m-tiles per warp (edge_mega): A loaded once per mt, B shared ----
__device__ __forceinline__ void mma_span_mt2(
    uint32_t aHi, uint32_t aLo, uint32_t bHi, uint32_t bLo,
    int astr, int bstr, int nk, float (*acc0)[4], float (*acc1)[4],
    int tile0, int wn, int lane)
{
    for (int ks = 0; ks < nk; ks++) {
        uint32_t bh[8], bl[8];
        #pragma unroll
        for (int np = 0; np < 2; np++) {
            int n = wn * 32 + np * 16 + ((lane >> 4) << 3) + (lane & 7);
            int koff = ((lane >> 3) & 1) << 3;
            uint32_t ad = bHi + n * bstr + (ks * 16 + koff) * 2;
            LDMX4(&bh[np * 4], ad);
            LDMX4(&bl[np * 4], ad + (bLo - bHi));
        }
        int koff = (lane >> 4) << 3;
        uint32_t ah0[4], al0[4], ah1[4], al1[4];
        {
            int r = tile0 * 16 + (lane & 15);
            uint32_t ad = aHi + r * astr + (ks * 16 + koff) * 2;
            LDMX4(ah0, ad);
            LDMX4(al0, ad + (aLo - aHi));
        }
        {
            int r = (tile0 + 1) * 16 + (lane & 15);
            uint32_t ad = aHi + r * astr + (ks * 16 + koff) * 2;
            LDMX4(ah1, ad);
            LDMX4(al1, ad + (aLo - aHi));
        }
        #pragma unroll
        for (int st = 0; st < 4; st++) {
            MMA16816(acc0[st], ah0, &bh[st * 2]);
            MMA16816(acc1[st], ah1, &bh[st * 2]);
            MMA16816(acc0[st], ah0, &bl[st * 2]);
            MMA16816(acc1[st], ah1, &bl[st * 2]);
            MMA16816(acc0[st], al0, &bh[st * 2]);
            MMA16816(acc1[st], al1, &bh[st * 2]);
        }
    }
}

// ---- 16-col-warp 3-pass MMA (np/tail kernels): wn in 0..7 ----
__device__ __forceinline__ void mma_span16(
    uint32_t aHi, uint32_t aLo, uint32_t bHi, uint32_t bLo,
    int astr, int bstr, int nk, float (*acc)[4], int tile, int wn, int lane)
{
    for (int ks = 0; ks < nk; ks++) {
        uint32_t bh[4], bl[4];
        int n = wn * 16 + ((lane >> 4) << 3) + (lane & 7);
        int koff = ((lane >> 3) & 1) << 3;
        uint32_t ad = bHi + n * bstr + (ks * 16 + koff) * 2;
        LDMX4(bh, ad);
        LDMX4(bl, ad + (bLo - bHi));
        int r = tile * 16 + (lane & 15);
        int koff2 = (lane >> 4) << 3;
        uint32_t ad2 = aHi + r * astr + (ks * 16 + koff2) * 2;
        uint32_t ah[4], al[4];
        LDMX4(ah, ad2);
        LDMX4(al, ad2 + (aLo - aHi));
        #pragma unroll
        for (int st = 0; st < 2; st++) {
            MMA16816(acc[st], ah, &bh[st * 2]);
            MMA16816(acc[st], ah, &bl[st * 2]);
            MMA16816(acc[st], al, &bh[st * 2]);
        }
    }
}

// async weight load with K-window (cp.async, caller commits/waits)
__device__ __forceinline__ void load_Bw_cp(uint32_t sbase, int plane,
    const __nv_bfloat16* Bhi, const __nv_bfloat16* Blo,
    int nrows, int kwin, int fullK, int k0, int bstr, int tid, int nth)
{
    int kg = kwin >> 3;
    int per = nrows * kg;
    for (int item = tid; item < per; item += nth) {
        int n = item / kg, g = item - n * kg;
        size_t goff = (size_t)n * fullK + k0 + (g << 3);
        uint32_t so = sbase + n * bstr + (g << 4);
        CP_ASYNC16(so, Bhi + goff);
        CP_ASYNC16(so + plane, Blo + goff);
    }
}

// 32-col-warp epilogue: relu(acc+bias(+resid)) -> repack A planes (+outf/outb)
__device__ __forceinline__ void epi_repack2(char* smem, int astr, int aplane,
    float (*acc)[4], int m0, int tile,
    const float* bias, const float* resid, float* outf, uint32_t* outb,
    int wn, int lane)
{
    #pragma unroll
    for (int st = 0; st < 4; st++) {
        int n = wn * 32 + st * 8 + ((lane & 3) << 1);
        float b0 = __ldg(bias + n), b1 = __ldg(bias + n + 1);
        int r0 = tile * 16 + (lane >> 2);
        #pragma unroll
        for (int h = 0; h < 2; h++) {
            int r = r0 + h * 8;
            float s0 = acc[st][h * 2 + 0] + b0;
            float s1 = acc[st][h * 2 + 1] + b1;
            if (resid) {
                float2 rv = *(const float2*)(resid + (((size_t)(m0 + r)) << 7) + n);
                s0 += rv.x; s1 += rv.y;
            }
            s0 = fmaxf(s0, 0.f); s1 = fmaxf(s1, 0.f);
            if (outf) *(float2*)(outf + (((size_t)(m0 + r)) << 7) + n) = make_float2(s0, s1);
            uint32_t p0 = packbfp(s0), p1 = packbfp(s1);
            if (outb) *(uint2*)(outb + (((size_t)(m0 + r)) << 7) + n) = make_uint2(p0, p1);
            int off = r * astr + n * 2;
            *(uint32_t*)(smem + off) = (p0 & 0xffffu) | (p1 << 16);
            *(uint32_t*)(smem + aplane + off) = (p0 >> 16) | (p1 & 0xffff0000u);
            acc[st][h * 2 + 0] = 0.f;
            acc[st][h * 2 + 1] = 0.f;
        }
    }
}

// 16-col-warp epilogue
__device__ __forceinline__ void epi_repack16(char* smem, int astr, int aplane,
    float (*acc)[4], int m0, int tile,
    const float* bias, const float* resid, float* outf,
    int wn, int lane)
{
    #pragma unroll
    for (int st = 0; st < 2; st++) {
        int n = wn * 16 + st * 8 + ((lane & 3) << 1);
        float b0 = __ldg(bias + n), b1 = __ldg(bias + n + 1);
        int r0 = tile * 16 + (lane >> 2);
        #pragma unroll
        for (int h = 0; h < 2; h++) {
            int r = r0 + h * 8;
            float s0 = acc[st][h * 2 + 0] + b0;
            float s1 = acc[st][h * 2 + 1] + b1;
            if (resid) {
                float2 rv = *(const float2*)(resid + (((size_t)(m0 + r)) << 7) + n);
                s0 += rv.x; s1 += rv.y;
            }
            s0 = fmaxf(s0, 0.f); s1 = fmaxf(s1, 0.f);
            if (outf) *(float2*)(outf + (((size_t)(m0 + r)) << 7) + n) = make_float2(s0, s1);
            uint32_t p0 = packbfp(s0), p1 = packbfp(s1);
            int off = r * astr + n * 2;
            *(uint32_t*)(smem + off) = (p0 & 0xffffu) | (p1 << 16);
            *(uint32_t*)(smem + aplane + off) = (p0 >> 16) | (p1 & 0xffff0000u);
            acc[st][h * 2 + 0] = 0.f;
            acc[st][h * 2 + 1] = 0.f;
        }
    }
}

// write acc f32 (32-col warps)
__device__ __forceinline__ void write_accf(float (*acc)[4], int m0, int tile,
    int wn, int lane, float* out, int nbase, int ldo)
{
    #pragma unroll
    for (int st = 0; st < 4; st++) {
        int n = nbase + wn * 32 + st * 8 + ((lane & 3) << 1);
        int r0 = tile * 16 + (lane >> 2);
        #pragma unroll
        for (int h = 0; h < 2; h++) {
            int m = m0 + r0 + h * 8;
            *(float2*)(out + (size_t)m * ldo + n) =
                make_float2(acc[st][h * 2 + 0], acc[st][h * 2 + 1]);
            acc[st][h * 2 + 0] = 0.f;
            acc[st][h * 2 + 1] = 0.f;
        }
    }
}

// write acc f32 (16-col warps)
__device__ __forceinline__ void write_accf16(float (*acc)[4], int m0, int tile,
    int wn, int lane, float* out, int nbase, int ldo)
{
    #pragma unroll
    for (int st = 0; st < 2; st++) {
        int n = nbase + wn * 16 + st * 8 + ((lane & 3) << 1);
        int r0 = tile * 16 + (lane >> 2);
        #pragma unroll
        for (int h = 0; h < 2; h++) {
            int m = m0 + r0 + h * 8;
            *(float2*)(out + (size_t)m * ldo + n) =
                make_float2(acc[st][h * 2 + 0], acc[st][h * 2 + 1]);
            acc[st][h * 2 + 0] = 0.f;
            acc[st][h * 2 + 1] = 0.f;
        }
    }
}

// ---------------- aux kernels ----------------
__global__ void extract_idx2_kernel(const float* __restrict__ Rr,
                                    const float* __restrict__ Rs,
                                    int* __restrict__ recv, int* __restrict__ send)
{
    int row = blockIdx.x * 8 + (threadIdx.x >> 5);
    int lane = threadIdx.x & 31;
    const float* R = (row < BE) ? Rr : Rs;
    int r = (row < BE) ? row : row - BE;
    const float4* p = (const float4*)(R + (size_t)r * Nn);
    int found = -1;
    #pragma unroll
    for (int i = 0; i < 4; i++) {
        int q = lane + i * 32;
        float4 v = p[q];
        if (v.x > 0.5f) found = q * 4 + 0;
        if (v.y > 0.5f) found = q * 4 + 1;
        if (v.z > 0.5f) found = q * 4 + 2;
        if (v.w > 0.5f) found = q * 4 + 3;
    }
    if (__ballot_sync(0xFFFFFFFFu, found >= 0) == 0u) {
        #pragma unroll
        for (int i = 4; i < 8; i++) {
            int q = lane + i * 32;
            float4 v = p[q];
            if (v.x > 0.5f) found = q * 4 + 0;
            if (v.y > 0.5f) found = q * 4 + 1;
            if (v.z > 0.5f) found = q * 4 + 2;
            if (v.w > 0.5f) found = q * 4 + 3;
        }
    }
    #pragma unroll
    for (int o = 16; o; o >>= 1) found = max(found, __shfl_xor_sync(0xFFFFFFFFu, found, o));
    if (lane == 0) {
        found = max(found, 0);
        if (row < BE) recv[r] = found; else send[r] = found;
    }
}

// matrices: 0 ne0 1 ne1 2 ne2 3 eers(R256) 4 ee1 5 ee2 6 ep_e 7 ep_rs(R256)
//           8 np(K256) 9 pp0a 10 pp0b 11 pp1
struct PArg { const float* W[12]; };
__constant__ int c_Ks[12]  = {32,128,128, 32,128,128,128,128,256,128,128,128};
__constant__ int c_Kps[12] = {64,128,128, 64,128,128,128,128,256,128,128,128};
__constant__ int c_Rs[12]  = {128,128,128,256,128,128,128,256,128,128,128,128};
__constant__ int c_r0a[12] = {0,0,0,0,0,0,0,128,0,0,128,0};
__constant__ int c_r0b[12] = {0,0,0,32,0,0,0,256,0,0,0,0};
__constant__ int c_off[12] = {0,8192,24576,40960,57344,73728,90112,106496,139264,172032,188416,204800};

__global__ void prep_weights(PArg a, __nv_bfloat16* __restrict__ hi, __nv_bfloat16* __restrict__ lo)
{
    int mid = blockIdx.x;
    int K = c_Ks[mid], Kp = c_Kps[mid], R = c_Rs[mid];
    int r0a = c_r0a[mid], r0b = c_r0b[mid];
    const float* W = a.W[mid];
    __nv_bfloat16* dh = hi + c_off[mid];
    __nv_bfloat16* dl = lo + c_off[mid];
    int total = R * Kp;
    for (int i = threadIdx.x + blockIdx.y * blockDim.x; i < total; i += blockDim.x * gridDim.y) {
        int n = i / Kp, k = i - n * Kp;
        int col = n & 127;
        int r0 = (n >> 7) ? r0b : r0a;
        float v = (k < K) ? W[(size_t)(r0 + k) * 128 + col] : 0.f;
        __nv_bfloat16 h = __float2bfloat16(v);
        dh[i] = h;
        dl[i] = __float2bfloat16(v - __bfloat162float(h));
    }
}

// step-1 scatter
__global__ void fused_scatter_kernel(const float* __restrict__ ec,
                                     const float* __restrict__ prpsp,
                                     const int* __restrict__ recv,
                                     const int* __restrict__ send,
                                     const float* __restrict__ bias,
                                     float* __restrict__ agg)
{
    int t = blockIdx.x * blockDim.x + threadIdx.x;
    if (t >= BE * 128) return;
    int e = t >> 7, h = t & 127;
    int bo = (e >> 13) << 10;
    int r = __ldg(recv + e) + bo, s = __ldg(send + e) + bo;
    float v = ec[t] + prpsp[(size_t)r * 256 + h] + prpsp[(size_t)s * 256 + 128 + h] + __ldg(bias + h);
    v = fmaxf(v, 0.f);
    atomicAdd(&agg[(size_t)r * 128 + h], v);
}

// ---------------- node_mega: eer,ees,ne0..ne2,epr,eps,pc (256 thr, ping-pong) ----------------
#define NM_STR   272
#define NM_ALO   (32 * NM_STR)
#define NM_B0    (2 * NM_ALO)
#define NM_BPL   (128 * NM_STR)
#define NM_SLOT  (2 * NM_BPL)
#define NM_SMEM  (NM_B0 + 2 * NM_SLOT)     // 156672

struct NodeArg {
    const float* x;
    const __nv_bfloat16 *eerh,*eerl,*eesh,*eesl;
    const __nv_bfloat16 *w0h,*w0l,*w1h,*w1l,*w2h,*w2l,*eprh,*eprl,*epsh,*epsl,*pqh,*pql;
    const float *b0,*b1,*b2;
    uint32_t* neb; float* nef; float* prs; float* prpsp; float* pc;
};

__global__ __launch_bounds__(256) void node_mega(NodeArg a)
{
    extern __shared__ char smem[];
    const uint32_t sb = smem_u32(smem);
    const int tid = threadIdx.x;
    const int wid = tid >> 5, lane = tid & 31;
    const int wm = wid & 1, wn = wid >> 1;
    const int m0 = blockIdx.x * 32;

    const uint32_t sA = sb + NM_B0;
    const uint32_t sB = sb + NM_B0 + NM_SLOT;

    float acc[4][4];
    #pragma unroll
    for (int st = 0; st < 4; st++)
        #pragma unroll
        for (int r = 0; r < 4; r++) acc[st][r] = 0.f;

    load_Bw_cp(sA, NM_BPL, a.eerh, a.eerl, 128, 64, 64, 0, NM_STR, tid, 256); CP_COMMIT();
    load_Bw_cp(sB, NM_BPL, a.eesh, a.eesl, 128, 64, 64, 0, NM_STR, tid, 256); CP_COMMIT();

    #pragma unroll
    for (int it = 0; it < 2; it++) {
        int item = tid + (it << 8);
        int r = item >> 4, g = item & 15;
        int kc = g << 2;
        uint32_t p0 = 0, p1 = 0, p2 = 0, p3 = 0;
        if (kc < 32) {
            float4 v = *(const float4*)(a.x + (size_t)(m0 + r) * 32 + kc);
            p0 = packbfp(v.x); p1 = packbfp(v.y); p2 = packbfp(v.z); p3 = packbfp(v.w);
        }
        uint32_t hi01 = (p0 & 0xffffu) | (p1 << 16);
        uint32_t hi23 = (p2 & 0xffffu) | (p3 << 16);
        uint32_t lo01 = (p0 >> 16) | (p1 & 0xffff0000u);
        uint32_t lo23 = (p2 >> 16) | (p3 & 0xffff0000u);
        int off = r * NM_STR + g * 8;
        *(uint2*)(smem + off) = make_uint2(hi01, hi23);
        *(uint2*)(smem + NM_ALO + off) = make_uint2(lo01, lo23);
    }

    // P0: eer -> prs[:,0:128]
    CP_WAIT1(); __syncthreads();
    mma_span1(sb, sb + NM_ALO, sA, sA + NM_BPL, NM_STR, NM_STR, 4, acc, wm, wn, lane);
    __syncthreads();
    write_accf(acc, m0, wm, wn, lane, a.prs, 0, 256);
    load_Bw_cp(sA, NM_BPL, a.w0h, a.w0l, 128, 64, 64, 0, NM_STR, tid, 256); CP_COMMIT();

    // P1: ees -> prs[:,128:256]
    CP_WAIT1(); __syncthreads();
    mma_span1(sb, sb + NM_ALO, sB, sB + NM_BPL, NM_STR, NM_STR, 4, acc, wm, wn, lane);
    __syncthreads();
    write_accf(acc, m0, wm, wn, lane, a.prs, 128, 256);
    load_Bw_cp(sB, NM_BPL, a.w1h, a.w1l, 128, 128, 128, 0, NM_STR, tid, 256); CP_COMMIT();

    // P2: ne0
    CP_WAIT1(); __syncthreads();
    mma_span1(sb, sb + NM_ALO, sA, sA + NM_BPL, NM_STR, NM_STR, 4, acc, wm, wn, lane);
    __syncthreads();
    epi_repack2(smem, NM_STR, NM_ALO, acc, m0, wm, a.b0, nullptr, nullptr, nullptr, wn, lane);
    load_Bw_cp(sA, NM_BPL, a.w2h, a.w2l, 128, 128, 128, 0, NM_STR, tid, 256); CP_COMMIT();

    // P3: ne1
    CP_WAIT1(); __syncthreads();
    mma_span1(sb, sb + NM_ALO, sB, sB + NM_BPL, NM_STR, NM_STR, 8, acc, wm, wn, lane);
    __syncthreads();
    epi_repack2(smem, NM_STR, NM_ALO, acc, m0, wm, a.b1, nullptr, nullptr, nullptr, wn, lane);
    load_Bw_cp(sB, NM_BPL, a.eprh, a.eprl, 128, 128, 128, 0, NM_STR, tid, 256); CP_COMMIT();

    // P4: ne2 -> neb/nef
    CP_WAIT1(); __syncthreads();
    mma_span1(sb, sb + NM_ALO, sA, sA + NM_BPL, NM_STR, NM_STR, 8, acc, wm, wn, lane);
    __syncthreads();
    epi_repack2(smem, NM_STR, NM_ALO, acc, m0, wm, a.b2, nullptr, a.nef, a.neb, wn, lane);
    load_Bw_cp(sA, NM_BPL, a.epsh, a.epsl, 128, 128, 128, 0, NM_STR, tid, 256); CP_COMMIT();

    // P5: epr -> prpspA[:,0:128]
    CP_WAIT1(); __syncthreads();
    mma_span1(sb, sb + NM_ALO, sB, sB + NM_BPL, NM_STR, NM_STR, 8, acc, wm, wn, lane);
    __syncthreads();
    write_accf(acc, m0, wm, wn, lane, a.prpsp, 0, 256);
    load_Bw_cp(sB, NM_BPL, a.pqh, a.pql, 128, 128, 128, 0, NM_STR, tid, 256); CP_COMMIT();

    // P6: eps -> prpspA[:,128:256]
    CP_WAIT1(); __syncthreads();
    mma_span1(sb, sb + NM_ALO, sA, sA + NM_BPL, NM_STR, NM_STR, 8, acc, wm, wn, lane);
    __syncthreads();
    write_accf(acc, m0, wm, wn, lane, a.prpsp, 128, 256);

    // P7: pc
    CP_WAIT0(); __syncthreads();
    mma_span1(sb, sb + NM_ALO, sB, sB + NM_BPL, NM_STR, NM_STR, 8, acc, wm, wn, lane);
    __syncthreads();
    write_accf(acc, m0, wm, wn, lane, a.pc, 0, 128);
}

// ---------------- edge_mega: 128-row tiles, 512 thr, 4m x 4n warps (mt=2,st=4) ----------------
#define EM_STR   272
#define EM_APL   (128 * EM_STR)            // 34816 (A plane)
#define EM_B0    (2 * EM_APL)              // 69632
#define EM_BPL   (128 * EM_STR)            // 34816
#define EM_SLOT  (2 * EM_BPL)              // 69632
#define EM_SMEM  (EM_B0 + 2 * EM_SLOT)     // 208896

struct EdgeArg {
    const float* prs; const int* recv; const int* send; const float* eeb0;
    const __nv_bfloat16 *w1h,*w1l,*w2h,*w2l,*weh,*wel;
    const float *b1,*b2;
    const float* prpsp; const float* epb;
    float* ec; float* agg;
};

__global__ __launch_bounds__(512, 1) void edge_mega(EdgeArg a)
{
    extern __shared__ char smem[];
    const uint32_t sb = smem_u32(smem);
    const int tid = threadIdx.x;
    const int wid = tid >> 5, lane = tid & 31;
    const int wm = wid & 3, wn = wid >> 2;      // 4m x 4n warp grid, 32 rows x 32 cols per warp
    const int m0 = blockIdx.x * 128;

    const uint32_t sA = sb + EM_B0;
    const uint32_t sB = sb + EM_B0 + EM_SLOT;

    float acc[2][4][4];
    #pragma unroll
    for (int mt = 0; mt < 2; mt++)
        #pragma unroll
        for (int st = 0; st < 4; st++)
            #pragma unroll
            for (int r = 0; r < 4; r++) acc[mt][st][r] = 0.f;

    load_Bw_cp(sA, EM_BPL, a.w1h, a.w1l, 128, 128, 128, 0, EM_STR, tid, 512); CP_COMMIT();
    load_Bw_cp(sB, EM_BPL, a.w2h, a.w2l, 128, 128, 128, 0, EM_STR, tid, 512); CP_COMMIT();

    // A <- edge layer0 on the fly: relu(Pr[recv]+Ps[send]+b0), 128 rows x 128 cols
    #pragma unroll
    for (int it = 0; it < 8; it++) {
        int item = tid + (it << 9);
        int r = item >> 5, g = item & 31;
        int kc = g << 2;
        int m = m0 + r;
        int bo = (m >> 13) << 10;
        int rr = __ldg(a.recv + m) + bo, ss = __ldg(a.send + m) + bo;
        float4 pr = *(const float4*)(a.prs + (size_t)rr * 256 + kc);
        float4 ps = *(const float4*)(a.prs + (size_t)ss * 256 + 128 + kc);
        float4 bb = *(const float4*)(a.eeb0 + kc);
        uint32_t p0 = packbfp(fmaxf(pr.x + ps.x + bb.x, 0.f));
        uint32_t p1 = packbfp(fmaxf(pr.y + ps.y + bb.y, 0.f));
        uint32_t p2 = packbfp(fmaxf(pr.z + ps.z + bb.z, 0.f));
        uint32_t p3 = packbfp(fmaxf(pr.w + ps.w + bb.w, 0.f));
        uint32_t hi01 = (p0 & 0xffffu) | (p1 << 16);
        uint32_t hi23 = (p2 & 0xffffu) | (p3 << 16);
        uint32_t lo01 = (p0 >> 16) | (p1 & 0xffff0000u);
        uint32_t lo23 = (p2 >> 16) | (p3 & 0xffff0000u);
        int off = r * EM_STR + g * 8;
        *(uint2*)(smem + off) = make_uint2(hi01, hi23);
        *(uint2*)(smem + EM_APL + off) = make_uint2(lo01, lo23);
    }

    // phase 1: ee1 (sA)
    CP_WAIT1(); __syncthreads();
    mma_span_mt2(sb, sb + EM_APL, sA, sA + EM_BPL, EM_STR, EM_STR, 8,
                 acc[0], acc[1], wm * 2, wn, lane);
    __syncthreads();
    #pragma unroll
    for (int mt = 0; mt < 2; mt++)
        epi_repack2(smem, EM_STR, EM_APL, acc[mt], m0, wm * 2 + mt, a.b1,
                    nullptr, nullptr, nullptr, wn, lane);
    load_Bw_cp(sA, EM_BPL, a.weh, a.wel, 128, 128, 128, 0, EM_STR, tid, 512); CP_COMMIT();

    // phase 2: ee2 (sB)
    CP_WAIT1(); __syncthreads();
    mma_span_mt2(sb, sb + EM_APL, sB, sB + EM_BPL, EM_STR, EM_STR, 8,
                 acc[0], acc[1], wm * 2, wn, lane);
    __syncthreads();
    #pragma unroll
    for (int mt = 0; mt < 2; mt++)
        epi_repack2(smem, EM_STR, EM_APL, acc[mt], m0, wm * 2 + mt, a.b2,
                    nullptr, nullptr, nullptr, wn, lane);

    // phase 3: ec (sA)
    CP_WAIT0(); __syncthreads();
    mma_span_mt2(sb, sb + EM_APL, sA, sA + EM_BPL, EM_STR, EM_STR, 8,
                 acc[0], acc[1], wm * 2, wn, lane);

    // epilogue: write ec + fused step-0 scatter
    #pragma unroll
    for (int mt = 0; mt < 2; mt++) {
        int row0 = m0 + (wm * 2 + mt) * 16 + (lane >> 2);
        #pragma unroll
        for (int st = 0; st < 4; st++) {
            int n = wn * 32 + st * 8 + ((lane & 3) << 1);
            float e0b = __ldg(a.epb + n), e1b = __ldg(a.epb + n + 1);
            #pragma unroll
            for (int h = 0; h < 2; h++) {
                int m = row0 + h * 8;
                float e0 = acc[mt][st][h * 2 + 0];
                float e1 = acc[mt][st][h * 2 + 1];
                *(float2*)(a.ec + ((size_t)m << 7) + n) = make_float2(e0, e1);
                int bo = (m >> 13) << 10;
                int r_ = __ldg(a.recv + m) + bo, s_ = __ldg(a.send + m) + bo;
                float2 pr = *(const float2*)(a.prpsp + (size_t)r_ * 256 + n);
                float2 ps = *(const float2*)(a.prpsp + (size_t)s_ * 256 + 128 + n);
                float v0 = fmaxf(e0 + pr.x + ps.x + e0b, 0.f);
                float v1 = fmaxf(e1 + pr.y + ps.y + e1b, 0.f);
                atomicAdd(&a.agg[(size_t)r_ * 128 + n], v0);
                atomicAdd(&a.agg[(size_t)r_ * 128 + n + 1], v1);
            }
        }
    }
}

// ---------------- np_prpsp / tail (512 threads, ping-pong, K-chunked np) ----------------
#define NSTR   528
#define N_ALO  (32 * NSTR)                 // 16896
#define N_B0   (2 * N_ALO)                 // 33792
#define N_BPL  (128 * 272)                 // 34816
#define N_SLOT (2 * N_BPL)                 // 69632
#define NT_SMEM (N_B0 + 2 * N_SLOT)        // 173056

__device__ __forceinline__ void load_A_npagg(char* smem, int m0,
    const uint32_t* neb, const float* agg, int tid)
{
    #pragma unroll
    for (int it = 0; it < 4; it++) {
        int item = tid + (it << 9);
        int r = item >> 6, g = item & 63;
        int kc = g << 2;
        int m = m0 + r;
        uint32_t p0, p1, p2, p3;
        if (kc < 128) {
            uint4 v = *(const uint4*)(neb + ((size_t)m << 7) + kc);
            p0 = v.x; p1 = v.y; p2 = v.z; p3 = v.w;
        } else {
            float4 v = *(const float4*)(agg + ((size_t)m << 7) + (kc - 128));
            p0 = packbfp(v.x); p1 = packbfp(v.y); p2 = packbfp(v.z); p3 = packbfp(v.w);
        }
        uint32_t hi01 = (p0 & 0xffffu) | (p1 << 16);
        uint32_t hi23 = (p2 & 0xffffu) | (p3 << 16);
        uint32_t lo01 = (p0 >> 16) | (p1 & 0xffff0000u);
        uint32_t lo23 = (p2 >> 16) | (p3 & 0xffff0000u);
        int off = r * NSTR + g * 8;
        *(uint2*)(smem + off) = make_uint2(hi01, hi23);
        *(uint2*)(smem + N_ALO + off) = make_uint2(lo01, lo23);
    }
}

__global__ __launch_bounds__(512, 1) void np_prpsp_kernel(
    const uint32_t* __restrict__ neb, const float* __restrict__ agg,
    const float* __restrict__ resid,
    const __nv_bfloat16* __restrict__ npHi, const __nv_bfloat16* __restrict__ npLo,
    const float* __restrict__ npb,
    const __nv_bfloat16* __restrict__ epHi, const __nv_bfloat16* __restrict__ epLo,
    float* __restrict__ nf_out, float* __restrict__ prpsp_out)
{
    extern __shared__ char smem[];
    const uint32_t sb = smem_u32(smem);
    const int tid = threadIdx.x;
    const int wid = tid >> 5, lane = tid & 31;
    const int wm = wid & 1, wn = wid >> 1;
    const int m0 = blockIdx.x * 32;

    const uint32_t sA = sb + N_B0;
    const uint32_t sB = sb + N_B0 + N_SLOT;

    float acc[2][4];
    #pragma unroll
    for (int st = 0; st < 2; st++)
        #pragma unroll
        for (int r = 0; r < 4; r++) acc[st][r] = 0.f;

    load_Bw_cp(sA, N_BPL, npHi, npLo, 128, 128, 256, 0,   272, tid, 512); CP_COMMIT();
    load_Bw_cp(sB, N_BPL, npHi, npLo, 128, 128, 256, 128, 272, tid, 512); CP_COMMIT();

    load_A_npagg(smem, m0, neb, agg, tid);

    CP_WAIT1(); __syncthreads();
    mma_span16(sb, sb + N_ALO, sA, sA + N_BPL, NSTR, 272, 8, acc, wm, wn, lane);
    __syncthreads();
    load_Bw_cp(sA, N_BPL, epHi, epLo, 128, 128, 128, 0, 272, tid, 512); CP_COMMIT();
    CP_WAIT1(); __syncthreads();
    mma_span16(sb + 256, sb + N_ALO + 256, sB, sB + N_BPL, NSTR, 272, 8, acc, wm, wn, lane);
    __syncthreads();
    epi_repack16(smem, NSTR, N_ALO, acc, m0, wm, npb, resid, nf_out, wn, lane);
    load_Bw_cp(sB, N_BPL, epHi + 128 * 128, epLo + 128 * 128, 128, 128, 128, 0, 272, tid, 512); CP_COMMIT();

    CP_WAIT1(); __syncthreads();
    mma_span16(sb, sb + N_ALO, sA, sA + N_BPL, NSTR, 272, 8, acc, wm, wn, lane);
    __syncthreads();
    write_accf16(acc, m0, wm, wn, lane, prpsp_out, 0, 256);

    CP_WAIT0(); __syncthreads();
    mma_span16(sb, sb + N_ALO, sB, sB + N_BPL, NSTR, 272, 8, acc, wm, wn, lane);
    __syncthreads();
    write_accf16(acc, m0, wm, wn, lane, prpsp_out, 128, 256);
}

__global__ __launch_bounds__(512, 1) void tail_kernel(
    const uint32_t* __restrict__ neb, const float* __restrict__ agg1,
    const float* __restrict__ nf1,
    const __nv_bfloat16* __restrict__ npHi, const __nv_bfloat16* __restrict__ npLo,
    const float* __restrict__ npb,
    const float* __restrict__ pc,
    const __nv_bfloat16* __restrict__ p0bHi, const __nv_bfloat16* __restrict__ p0bLo,
    const float* __restrict__ ppb0,
    const __nv_bfloat16* __restrict__ p1Hi, const __nv_bfloat16* __restrict__ p1Lo,
    const float* __restrict__ ppb1,
    const float* __restrict__ ppW2, const float* __restrict__ ppb2,
    float* __restrict__ out)
{
    extern __shared__ char smem[];
    const uint32_t sb = smem_u32(smem);
    const int tid = threadIdx.x;
    const int wid = tid >> 5, lane = tid & 31;
    const int wm = wid & 1, wn = wid >> 1;
    const int m0 = blockIdx.x * 32;

    const uint32_t sA = sb + N_B0;
    const uint32_t sB = sb + N_B0 + N_SLOT;

    float acc[2][4];
    #pragma unroll
    for (int st = 0; st < 2; st++)
        #pragma unroll
        for (int r = 0; r < 4; r++) acc[st][r] = 0.f;

    load_Bw_cp(sA, N_BPL, npHi, npLo, 128, 128, 256, 0,   272, tid, 512); CP_COMMIT();
    load_Bw_cp(sB, N_BPL, npHi, npLo, 128, 128, 256, 128, 272, tid, 512); CP_COMMIT();

    load_A_npagg(smem, m0, neb, agg1, tid);

    CP_WAIT1(); __syncthreads();
    mma_span16(sb, sb + N_ALO, sA, sA + N_BPL, NSTR, 272, 8, acc, wm, wn, lane);
    __syncthreads();
    load_Bw_cp(sA, N_BPL, p0bHi, p0bLo, 128, 128, 128, 0, 272, tid, 512); CP_COMMIT();
    CP_WAIT1(); __syncthreads();
    mma_span16(sb + 256, sb + N_ALO + 256, sB, sB + N_BPL, NSTR, 272, 8, acc, wm, wn, lane);
    __syncthreads();
    epi_repack16(smem, NSTR, N_ALO, acc, m0, wm, npb, nf1, nullptr, wn, lane);
    load_Bw_cp(sB, N_BPL, p1Hi, p1Lo, 128, 128, 128, 0, 272, tid, 512); CP_COMMIT();

    CP_WAIT1(); __syncthreads();
    mma_span16(sb, sb + N_ALO, sA, sA + N_BPL, NSTR, 272, 8, acc, wm, wn, lane);
    __syncthreads();
    epi_repack16(smem, NSTR, N_ALO, acc, m0, wm, ppb0, pc, nullptr, wn, lane);

    CP_WAIT0(); __syncthreads();
    mma_span16(sb, sb + N_ALO, sB, sB + N_BPL, NSTR, 272, 8, acc, wm, wn, lane);
    __syncthreads();
    float* stage = (float*)(smem + N_B0);
    #pragma unroll
    for (int st = 0; st < 2; st++) {
        int n = wn * 16 + st * 8 + ((lane & 3) << 1);
        float b0 = __ldg(ppb1 + n), b1 = __ldg(ppb1 + n + 1);
        int r0 = wm * 16 + (lane >> 2);
        #pragma unroll
        for (int h = 0; h < 2; h++) {
            int r = r0 + h * 8;
            stage[r * 132 + n]     = fmaxf(acc[st][h * 2 + 0] + b0, 0.f);
            stage[r * 132 + n + 1] = fmaxf(acc[st][h * 2 + 1] + b1, 0.f);
        }
    }
    __syncthreads();
    if (tid < 96) {
        int m = tid / 3, n = tid - (tid / 3) * 3;
        const float* aa = stage + m * 132;
        float s = __ldg(ppb2 + n);
        #pragma unroll 16
        for (int k = 0; k < 128; k++) s += aa[k] * __ldg(ppW2 + k * 3 + n);
        out[(size_t)(m0 + m) * 3 + n] = s;
    }
}

// ---------------- launch ----------------
extern "C" void kernel_launch(void* const* d_in, const int* in_sizes, int n_in,
                              void* d_out, int out_size)
{
    const float* x    = (const float*)d_in[0];
    const float* Rr   = (const float*)d_in[1];
    const float* Rs   = (const float*)d_in[2];
    const float* neW0 = (const float*)d_in[4];  const float* neb0 = (const float*)d_in[5];
    const float* neW1 = (const float*)d_in[6];  const float* neb1 = (const float*)d_in[7];
    const float* neW2 = (const float*)d_in[8];  const float* neb2 = (const float*)d_in[9];
    const float* eeW0 = (const float*)d_in[10]; const float* eeb0 = (const float*)d_in[11];
    const float* eeW1 = (const float*)d_in[12]; const float* eeb1 = (const float*)d_in[13];
    const float* eeW2 = (const float*)d_in[14]; const float* eeb2 = (const float*)d_in[15];
    const float* npW  = (const float*)d_in[16]; const float* npb  = (const float*)d_in[17];
    const float* epW  = (const float*)d_in[18]; const float* epb  = (const float*)d_in[19];
    const float* ppW0 = (const float*)d_in[20]; const float* ppb0 = (const float*)d_in[21];
    const float* ppW1 = (const float*)d_in[22]; const float* ppb1 = (const float*)d_in[23];
    const float* ppW2 = (const float*)d_in[24]; const float* ppb2 = (const float*)d_in[25];
    float* out = (float*)d_out;

    uint32_t* arena; cudaGetSymbolAddress((void**)&arena, g_arena);
    int* recv; cudaGetSymbolAddress((void**)&recv, g_recv);
    int* send; cudaGetSymbolAddress((void**)&send, g_send);
    __nv_bfloat16* whi; cudaGetSymbolAddress((void**)&whi, g_whi);
    __nv_bfloat16* wlo; cudaGetSymbolAddress((void**)&wlo, g_wlo);

    uint32_t* neb    = arena + OFF_NEB;
    float*    nef    = (float*)(arena + OFF_NEF);
    float*    nf1f   = (float*)(arena + OFF_NF1F);
    float*    pc     = (float*)(arena + OFF_PC);
    float*    agg0   = (float*)(arena + OFF_AGG0);
    float*    agg1   = (float*)(arena + OFF_AGG1);
    float*    prs    = (float*)(arena + OFF_PRS);
    float*    prpspA = (float*)(arena + OFF_PRPSPA);
    float*    prpspB = (float*)(arena + OFF_PRPSPB);
    float*    ec     = (float*)(arena + OFF_EC);

    const int WO[12] = {0,8192,24576,40960,57344,73728,90112,106496,139264,172032,188416,204800};

    static bool s_init = false;
    static cudaStream_t s1, s2;
    static cudaEvent_t evStart, evPrep, evS1, evNE;
    if (!s_init) {
        cudaStreamCreateWithFlags(&s1, cudaStreamNonBlocking);
        cudaStreamCreateWithFlags(&s2, cudaStreamNonBlocking);
        cudaEventCreateWithFlags(&evStart, cudaEventDisableTiming);
        cudaEventCreateWithFlags(&evPrep,  cudaEventDisableTiming);
        cudaEventCreateWithFlags(&evS1,    cudaEventDisableTiming);
        cudaEventCreateWithFlags(&evNE,    cudaEventDisableTiming);
        cudaFuncSetAttribute(node_mega,       cudaFuncAttributeMaxDynamicSharedMemorySize, NM_SMEM);
        cudaFuncSetAttribute(edge_mega,       cudaFuncAttributeMaxDynamicSharedMemorySize, EM_SMEM);
        cudaFuncSetAttribute(np_prpsp_kernel, cudaFuncAttributeMaxDynamicSharedMemorySize, NT_SMEM);
        cudaFuncSetAttribute(tail_kernel,     cudaFuncAttributeMaxDynamicSharedMemorySize, NT_SMEM);
        s_init = true;
    }

    // fork at root: extract + agg zeros on s1
    cudaEventRecord(evStart, 0);
    cudaStreamWaitEvent(s1, evStart, 0);
    extract_idx2_kernel<<<2 * BE / 8, 256, 0, s1>>>(Rr, Rs, recv, send);
    cudaMemsetAsync(agg0, 0, (size_t)2 * BN * 128 * sizeof(float), s1);
    cudaEventRecord(evS1, s1);

    // origin: weight prep
    PArg pa;
    pa.W[0] = neW0; pa.W[1] = neW1; pa.W[2] = neW2;
    pa.W[3] = eeW0; pa.W[4] = eeW1; pa.W[5] = eeW2;
    pa.W[6] = epW;  pa.W[7] = epW;  pa.W[8] = npW;
    pa.W[9] = ppW0; pa.W[10] = ppW0; pa.W[11] = ppW1;
    prep_weights<<<dim3(12, 8), 256>>>(pa, whi, wlo);
    cudaEventRecord(evPrep, 0);
    cudaStreamWaitEvent(s2, evPrep, 0);

    // s2: fused node mega-chain (PrPs + encoder + projections + pc)
    {
        NodeArg na;
        na.x = x;
        na.eerh = whi + WO[3];        na.eerl = wlo + WO[3];
        na.eesh = whi + WO[3] + 8192; na.eesl = wlo + WO[3] + 8192;
        na.w0h = whi + WO[0]; na.w0l = wlo + WO[0];
        na.w1h = whi + WO[1]; na.w1l = wlo + WO[1];
        na.w2h = whi + WO[2]; na.w2l = wlo + WO[2];
        na.eprh = whi + WO[7];          na.eprl = wlo + WO[7];
        na.epsh = whi + WO[7] + 16384;  na.epsl = wlo + WO[7] + 16384;
        na.pqh = whi + WO[9];  na.pql = wlo + WO[9];
        na.b0 = neb0; na.b1 = neb1; na.b2 = neb2;
        na.neb = neb; na.nef = nef; na.prs = prs; na.prpsp = prpspA; na.pc = pc;
        node_mega<<<BN / 32, 256, NM_SMEM, s2>>>(na);
    }
    cudaEventRecord(evNE, s2);

    // join: indices + node outputs
    cudaStreamWaitEvent(0, evS1, 0);
    cudaStreamWaitEvent(0, evNE, 0);

    // fused edge chain + step-0 scatter (128-row tiles)
    {
        EdgeArg ea;
        ea.prs = prs; ea.recv = recv; ea.send = send; ea.eeb0 = eeb0;
        ea.w1h = whi + WO[4]; ea.w1l = wlo + WO[4];
        ea.w2h = whi + WO[5]; ea.w2l = wlo + WO[5];
        ea.weh = whi + WO[6]; ea.wel = wlo + WO[6];
        ea.b1 = eeb1; ea.b2 = eeb2;
        ea.prpsp = prpspA; ea.epb = epb;
        ea.ec = ec; ea.agg = agg0;
        edge_mega<<<BE / 128, 512, EM_SMEM>>>(ea);
    }

    // fused np(step0) + prpsp(step1), pipelined weights
    np_prpsp_kernel<<<BN / 32, 512, NT_SMEM>>>(neb, agg0, nef,
        whi + WO[8], wlo + WO[8], npb, whi + WO[7], wlo + WO[7],
        nf1f, prpspB);

    // step-1 scatter
    fused_scatter_kernel<<<BE * 128 / 256, 256>>>(ec, prpspB, recv, send, epb, agg1);

    // fused np(step1) + predictor + output, pipelined weights
    tail_kernel<<<BN / 32, 512, NT_SMEM>>>(neb, agg1, nf1f,
        whi + WO[8], wlo + WO[8], npb, pc,
        whi + WO[10], wlo + WO[10], ppb0,
        whi + WO[11], wlo + WO[11], ppb1,
        ppW2, ppb2, out);
}

// round 14
// speedup vs baseline: 3.3200x; 1.0489x over previous
#include <cuda_runtime.h>
#include <cuda_bf16.h>
#include <cstdint>

// ---------------- problem dims ----------------
#define Nn 1024
#define Ee 8192
#define BN 4096    // B*N
#define BE 32768   // B*E

// ---------------- device scratch ----------------
#define OFF_NEB    ((size_t)0)                       // node_enc bfp
#define OFF_NEF    (OFF_NEB + (size_t)BN*128)        // node_enc f32
#define OFF_NF1F   (OFF_NEF + (size_t)BN*128)        // nf1 f32
#define OFF_PC     (OFF_NF1F + (size_t)BN*128)       // neb@pp0a f32
#define OFF_AGG0   (OFF_PC + (size_t)BN*128)
#define OFF_AGG1   (OFF_AGG0 + (size_t)BN*128)       // adjacent to agg0
#define OFF_PRS    (OFF_AGG1 + (size_t)BN*128)       // [BN,256] f32 (x@Wr | x@Ws)
#define OFF_PRPSPA (OFF_PRS + (size_t)BN*256)        // [BN,256] f32 step0
#define OFF_PRPSPB (OFF_PRPSPA + (size_t)BN*256)     // [BN,256] f32 step1
#define OFF_EC     (OFF_PRPSPB + (size_t)BN*256)     // [BE,128] f32
#define ARENA_U32  (OFF_EC + (size_t)BE*128)

__device__ uint32_t g_arena[ARENA_U32];
__device__ int g_recv[BE];
__device__ int g_send[BE];
__device__ float g_zero[256];

// split/transposed weights [n][kpad] bf16, 12 matrices
#define WT_TOTAL 221184
__device__ __nv_bfloat16 g_whi[WT_TOTAL];
__device__ __nv_bfloat16 g_wlo[WT_TOTAL];

// ---------------- helpers ----------------
__device__ __forceinline__ uint32_t smem_u32(const void* p) {
    uint32_t a;
    asm("{ .reg .u64 t; cvta.to.shared.u64 t, %1; cvt.u32.u64 %0, t; }" : "=r"(a) : "l"(p));
    return a;
}

#define LDMX4(r, ad) \
    asm volatile("ldmatrix.sync.aligned.m8n8.x4.shared.b16 {%0,%1,%2,%3}, [%4];" \
        : "=r"((r)[0]), "=r"((r)[1]), "=r"((r)[2]), "=r"((r)[3]) : "r"(ad))

#define MMA16816(d, av, bv) \
    asm volatile("mma.sync.aligned.m16n8k16.row.col.f32.bf16.bf16.f32 " \
        "{%0,%1,%2,%3},{%4,%5,%6,%7},{%8,%9},{%0,%1,%2,%3};" \
        : "+f"((d)[0]), "+f"((d)[1]), "+f"((d)[2]), "+f"((d)[3]) \
        : "r"((av)[0]), "r"((av)[1]), "r"((av)[2]), "r"((av)[3]), \
          "r"((bv)[0]), "r"((bv)[1]))

#define CP_ASYNC16(sa, gp) \
    asm volatile("cp.async.cg.shared.global [%0], [%1], 16;" :: "r"(sa), "l"(gp))
#define CP_COMMIT()  asm volatile("cp.async.commit_group;" ::: "memory")
#define CP_WAIT1()   asm volatile("cp.async.wait_group 1;" ::: "memory")
#define CP_WAIT0()   asm volatile("cp.async.wait_group 0;" ::: "memory")

#define REDV2(ptr, v0, v1) \
    asm volatile("red.global.add.v2.f32 [%0], {%1, %2};" \
        :: "l"(ptr), "f"(v0), "f"(v1) : "memory")
#define REDV4(ptr, v0, v1, v2, v3) \
    asm volatile("red.global.add.v4.f32 [%0], {%1, %2, %3, %4};" \
        :: "l"(ptr), "f"(v0), "f"(v1), "f"(v2), "f"(v3) : "memory")

__device__ __forceinline__ uint32_t packbfp(float v) {
    __nv_bfloat16 h = __float2bfloat16(v);
    float hf = __bfloat162float(h);
    __nv_bfloat16 l = __float2bfloat16(v - hf);
    return (uint32_t)__bfloat16_as_ushort(h) | ((uint32_t)__bfloat16_as_ushort(l) << 16);
}

// ---- 32-col-warp 3-pass MMA ----
__device__ __forceinline__ void mma_span1(
    uint32_t aHi, uint32_t aLo, uint32_t bHi, uint32_t bLo,
    int astr, int bstr, int nk, float (*acc)[4], int tile, int wn, int lane)
{
    for (int ks = 0; ks < nk; ks++) {
        uint32_t bh[8], bl[8];
        #pragma unroll
        for (int np = 0; np < 2; np++) {
            int n = wn * 32 + np * 16 + ((lane >> 4) << 3) + (lane & 7);
            int koff = ((lane >> 3) & 1) << 3;
            uint32_t ad = bHi + n * bstr + (ks * 16 + koff) * 2;
            LDMX4(&bh[np * 4], ad);
            LDMX4(&bl[np * 4], ad + (bLo - bHi));
        }
        int r = tile * 16 + (lane & 15);
        int koff = (lane >> 4) << 3;
        uint32_t ad = aHi + r * astr + (ks * 16 + koff) * 2;
        uint32_t ah[4], al[4];
        LDMX4(ah, ad);
        LDMX4(al, ad + (aLo - aHi));
        #pragma unroll
        for (int st = 0; st < 4; st++) {
            MMA16816(acc[st], ah, &bh[st * 2]);
            MMA16816(acc[st], ah, &bl[st * 2]);
            MMA16816(acc[st], al, &bh[st * 2]);
        }
    }
}

// ---- 32-col-warp, 2 m-tiles per warp (edge_mega) ----
__device__ __forceinline__ void mma_span_mt2(
    uint32_t aHi, uint32_t aLo, uint32_t bHi, uint32_t bLo,
    int astr, int bstr, int nk, float (*acc0)[4], float (*acc1)[4],
    int tile0, int wn, int lane)
{
    for (int ks = 0; ks < nk; ks++) {
        uint32_t bh[8], bl[8];
        #pragma unroll
        for (int np = 0; np < 2; np++) {
            int n = wn * 32 + np * 16 + ((lane >> 4) << 3) + (lane & 7);
            int koff = ((lane >> 3) & 1) << 3;
            uint32_t ad = bHi + n * bstr + (ks * 16 + koff) * 2;
            LDMX4(&bh[np * 4], ad);
            LDMX4(&bl[np * 4], ad + (bLo - bHi));
        }
        int koff = (lane >> 4) << 3;
        uint32_t ah0[4], al0[4], ah1[4], al1[4];
        {
            int r = tile0 * 16 + (lane & 15);
            uint32_t ad = aHi + r * astr + (ks * 16 + koff) * 2;
            LDMX4(ah0, ad);
            LDMX4(al0, ad + (aLo - aHi));
        }
        {
            int r = (tile0 + 1) * 16 + (lane & 15);
            uint32_t ad = aHi + r * astr + (ks * 16 + koff) * 2;
            LDMX4(ah1, ad);
            LDMX4(al1, ad + (aLo - aHi));
        }
        #pragma unroll
        for (int st = 0; st < 4; st++) {
            MMA16816(acc0[st], ah0, &bh[st * 2]);
            MMA16816(acc1[st], ah1, &bh[st * 2]);
            MMA16816(acc0[st], ah0, &bl[st * 2]);
            MMA16816(acc1[st], ah1, &bl[st * 2]);
            MMA16816(acc0[st], al0, &bh[st * 2]);
            MMA16816(acc1[st], al1, &bh[st * 2]);
        }
    }
}

// ---- 16-col-warp 3-pass MMA (np/tail kernels): wn in 0..7 ----
__device__ __forceinline__ void mma_span16(
    uint32_t aHi, uint32_t aLo, uint32_t bHi, uint32_t bLo,
    int astr, int bstr, int nk, float (*acc)[4], int tile, int wn, int lane)
{
    for (int ks = 0; ks < nk; ks++) {
        uint32_t bh[4], bl[4];
        int n = wn * 16 + ((lane >> 4) << 3) + (lane & 7);
        int koff = ((lane >> 3) & 1) << 3;
        uint32_t ad = bHi + n * bstr + (ks * 16 + koff) * 2;
        LDMX4(bh, ad);
        LDMX4(bl, ad + (bLo - bHi));
        int r = tile * 16 + (lane & 15);
        int koff2 = (lane >> 4) << 3;
        uint32_t ad2 = aHi + r * astr + (ks * 16 + koff2) * 2;
        uint32_t ah[4], al[4];
        LDMX4(ah, ad2);
        LDMX4(al, ad2 + (aLo - aHi));
        #pragma unroll
        for (int st = 0; st < 2; st++) {
            MMA16816(acc[st], ah, &bh[st * 2]);
            MMA16816(acc[st], ah, &bl[st * 2]);
            MMA16816(acc[st], al, &bh[st * 2]);
        }
    }
}

// async weight load with K-window (cp.async, caller commits/waits)
__device__ __forceinline__ void load_Bw_cp(uint32_t sbase, int plane,
    const __nv_bfloat16* Bhi, const __nv_bfloat16* Blo,
    int nrows, int kwin, int fullK, int k0, int bstr, int tid, int nth)
{
    int kg = kwin >> 3;
    int per = nrows * kg;
    for (int item = tid; item < per; item += nth) {
        int n = item / kg, g = item - n * kg;
        size_t goff = (size_t)n * fullK + k0 + (g << 3);
        uint32_t so = sbase + n * bstr + (g << 4);
        CP_ASYNC16(so, Bhi + goff);
        CP_ASYNC16(so + plane, Blo + goff);
    }
}

// 32-col-warp epilogue: relu(acc+bias(+resid)) -> repack A planes (+outf/outb)
__device__ __forceinline__ void epi_repack2(char* smem, int astr, int aplane,
    float (*acc)[4], int m0, int tile,
    const float* bias, const float* resid, float* outf, uint32_t* outb,
    int wn, int lane)
{
    #pragma unroll
    for (int st = 0; st < 4; st++) {
        int n = wn * 32 + st * 8 + ((lane & 3) << 1);
        float b0 = __ldg(bias + n), b1 = __ldg(bias + n + 1);
        int r0 = tile * 16 + (lane >> 2);
        #pragma unroll
        for (int h = 0; h < 2; h++) {
            int r = r0 + h * 8;
            float s0 = acc[st][h * 2 + 0] + b0;
            float s1 = acc[st][h * 2 + 1] + b1;
            if (resid) {
                float2 rv = *(const float2*)(resid + (((size_t)(m0 + r)) << 7) + n);
                s0 += rv.x; s1 += rv.y;
            }
            s0 = fmaxf(s0, 0.f); s1 = fmaxf(s1, 0.f);
            if (outf) *(float2*)(outf + (((size_t)(m0 + r)) << 7) + n) = make_float2(s0, s1);
            uint32_t p0 = packbfp(s0), p1 = packbfp(s1);
            if (outb) *(uint2*)(outb + (((size_t)(m0 + r)) << 7) + n) = make_uint2(p0, p1);
            int off = r * astr + n * 2;
            *(uint32_t*)(smem + off) = (p0 & 0xffffu) | (p1 << 16);
            *(uint32_t*)(smem + aplane + off) = (p0 >> 16) | (p1 & 0xffff0000u);
            acc[st][h * 2 + 0] = 0.f;
            acc[st][h * 2 + 1] = 0.f;
        }
    }
}

// 16-col-warp epilogue
__device__ __forceinline__ void epi_repack16(char* smem, int astr, int aplane,
    float (*acc)[4], int m0, int tile,
    const float* bias, const float* resid, float* outf,
    int wn, int lane)
{
    #pragma unroll
    for (int st = 0; st < 2; st++) {
        int n = wn * 16 + st * 8 + ((lane & 3) << 1);
        float b0 = __ldg(bias + n), b1 = __ldg(bias + n + 1);
        int r0 = tile * 16 + (lane >> 2);
        #pragma unroll
        for (int h = 0; h < 2; h++) {
            int r = r0 + h * 8;
            float s0 = acc[st][h * 2 + 0] + b0;
            float s1 = acc[st][h * 2 + 1] + b1;
            if (resid) {
                float2 rv = *(const float2*)(resid + (((size_t)(m0 + r)) << 7) + n);
                s0 += rv.x; s1 += rv.y;
            }
            s0 = fmaxf(s0, 0.f); s1 = fmaxf(s1, 0.f);
            if (outf) *(float2*)(outf + (((size_t)(m0 + r)) << 7) + n) = make_float2(s0, s1);
            uint32_t p0 = packbfp(s0), p1 = packbfp(s1);
            int off = r * astr + n * 2;
            *(uint32_t*)(smem + off) = (p0 & 0xffffu) | (p1 << 16);
            *(uint32_t*)(smem + aplane + off) = (p0 >> 16) | (p1 & 0xffff0000u);
            acc[st][h * 2 + 0] = 0.f;
            acc[st][h * 2 + 1] = 0.f;
        }
    }
}

// write acc f32 (32-col warps)
__device__ __forceinline__ void write_accf(float (*acc)[4], int m0, int tile,
    int wn, int lane, float* out, int nbase, int ldo)
{
    #pragma unroll
    for (int st = 0; st < 4; st++) {
        int n = nbase + wn * 32 + st * 8 + ((lane & 3) << 1);
        int r0 = tile * 16 + (lane >> 2);
        #pragma unroll
        for (int h = 0; h < 2; h++) {
            int m = m0 + r0 + h * 8;
            *(float2*)(out + (size_t)m * ldo + n) =
                make_float2(acc[st][h * 2 + 0], acc[st][h * 2 + 1]);
            acc[st][h * 2 + 0] = 0.f;
            acc[st][h * 2 + 1] = 0.f;
        }
    }
}

// write acc f32 (16-col warps)
__device__ __forceinline__ void write_accf16(float (*acc)[4], int m0, int tile,
    int wn, int lane, float* out, int nbase, int ldo)
{
    #pragma unroll
    for (int st = 0; st < 2; st++) {
        int n = nbase + wn * 16 + st * 8 + ((lane & 3) << 1);
        int r0 = tile * 16 + (lane >> 2);
        #pragma unroll
        for (int h = 0; h < 2; h++) {
            int m = m0 + r0 + h * 8;
            *(float2*)(out + (size_t)m * ldo + n) =
                make_float2(acc[st][h * 2 + 0], acc[st][h * 2 + 1]);
            acc[st][h * 2 + 0] = 0.f;
            acc[st][h * 2 + 1] = 0.f;
        }
    }
}

// ---------------- aux kernels ----------------
__global__ void extract_idx2_kernel(const float* __restrict__ Rr,
                                    const float* __restrict__ Rs,
                                    int* __restrict__ recv, int* __restrict__ send)
{
    int row = blockIdx.x * 8 + (threadIdx.x >> 5);
    int lane = threadIdx.x & 31;
    const float* R = (row < BE) ? Rr : Rs;
    int r = (row < BE) ? row : row - BE;
    const float4* p = (const float4*)(R + (size_t)r * Nn);
    int found = -1;
    #pragma unroll
    for (int i = 0; i < 4; i++) {
        int q = lane + i * 32;
        float4 v = p[q];
        if (v.x > 0.5f) found = q * 4 + 0;
        if (v.y > 0.5f) found = q * 4 + 1;
        if (v.z > 0.5f) found = q * 4 + 2;
        if (v.w > 0.5f) found = q * 4 + 3;
    }
    if (__ballot_sync(0xFFFFFFFFu, found >= 0) == 0u) {
        #pragma unroll
        for (int i = 4; i < 8; i++) {
            int q = lane + i * 32;
            float4 v = p[q];
            if (v.x > 0.5f) found = q * 4 + 0;
            if (v.y > 0.5f) found = q * 4 + 1;
            if (v.z > 0.5f) found = q * 4 + 2;
            if (v.w > 0.5f) found = q * 4 + 3;
        }
    }
    #pragma unroll
    for (int o = 16; o; o >>= 1) found = max(found, __shfl_xor_sync(0xFFFFFFFFu, found, o));
    if (lane == 0) {
        found = max(found, 0);
        if (row < BE) recv[r] = found; else send[r] = found;
    }
}

// matrices: 0 ne0 1 ne1 2 ne2 3 eers(R256) 4 ee1 5 ee2 6 ep_e 7 ep_rs(R256)
//           8 np(K256) 9 pp0a 10 pp0b 11 pp1
struct PArg { const float* W[12]; };
__constant__ int c_Ks[12]  = {32,128,128, 32,128,128,128,128,256,128,128,128};
__constant__ int c_Kps[12] = {64,128,128, 64,128,128,128,128,256,128,128,128};
__constant__ int c_Rs[12]  = {128,128,128,256,128,128,128,256,128,128,128,128};
__constant__ int c_r0a[12] = {0,0,0,0,0,0,0,128,0,0,128,0};
__constant__ int c_r0b[12] = {0,0,0,32,0,0,0,256,0,0,0,0};
__constant__ int c_off[12] = {0,8192,24576,40960,57344,73728,90112,106496,139264,172032,188416,204800};

__global__ void prep_weights(PArg a, __nv_bfloat16* __restrict__ hi, __nv_bfloat16* __restrict__ lo)
{
    int mid = blockIdx.x;
    int K = c_Ks[mid], Kp = c_Kps[mid], R = c_Rs[mid];
    int r0a = c_r0a[mid], r0b = c_r0b[mid];
    const float* W = a.W[mid];
    __nv_bfloat16* dh = hi + c_off[mid];
    __nv_bfloat16* dl = lo + c_off[mid];
    int total = R * Kp;
    for (int i = threadIdx.x + blockIdx.y * blockDim.x; i < total; i += blockDim.x * gridDim.y) {
        int n = i / Kp, k = i - n * Kp;
        int col = n & 127;
        int r0 = (n >> 7) ? r0b : r0a;
        float v = (k < K) ? W[(size_t)(r0 + k) * 128 + col] : 0.f;
        __nv_bfloat16 h = __float2bfloat16(v);
        dh[i] = h;
        dl[i] = __float2bfloat16(v - __bfloat162float(h));
    }
}

// step-1 scatter: 4 h-values per thread, vector reduction
__global__ void fused_scatter_kernel(const float* __restrict__ ec,
                                     const float* __restrict__ prpsp,
                                     const int* __restrict__ recv,
                                     const int* __restrict__ send,
                                     const float* __restrict__ bias,
                                     float* __restrict__ agg)
{
    int t = blockIdx.x * blockDim.x + threadIdx.x;   // BE*32
    if (t >= BE * 32) return;
    int e = t >> 5, q = t & 31;
    int h = q << 2;
    int bo = (e >> 13) << 10;
    int r = __ldg(recv + e) + bo, s = __ldg(send + e) + bo;
    float4 ev = *(const float4*)(ec + ((size_t)e << 7) + h);
    float4 pr = *(const float4*)(prpsp + (size_t)r * 256 + h);
    float4 ps = *(const float4*)(prpsp + (size_t)s * 256 + 128 + h);
    float4 bb = *(const float4*)(bias + h);
    float v0 = fmaxf(ev.x + pr.x + ps.x + bb.x, 0.f);
    float v1 = fmaxf(ev.y + pr.y + ps.y + bb.y, 0.f);
    float v2 = fmaxf(ev.z + pr.z + ps.z + bb.z, 0.f);
    float v3 = fmaxf(ev.w + pr.w + ps.w + bb.w, 0.f);
    REDV4(agg + (size_t)r * 128 + h, v0, v1, v2, v3);
}

// ---------------- node_mega: eer,ees,ne0..ne2,epr,eps,pc (256 thr, ping-pong) ----------------
#define NM_STR   272
#define NM_ALO   (32 * NM_STR)
#define NM_B0    (2 * NM_ALO)
#define NM_BPL   (128 * NM_STR)
#define NM_SLOT  (2 * NM_BPL)
#define NM_SMEM  (NM_B0 + 2 * NM_SLOT)     // 156672

struct NodeArg {
    const float* x;
    const __nv_bfloat16 *eerh,*eerl,*eesh,*eesl;
    const __nv_bfloat16 *w0h,*w0l,*w1h,*w1l,*w2h,*w2l,*eprh,*eprl,*epsh,*epsl,*pqh,*pql;
    const float *b0,*b1,*b2;
    uint32_t* neb; float* nef; float* prs; float* prpsp; float* pc;
};

__global__ __launch_bounds__(256) void node_mega(NodeArg a)
{
    extern __shared__ char smem[];
    const uint32_t sb = smem_u32(smem);
    const int tid = threadIdx.x;
    const int wid = tid >> 5, lane = tid & 31;
    const int wm = wid & 1, wn = wid >> 1;
    const int m0 = blockIdx.x * 32;

    const uint32_t sA = sb + NM_B0;
    const uint32_t sB = sb + NM_B0 + NM_SLOT;

    float acc[4][4];
    #pragma unroll
    for (int st = 0; st < 4; st++)
        #pragma unroll
        for (int r = 0; r < 4; r++) acc[st][r] = 0.f;

    load_Bw_cp(sA, NM_BPL, a.eerh, a.eerl, 128, 64, 64, 0, NM_STR, tid, 256); CP_COMMIT();
    load_Bw_cp(sB, NM_BPL, a.eesh, a.eesl, 128, 64, 64, 0, NM_STR, tid, 256); CP_COMMIT();

    #pragma unroll
    for (int it = 0; it < 2; it++) {
        int item = tid + (it << 8);
        int r = item >> 4, g = item & 15;
        int kc = g << 2;
        uint32_t p0 = 0, p1 = 0, p2 = 0, p3 = 0;
        if (kc < 32) {
            float4 v = *(const float4*)(a.x + (size_t)(m0 + r) * 32 + kc);
            p0 = packbfp(v.x); p1 = packbfp(v.y); p2 = packbfp(v.z); p3 = packbfp(v.w);
        }
        uint32_t hi01 = (p0 & 0xffffu) | (p1 << 16);
        uint32_t hi23 = (p2 & 0xffffu) | (p3 << 16);
        uint32_t lo01 = (p0 >> 16) | (p1 & 0xffff0000u);
        uint32_t lo23 = (p2 >> 16) | (p3 & 0xffff0000u);
        int off = r * NM_STR + g * 8;
        *(uint2*)(smem + off) = make_uint2(hi01, hi23);
        *(uint2*)(smem + NM_ALO + off) = make_uint2(lo01, lo23);
    }

    // P0: eer -> prs[:,0:128]
    CP_WAIT1(); __syncthreads();
    mma_span1(sb, sb + NM_ALO, sA, sA + NM_BPL, NM_STR, NM_STR, 4, acc, wm, wn, lane);
    __syncthreads();
    write_accf(acc, m0, wm, wn, lane, a.prs, 0, 256);
    load_Bw_cp(sA, NM_BPL, a.w0h, a.w0l, 128, 64, 64, 0, NM_STR, tid, 256); CP_COMMIT();

    // P1: ees -> prs[:,128:256]
    CP_WAIT1(); __syncthreads();
    mma_span1(sb, sb + NM_ALO, sB, sB + NM_BPL, NM_STR, NM_STR, 4, acc, wm, wn, lane);
    __syncthreads();
    write_accf(acc, m0, wm, wn, lane, a.prs, 128, 256);
    load_Bw_cp(sB, NM_BPL, a.w1h, a.w1l, 128, 128, 128, 0, NM_STR, tid, 256); CP_COMMIT();

    // P2: ne0
    CP_WAIT1(); __syncthreads();
    mma_span1(sb, sb + NM_ALO, sA, sA + NM_BPL, NM_STR, NM_STR, 4, acc, wm, wn, lane);
    __syncthreads();
    epi_repack2(smem, NM_STR, NM_ALO, acc, m0, wm, a.b0, nullptr, nullptr, nullptr, wn, lane);
    load_Bw_cp(sA, NM_BPL, a.w2h, a.w2l, 128, 128, 128, 0, NM_STR, tid, 256); CP_COMMIT();

    // P3: ne1
    CP_WAIT1(); __syncthreads();
    mma_span1(sb, sb + NM_ALO, sB, sB + NM_BPL, NM_STR, NM_STR, 8, acc, wm, wn, lane);
    __syncthreads();
    epi_repack2(smem, NM_STR, NM_ALO, acc, m0, wm, a.b1, nullptr, nullptr, nullptr, wn, lane);
    load_Bw_cp(sB, NM_BPL, a.eprh, a.eprl, 128, 128, 128, 0, NM_STR, tid, 256); CP_COMMIT();

    // P4: ne2 -> neb/nef
    CP_WAIT1(); __syncthreads();
    mma_span1(sb, sb + NM_ALO, sA, sA + NM_BPL, NM_STR, NM_STR, 8, acc, wm, wn, lane);
    __syncthreads();
    epi_repack2(smem, NM_STR, NM_ALO, acc, m0, wm, a.b2, nullptr, a.nef, a.neb, wn, lane);
    load_Bw_cp(sA, NM_BPL, a.epsh, a.epsl, 128, 128, 128, 0, NM_STR, tid, 256); CP_COMMIT();

    // P5: epr -> prpspA[:,0:128]
    CP_WAIT1(); __syncthreads();
    mma_span1(sb, sb + NM_ALO, sB, sB + NM_BPL, NM_STR, NM_STR, 8, acc, wm, wn, lane);
    __syncthreads();
    write_accf(acc, m0, wm, wn, lane, a.prpsp, 0, 256);
    load_Bw_cp(sB, NM_BPL, a.pqh, a.pql, 128, 128, 128, 0, NM_STR, tid, 256); CP_COMMIT();

    // P6: eps -> prpspA[:,128:256]
    CP_WAIT1(); __syncthreads();
    mma_span1(sb, sb + NM_ALO, sA, sA + NM_BPL, NM_STR, NM_STR, 8, acc, wm, wn, lane);
    __syncthreads();
    write_accf(acc, m0, wm, wn, lane, a.prpsp, 128, 256);

    // P7: pc
    CP_WAIT0(); __syncthreads();
    mma_span1(sb, sb + NM_ALO, sB, sB + NM_BPL, NM_STR, NM_STR, 8, acc, wm, wn, lane);
    __syncthreads();
    write_accf(acc, m0, wm, wn, lane, a.pc, 0, 128);
}

// ---------------- edge_mega: 128-row tiles, 512 thr, 4m x 4n warps ----------------
#define EM_STR   272
#define EM_APL   (128 * EM_STR)
#define EM_B0    (2 * EM_APL)
#define EM_BPL   (128 * EM_STR)
#define EM_SLOT  (2 * EM_BPL)
#define EM_SMEM  (EM_B0 + 2 * EM_SLOT)     // 208896

struct EdgeArg {
    const float* prs; const int* recv; const int* send; const float* eeb0;
    const __nv_bfloat16 *w1h,*w1l,*w2h,*w2l,*weh,*wel;
    const float *b1,*b2;
    const float* prpsp; const float* epb;
    float* ec; float* agg;
};

__global__ __launch_bounds__(512, 1) void edge_mega(EdgeArg a)
{
    extern __shared__ char smem[];
    const uint32_t sb = smem_u32(smem);
    const int tid = threadIdx.x;
    const int wid = tid >> 5, lane = tid & 31;
    const int wm = wid & 3, wn = wid >> 2;
    const int m0 = blockIdx.x * 128;

    const uint32_t sA = sb + EM_B0;
    const uint32_t sB = sb + EM_B0 + EM_SLOT;

    float acc[2][4][4];
    #pragma unroll
    for (int mt = 0; mt < 2; mt++)
        #pragma unroll
        for (int st = 0; st < 4; st++)
            #pragma unroll
            for (int r = 0; r < 4; r++) acc[mt][st][r] = 0.f;

    load_Bw_cp(sA, EM_BPL, a.w1h, a.w1l, 128, 128, 128, 0, EM_STR, tid, 512); CP_COMMIT();
    load_Bw_cp(sB, EM_BPL, a.w2h, a.w2l, 128, 128, 128, 0, EM_STR, tid, 512); CP_COMMIT();

    // A <- edge layer0 on the fly
    #pragma unroll
    for (int it = 0; it < 8; it++) {
        int item = tid + (it << 9);
        int r = item >> 5, g = item & 31;
        int kc = g << 2;
        int m = m0 + r;
        int bo = (m >> 13) << 10;
        int rr = __ldg(a.recv + m) + bo, ss = __ldg(a.send + m) + bo;
        float4 pr = *(const float4*)(a.prs + (size_t)rr * 256 + kc);
        float4 ps = *(const float4*)(a.prs + (size_t)ss * 256 + 128 + kc);
        float4 bb = *(const float4*)(a.eeb0 + kc);
        uint32_t p0 = packbfp(fmaxf(pr.x + ps.x + bb.x, 0.f));
        uint32_t p1 = packbfp(fmaxf(pr.y + ps.y + bb.y, 0.f));
        uint32_t p2 = packbfp(fmaxf(pr.z + ps.z + bb.z, 0.f));
        uint32_t p3 = packbfp(fmaxf(pr.w + ps.w + bb.w, 0.f));
        uint32_t hi01 = (p0 & 0xffffu) | (p1 << 16);
        uint32_t hi23 = (p2 & 0xffffu) | (p3 << 16);
        uint32_t lo01 = (p0 >> 16) | (p1 & 0xffff0000u);
        uint32_t lo23 = (p2 >> 16) | (p3 & 0xffff0000u);
        int off = r * EM_STR + g * 8;
        *(uint2*)(smem + off) = make_uint2(hi01, hi23);
        *(uint2*)(smem + EM_APL + off) = make_uint2(lo01, lo23);
    }

    // phase 1: ee1 (sA)
    CP_WAIT1(); __syncthreads();
    mma_span_mt2(sb, sb + EM_APL, sA, sA + EM_BPL, EM_STR, EM_STR, 8,
                 acc[0], acc[1], wm * 2, wn, lane);
    __syncthreads();
    #pragma unroll
    for (int mt = 0; mt < 2; mt++)
        epi_repack2(smem, EM_STR, EM_APL, acc[mt], m0, wm * 2 + mt, a.b1,
                    nullptr, nullptr, nullptr, wn, lane);
    load_Bw_cp(sA, EM_BPL, a.weh, a.wel, 128, 128, 128, 0, EM_STR, tid, 512); CP_COMMIT();

    // phase 2: ee2 (sB)
    CP_WAIT1(); __syncthreads();
    mma_span_mt2(sb, sb + EM_APL, sB, sB + EM_BPL, EM_STR, EM_STR, 8,
                 acc[0], acc[1], wm * 2, wn, lane);
    __syncthreads();
    #pragma unroll
    for (int mt = 0; mt < 2; mt++)
        epi_repack2(smem, EM_STR, EM_APL, acc[mt], m0, wm * 2 + mt, a.b2,
                    nullptr, nullptr, nullptr, wn, lane);

    // phase 3: ec (sA)
    CP_WAIT0(); __syncthreads();
    mma_span_mt2(sb, sb + EM_APL, sA, sA + EM_BPL, EM_STR, EM_STR, 8,
                 acc[0], acc[1], wm * 2, wn, lane);

    // epilogue: write ec + fused step-0 scatter (vector reductions)
    #pragma unroll
    for (int mt = 0; mt < 2; mt++) {
        int row0 = m0 + (wm * 2 + mt) * 16 + (lane >> 2);
        #pragma unroll
        for (int st = 0; st < 4; st++) {
            int n = wn * 32 + st * 8 + ((lane & 3) << 1);
            float e0b = __ldg(a.epb + n), e1b = __ldg(a.epb + n + 1);
            #pragma unroll
            for (int h = 0; h < 2; h++) {
                int m = row0 + h * 8;
                float e0 = acc[mt][st][h * 2 + 0];
                float e1 = acc[mt][st][h * 2 + 1];
                *(float2*)(a.ec + ((size_t)m << 7) + n) = make_float2(e0, e1);
                int bo = (m >> 13) << 10;
                int r_ = __ldg(a.recv + m) + bo, s_ = __ldg(a.send + m) + bo;
                float2 pr = *(const float2*)(a.prpsp + (size_t)r_ * 256 + n);
                float2 ps = *(const float2*)(a.prpsp + (size_t)s_ * 256 + 128 + n);
                float v0 = fmaxf(e0 + pr.x + ps.x + e0b, 0.f);
                float v1 = fmaxf(e1 + pr.y + ps.y + e1b, 0.f);
                REDV2(a.agg + (size_t)r_ * 128 + n, v0, v1);
            }
        }
    }
}

// ---------------- np_prpsp / tail (512 threads, ping-pong, K-chunked np) ----------------
#define NSTR   528
#define N_ALO  (32 * NSTR)
#define N_B0   (2 * N_ALO)
#define N_BPL  (128 * 272)
#define N_SLOT (2 * N_BPL)
#define NT_SMEM (N_B0 + 2 * N_SLOT)        // 173056

__device__ __forceinline__ void load_A_npagg(char* smem, int m0,
    const uint32_t* neb, const float* agg, int tid)
{
    #pragma unroll
    for (int it = 0; it < 4; it++) {
        int item = tid + (it << 9);
        int r = item >> 6, g = item & 63;
        int kc = g << 2;
        int m = m0 + r;
        uint32_t p0, p1, p2, p3;
        if (kc < 128) {
            uint4 v = *(const uint4*)(neb + ((size_t)m << 7) + kc);
            p0 = v.x; p1 = v.y; p2 = v.z; p3 = v.w;
        } else {
            float4 v = *(const float4*)(agg + ((size_t)m << 7) + (kc - 128));
            p0 = packbfp(v.x); p1 = packbfp(v.y); p2 = packbfp(v.z); p3 = packbfp(v.w);
        }
        uint32_t hi01 = (p0 & 0xffffu) | (p1 << 16);
        uint32_t hi23 = (p2 & 0xffffu) | (p3 << 16);
        uint32_t lo01 = (p0 >> 16) | (p1 & 0xffff0000u);
        uint32_t lo23 = (p2 >> 16) | (p3 & 0xffff0000u);
        int off = r * NSTR + g * 8;
        *(uint2*)(smem + off) = make_uint2(hi01, hi23);
        *(uint2*)(smem + N_ALO + off) = make_uint2(lo01, lo23);
    }
}

__global__ __launch_bounds__(512, 1) void np_prpsp_kernel(
    const uint32_t* __restrict__ neb, const float* __restrict__ agg,
    const float* __restrict__ resid,
    const __nv_bfloat16* __restrict__ npHi, const __nv_bfloat16* __restrict__ npLo,
    const float* __restrict__ npb,
    const __nv_bfloat16* __restrict__ epHi, const __nv_bfloat16* __restrict__ epLo,
    float* __restrict__ nf_out, float* __restrict__ prpsp_out)
{
    extern __shared__ char smem[];
    const uint32_t sb = smem_u32(smem);
    const int tid = threadIdx.x;
    const int wid = tid >> 5, lane = tid & 31;
    const int wm = wid & 1, wn = wid >> 1;
    const int m0 = blockIdx.x * 32;

    const uint32_t sA = sb + N_B0;
    const uint32_t sB = sb + N_B0 + N_SLOT;

    float acc[2][4];
    #pragma unroll
    for (int st = 0; st < 2; st++)
        #pragma unroll
        for (int r = 0; r < 4; r++) acc[st][r] = 0.f;

    load_Bw_cp(sA, N_BPL, npHi, npLo, 128, 128, 256, 0,   272, tid, 512); CP_COMMIT();
    load_Bw_cp(sB, N_BPL, npHi, npLo, 128, 128, 256, 128, 272, tid, 512); CP_COMMIT();

    load_A_npagg(smem, m0, neb, agg, tid);

    CP_WAIT1(); __syncthreads();
    mma_span16(sb, sb + N_ALO, sA, sA + N_BPL, NSTR, 272, 8, acc, wm, wn, lane);
    __syncthreads();
    load_Bw_cp(sA, N_BPL, epHi, epLo, 128, 128, 128, 0, 272, tid, 512); CP_COMMIT();
    CP_WAIT1(); __syncthreads();
    mma_span16(sb + 256, sb + N_ALO + 256, sB, sB + N_BPL, NSTR, 272, 8, acc, wm, wn, lane);
    __syncthreads();
    epi_repack16(smem, NSTR, N_ALO, acc, m0, wm, npb, resid, nf_out, wn, lane);
    load_Bw_cp(sB, N_BPL, epHi + 128 * 128, epLo + 128 * 128, 128, 128, 128, 0, 272, tid, 512); CP_COMMIT();

    CP_WAIT1(); __syncthreads();
    mma_span16(sb, sb + N_ALO, sA, sA + N_BPL, NSTR, 272, 8, acc, wm, wn, lane);
    __syncthreads();
    write_accf16(acc, m0, wm, wn, lane, prpsp_out, 0, 256);

    CP_WAIT0(); __syncthreads();
    mma_span16(sb, sb + N_ALO, sB, sB + N_BPL, NSTR, 272, 8, acc, wm, wn, lane);
    __syncthreads();
    write_accf16(acc, m0, wm, wn, lane, prpsp_out, 128, 256);
}

__global__ __launch_bounds__(512, 1) void tail_kernel(
    const uint32_t* __restrict__ neb, const float* __restrict__ agg1,
    const float* __restrict__ nf1,
    const __nv_bfloat16* __restrict__ npHi, const __nv_bfloat16* __restrict__ npLo,
    const float* __restrict__ npb,
    const float* __restrict__ pc,
    const __nv_bfloat16* __restrict__ p0bHi, const __nv_bfloat16* __restrict__ p0bLo,
    const float* __restrict__ ppb0,
    const __nv_bfloat16* __restrict__ p1Hi, const __nv_bfloat16* __restrict__ p1Lo,
    const float* __restrict__ ppb1,
    const float* __restrict__ ppW2, const float* __restrict__ ppb2,
    float* __restrict__ out)
{
    extern __shared__ char smem[];
    const uint32_t sb = smem_u32(smem);
    const int tid = threadIdx.x;
    const int wid = tid >> 5, lane = tid & 31;
    const int wm = wid & 1, wn = wid >> 1;
    const int m0 = blockIdx.x * 32;

    const uint32_t sA = sb + N_B0;
    const uint32_t sB = sb + N_B0 + N_SLOT;

    float acc[2][4];
    #pragma unroll
    for (int st = 0; st < 2; st++)
        #pragma unroll
        for (int r = 0; r < 4; r++) acc[st][r] = 0.f;

    load_Bw_cp(sA, N_BPL, npHi, npLo, 128, 128, 256, 0,   272, tid, 512); CP_COMMIT();
    load_Bw_cp(sB, N_BPL, npHi, npLo, 128, 128, 256, 128, 272, tid, 512); CP_COMMIT();

    load_A_npagg(smem, m0, neb, agg1, tid);

    CP_WAIT1(); __syncthreads();
    mma_span16(sb, sb + N_ALO, sA, sA + N_BPL, NSTR, 272, 8, acc, wm, wn, lane);
    __syncthreads();
    load_Bw_cp(sA, N_BPL, p0bHi, p0bLo, 128, 128, 128, 0, 272, tid, 512); CP_COMMIT();
    CP_WAIT1(); __syncthreads();
    mma_span16(sb + 256, sb + N_ALO + 256, sB, sB + N_BPL, NSTR, 272, 8, acc, wm, wn, lane);
    __syncthreads();
    epi_repack16(smem, NSTR, N_ALO, acc, m0, wm, npb, nf1, nullptr, wn, lane);
    load_Bw_cp(sB, N_BPL, p1Hi, p1Lo, 128, 128, 128, 0, 272, tid, 512); CP_COMMIT();

    CP_WAIT1(); __syncthreads();
    mma_span16(sb, sb + N_ALO, sA, sA + N_BPL, NSTR, 272, 8, acc, wm, wn, lane);
    __syncthreads();
    epi_repack16(smem, NSTR, N_ALO, acc, m0, wm, ppb0, pc, nullptr, wn, lane);

    CP_WAIT0(); __syncthreads();
    mma_span16(sb, sb + N_ALO, sB, sB + N_BPL, NSTR, 272, 8, acc, wm, wn, lane);
    __syncthreads();
    float* stage = (float*)(smem + N_B0);
    #pragma unroll
    for (int st = 0; st < 2; st++) {
        int n = wn * 16 + st * 8 + ((lane & 3) << 1);
        float b0 = __ldg(ppb1 + n), b1 = __ldg(ppb1 + n + 1);
        int r0 = wm * 16 + (lane >> 2);
        #pragma unroll
        for (int h = 0; h < 2; h++) {
            int r = r0 + h * 8;
            stage[r * 132 + n]     = fmaxf(acc[st][h * 2 + 0] + b0, 0.f);
            stage[r * 132 + n + 1] = fmaxf(acc[st][h * 2 + 1] + b1, 0.f);
        }
    }
    __syncthreads();
    if (tid < 96) {
        int m = tid / 3, n = tid - (tid / 3) * 3;
        const float* aa = stage + m * 132;
        float s = __ldg(ppb2 + n);
        #pragma unroll 16
        for (int k = 0; k < 128; k++) s += aa[k] * __ldg(ppW2 + k * 3 + n);
        out[(size_t)(m0 + m) * 3 + n] = s;
    }
}

// ---------------- launch ----------------
extern "C" void kernel_launch(void* const* d_in, const int* in_sizes, int n_in,
                              void* d_out, int out_size)
{
    const float* x    = (const float*)d_in[0];
    const float* Rr   = (const float*)d_in[1];
    const float* Rs   = (const float*)d_in[2];
    const float* neW0 = (const float*)d_in[4];  const float* neb0 = (const float*)d_in[5];
    const float* neW1 = (const float*)d_in[6];  const float* neb1 = (const float*)d_in[7];
    const float* neW2 = (const float*)d_in[8];  const float* neb2 = (const float*)d_in[9];
    const float* eeW0 = (const float*)d_in[10]; const float* eeb0 = (const float*)d_in[11];
    const float* eeW1 = (const float*)d_in[12]; const float* eeb1 = (const float*)d_in[13];
    const float* eeW2 = (const float*)d_in[14]; const float* eeb2 = (const float*)d_in[15];
    const float* npW  = (const float*)d_in[16]; const float* npb  = (const float*)d_in[17];
    const float* epW  = (const float*)d_in[18]; const float* epb  = (const float*)d_in[19];
    const float* ppW0 = (const float*)d_in[20]; const float* ppb0 = (const float*)d_in[21];
    const float* ppW1 = (const float*)d_in[22]; const float* ppb1 = (const float*)d_in[23];
    const float* ppW2 = (const float*)d_in[24]; const float* ppb2 = (const float*)d_in[25];
    float* out = (float*)d_out;

    uint32_t* arena; cudaGetSymbolAddress((void**)&arena, g_arena);
    int* recv; cudaGetSymbolAddress((void**)&recv, g_recv);
    int* send; cudaGetSymbolAddress((void**)&send, g_send);
    __nv_bfloat16* whi; cudaGetSymbolAddress((void**)&whi, g_whi);
    __nv_bfloat16* wlo; cudaGetSymbolAddress((void**)&wlo, g_wlo);

    uint32_t* neb    = arena + OFF_NEB;
    float*    nef    = (float*)(arena + OFF_NEF);
    float*    nf1f   = (float*)(arena + OFF_NF1F);
    float*    pc     = (float*)(arena + OFF_PC);
    float*    agg0   = (float*)(arena + OFF_AGG0);
    float*    agg1   = (float*)(arena + OFF_AGG1);
    float*    prs    = (float*)(arena + OFF_PRS);
    float*    prpspA = (float*)(arena + OFF_PRPSPA);
    float*    prpspB = (float*)(arena + OFF_PRPSPB);
    float*    ec     = (float*)(arena + OFF_EC);

    const int WO[12] = {0,8192,24576,40960,57344,73728,90112,106496,139264,172032,188416,204800};

    static bool s_init = false;
    static cudaStream_t s1, s2;
    static cudaEvent_t evStart, evPrep, evS1, evNE;
    if (!s_init) {
        cudaStreamCreateWithFlags(&s1, cudaStreamNonBlocking);
        cudaStreamCreateWithFlags(&s2, cudaStreamNonBlocking);
        cudaEventCreateWithFlags(&evStart, cudaEventDisableTiming);
        cudaEventCreateWithFlags(&evPrep,  cudaEventDisableTiming);
        cudaEventCreateWithFlags(&evS1,    cudaEventDisableTiming);
        cudaEventCreateWithFlags(&evNE,    cudaEventDisableTiming);
        cudaFuncSetAttribute(node_mega,       cudaFuncAttributeMaxDynamicSharedMemorySize, NM_SMEM);
        cudaFuncSetAttribute(edge_mega,       cudaFuncAttributeMaxDynamicSharedMemorySize, EM_SMEM);
        cudaFuncSetAttribute(np_prpsp_kernel, cudaFuncAttributeMaxDynamicSharedMemorySize, NT_SMEM);
        cudaFuncSetAttribute(tail_kernel,     cudaFuncAttributeMaxDynamicSharedMemorySize, NT_SMEM);
        s_init = true;
    }

    // fork at root: extract + agg zeros on s1
    cudaEventRecord(evStart, 0);
    cudaStreamWaitEvent(s1, evStart, 0);
    extract_idx2_kernel<<<2 * BE / 8, 256, 0, s1>>>(Rr, Rs, recv, send);
    cudaMemsetAsync(agg0, 0, (size_t)2 * BN * 128 * sizeof(float), s1);
    cudaEventRecord(evS1, s1);

    // origin: weight prep
    PArg pa;
    pa.W[0] = neW0; pa.W[1] = neW1; pa.W[2] = neW2;
    pa.W[3] = eeW0; pa.W[4] = eeW1; pa.W[5] = eeW2;
    pa.W[6] = epW;  pa.W[7] = epW;  pa.W[8] = npW;
    pa.W[9] = ppW0; pa.W[10] = ppW0; pa.W[11] = ppW1;
    prep_weights<<<dim3(12, 8), 256>>>(pa, whi, wlo);
    cudaEventRecord(evPrep, 0);
    cudaStreamWaitEvent(s2, evPrep, 0);

    // s2: fused node mega-chain (PrPs + encoder + projections + pc)
    {
        NodeArg na;
        na.x = x;
        na.eerh = whi + WO[3];        na.eerl = wlo + WO[3];
        na.eesh = whi + WO[3] + 8192; na.eesl = wlo + WO[3] + 8192;
        na.w0h = whi + WO[0]; na.w0l = wlo + WO[0];
        na.w1h = whi + WO[1]; na.w1l = wlo + WO[1];
        na.w2h = whi + WO[2]; na.w2l = wlo + WO[2];
        na.eprh = whi + WO[7];          na.eprl = wlo + WO[7];
        na.epsh = whi + WO[7] + 16384;  na.epsl = wlo + WO[7] + 16384;
        na.pqh = whi + WO[9];  na.pql = wlo + WO[9];
        na.b0 = neb0; na.b1 = neb1; na.b2 = neb2;
        na.neb = neb; na.nef = nef; na.prs = prs; na.prpsp = prpspA; na.pc = pc;
        node_mega<<<BN / 32, 256, NM_SMEM, s2>>>(na);
    }
    cudaEventRecord(evNE, s2);

    // join: indices + node outputs
    cudaStreamWaitEvent(0, evS1, 0);
    cudaStreamWaitEvent(0, evNE, 0);

    // fused edge chain + step-0 scatter (128-row tiles, vector red)
    {
        EdgeArg ea;
        ea.prs = prs; ea.recv = recv; ea.send = send; ea.eeb0 = eeb0;
        ea.w1h = whi + WO[4]; ea.w1l = wlo + WO[4];
        ea.w2h = whi + WO[5]; ea.w2l = wlo + WO[5];
        ea.weh = whi + WO[6]; ea.wel = wlo + WO[6];
        ea.b1 = eeb1; ea.b2 = eeb2;
        ea.prpsp = prpspA; ea.epb = epb;
        ea.ec = ec; ea.agg = agg0;
        edge_mega<<<BE / 128, 512, EM_SMEM>>>(ea);
    }

    // fused np(step0) + prpsp(step1), pipelined weights
    np_prpsp_kernel<<<BN / 32, 512, NT_SMEM>>>(neb, agg0, nef,
        whi + WO[8], wlo + WO[8], npb, whi + WO[7], wlo + WO[7],
        nf1f, prpspB);

    // step-1 scatter (vectorized, v4 reductions)
    fused_scatter_kernel<<<BE * 32 / 256, 256>>>(ec, prpspB, recv, send, epb, agg1);

    // fused np(step1) + predictor + output, pipelined weights
    tail_kernel<<<BN / 32, 512, NT_SMEM>>>(neb, agg1, nf1f,
        whi + WO[8], wlo + WO[8], npb, pc,
        whi + WO[10], wlo + WO[10], ppb0,
        whi + WO[11], wlo + WO[11], ppb1,
        ppW2, ppb2, out);
}